// round 2
// baseline (speedup 1.0000x reference)
#include <cuda_runtime.h>
#include <math.h>

#define BATCH 8
#define CDIM  256
#define NTOK  4096
#define NTOKG 256
#define MFINE 32768
#define MGLOB 2048
#define LN_EPS 1e-5f

static const size_t U_SZ  = (size_t)MFINE * CDIM;
static const size_t SG_SZ = (size_t)MGLOB * CDIM;

// big buffers
static const size_t OFF_SEQ   = 0*U_SZ;
static const size_t OFF_U     = 1*U_SZ;
static const size_t OFF_GA    = 2*U_SZ;
static const size_t OFF_GB    = 3*U_SZ;
static const size_t OFF_GO    = 4*U_SZ;
static const size_t OFF_YF    = 5*U_SZ;
static const size_t OFF_YB    = 6*U_SZ;
static const size_t OFF_Y     = 7*U_SZ;
static const size_t OFF_YGS   = 8*U_SZ;
static const size_t OFF_Z     = 9*U_SZ;
static const size_t OFF_VM    = 10*U_SZ;
static const size_t OFF_V     = 11*U_SZ;
static const size_t OFF_UOUT  = 12*U_SZ;
static const size_t OFF_PROJ  = 13*U_SZ;
static const size_t OFF_TMP   = 14*U_SZ;
static const size_t SMALL0    = 15*U_SZ;
// global-branch buffers
static const size_t OFF_SEQG  = SMALL0 + 0*SG_SZ;
static const size_t OFF_UG    = SMALL0 + 1*SG_SZ;
static const size_t OFF_GAG   = SMALL0 + 2*SG_SZ;
static const size_t OFF_GBG   = SMALL0 + 3*SG_SZ;
static const size_t OFF_GOG   = SMALL0 + 4*SG_SZ;
static const size_t OFF_YG    = SMALL0 + 5*SG_SZ;
static const size_t SMALL1    = SMALL0 + 6*SG_SZ;
static const size_t OFF_POSF  = SMALL1;                    // 4096*256
static const size_t OFF_POSG  = OFF_POSF + 4096*256;       // 256*256
static const size_t OFF_PART  = OFF_POSG + 65536;          // 8*256
static const size_t OFF_PARTG = OFF_PART + 2048;
static const size_t OFF_CLN   = OFF_PARTG + 2048;
static const size_t OFF_CLNG  = OFF_CLN + 2048;
static const size_t OFF_FB    = OFF_CLNG + 2048;
static const size_t OFF_WB    = OFF_FB + 2048;
static const size_t OFF_OB    = OFF_WB + 2048;
static const size_t OFF_FBG   = OFF_OB + 2048;
static const size_t OFF_WBG   = OFF_FBG + 2048;
static const size_t OFF_OBG   = OFF_WBG + 2048;
static const size_t OFF_AGA   = OFF_OBG + 2048;            // 8*32*256
static const size_t OFF_ABF   = OFF_AGA + 65536;
static const size_t OFF_ABB   = OFF_ABF + 65536;
static const size_t OFF_SIF   = OFF_ABB + 65536;
static const size_t OFF_SIB   = OFF_SIF + 65536;
static const size_t TOTAL_SCRATCH = OFF_SIB + 65536 + 1024;

__device__ __align__(16) float g_scratch[TOTAL_SCRATCH];

__device__ __forceinline__ float sigf(float x) { return 1.0f / (1.0f + expf(-x)); }
__device__ __forceinline__ int clampi(int v, int lo, int hi) { return v < lo ? lo : (v > hi ? hi : v); }

// ---------- x [B,C,4096] -> seq [B*4096, C] ----------
__global__ void k_transpose(const float* __restrict__ x, float* __restrict__ seq) {
    __shared__ float tile[32][33];
    int b = blockIdx.z;
    int t0 = blockIdx.x * 32, c0 = blockIdx.y * 32;
    int tx = threadIdx.x, ty = threadIdx.y;
    const float* src = x + (size_t)b * CDIM * NTOK;
#pragma unroll
    for (int j = 0; j < 4; j++)
        tile[ty + 8*j][tx] = src[(size_t)(c0 + ty + 8*j) * NTOK + t0 + tx];
    __syncthreads();
    float* dst = seq + (size_t)b * NTOK * CDIM;
#pragma unroll
    for (int j = 0; j < 4; j++)
        dst[(size_t)(t0 + ty + 8*j) * CDIM + c0 + tx] = tile[tx][ty + 8*j];
}

// ---------- proj [B,4096,C] + x -> out [B,C,4096] ----------
__global__ void k_output(const float* __restrict__ proj, const float* __restrict__ x,
                         float* __restrict__ outp) {
    __shared__ float tile[32][33];
    int b = blockIdx.z;
    int t0 = blockIdx.x * 32, c0 = blockIdx.y * 32;
    int tx = threadIdx.x, ty = threadIdx.y;
    const float* src = proj + (size_t)b * NTOK * CDIM;
#pragma unroll
    for (int j = 0; j < 4; j++)
        tile[ty + 8*j][tx] = src[(size_t)(t0 + ty + 8*j) * CDIM + c0 + tx];
    __syncthreads();
    size_t base = (size_t)b * CDIM * NTOK;
#pragma unroll
    for (int j = 0; j < 4; j++) {
        size_t o = base + (size_t)(c0 + ty + 8*j) * NTOK + t0 + tx;
        outp[o] = x[o] + tile[tx][ty + 8*j];
    }
}

// ---------- pos bilinear upsample 32x32 -> OHxOW, channel-major in, token-major out ----------
__global__ void k_posup(const float* __restrict__ pos, float* __restrict__ outp, int OH, int OW) {
    int t = blockIdx.x, c = threadIdx.x;
    int oh = t / OW, ow = t % OW;
    float sy = (oh + 0.5f) * (32.0f / OH) - 0.5f;
    float sx = (ow + 0.5f) * (32.0f / OW) - 0.5f;
    int y0 = (int)floorf(sy); float fy = sy - y0;
    int x0 = (int)floorf(sx); float fx = sx - x0;
    int y0c = clampi(y0, 0, 31), y1c = clampi(y0 + 1, 0, 31);
    int x0c = clampi(x0, 0, 31), x1c = clampi(x0 + 1, 0, 31);
    const float* p = pos + (size_t)c * 1024;
    float v = (1.f - fy) * ((1.f - fx) * p[y0c*32 + x0c] + fx * p[y0c*32 + x1c])
            + fy * ((1.f - fx) * p[y1c*32 + x0c] + fx * p[y1c*32 + x1c]);
    outp[(size_t)t * CDIM + c] = v;
}

// ---------- pos antialiased downsample 32x32 -> 16x16 ----------
__global__ void k_posdown(const float* __restrict__ pos, float* __restrict__ outp) {
    int t = blockIdx.x, c = threadIdx.x;
    int gh = t / 16, gw = t % 16;
    const float W4[4] = {0.125f, 0.375f, 0.375f, 0.125f};
    float wy[4], wx[4]; int ky[4], kx[4];
    float sy = 0.f, sx = 0.f;
#pragma unroll
    for (int d = 0; d < 4; d++) {
        ky[d] = 2*gh - 1 + d; wy[d] = (ky[d] >= 0 && ky[d] < 32) ? W4[d] : 0.f; sy += wy[d];
        kx[d] = 2*gw - 1 + d; wx[d] = (kx[d] >= 0 && kx[d] < 32) ? W4[d] : 0.f; sx += wx[d];
    }
    const float* p = pos + (size_t)c * 1024;
    float acc = 0.f;
#pragma unroll
    for (int d = 0; d < 4; d++) {
        if (wy[d] == 0.f) continue;
        float rowacc = 0.f;
#pragma unroll
        for (int e = 0; e < 4; e++)
            if (wx[e] != 0.f) rowacc += wx[e] * p[ky[d]*32 + kx[e]];
        acc += wy[d] * rowacc;
    }
    outp[(size_t)t * CDIM + c] = acc / (sy * sx);
}

// ---------- SGEMM: C[M,256] = A[M,256] @ B[256,256] (+bias) (+=) ----------
__global__ void k_gemm(const float* __restrict__ A, const float* __restrict__ Bm,
                       float* __restrict__ C, const float* __restrict__ bias, int acc) {
    __shared__ float As[16][128];
    __shared__ float Bs[16][128];
    int bx = blockIdx.x, by = blockIdx.y;
    int tid = threadIdx.x;
    int tx = tid & 15, ty = tid >> 4;
    const float* Ab = A + (size_t)by * 128 * 256;
    const float* Bb = Bm + bx * 128;
    float cr[8][8];
#pragma unroll
    for (int i = 0; i < 8; i++)
#pragma unroll
        for (int j = 0; j < 8; j++) cr[i][j] = 0.f;
    int aRow = tid >> 2, aCol = (tid & 3) * 4;
    int bRow = tid >> 5, bCol = (tid & 31) * 4;
    for (int k0 = 0; k0 < 256; k0 += 16) {
#pragma unroll
        for (int h = 0; h < 2; h++) {
            int r = aRow + h * 64;
            float4 v = *(const float4*)(Ab + (size_t)r * 256 + k0 + aCol);
            As[aCol + 0][r] = v.x; As[aCol + 1][r] = v.y;
            As[aCol + 2][r] = v.z; As[aCol + 3][r] = v.w;
        }
#pragma unroll
        for (int h = 0; h < 2; h++) {
            int r = bRow + h * 8;
            float4 v = *(const float4*)(Bb + (size_t)(k0 + r) * 256 + bCol);
            *(float4*)(&Bs[r][bCol]) = v;
        }
        __syncthreads();
#pragma unroll
        for (int k = 0; k < 16; k++) {
            float ar[8], br[8];
#pragma unroll
            for (int i = 0; i < 8; i++) ar[i] = As[k][ty + i * 16];
#pragma unroll
            for (int j = 0; j < 8; j++) br[j] = Bs[k][tx + j * 16];
#pragma unroll
            for (int i = 0; i < 8; i++)
#pragma unroll
                for (int j = 0; j < 8; j++) cr[i][j] += ar[i] * br[j];
        }
        __syncthreads();
    }
#pragma unroll
    for (int i = 0; i < 8; i++) {
        int gr = by * 128 + ty + i * 16;
#pragma unroll
        for (int j = 0; j < 8; j++) {
            int gc = bx * 128 + tx + j * 16;
            float v = cr[i][j];
            if (bias) v += bias[gc];
            size_t o = (size_t)gr * 256 + gc;
            if (acc) C[o] += v; else C[o] = v;
        }
    }
}

// ---------- u += pos[token] ----------
__global__ void k_addpos(float* __restrict__ U, const float* __restrict__ pos, int ntok) {
    int r = blockIdx.x, c = threadIdx.x;
    int t = r % ntok;
    U[(size_t)r * CDIM + c] += pos[(size_t)t * CDIM + c];
}

// ---------- per-(b,c) mean over tokens ----------
__global__ void k_colmean(const float* __restrict__ U, float* __restrict__ part, int ntok) {
    int b = blockIdx.x, c = threadIdx.x;
    const float* p = U + (size_t)b * ntok * CDIM + c;
    float s0 = 0.f, s1 = 0.f, s2 = 0.f, s3 = 0.f;
    for (int t = 0; t < ntok; t += 4) {
        s0 += p[(size_t)t * CDIM];
        s1 += p[(size_t)(t + 1) * CDIM];
        s2 += p[(size_t)(t + 2) * CDIM];
        s3 += p[(size_t)(t + 3) * CDIM];
    }
    part[b * CDIM + c] = (s0 + s1 + s2 + s3) / (float)ntok;
}

// ---------- layernorm over channels of pooled mean ----------
__global__ void k_ln(const float* __restrict__ part, const float* __restrict__ g,
                     const float* __restrict__ be, float* __restrict__ cln) {
    int b = blockIdx.x, c = threadIdx.x;
    __shared__ float red[256];
    float m = part[b * 256 + c];
    red[c] = m; __syncthreads();
    for (int s = 128; s > 0; s >>= 1) { if (c < s) red[c] += red[c + s]; __syncthreads(); }
    float mu = red[0] * (1.f / 256.f); __syncthreads();
    float d = m - mu;
    red[c] = d * d; __syncthreads();
    for (int s = 128; s > 0; s >>= 1) { if (c < s) red[c] += red[c + s]; __syncthreads(); }
    float var = red[0] * (1.f / 256.f);
    cln[b * 256 + c] = d * rsqrtf(var + LN_EPS) * g[c] + be[c];
}

// ---------- per-batch gate bias: bias + cln @ W[256:512] ----------
__global__ void k_gatebias(const float* __restrict__ cln,
                           const float* __restrict__ Wf, const float* __restrict__ bf,
                           const float* __restrict__ Ww, const float* __restrict__ bw,
                           const float* __restrict__ Wo, const float* __restrict__ bo,
                           float* __restrict__ fb, float* __restrict__ wb, float* __restrict__ ob) {
    int which = blockIdx.x, b = blockIdx.y, c = threadIdx.x;
    __shared__ float sc[256];
    sc[c] = cln[b * 256 + c]; __syncthreads();
    const float* W  = (which == 0) ? Wf : (which == 1) ? Ww : Wo;
    const float* bi = (which == 0) ? bf : (which == 1) ? bw : bo;
    float* o        = (which == 0) ? fb : (which == 1) ? wb : ob;
    float acc = bi[c];
    for (int k = 0; k < 256; k++) acc += sc[k] * W[(size_t)(256 + k) * 256 + c];
    o[b * 256 + c] = acc;
}

// ---------- gate nonlinearities: GA<-a, GB<-(1-a)*g*u, GO<-o ----------
__global__ void k_gates(const float* __restrict__ U, float* __restrict__ GA,
                        float* __restrict__ GB, float* __restrict__ GO,
                        const float* __restrict__ fb, const float* __restrict__ wb,
                        const float* __restrict__ ob, int ntok) {
    int r = blockIdx.x, c = threadIdx.x;
    int b = r / ntok;
    size_t i = (size_t)r * CDIM + c;
    int bc = b * CDIM + c;
    float u = U[i];
    float araw = GA[i] + fb[bc];
    float a = 1.0f / (1.0f + expf(araw));          // exp(-softplus(x)) == sigmoid(-x)
    float g = sigf(GB[i] + wb[bc]);
    float o = sigf(GO[i] + ob[bc]);
    GA[i] = a; GB[i] = (1.0f - a) * g * u; GO[i] = o;
}

// ---------- scan phase 1: chunk aggregates (fwd & bwd) ----------
__global__ void k_scan1(const float* __restrict__ GA, const float* __restrict__ GB,
                        float* __restrict__ AGA, float* __restrict__ ABF, float* __restrict__ ABB) {
    int j = blockIdx.x, b = blockIdx.y, c = threadIdx.x;
    size_t base = ((size_t)b * NTOK + j * 128) * CDIM + c;
    float A = 1.f, sf = 0.f;
    for (int t = 0; t < 128; t++) {
        float a = GA[base + (size_t)t * CDIM], bb = GB[base + (size_t)t * CDIM];
        A *= a; sf = a * sf + bb;
    }
    float sb = 0.f;
    for (int t = 127; t >= 0; t--) {
        float a = GA[base + (size_t)t * CDIM], bb = GB[base + (size_t)t * CDIM];
        sb = a * sb + bb;
    }
    int o = (b * 32 + j) * 256 + c;
    AGA[o] = A; ABF[o] = sf; ABB[o] = sb;
}

// ---------- scan phase 2: cross-chunk states ----------
__global__ void k_scan2(const float* __restrict__ AGA, const float* __restrict__ ABF,
                        const float* __restrict__ ABB, float* __restrict__ SIF, float* __restrict__ SIB) {
    int b = blockIdx.x, c = threadIdx.x;
    float s = 0.f;
    for (int j = 0; j < 32; j++) {
        int o = (b * 32 + j) * 256 + c;
        SIF[o] = s; s = AGA[o] * s + ABF[o];
    }
    s = 0.f;
    for (int j = 31; j >= 0; j--) {
        int o = (b * 32 + j) * 256 + c;
        SIB[o] = s; s = AGA[o] * s + ABB[o];
    }
}

// ---------- scan phase 3: produce y_f and y_b ----------
__global__ void k_scan3(const float* __restrict__ GA, const float* __restrict__ GB,
                        const float* __restrict__ GO, const float* __restrict__ U,
                        const float* __restrict__ SIF, const float* __restrict__ SIB,
                        float* __restrict__ YF, float* __restrict__ YB) {
    int j = blockIdx.x, b = blockIdx.y, c = threadIdx.x;
    size_t base = ((size_t)b * NTOK + j * 128) * CDIM + c;
    int ao = (b * 32 + j) * 256 + c;
    float s = SIF[ao];
    for (int t = 0; t < 128; t++) {
        size_t i = base + (size_t)t * CDIM;
        s = GA[i] * s + GB[i];
        float o = GO[i];
        YF[i] = o * s + (1.f - o) * U[i];
    }
    s = SIB[ao];
    for (int t = 127; t >= 0; t--) {
        size_t i = base + (size_t)t * CDIM;
        s = GA[i] * s + GB[i];
        float o = GO[i];
        YB[i] = o * s + (1.f - o) * U[i];
    }
}

// ---------- global branch: direct serial forward scan (256 tokens) ----------
__global__ void k_scanglob(const float* __restrict__ GA, const float* __restrict__ GB,
                           const float* __restrict__ GO, const float* __restrict__ U,
                           float* __restrict__ YG) {
    int b = blockIdx.x, c = threadIdx.x;
    size_t base = (size_t)b * NTOKG * CDIM + c;
    float s = 0.f;
    for (int t = 0; t < NTOKG; t++) {
        size_t i = base + (size_t)t * CDIM;
        s = GA[i] * s + GB[i];
        float o = GO[i];
        YG[i] = o * s + (1.f - o) * U[i];
    }
}

// ---------- 4x4 avg pool on token-major seq ----------
__global__ void k_pool(const float* __restrict__ seq, float* __restrict__ seqg) {
    int tg = blockIdx.x, b = blockIdx.y, c = threadIdx.x;
    int gh = tg / 16, gw = tg % 16;
    float s = 0.f;
#pragma unroll
    for (int i = 0; i < 4; i++)
#pragma unroll
        for (int j = 0; j < 4; j++)
            s += seq[((size_t)b * NTOK + (gh * 4 + i) * 64 + gw * 4 + j) * CDIM + c];
    seqg[((size_t)b * NTOKG + tg) * CDIM + c] = s * (1.0f / 16.0f);
}

// ---------- bilinear upsample y_g 16x16 -> 64x64 (token-major both) ----------
__global__ void k_upsample(const float* __restrict__ YG, float* __restrict__ YGS) {
    int t = blockIdx.x, b = blockIdx.y, c = threadIdx.x;
    int oh = t / 64, ow = t % 64;
    float sy = (oh + 0.5f) * 0.25f - 0.5f;
    float sx = (ow + 0.5f) * 0.25f - 0.5f;
    int y0 = (int)floorf(sy); float fy = sy - y0;
    int x0 = (int)floorf(sx); float fx = sx - x0;
    int y0c = clampi(y0, 0, 15), y1c = clampi(y0 + 1, 0, 15);
    int x0c = clampi(x0, 0, 15), x1c = clampi(x0 + 1, 0, 15);
    const float* base = YG + (size_t)b * NTOKG * CDIM + c;
    float v00 = base[(size_t)(y0c * 16 + x0c) * CDIM];
    float v01 = base[(size_t)(y0c * 16 + x1c) * CDIM];
    float v10 = base[(size_t)(y1c * 16 + x0c) * CDIM];
    float v11 = base[(size_t)(y1c * 16 + x1c) * CDIM];
    YGS[((size_t)b * NTOK + t) * CDIM + c] =
        (1.f - fy) * ((1.f - fx) * v00 + fx * v01) + fy * ((1.f - fx) * v10 + fx * v11);
}

// ---------- mixing epilogues ----------
__global__ void k_mix_rho(const float* __restrict__ T, const float* __restrict__ YF,
                          const float* __restrict__ YB, float* __restrict__ Y) {
    size_t i = (size_t)blockIdx.x * CDIM + threadIdx.x;
    float r = sigf(T[i]);
    Y[i] = r * YF[i] + (1.f - r) * YB[i];
}
__global__ void k_mix_lam(const float* __restrict__ T, const float* __restrict__ Y,
                          const float* __restrict__ YGS, float* __restrict__ Z) {
    size_t i = (size_t)blockIdx.x * CDIM + threadIdx.x;
    Z[i] = Y[i] + sigf(T[i]) * YGS[i];
}
__global__ void k_mix_eta(const float* __restrict__ T, const float* __restrict__ V,
                          const float* __restrict__ Z, float* __restrict__ UO) {
    size_t i = (size_t)blockIdx.x * CDIM + threadIdx.x;
    float e = sigf(T[i]);
    UO[i] = e * V[i] + (1.f - e) * Z[i];
}

// ---------- depthwise 3x3 conv (SAME) on token-major seq ----------
__global__ void k_dwconv(const float* __restrict__ seq, const float* __restrict__ w,
                         const float* __restrict__ bias, float* __restrict__ VM) {
    int h = blockIdx.x, b = blockIdx.y, c = threadIdx.x;
    float wr[9];
#pragma unroll
    for (int k = 0; k < 9; k++) wr[k] = w[c * 9 + k];
    float bi = bias[c];
    const float* sp = seq + (size_t)b * NTOK * CDIM + c;
    for (int x = 0; x < 64; x++) {
        float acc = bi;
#pragma unroll
        for (int i = 0; i < 3; i++) {
            int hh = h + i - 1;
            if (hh < 0 || hh > 63) continue;
#pragma unroll
            for (int j = 0; j < 3; j++) {
                int ww = x + j - 1;
                if (ww < 0 || ww > 63) continue;
                acc += wr[i * 3 + j] * sp[(size_t)(hh * 64 + ww) * CDIM];
            }
        }
        VM[((size_t)b * NTOK + h * 64 + x) * CDIM + c] = acc;
    }
}

extern "C" void kernel_launch(void* const* d_in, const int* in_sizes, int n_in,
                              void* d_out, int out_size) {
    const float* x        = (const float*)d_in[0];
    const float* Wt       = (const float*)d_in[1];
    const float* bt       = (const float*)d_in[2];
    const float* pos_fine = (const float*)d_in[3];
    const float* pos_glob = (const float*)d_in[4];
    const float* ln_g     = (const float*)d_in[5];
    const float* ln_b     = (const float*)d_in[6];
    const float* Wf       = (const float*)d_in[7];
    const float* bf       = (const float*)d_in[8];
    const float* Ww       = (const float*)d_in[9];
    const float* bw       = (const float*)d_in[10];
    const float* Wo       = (const float*)d_in[11];
    const float* bo       = (const float*)d_in[12];
    const float* Wr       = (const float*)d_in[13];
    const float* br       = (const float*)d_in[14];
    const float* Wgi      = (const float*)d_in[15];
    const float* bgi      = (const float*)d_in[16];
    const float* dw_w     = (const float*)d_in[17];
    const float* dw_b     = (const float*)d_in[18];
    const float* Wl       = (const float*)d_in[19];
    const float* bl       = (const float*)d_in[20];
    const float* Wlf      = (const float*)d_in[21];
    const float* blf      = (const float*)d_in[22];
    const float* Wout     = (const float*)d_in[23];
    const float* bout     = (const float*)d_in[24];
    float* outp = (float*)d_out;

    float* S = nullptr;
    cudaGetSymbolAddress((void**)&S, g_scratch);
    float* SEQ  = S + OFF_SEQ;  float* U    = S + OFF_U;
    float* GA   = S + OFF_GA;   float* GB   = S + OFF_GB;   float* GO  = S + OFF_GO;
    float* YF   = S + OFF_YF;   float* YB   = S + OFF_YB;   float* Y   = S + OFF_Y;
    float* YGS  = S + OFF_YGS;  float* Z    = S + OFF_Z;
    float* VM   = S + OFF_VM;   float* V    = S + OFF_V;
    float* UO   = S + OFF_UOUT; float* PROJ = S + OFF_PROJ; float* T   = S + OFF_TMP;
    float* SEQG = S + OFF_SEQG; float* UG   = S + OFF_UG;
    float* GAG  = S + OFF_GAG;  float* GBG  = S + OFF_GBG;  float* GOG = S + OFF_GOG;
    float* YG   = S + OFF_YG;
    float* POSF = S + OFF_POSF; float* POSG = S + OFF_POSG;
    float* PART = S + OFF_PART; float* PARTG = S + OFF_PARTG;
    float* CLN  = S + OFF_CLN;  float* CLNG = S + OFF_CLNG;
    float* FB = S + OFF_FB, *WB = S + OFF_WB, *OB = S + OFF_OB;
    float* FBG = S + OFF_FBG, *WBG = S + OFF_WBG, *OBG = S + OFF_OBG;
    float* AGA = S + OFF_AGA, *ABF = S + OFF_ABF, *ABB = S + OFF_ABB;
    float* SIF = S + OFF_SIF, *SIB = S + OFF_SIB;

    dim3 tb(32, 8);
    dim3 tg(128, 8, 8);
    dim3 gemF(2, MFINE / 128), gemG(2, MGLOB / 128);

    // fine sequence + pos
    k_transpose<<<tg, tb>>>(x, SEQ);
    k_posup<<<4096, 256>>>(pos_fine, POSF, 64, 64);
    k_posdown<<<256, 256>>>(pos_glob, POSG);
    k_gemm<<<gemF, 256>>>(SEQ, Wt, U, bt, 0);
    k_addpos<<<MFINE, 256>>>(U, POSF, NTOK);

    // gates (fine)
    k_colmean<<<BATCH, 256>>>(U, PART, NTOK);
    k_ln<<<BATCH, 256>>>(PART, ln_g, ln_b, CLN);
    k_gatebias<<<dim3(3, BATCH), 256>>>(CLN, Wf, bf, Ww, bw, Wo, bo, FB, WB, OB);
    k_gemm<<<gemF, 256>>>(U, Wf, GA, nullptr, 0);
    k_gemm<<<gemF, 256>>>(U, Ww, GB, nullptr, 0);
    k_gemm<<<gemF, 256>>>(U, Wo, GO, nullptr, 0);
    k_gates<<<MFINE, 256>>>(U, GA, GB, GO, FB, WB, OB, NTOK);

    // bidirectional chunked scan
    k_scan1<<<dim3(32, BATCH), 256>>>(GA, GB, AGA, ABF, ABB);
    k_scan2<<<BATCH, 256>>>(AGA, ABF, ABB, SIF, SIB);
    k_scan3<<<dim3(32, BATCH), 256>>>(GA, GB, GO, U, SIF, SIB, YF, YB);

    // rho mixing
    k_gemm<<<gemF, 256>>>(U,  Wr,            T, br, 0);
    k_gemm<<<gemF, 256>>>(YF, Wr + 65536,    T, nullptr, 1);
    k_gemm<<<gemF, 256>>>(YB, Wr + 131072,   T, nullptr, 1);
    k_mix_rho<<<MFINE, 256>>>(T, YF, YB, Y);

    // global branch
    k_pool<<<dim3(256, BATCH), 256>>>(SEQ, SEQG);
    k_gemm<<<gemG, 256>>>(SEQG, Wt, UG, bt, 0);
    k_addpos<<<MGLOB, 256>>>(UG, POSG, NTOKG);
    k_colmean<<<BATCH, 256>>>(UG, PARTG, NTOKG);
    k_ln<<<BATCH, 256>>>(PARTG, ln_g, ln_b, CLNG);
    k_gatebias<<<dim3(3, BATCH), 256>>>(CLNG, Wf, bf, Ww, bw, Wo, bo, FBG, WBG, OBG);
    k_gemm<<<gemG, 256>>>(UG, Wf, GAG, nullptr, 0);
    k_gemm<<<gemG, 256>>>(UG, Ww, GBG, nullptr, 0);
    k_gemm<<<gemG, 256>>>(UG, Wo, GOG, nullptr, 0);
    k_gates<<<MGLOB, 256>>>(UG, GAG, GBG, GOG, FBG, WBG, OBG, NTOKG);
    k_scanglob<<<BATCH, 256>>>(GAG, GBG, GOG, UG, YG);
    k_upsample<<<dim3(4096, BATCH), 256>>>(YG, YGS);

    // lam mixing
    k_gemm<<<gemF, 256>>>(Y,   Wgi,          T, bgi, 0);
    k_gemm<<<gemF, 256>>>(YGS, Wgi + 65536,  T, nullptr, 1);
    k_gemm<<<gemF, 256>>>(U,   Wgi + 131072, T, nullptr, 1);
    k_mix_lam<<<MFINE, 256>>>(T, Y, YGS, Z);

    // local depthwise branch
    k_dwconv<<<dim3(64, BATCH), 256>>>(SEQ, dw_w, dw_b, VM);
    k_gemm<<<gemF, 256>>>(VM, Wl, V, bl, 0);
    k_gemm<<<gemF, 256>>>(V, Wlf,         T, blf, 0);
    k_gemm<<<gemF, 256>>>(Z, Wlf + 65536, T, nullptr, 1);
    k_mix_eta<<<MFINE, 256>>>(T, V, Z, UO);

    // output proj + residual
    k_gemm<<<gemF, 256>>>(UO, Wout, PROJ, bout, 0);
    k_output<<<tg, tb>>>(PROJ, x, outp);
}

// round 4
// speedup vs baseline: 1.5053x; 1.5053x over previous
#include <cuda_runtime.h>
#include <math.h>
#include <stdint.h>

#define BATCH 8
#define CDIM  256
#define NTOK  4096
#define NTOKG 256
#define MFINE 32768
#define MGLOB 2048
#define LN_EPS 1e-5f

static const size_t U_SZ  = (size_t)MFINE * CDIM;
static const size_t SG_SZ = (size_t)MGLOB * CDIM;

// big buffers
static const size_t OFF_SEQ   = 0*U_SZ;
static const size_t OFF_U     = 1*U_SZ;
static const size_t OFF_GA    = 2*U_SZ;
static const size_t OFF_GB    = 3*U_SZ;
static const size_t OFF_GO    = 4*U_SZ;
static const size_t OFF_YF    = 5*U_SZ;
static const size_t OFF_YB    = 6*U_SZ;
static const size_t OFF_Y     = 7*U_SZ;
static const size_t OFF_YGS   = 8*U_SZ;
static const size_t OFF_Z     = 9*U_SZ;
static const size_t OFF_VM    = 10*U_SZ;
static const size_t OFF_V     = 11*U_SZ;
static const size_t OFF_UOUT  = 12*U_SZ;
static const size_t OFF_PROJ  = 13*U_SZ;
static const size_t OFF_TMP   = 14*U_SZ;
static const size_t SMALL0    = 15*U_SZ;
// global-branch buffers
static const size_t OFF_SEQG  = SMALL0 + 0*SG_SZ;
static const size_t OFF_UG    = SMALL0 + 1*SG_SZ;
static const size_t OFF_GAG   = SMALL0 + 2*SG_SZ;
static const size_t OFF_GBG   = SMALL0 + 3*SG_SZ;
static const size_t OFF_GOG   = SMALL0 + 4*SG_SZ;
static const size_t OFF_YG    = SMALL0 + 5*SG_SZ;
static const size_t SMALL1    = SMALL0 + 6*SG_SZ;
static const size_t OFF_POSF  = SMALL1;                    // 4096*256
static const size_t OFF_POSG  = OFF_POSF + 4096*256;       // 256*256
static const size_t OFF_PART  = OFF_POSG + 65536;          // 8*256
static const size_t OFF_PARTG = OFF_PART + 2048;
static const size_t OFF_CLN   = OFF_PARTG + 2048;
static const size_t OFF_CLNG  = OFF_CLN + 2048;
static const size_t OFF_FB    = OFF_CLNG + 2048;
static const size_t OFF_WB    = OFF_FB + 2048;
static const size_t OFF_OB    = OFF_WB + 2048;
static const size_t OFF_FBG   = OFF_OB + 2048;
static const size_t OFF_WBG   = OFF_FBG + 2048;
static const size_t OFF_OBG   = OFF_WBG + 2048;
static const size_t OFF_AGA   = OFF_OBG + 2048;            // 8*32*256
static const size_t OFF_ABF   = OFF_AGA + 65536;
static const size_t OFF_ABB   = OFF_ABF + 65536;
static const size_t OFF_SIF   = OFF_ABB + 65536;
static const size_t OFF_SIB   = OFF_SIF + 65536;
static const size_t TOTAL_SCRATCH = OFF_SIB + 65536 + 1024;

__device__ __align__(16) float g_scratch[TOTAL_SCRATCH];

__device__ __forceinline__ float sigf(float x) { return 1.0f / (1.0f + expf(-x)); }
__device__ __forceinline__ int clampi(int v, int lo, int hi) { return v < lo ? lo : (v > hi ? hi : v); }

__device__ __forceinline__ uint32_t f2tf32(float x) {
    uint32_t r;
    asm("cvt.rna.tf32.f32 %0, %1;" : "=r"(r) : "f"(x));
    return r;
}

__device__ __forceinline__ void mma_tf32(float* c, const uint32_t* a, const uint32_t* b) {
    asm volatile(
        "mma.sync.aligned.m16n8k8.row.col.f32.tf32.tf32.f32 "
        "{%0,%1,%2,%3}, {%4,%5,%6,%7}, {%8,%9}, {%0,%1,%2,%3};\n"
        : "+f"(c[0]), "+f"(c[1]), "+f"(c[2]), "+f"(c[3])
        : "r"(a[0]), "r"(a[1]), "r"(a[2]), "r"(a[3]), "r"(b[0]), "r"(b[1]));
}

// ---------- x [B,C,4096] -> seq [B*4096, C] ----------
__global__ void k_transpose(const float* __restrict__ x, float* __restrict__ seq) {
    __shared__ float tile[32][33];
    int b = blockIdx.z;
    int t0 = blockIdx.x * 32, c0 = blockIdx.y * 32;
    int tx = threadIdx.x, ty = threadIdx.y;
    const float* src = x + (size_t)b * CDIM * NTOK;
#pragma unroll
    for (int j = 0; j < 4; j++)
        tile[ty + 8*j][tx] = src[(size_t)(c0 + ty + 8*j) * NTOK + t0 + tx];
    __syncthreads();
    float* dst = seq + (size_t)b * NTOK * CDIM;
#pragma unroll
    for (int j = 0; j < 4; j++)
        dst[(size_t)(t0 + ty + 8*j) * CDIM + c0 + tx] = tile[tx][ty + 8*j];
}

// ---------- proj [B,4096,C] + x -> out [B,C,4096] ----------
__global__ void k_output(const float* __restrict__ proj, const float* __restrict__ x,
                         float* __restrict__ outp) {
    __shared__ float tile[32][33];
    int b = blockIdx.z;
    int t0 = blockIdx.x * 32, c0 = blockIdx.y * 32;
    int tx = threadIdx.x, ty = threadIdx.y;
    const float* src = proj + (size_t)b * NTOK * CDIM;
#pragma unroll
    for (int j = 0; j < 4; j++)
        tile[ty + 8*j][tx] = src[(size_t)(t0 + ty + 8*j) * CDIM + c0 + tx];
    __syncthreads();
    size_t base = (size_t)b * CDIM * NTOK;
#pragma unroll
    for (int j = 0; j < 4; j++) {
        size_t o = base + (size_t)(c0 + ty + 8*j) * NTOK + t0 + tx;
        outp[o] = x[o] + tile[tx][ty + 8*j];
    }
}

// ---------- pos bilinear upsample 32x32 -> OHxOW ----------
__global__ void k_posup(const float* __restrict__ pos, float* __restrict__ outp, int OH, int OW) {
    int t = blockIdx.x, c = threadIdx.x;
    int oh = t / OW, ow = t % OW;
    float sy = (oh + 0.5f) * (32.0f / OH) - 0.5f;
    float sx = (ow + 0.5f) * (32.0f / OW) - 0.5f;
    int y0 = (int)floorf(sy); float fy = sy - y0;
    int x0 = (int)floorf(sx); float fx = sx - x0;
    int y0c = clampi(y0, 0, 31), y1c = clampi(y0 + 1, 0, 31);
    int x0c = clampi(x0, 0, 31), x1c = clampi(x0 + 1, 0, 31);
    const float* p = pos + (size_t)c * 1024;
    float v = (1.f - fy) * ((1.f - fx) * p[y0c*32 + x0c] + fx * p[y0c*32 + x1c])
            + fy * ((1.f - fx) * p[y1c*32 + x0c] + fx * p[y1c*32 + x1c]);
    outp[(size_t)t * CDIM + c] = v;
}

// ---------- pos antialiased downsample 32x32 -> 16x16 ----------
__global__ void k_posdown(const float* __restrict__ pos, float* __restrict__ outp) {
    int t = blockIdx.x, c = threadIdx.x;
    int gh = t / 16, gw = t % 16;
    const float W4[4] = {0.125f, 0.375f, 0.375f, 0.125f};
    float wy[4], wx[4]; int ky[4], kx[4];
    float sy = 0.f, sx = 0.f;
#pragma unroll
    for (int d = 0; d < 4; d++) {
        ky[d] = 2*gh - 1 + d; wy[d] = (ky[d] >= 0 && ky[d] < 32) ? W4[d] : 0.f; sy += wy[d];
        kx[d] = 2*gw - 1 + d; wx[d] = (kx[d] >= 0 && kx[d] < 32) ? W4[d] : 0.f; sx += wx[d];
    }
    const float* p = pos + (size_t)c * 1024;
    float acc = 0.f;
#pragma unroll
    for (int d = 0; d < 4; d++) {
        if (wy[d] == 0.f) continue;
        float rowacc = 0.f;
#pragma unroll
        for (int e = 0; e < 4; e++)
            if (wx[e] != 0.f) rowacc += wx[e] * p[ky[d]*32 + kx[e]];
        acc += wy[d] * rowacc;
    }
    outp[(size_t)t * CDIM + c] = acc / (sy * sx);
}

// ---------- tf32 tensor-core GEMM ----------
// C[M,256] = sum_p A_p[M,256] @ W_p[256,256]  (+bias)
// block: 256 threads (8 warps, 2x4), tile 128x128, BK=32, warp tile 64x32
#define TCBK 32
#define ASTRIDE 136
__global__ void __launch_bounds__(256, 2)
k_gemm_tc(const float* __restrict__ A0, const float* __restrict__ W0,
          const float* __restrict__ A1, const float* __restrict__ W1,
          const float* __restrict__ A2, const float* __restrict__ W2,
          int npairs, float* __restrict__ C, const float* __restrict__ bias) {
    __shared__ uint32_t As[TCBK][ASTRIDE];   // [k][m], pad 8 -> conflict-free frag loads
    __shared__ uint32_t Bs[TCBK][ASTRIDE];   // [k][n]
    int bx = blockIdx.x, by = blockIdx.y;
    int tid = threadIdx.x;
    int warp = tid >> 5, lane = tid & 31;
    int wm = warp >> 2;        // 0..1 -> m offset *64
    int wn = warp & 3;         // 0..3 -> n offset *32
    int g = lane >> 2;         // 0..7
    int tq = lane & 3;         // 0..3

    float acc[4][4][4];
#pragma unroll
    for (int i = 0; i < 4; i++)
#pragma unroll
        for (int j = 0; j < 4; j++)
#pragma unroll
            for (int r = 0; r < 4; r++) acc[i][j][r] = 0.f;

    int aRow = tid >> 1;       // 0..127
    int aC4  = tid & 1;        // 0..1, step 2
    int bRow = tid >> 3;       // 0..31
    int bC4  = tid & 7;        // 0..7, step 8

    for (int p = 0; p < npairs; p++) {
        const float* A = (p == 0) ? A0 : (p == 1) ? A1 : A2;
        const float* W = (p == 0) ? W0 : (p == 1) ? W1 : W2;
        for (int k0 = 0; k0 < 256; k0 += TCBK) {
            // A tile: rows by*128.., k chunk k0..k0+31 -> As[k][m]
#pragma unroll
            for (int it = 0; it < 4; it++) {
                int c4 = aC4 + 2 * it;
                float4 v = *(const float4*)(A + (size_t)(by * 128 + aRow) * 256 + k0 + c4 * 4);
                int kk = c4 * 4;
                As[kk + 0][aRow] = f2tf32(v.x);
                As[kk + 1][aRow] = f2tf32(v.y);
                As[kk + 2][aRow] = f2tf32(v.z);
                As[kk + 3][aRow] = f2tf32(v.w);
            }
            // B tile: rows k0..k0+31, cols bx*128.. -> Bs[k][n]
#pragma unroll
            for (int it = 0; it < 4; it++) {
                int cc = (bC4 + 8 * it) * 4;
                float4 v = *(const float4*)(W + (size_t)(k0 + bRow) * 256 + bx * 128 + cc);
                Bs[bRow][cc + 0] = f2tf32(v.x);
                Bs[bRow][cc + 1] = f2tf32(v.y);
                Bs[bRow][cc + 2] = f2tf32(v.z);
                Bs[bRow][cc + 3] = f2tf32(v.w);
            }
            __syncthreads();
#pragma unroll
            for (int ks = 0; ks < TCBK; ks += 8) {
                uint32_t af[4][4];
#pragma unroll
                for (int mt = 0; mt < 4; mt++) {
                    int mb = wm * 64 + mt * 16;
                    af[mt][0] = As[ks + tq][mb + g];
                    af[mt][1] = As[ks + tq][mb + g + 8];
                    af[mt][2] = As[ks + tq + 4][mb + g];
                    af[mt][3] = As[ks + tq + 4][mb + g + 8];
                }
                uint32_t bf[4][2];
#pragma unroll
                for (int nt = 0; nt < 4; nt++) {
                    int nb = wn * 32 + nt * 8;
                    bf[nt][0] = Bs[ks + tq][nb + g];
                    bf[nt][1] = Bs[ks + tq + 4][nb + g];
                }
#pragma unroll
                for (int mt = 0; mt < 4; mt++)
#pragma unroll
                    for (int nt = 0; nt < 4; nt++)
                        mma_tf32(acc[mt][nt], af[mt], bf[nt]);
            }
            __syncthreads();
        }
    }
    // epilogue
#pragma unroll
    for (int mt = 0; mt < 4; mt++) {
        int r = by * 128 + wm * 64 + mt * 16 + g;
#pragma unroll
        for (int nt = 0; nt < 4; nt++) {
            int col = bx * 128 + wn * 32 + nt * 8 + tq * 2;
            float b0 = 0.f, b1 = 0.f;
            if (bias) { b0 = bias[col]; b1 = bias[col + 1]; }
            float2 v0 = make_float2(acc[mt][nt][0] + b0, acc[mt][nt][1] + b1);
            float2 v1 = make_float2(acc[mt][nt][2] + b0, acc[mt][nt][3] + b1);
            *(float2*)(C + (size_t)r * 256 + col) = v0;
            *(float2*)(C + (size_t)(r + 8) * 256 + col) = v1;
        }
    }
}

// ---------- u += pos[token] ----------
__global__ void k_addpos(float* __restrict__ U, const float* __restrict__ pos, int ntok) {
    int r = blockIdx.x, c = threadIdx.x;
    int t = r % ntok;
    U[(size_t)r * CDIM + c] += pos[(size_t)t * CDIM + c];
}

// ---------- per-(b,c) mean over tokens ----------
__global__ void k_colmean(const float* __restrict__ U, float* __restrict__ part, int ntok) {
    int b = blockIdx.x, c = threadIdx.x;
    const float* p = U + (size_t)b * ntok * CDIM + c;
    float s0 = 0.f, s1 = 0.f, s2 = 0.f, s3 = 0.f;
    for (int t = 0; t < ntok; t += 4) {
        s0 += p[(size_t)t * CDIM];
        s1 += p[(size_t)(t + 1) * CDIM];
        s2 += p[(size_t)(t + 2) * CDIM];
        s3 += p[(size_t)(t + 3) * CDIM];
    }
    part[b * CDIM + c] = (s0 + s1 + s2 + s3) / (float)ntok;
}

// ---------- layernorm over channels of pooled mean ----------
__global__ void k_ln(const float* __restrict__ part, const float* __restrict__ g,
                     const float* __restrict__ be, float* __restrict__ cln) {
    int b = blockIdx.x, c = threadIdx.x;
    __shared__ float red[256];
    float m = part[b * 256 + c];
    red[c] = m; __syncthreads();
    for (int s = 128; s > 0; s >>= 1) { if (c < s) red[c] += red[c + s]; __syncthreads(); }
    float mu = red[0] * (1.f / 256.f); __syncthreads();
    float d = m - mu;
    red[c] = d * d; __syncthreads();
    for (int s = 128; s > 0; s >>= 1) { if (c < s) red[c] += red[c + s]; __syncthreads(); }
    float var = red[0] * (1.f / 256.f);
    cln[b * 256 + c] = d * rsqrtf(var + LN_EPS) * g[c] + be[c];
}

// ---------- per-batch gate bias: bias + cln @ W[256:512] ----------
__global__ void k_gatebias(const float* __restrict__ cln,
                           const float* __restrict__ Wf, const float* __restrict__ bf,
                           const float* __restrict__ Ww, const float* __restrict__ bw,
                           const float* __restrict__ Wo, const float* __restrict__ bo,
                           float* __restrict__ fb, float* __restrict__ wb, float* __restrict__ ob) {
    int which = blockIdx.x, b = blockIdx.y, c = threadIdx.x;
    __shared__ float sc[256];
    sc[c] = cln[b * 256 + c]; __syncthreads();
    const float* W  = (which == 0) ? Wf : (which == 1) ? Ww : Wo;
    const float* bi = (which == 0) ? bf : (which == 1) ? bw : bo;
    float* o        = (which == 0) ? fb : (which == 1) ? wb : ob;
    float acc = bi[c];
    for (int k = 0; k < 256; k++) acc += sc[k] * W[(size_t)(256 + k) * 256 + c];
    o[b * 256 + c] = acc;
}

// ---------- gate nonlinearities ----------
__global__ void k_gates(const float* __restrict__ U, float* __restrict__ GA,
                        float* __restrict__ GB, float* __restrict__ GO,
                        const float* __restrict__ fb, const float* __restrict__ wb,
                        const float* __restrict__ ob, int ntok) {
    int r = blockIdx.x, c = threadIdx.x;
    int b = r / ntok;
    size_t i = (size_t)r * CDIM + c;
    int bc = b * CDIM + c;
    float u = U[i];
    float araw = GA[i] + fb[bc];
    float a = 1.0f / (1.0f + expf(araw));
    float g = sigf(GB[i] + wb[bc]);
    float o = sigf(GO[i] + ob[bc]);
    GA[i] = a; GB[i] = (1.0f - a) * g * u; GO[i] = o;
}

// ---------- scan phase 1 ----------
__global__ void k_scan1(const float* __restrict__ GA, const float* __restrict__ GB,
                        float* __restrict__ AGA, float* __restrict__ ABF, float* __restrict__ ABB) {
    int j = blockIdx.x, b = blockIdx.y, c = threadIdx.x;
    size_t base = ((size_t)b * NTOK + j * 128) * CDIM + c;
    float A = 1.f, sf = 0.f;
    for (int t = 0; t < 128; t++) {
        float a = GA[base + (size_t)t * CDIM], bb = GB[base + (size_t)t * CDIM];
        A *= a; sf = a * sf + bb;
    }
    float sb = 0.f;
    for (int t = 127; t >= 0; t--) {
        float a = GA[base + (size_t)t * CDIM], bb = GB[base + (size_t)t * CDIM];
        sb = a * sb + bb;
    }
    int o = (b * 32 + j) * 256 + c;
    AGA[o] = A; ABF[o] = sf; ABB[o] = sb;
}

// ---------- scan phase 2 ----------
__global__ void k_scan2(const float* __restrict__ AGA, const float* __restrict__ ABF,
                        const float* __restrict__ ABB, float* __restrict__ SIF, float* __restrict__ SIB) {
    int b = blockIdx.x, c = threadIdx.x;
    float s = 0.f;
    for (int j = 0; j < 32; j++) {
        int o = (b * 32 + j) * 256 + c;
        SIF[o] = s; s = AGA[o] * s + ABF[o];
    }
    s = 0.f;
    for (int j = 31; j >= 0; j--) {
        int o = (b * 32 + j) * 256 + c;
        SIB[o] = s; s = AGA[o] * s + ABB[o];
    }
}

// ---------- scan phase 3 ----------
__global__ void k_scan3(const float* __restrict__ GA, const float* __restrict__ GB,
                        const float* __restrict__ GO, const float* __restrict__ U,
                        const float* __restrict__ SIF, const float* __restrict__ SIB,
                        float* __restrict__ YF, float* __restrict__ YB) {
    int j = blockIdx.x, b = blockIdx.y, c = threadIdx.x;
    size_t base = ((size_t)b * NTOK + j * 128) * CDIM + c;
    int ao = (b * 32 + j) * 256 + c;
    float s = SIF[ao];
    for (int t = 0; t < 128; t++) {
        size_t i = base + (size_t)t * CDIM;
        s = GA[i] * s + GB[i];
        float o = GO[i];
        YF[i] = o * s + (1.f - o) * U[i];
    }
    s = SIB[ao];
    for (int t = 127; t >= 0; t--) {
        size_t i = base + (size_t)t * CDIM;
        s = GA[i] * s + GB[i];
        float o = GO[i];
        YB[i] = o * s + (1.f - o) * U[i];
    }
}

// ---------- global branch serial scan ----------
__global__ void k_scanglob(const float* __restrict__ GA, const float* __restrict__ GB,
                           const float* __restrict__ GO, const float* __restrict__ U,
                           float* __restrict__ YG) {
    int b = blockIdx.x, c = threadIdx.x;
    size_t base = (size_t)b * NTOKG * CDIM + c;
    float s = 0.f;
    for (int t = 0; t < NTOKG; t++) {
        size_t i = base + (size_t)t * CDIM;
        s = GA[i] * s + GB[i];
        float o = GO[i];
        YG[i] = o * s + (1.f - o) * U[i];
    }
}

// ---------- 4x4 avg pool ----------
__global__ void k_pool(const float* __restrict__ seq, float* __restrict__ seqg) {
    int tg = blockIdx.x, b = blockIdx.y, c = threadIdx.x;
    int gh = tg / 16, gw = tg % 16;
    float s = 0.f;
#pragma unroll
    for (int i = 0; i < 4; i++)
#pragma unroll
        for (int j = 0; j < 4; j++)
            s += seq[((size_t)b * NTOK + (gh * 4 + i) * 64 + gw * 4 + j) * CDIM + c];
    seqg[((size_t)b * NTOKG + tg) * CDIM + c] = s * (1.0f / 16.0f);
}

// ---------- bilinear upsample y_g 16x16 -> 64x64 ----------
__global__ void k_upsample(const float* __restrict__ YG, float* __restrict__ YGS) {
    int t = blockIdx.x, b = blockIdx.y, c = threadIdx.x;
    int oh = t / 64, ow = t % 64;
    float sy = (oh + 0.5f) * 0.25f - 0.5f;
    float sx = (ow + 0.5f) * 0.25f - 0.5f;
    int y0 = (int)floorf(sy); float fy = sy - y0;
    int x0 = (int)floorf(sx); float fx = sx - x0;
    int y0c = clampi(y0, 0, 15), y1c = clampi(y0 + 1, 0, 15);
    int x0c = clampi(x0, 0, 15), x1c = clampi(x0 + 1, 0, 15);
    const float* base = YG + (size_t)b * NTOKG * CDIM + c;
    float v00 = base[(size_t)(y0c * 16 + x0c) * CDIM];
    float v01 = base[(size_t)(y0c * 16 + x1c) * CDIM];
    float v10 = base[(size_t)(y1c * 16 + x0c) * CDIM];
    float v11 = base[(size_t)(y1c * 16 + x1c) * CDIM];
    YGS[((size_t)b * NTOK + t) * CDIM + c] =
        (1.f - fy) * ((1.f - fx) * v00 + fx * v01) + fy * ((1.f - fx) * v10 + fx * v11);
}

// ---------- mixing epilogues ----------
__global__ void k_mix_rho(const float* __restrict__ T, const float* __restrict__ YF,
                          const float* __restrict__ YB, float* __restrict__ Y) {
    size_t i = (size_t)blockIdx.x * CDIM + threadIdx.x;
    float r = sigf(T[i]);
    Y[i] = r * YF[i] + (1.f - r) * YB[i];
}
__global__ void k_mix_lam(const float* __restrict__ T, const float* __restrict__ Y,
                          const float* __restrict__ YGS, float* __restrict__ Z) {
    size_t i = (size_t)blockIdx.x * CDIM + threadIdx.x;
    Z[i] = Y[i] + sigf(T[i]) * YGS[i];
}
__global__ void k_mix_eta(const float* __restrict__ T, const float* __restrict__ V,
                          const float* __restrict__ Z, float* __restrict__ UO) {
    size_t i = (size_t)blockIdx.x * CDIM + threadIdx.x;
    float e = sigf(T[i]);
    UO[i] = e * V[i] + (1.f - e) * Z[i];
}

// ---------- depthwise 3x3 conv ----------
__global__ void k_dwconv(const float* __restrict__ seq, const float* __restrict__ w,
                         const float* __restrict__ bias, float* __restrict__ VM) {
    int h = blockIdx.x, b = blockIdx.y, c = threadIdx.x;
    float wr[9];
#pragma unroll
    for (int k = 0; k < 9; k++) wr[k] = w[c * 9 + k];
    float bi = bias[c];
    const float* sp = seq + (size_t)b * NTOK * CDIM + c;
    for (int x = 0; x < 64; x++) {
        float acc = bi;
#pragma unroll
        for (int i = 0; i < 3; i++) {
            int hh = h + i - 1;
            if (hh < 0 || hh > 63) continue;
#pragma unroll
            for (int j = 0; j < 3; j++) {
                int ww = x + j - 1;
                if (ww < 0 || ww > 63) continue;
                acc += wr[i * 3 + j] * sp[(size_t)(hh * 64 + ww) * CDIM];
            }
        }
        VM[((size_t)b * NTOK + h * 64 + x) * CDIM + c] = acc;
    }
}

extern "C" void kernel_launch(void* const* d_in, const int* in_sizes, int n_in,
                              void* d_out, int out_size) {
    const float* x        = (const float*)d_in[0];
    const float* Wt       = (const float*)d_in[1];
    const float* bt       = (const float*)d_in[2];
    const float* pos_fine = (const float*)d_in[3];
    const float* pos_glob = (const float*)d_in[4];
    const float* ln_g     = (const float*)d_in[5];
    const float* ln_b     = (const float*)d_in[6];
    const float* Wf       = (const float*)d_in[7];
    const float* bf       = (const float*)d_in[8];
    const float* Ww       = (const float*)d_in[9];
    const float* bw       = (const float*)d_in[10];
    const float* Wo       = (const float*)d_in[11];
    const float* bo       = (const float*)d_in[12];
    const float* Wr       = (const float*)d_in[13];
    const float* br       = (const float*)d_in[14];
    const float* Wgi      = (const float*)d_in[15];
    const float* bgi      = (const float*)d_in[16];
    const float* dw_w     = (const float*)d_in[17];
    const float* dw_b     = (const float*)d_in[18];
    const float* Wl       = (const float*)d_in[19];
    const float* bl       = (const float*)d_in[20];
    const float* Wlf      = (const float*)d_in[21];
    const float* blf      = (const float*)d_in[22];
    const float* Wout     = (const float*)d_in[23];
    const float* bout     = (const float*)d_in[24];
    float* outp = (float*)d_out;

    float* S = nullptr;
    cudaGetSymbolAddress((void**)&S, g_scratch);
    float* SEQ  = S + OFF_SEQ;  float* U    = S + OFF_U;
    float* GA   = S + OFF_GA;   float* GB   = S + OFF_GB;   float* GO  = S + OFF_GO;
    float* YF   = S + OFF_YF;   float* YB   = S + OFF_YB;   float* Y   = S + OFF_Y;
    float* YGS  = S + OFF_YGS;  float* Z    = S + OFF_Z;
    float* VM   = S + OFF_VM;   float* V    = S + OFF_V;
    float* UO   = S + OFF_UOUT; float* PROJ = S + OFF_PROJ; float* T   = S + OFF_TMP;
    float* SEQG = S + OFF_SEQG; float* UG   = S + OFF_UG;
    float* GAG  = S + OFF_GAG;  float* GBG  = S + OFF_GBG;  float* GOG = S + OFF_GOG;
    float* YG   = S + OFF_YG;
    float* POSF = S + OFF_POSF; float* POSG = S + OFF_POSG;
    float* PART = S + OFF_PART; float* PARTG = S + OFF_PARTG;
    float* CLN  = S + OFF_CLN;  float* CLNG = S + OFF_CLNG;
    float* FB = S + OFF_FB, *WB = S + OFF_WB, *OB = S + OFF_OB;
    float* FBG = S + OFF_FBG, *WBG = S + OFF_WBG, *OBG = S + OFF_OBG;
    float* AGA = S + OFF_AGA, *ABF = S + OFF_ABF, *ABB = S + OFF_ABB;
    float* SIF = S + OFF_SIF, *SIB = S + OFF_SIB;

    dim3 tb(32, 8);
    dim3 tg(128, 8, 8);
    dim3 gemF(2, MFINE / 128), gemG(2, MGLOB / 128);
    const float* NP = nullptr;

    // fine sequence + pos
    k_transpose<<<tg, tb>>>(x, SEQ);
    k_posup<<<4096, 256>>>(pos_fine, POSF, 64, 64);
    k_posdown<<<256, 256>>>(pos_glob, POSG);
    k_gemm_tc<<<gemF, 256>>>(SEQ, Wt, NP, NP, NP, NP, 1, U, bt);
    k_addpos<<<MFINE, 256>>>(U, POSF, NTOK);

    // gates (fine)
    k_colmean<<<BATCH, 256>>>(U, PART, NTOK);
    k_ln<<<BATCH, 256>>>(PART, ln_g, ln_b, CLN);
    k_gatebias<<<dim3(3, BATCH), 256>>>(CLN, Wf, bf, Ww, bw, Wo, bo, FB, WB, OB);
    k_gemm_tc<<<gemF, 256>>>(U, Wf, NP, NP, NP, NP, 1, GA, NP);
    k_gemm_tc<<<gemF, 256>>>(U, Ww, NP, NP, NP, NP, 1, GB, NP);
    k_gemm_tc<<<gemF, 256>>>(U, Wo, NP, NP, NP, NP, 1, GO, NP);
    k_gates<<<MFINE, 256>>>(U, GA, GB, GO, FB, WB, OB, NTOK);

    // bidirectional chunked scan
    k_scan1<<<dim3(32, BATCH), 256>>>(GA, GB, AGA, ABF, ABB);
    k_scan2<<<BATCH, 256>>>(AGA, ABF, ABB, SIF, SIB);
    k_scan3<<<dim3(32, BATCH), 256>>>(GA, GB, GO, U, SIF, SIB, YF, YB);

    // rho mixing (K-fused: 3 pairs, one launch)
    k_gemm_tc<<<gemF, 256>>>(U, Wr, YF, Wr + 65536, YB, Wr + 131072, 3, T, br);
    k_mix_rho<<<MFINE, 256>>>(T, YF, YB, Y);

    // global branch
    k_pool<<<dim3(256, BATCH), 256>>>(SEQ, SEQG);
    k_gemm_tc<<<gemG, 256>>>(SEQG, Wt, NP, NP, NP, NP, 1, UG, bt);
    k_addpos<<<MGLOB, 256>>>(UG, POSG, NTOKG);
    k_colmean<<<BATCH, 256>>>(UG, PARTG, NTOKG);
    k_ln<<<BATCH, 256>>>(PARTG, ln_g, ln_b, CLNG);
    k_gatebias<<<dim3(3, BATCH), 256>>>(CLNG, Wf, bf, Ww, bw, Wo, bo, FBG, WBG, OBG);
    k_gemm_tc<<<gemG, 256>>>(UG, Wf, NP, NP, NP, NP, 1, GAG, NP);
    k_gemm_tc<<<gemG, 256>>>(UG, Ww, NP, NP, NP, NP, 1, GBG, NP);
    k_gemm_tc<<<gemG, 256>>>(UG, Wo, NP, NP, NP, NP, 1, GOG, NP);
    k_gates<<<MGLOB, 256>>>(UG, GAG, GBG, GOG, FBG, WBG, OBG, NTOKG);
    k_scanglob<<<BATCH, 256>>>(GAG, GBG, GOG, UG, YG);
    k_upsample<<<dim3(4096, BATCH), 256>>>(YG, YGS);

    // lam mixing (K-fused: 3 pairs)
    k_gemm_tc<<<gemF, 256>>>(Y, Wgi, YGS, Wgi + 65536, U, Wgi + 131072, 3, T, bgi);
    k_mix_lam<<<MFINE, 256>>>(T, Y, YGS, Z);

    // local depthwise branch
    k_dwconv<<<dim3(64, BATCH), 256>>>(SEQ, dw_w, dw_b, VM);
    k_gemm_tc<<<gemF, 256>>>(VM, Wl, NP, NP, NP, NP, 1, V, bl);
    k_gemm_tc<<<gemF, 256>>>(V, Wlf, Z, Wlf + 65536, NP, NP, 2, T, blf);
    k_mix_eta<<<MFINE, 256>>>(T, V, Z, UO);

    // output proj + residual
    k_gemm_tc<<<gemF, 256>>>(UO, Wout, NP, NP, NP, NP, 1, PROJ, bout);
    k_output<<<tg, tb>>>(PROJ, x, outp);
}

// round 5
// speedup vs baseline: 2.1518x; 1.4295x over previous
#include <cuda_runtime.h>
#include <math.h>
#include <stdint.h>

#define BATCH 8
#define CDIM  256
#define NTOK  4096
#define NTOKG 256
#define MFINE 32768
#define MGLOB 2048
#define LN_EPS 1e-5f

static const size_t U_SZ  = (size_t)MFINE * CDIM;
static const size_t SG_SZ = (size_t)MGLOB * CDIM;

static const size_t OFF_SEQ   = 0*U_SZ;
static const size_t OFF_U     = 1*U_SZ;
static const size_t OFF_GA    = 2*U_SZ;
static const size_t OFF_GB    = 3*U_SZ;
static const size_t OFF_GO    = 4*U_SZ;
static const size_t OFF_YF    = 5*U_SZ;
static const size_t OFF_YB    = 6*U_SZ;
static const size_t OFF_Y     = 7*U_SZ;
static const size_t OFF_YGS   = 8*U_SZ;
static const size_t OFF_Z     = 9*U_SZ;
static const size_t OFF_VM    = 10*U_SZ;
static const size_t OFF_V     = 11*U_SZ;
static const size_t OFF_UOUT  = 12*U_SZ;
static const size_t OFF_PROJ  = 13*U_SZ;
static const size_t SMALL0    = 14*U_SZ;
static const size_t OFF_SEQG  = SMALL0 + 0*SG_SZ;
static const size_t OFF_UG    = SMALL0 + 1*SG_SZ;
static const size_t OFF_GAG   = SMALL0 + 2*SG_SZ;
static const size_t OFF_GBG   = SMALL0 + 3*SG_SZ;
static const size_t OFF_GOG   = SMALL0 + 4*SG_SZ;
static const size_t OFF_YG    = SMALL0 + 5*SG_SZ;
static const size_t SMALL1    = SMALL0 + 6*SG_SZ;
static const size_t OFF_POSF  = SMALL1;
static const size_t OFF_POSG  = OFF_POSF + 4096*256;
static const size_t OFF_PART  = OFF_POSG + 65536;
static const size_t OFF_PARTG = OFF_PART + 2048;
static const size_t OFF_CLN   = OFF_PARTG + 2048;
static const size_t OFF_CLNG  = OFF_CLN + 2048;
static const size_t OFF_FB    = OFF_CLNG + 2048;
static const size_t OFF_WB    = OFF_FB + 2048;
static const size_t OFF_OB    = OFF_WB + 2048;
static const size_t OFF_FBG   = OFF_OB + 2048;
static const size_t OFF_WBG   = OFF_FBG + 2048;
static const size_t OFF_OBG   = OFF_WBG + 2048;
static const size_t OFF_AGA   = OFF_OBG + 2048;
static const size_t OFF_ABF   = OFF_AGA + 65536;
static const size_t OFF_ABB   = OFF_ABF + 65536;
static const size_t OFF_SIF   = OFF_ABB + 65536;
static const size_t OFF_SIB   = OFF_SIF + 65536;
static const size_t OFF_P16   = OFF_SIB + 65536;           // 8*16*256
static const size_t TOTAL_SCRATCH = OFF_P16 + 32768 + 1024;

__device__ __align__(16) float g_scratch[TOTAL_SCRATCH];

__device__ __forceinline__ float sigf(float x) { return 1.0f / (1.0f + expf(-x)); }
__device__ __forceinline__ int clampi(int v, int lo, int hi) { return v < lo ? lo : (v > hi ? hi : v); }

__device__ __forceinline__ void mma_tf32(float* c, const uint32_t* a, const uint32_t* b) {
    asm volatile(
        "mma.sync.aligned.m16n8k8.row.col.f32.tf32.tf32.f32 "
        "{%0,%1,%2,%3}, {%4,%5,%6,%7}, {%8,%9}, {%0,%1,%2,%3};\n"
        : "+f"(c[0]), "+f"(c[1]), "+f"(c[2]), "+f"(c[3])
        : "r"(a[0]), "r"(a[1]), "r"(a[2]), "r"(a[3]), "r"(b[0]), "r"(b[1]));
}

__device__ __forceinline__ void cpa16(uint32_t dst, const void* src) {
    asm volatile("cp.async.cg.shared.global [%0], [%1], 16;" :: "r"(dst), "l"(src));
}
#define CP_COMMIT() asm volatile("cp.async.commit_group;")
#define CP_WAIT0()  asm volatile("cp.async.wait_group 0;")

__device__ __forceinline__ const float* selp(const float* a0, const float* a1,
                                             const float* a2, int p) {
    return p == 0 ? a0 : (p == 1 ? a1 : a2);
}

// ---------- x [B,C,4096] -> seq [B*4096, C] ----------
__global__ void k_transpose(const float* __restrict__ x, float* __restrict__ seq) {
    __shared__ float tile[32][33];
    int b = blockIdx.z;
    int t0 = blockIdx.x * 32, c0 = blockIdx.y * 32;
    int tx = threadIdx.x, ty = threadIdx.y;
    const float* src = x + (size_t)b * CDIM * NTOK;
#pragma unroll
    for (int j = 0; j < 4; j++)
        tile[ty + 8*j][tx] = src[(size_t)(c0 + ty + 8*j) * NTOK + t0 + tx];
    __syncthreads();
    float* dst = seq + (size_t)b * NTOK * CDIM;
#pragma unroll
    for (int j = 0; j < 4; j++)
        dst[(size_t)(t0 + ty + 8*j) * CDIM + c0 + tx] = tile[tx][ty + 8*j];
}

// ---------- proj [B,4096,C] + x -> out [B,C,4096] ----------
__global__ void k_output(const float* __restrict__ proj, const float* __restrict__ x,
                         float* __restrict__ outp) {
    __shared__ float tile[32][33];
    int b = blockIdx.z;
    int t0 = blockIdx.x * 32, c0 = blockIdx.y * 32;
    int tx = threadIdx.x, ty = threadIdx.y;
    const float* src = proj + (size_t)b * NTOK * CDIM;
#pragma unroll
    for (int j = 0; j < 4; j++)
        tile[ty + 8*j][tx] = src[(size_t)(t0 + ty + 8*j) * CDIM + c0 + tx];
    __syncthreads();
    size_t base = (size_t)b * CDIM * NTOK;
#pragma unroll
    for (int j = 0; j < 4; j++) {
        size_t o = base + (size_t)(c0 + ty + 8*j) * NTOK + t0 + tx;
        outp[o] = x[o] + tile[tx][ty + 8*j];
    }
}

// ---------- pos bilinear upsample ----------
__global__ void k_posup(const float* __restrict__ pos, float* __restrict__ outp, int OH, int OW) {
    int t = blockIdx.x, c = threadIdx.x;
    int oh = t / OW, ow = t % OW;
    float sy = (oh + 0.5f) * (32.0f / OH) - 0.5f;
    float sx = (ow + 0.5f) * (32.0f / OW) - 0.5f;
    int y0 = (int)floorf(sy); float fy = sy - y0;
    int x0 = (int)floorf(sx); float fx = sx - x0;
    int y0c = clampi(y0, 0, 31), y1c = clampi(y0 + 1, 0, 31);
    int x0c = clampi(x0, 0, 31), x1c = clampi(x0 + 1, 0, 31);
    const float* p = pos + (size_t)c * 1024;
    float v = (1.f - fy) * ((1.f - fx) * p[y0c*32 + x0c] + fx * p[y0c*32 + x1c])
            + fy * ((1.f - fx) * p[y1c*32 + x0c] + fx * p[y1c*32 + x1c]);
    outp[(size_t)t * CDIM + c] = v;
}

// ---------- pos antialiased downsample 32->16 ----------
__global__ void k_posdown(const float* __restrict__ pos, float* __restrict__ outp) {
    int t = blockIdx.x, c = threadIdx.x;
    int gh = t / 16, gw = t % 16;
    const float W4[4] = {0.125f, 0.375f, 0.375f, 0.125f};
    float wy[4], wx[4]; int ky[4], kx[4];
    float sy = 0.f, sx = 0.f;
#pragma unroll
    for (int d = 0; d < 4; d++) {
        ky[d] = 2*gh - 1 + d; wy[d] = (ky[d] >= 0 && ky[d] < 32) ? W4[d] : 0.f; sy += wy[d];
        kx[d] = 2*gw - 1 + d; wx[d] = (kx[d] >= 0 && kx[d] < 32) ? W4[d] : 0.f; sx += wx[d];
    }
    const float* p = pos + (size_t)c * 1024;
    float acc = 0.f;
#pragma unroll
    for (int d = 0; d < 4; d++) {
        if (wy[d] == 0.f) continue;
        float rowacc = 0.f;
#pragma unroll
        for (int e = 0; e < 4; e++)
            if (wx[e] != 0.f) rowacc += wx[e] * p[ky[d]*32 + kx[e]];
        acc += wy[d] * rowacc;
    }
    outp[(size_t)t * CDIM + c] = acc / (sy * sx);
}

// ---------- tf32 tensor-core GEMM, cp.async double-buffered, fused epilogues ----
// C[M,256] = sum_p A_p[M,256] @ W_p[256,256] (+bias), modes:
//   0: store   1: += P1[(r&tokmask)*256+col] (pos)   2: s=sig(t); s*P1+(1-s)*P2
//   3: P1 + sig(t)*P2
// multi: grid.z selects W (W0/W1/W2) and output (C0/C1/C2), A=A0, npairs ignored.
#define AS_STRIDE 36
#define BS_STRIDE 136
#define A_ELEMS (128*AS_STRIDE)
#define B_ELEMS (32*BS_STRIDE)
#define STAGE_ELEMS (A_ELEMS + B_ELEMS)
extern __shared__ float smx[];

__global__ void __launch_bounds__(256, 2)
k_gemm_tc(const float* __restrict__ A0, const float* __restrict__ W0,
          const float* __restrict__ A1, const float* __restrict__ W1,
          const float* __restrict__ A2, const float* __restrict__ W2,
          int npairs,
          float* __restrict__ C0, float* __restrict__ C1, float* __restrict__ C2,
          const float* __restrict__ bias, int mode,
          const float* __restrict__ P1, const float* __restrict__ P2,
          int tokmask, int multi) {
    int bx = blockIdx.x, by = blockIdx.y, bz = blockIdx.z;
    int tid = threadIdx.x;
    int warp = tid >> 5, lane = tid & 31;
    int wm = warp >> 2, wn = warp & 3;
    int g = lane >> 2, tq = lane & 3;

    uint32_t smem_u32 = (uint32_t)__cvta_generic_to_shared(smx);

    float acc[4][4][4];
#pragma unroll
    for (int i = 0; i < 4; i++)
#pragma unroll
        for (int j = 0; j < 4; j++)
#pragma unroll
            for (int r = 0; r < 4; r++) acc[i][j][r] = 0.f;

    int nst = (multi ? 1 : npairs) * 8;

    // stage loader
    auto load_stage = [&](int st, int buf) {
        int p = multi ? bz : (st >> 3);
        const float* A = multi ? A0 : selp(A0, A1, A2, p);
        const float* W = selp(W0, W1, W2, p);
        int k0 = (st & 7) * 32;
        uint32_t abase = smem_u32 + (uint32_t)(buf * STAGE_ELEMS) * 4u;
        uint32_t bbase = abase + (uint32_t)A_ELEMS * 4u;
#pragma unroll
        for (int i = 0; i < 4; i++) {
            int idx = tid + 256 * i;
            int row = idx >> 3, c4 = idx & 7;
            cpa16(abase + (uint32_t)(row * AS_STRIDE + c4 * 4) * 4u,
                  A + (size_t)(by * 128 + row) * 256 + k0 + c4 * 4);
        }
#pragma unroll
        for (int i = 0; i < 4; i++) {
            int idx = tid + 256 * i;
            int row = idx >> 5, c4 = idx & 31;
            cpa16(bbase + (uint32_t)(row * BS_STRIDE + c4 * 4) * 4u,
                  W + (size_t)(k0 + row) * 256 + bx * 128 + c4 * 4);
        }
        CP_COMMIT();
    };

    load_stage(0, 0);
    for (int st = 0; st < nst; st++) {
        int pb = st & 1;
        CP_WAIT0();
        __syncthreads();
        if (st + 1 < nst) load_stage(st + 1, pb ^ 1);
        const uint32_t* Asu = (const uint32_t*)(smx + pb * STAGE_ELEMS);
        const uint32_t* Bsu = Asu + A_ELEMS;
#pragma unroll
        for (int ks = 0; ks < 32; ks += 8) {
            uint32_t af[4][4];
#pragma unroll
            for (int mt = 0; mt < 4; mt++) {
                int mb = wm * 64 + mt * 16;
                af[mt][0] = Asu[(mb + g) * AS_STRIDE + ks + tq];
                af[mt][1] = Asu[(mb + g + 8) * AS_STRIDE + ks + tq];
                af[mt][2] = Asu[(mb + g) * AS_STRIDE + ks + tq + 4];
                af[mt][3] = Asu[(mb + g + 8) * AS_STRIDE + ks + tq + 4];
            }
            uint32_t bf[4][2];
#pragma unroll
            for (int nt = 0; nt < 4; nt++) {
                int nb = wn * 32 + nt * 8;
                bf[nt][0] = Bsu[(ks + tq) * BS_STRIDE + nb + g];
                bf[nt][1] = Bsu[(ks + tq + 4) * BS_STRIDE + nb + g];
            }
#pragma unroll
            for (int mt = 0; mt < 4; mt++)
#pragma unroll
                for (int nt = 0; nt < 4; nt++)
                    mma_tf32(acc[mt][nt], af[mt], bf[nt]);
        }
        __syncthreads();
    }

    float* C = multi ? (bz == 0 ? C0 : (bz == 1 ? C1 : C2)) : C0;
#pragma unroll
    for (int mt = 0; mt < 4; mt++) {
        int r0 = by * 128 + wm * 64 + mt * 16 + g;
#pragma unroll
        for (int nt = 0; nt < 4; nt++) {
            int col = bx * 128 + wn * 32 + nt * 8 + tq * 2;
            float b0 = 0.f, b1 = 0.f;
            if (bias) { b0 = bias[col]; b1 = bias[col + 1]; }
#pragma unroll
            for (int h = 0; h < 2; h++) {
                int r = r0 + h * 8;
                float t0 = acc[mt][nt][2*h + 0] + b0;
                float t1 = acc[mt][nt][2*h + 1] + b1;
                size_t i0 = (size_t)r * 256 + col;
                float o0, o1;
                if (mode == 0) {
                    o0 = t0; o1 = t1;
                } else if (mode == 1) {
                    size_t pi = (size_t)(r & tokmask) * 256 + col;
                    o0 = t0 + P1[pi]; o1 = t1 + P1[pi + 1];
                } else if (mode == 2) {
                    float s0 = sigf(t0), s1 = sigf(t1);
                    o0 = s0 * P1[i0] + (1.f - s0) * P2[i0];
                    o1 = s1 * P1[i0 + 1] + (1.f - s1) * P2[i0 + 1];
                } else {
                    o0 = P1[i0] + sigf(t0) * P2[i0];
                    o1 = P1[i0 + 1] + sigf(t1) * P2[i0 + 1];
                }
                *(float2*)(C + i0) = make_float2(o0, o1);
            }
        }
    }
}

// ---------- two-stage column mean ----------
__global__ void k_colmean_a(const float* __restrict__ U, float* __restrict__ part16, int chunk) {
    int j = blockIdx.x, b = blockIdx.y, c = threadIdx.x;
    const float* p = U + ((size_t)(b * gridDim.x + j) * chunk) * CDIM + c;
    float s0 = 0.f, s1 = 0.f, s2 = 0.f, s3 = 0.f;
    for (int t = 0; t < chunk; t += 4) {
        s0 += p[(size_t)t * CDIM];
        s1 += p[(size_t)(t + 1) * CDIM];
        s2 += p[(size_t)(t + 2) * CDIM];
        s3 += p[(size_t)(t + 3) * CDIM];
    }
    part16[(b * 16 + j) * 256 + c] = s0 + s1 + s2 + s3;
}
__global__ void k_colmean_b(const float* __restrict__ part16, float* __restrict__ part, float inv) {
    int b = blockIdx.x, c = threadIdx.x;
    float s = 0.f;
    for (int j = 0; j < 16; j++) s += part16[(b * 16 + j) * 256 + c];
    part[b * 256 + c] = s * inv;
}

// ---------- layernorm over channels ----------
__global__ void k_ln(const float* __restrict__ part, const float* __restrict__ g,
                     const float* __restrict__ be, float* __restrict__ cln) {
    int b = blockIdx.x, c = threadIdx.x;
    __shared__ float red[256];
    float m = part[b * 256 + c];
    red[c] = m; __syncthreads();
    for (int s = 128; s > 0; s >>= 1) { if (c < s) red[c] += red[c + s]; __syncthreads(); }
    float mu = red[0] * (1.f / 256.f); __syncthreads();
    float d = m - mu;
    red[c] = d * d; __syncthreads();
    for (int s = 128; s > 0; s >>= 1) { if (c < s) red[c] += red[c + s]; __syncthreads(); }
    float var = red[0] * (1.f / 256.f);
    cln[b * 256 + c] = d * rsqrtf(var + LN_EPS) * g[c] + be[c];
}

// ---------- per-batch gate bias ----------
__global__ void k_gatebias(const float* __restrict__ cln,
                           const float* __restrict__ Wf, const float* __restrict__ bf,
                           const float* __restrict__ Ww, const float* __restrict__ bw,
                           const float* __restrict__ Wo, const float* __restrict__ bo,
                           float* __restrict__ fb, float* __restrict__ wb, float* __restrict__ ob) {
    int which = blockIdx.x, b = blockIdx.y, c = threadIdx.x;
    __shared__ float sc[256];
    sc[c] = cln[b * 256 + c]; __syncthreads();
    const float* W  = (which == 0) ? Wf : (which == 1) ? Ww : Wo;
    const float* bi = (which == 0) ? bf : (which == 1) ? bw : bo;
    float* o        = (which == 0) ? fb : (which == 1) ? wb : ob;
    float acc = bi[c];
    for (int k = 0; k < 256; k++) acc += sc[k] * W[(size_t)(256 + k) * 256 + c];
    o[b * 256 + c] = acc;
}

// ---------- gate nonlinearities ----------
__global__ void k_gates(const float* __restrict__ U, float* __restrict__ GA,
                        float* __restrict__ GB, float* __restrict__ GO,
                        const float* __restrict__ fb, const float* __restrict__ wb,
                        const float* __restrict__ ob, int ntok) {
    int r = blockIdx.x, c = threadIdx.x;
    int b = r / ntok;
    size_t i = (size_t)r * CDIM + c;
    int bc = b * CDIM + c;
    float u = U[i];
    float araw = GA[i] + fb[bc];
    float a = 1.0f / (1.0f + expf(araw));
    float g = sigf(GB[i] + wb[bc]);
    float o = sigf(GO[i] + ob[bc]);
    GA[i] = a; GB[i] = (1.0f - a) * g * u; GO[i] = o;
}

// ---------- scan phase 1 ----------
__global__ void k_scan1(const float* __restrict__ GA, const float* __restrict__ GB,
                        float* __restrict__ AGA, float* __restrict__ ABF, float* __restrict__ ABB) {
    int j = blockIdx.x, b = blockIdx.y, c = threadIdx.x;
    size_t base = ((size_t)b * NTOK + j * 128) * CDIM + c;
    float A = 1.f, sf = 0.f;
    for (int t = 0; t < 128; t++) {
        float a = GA[base + (size_t)t * CDIM], bb = GB[base + (size_t)t * CDIM];
        A *= a; sf = a * sf + bb;
    }
    float sb = 0.f;
    for (int t = 127; t >= 0; t--) {
        float a = GA[base + (size_t)t * CDIM], bb = GB[base + (size_t)t * CDIM];
        sb = a * sb + bb;
    }
    int o = (b * 32 + j) * 256 + c;
    AGA[o] = A; ABF[o] = sf; ABB[o] = sb;
}

// ---------- scan phase 2 ----------
__global__ void k_scan2(const float* __restrict__ AGA, const float* __restrict__ ABF,
                        const float* __restrict__ ABB, float* __restrict__ SIF, float* __restrict__ SIB) {
    int b = blockIdx.x, c = threadIdx.x;
    float s = 0.f;
    for (int j = 0; j < 32; j++) {
        int o = (b * 32 + j) * 256 + c;
        SIF[o] = s; s = AGA[o] * s + ABF[o];
    }
    s = 0.f;
    for (int j = 31; j >= 0; j--) {
        int o = (b * 32 + j) * 256 + c;
        SIB[o] = s; s = AGA[o] * s + ABB[o];
    }
}

// ---------- scan phase 3 ----------
__global__ void k_scan3(const float* __restrict__ GA, const float* __restrict__ GB,
                        const float* __restrict__ GO, const float* __restrict__ U,
                        const float* __restrict__ SIF, const float* __restrict__ SIB,
                        float* __restrict__ YF, float* __restrict__ YB) {
    int j = blockIdx.x, b = blockIdx.y, c = threadIdx.x;
    size_t base = ((size_t)b * NTOK + j * 128) * CDIM + c;
    int ao = (b * 32 + j) * 256 + c;
    float s = SIF[ao];
    for (int t = 0; t < 128; t++) {
        size_t i = base + (size_t)t * CDIM;
        s = GA[i] * s + GB[i];
        float o = GO[i];
        YF[i] = o * s + (1.f - o) * U[i];
    }
    s = SIB[ao];
    for (int t = 127; t >= 0; t--) {
        size_t i = base + (size_t)t * CDIM;
        s = GA[i] * s + GB[i];
        float o = GO[i];
        YB[i] = o * s + (1.f - o) * U[i];
    }
}

// ---------- global branch serial scan ----------
__global__ void k_scanglob(const float* __restrict__ GA, const float* __restrict__ GB,
                           const float* __restrict__ GO, const float* __restrict__ U,
                           float* __restrict__ YG) {
    int b = blockIdx.x, c = threadIdx.x;
    size_t base = (size_t)b * NTOKG * CDIM + c;
    float s = 0.f;
    for (int t = 0; t < NTOKG; t++) {
        size_t i = base + (size_t)t * CDIM;
        s = GA[i] * s + GB[i];
        float o = GO[i];
        YG[i] = o * s + (1.f - o) * U[i];
    }
}

// ---------- 4x4 avg pool ----------
__global__ void k_pool(const float* __restrict__ seq, float* __restrict__ seqg) {
    int tg = blockIdx.x, b = blockIdx.y, c = threadIdx.x;
    int gh = tg / 16, gw = tg % 16;
    float s = 0.f;
#pragma unroll
    for (int i = 0; i < 4; i++)
#pragma unroll
        for (int j = 0; j < 4; j++)
            s += seq[((size_t)b * NTOK + (gh * 4 + i) * 64 + gw * 4 + j) * CDIM + c];
    seqg[((size_t)b * NTOKG + tg) * CDIM + c] = s * (1.0f / 16.0f);
}

// ---------- bilinear upsample y_g 16x16 -> 64x64 ----------
__global__ void k_upsample(const float* __restrict__ YG, float* __restrict__ YGS) {
    int t = blockIdx.x, b = blockIdx.y, c = threadIdx.x;
    int oh = t / 64, ow = t % 64;
    float sy = (oh + 0.5f) * 0.25f - 0.5f;
    float sx = (ow + 0.5f) * 0.25f - 0.5f;
    int y0 = (int)floorf(sy); float fy = sy - y0;
    int x0 = (int)floorf(sx); float fx = sx - x0;
    int y0c = clampi(y0, 0, 15), y1c = clampi(y0 + 1, 0, 15);
    int x0c = clampi(x0, 0, 15), x1c = clampi(x0 + 1, 0, 15);
    const float* base = YG + (size_t)b * NTOKG * CDIM + c;
    float v00 = base[(size_t)(y0c * 16 + x0c) * CDIM];
    float v01 = base[(size_t)(y0c * 16 + x1c) * CDIM];
    float v10 = base[(size_t)(y1c * 16 + x0c) * CDIM];
    float v11 = base[(size_t)(y1c * 16 + x1c) * CDIM];
    YGS[((size_t)b * NTOK + t) * CDIM + c] =
        (1.f - fy) * ((1.f - fx) * v00 + fx * v01) + fy * ((1.f - fx) * v10 + fx * v11);
}

// ---------- depthwise 3x3 conv ----------
__global__ void k_dwconv(const float* __restrict__ seq, const float* __restrict__ w,
                         const float* __restrict__ bias, float* __restrict__ VM) {
    int h = blockIdx.x, b = blockIdx.y, c = threadIdx.x;
    float wr[9];
#pragma unroll
    for (int k = 0; k < 9; k++) wr[k] = w[c * 9 + k];
    float bi = bias[c];
    const float* sp = seq + (size_t)b * NTOK * CDIM + c;
    for (int x = 0; x < 64; x++) {
        float acc = bi;
#pragma unroll
        for (int i = 0; i < 3; i++) {
            int hh = h + i - 1;
            if (hh < 0 || hh > 63) continue;
#pragma unroll
            for (int j = 0; j < 3; j++) {
                int ww = x + j - 1;
                if (ww < 0 || ww > 63) continue;
                acc += wr[i * 3 + j] * sp[(size_t)(hh * 64 + ww) * CDIM];
            }
        }
        VM[((size_t)b * NTOK + h * 64 + x) * CDIM + c] = acc;
    }
}

extern "C" void kernel_launch(void* const* d_in, const int* in_sizes, int n_in,
                              void* d_out, int out_size) {
    const float* x        = (const float*)d_in[0];
    const float* Wt       = (const float*)d_in[1];
    const float* bt       = (const float*)d_in[2];
    const float* pos_fine = (const float*)d_in[3];
    const float* pos_glob = (const float*)d_in[4];
    const float* ln_g     = (const float*)d_in[5];
    const float* ln_b     = (const float*)d_in[6];
    const float* Wf       = (const float*)d_in[7];
    const float* bf       = (const float*)d_in[8];
    const float* Ww       = (const float*)d_in[9];
    const float* bw       = (const float*)d_in[10];
    const float* Wo       = (const float*)d_in[11];
    const float* bo       = (const float*)d_in[12];
    const float* Wr       = (const float*)d_in[13];
    const float* br       = (const float*)d_in[14];
    const float* Wgi      = (const float*)d_in[15];
    const float* bgi      = (const float*)d_in[16];
    const float* dw_w     = (const float*)d_in[17];
    const float* dw_b     = (const float*)d_in[18];
    const float* Wl       = (const float*)d_in[19];
    const float* bl       = (const float*)d_in[20];
    const float* Wlf      = (const float*)d_in[21];
    const float* blf      = (const float*)d_in[22];
    const float* Wout     = (const float*)d_in[23];
    const float* bout     = (const float*)d_in[24];
    float* outp = (float*)d_out;

    float* S = nullptr;
    cudaGetSymbolAddress((void**)&S, g_scratch);
    float* SEQ  = S + OFF_SEQ;  float* U    = S + OFF_U;
    float* GA   = S + OFF_GA;   float* GB   = S + OFF_GB;   float* GO  = S + OFF_GO;
    float* YF   = S + OFF_YF;   float* YB   = S + OFF_YB;   float* Y   = S + OFF_Y;
    float* YGS  = S + OFF_YGS;  float* Z    = S + OFF_Z;
    float* VM   = S + OFF_VM;   float* V    = S + OFF_V;
    float* UO   = S + OFF_UOUT; float* PROJ = S + OFF_PROJ;
    float* SEQG = S + OFF_SEQG; float* UG   = S + OFF_UG;
    float* GAG  = S + OFF_GAG;  float* GBG  = S + OFF_GBG;  float* GOG = S + OFF_GOG;
    float* YG   = S + OFF_YG;
    float* POSF = S + OFF_POSF; float* POSG = S + OFF_POSG;
    float* PART = S + OFF_PART; float* PARTG = S + OFF_PARTG;
    float* CLN  = S + OFF_CLN;  float* CLNG = S + OFF_CLNG;
    float* FB = S + OFF_FB, *WB = S + OFF_WB, *OB = S + OFF_OB;
    float* FBG = S + OFF_FBG, *WBG = S + OFF_WBG, *OBG = S + OFF_OBG;
    float* AGA = S + OFF_AGA, *ABF = S + OFF_ABF, *ABB = S + OFF_ABB;
    float* SIF = S + OFF_SIF, *SIB = S + OFF_SIB;
    float* P16 = S + OFF_P16;

    static int smem_set = 0;
    int smem_bytes = 2 * STAGE_ELEMS * 4;
    if (!smem_set) {
        cudaFuncSetAttribute(k_gemm_tc, cudaFuncAttributeMaxDynamicSharedMemorySize, smem_bytes);
        smem_set = 1;
    }

    dim3 tb(32, 8);
    dim3 tg(128, 8, 8);
    dim3 gemF(2, MFINE / 128), gemG(2, MGLOB / 128);
    dim3 gemF3(2, MFINE / 128, 3), gemG3(2, MGLOB / 128, 3);
    const float* NP = nullptr;
    float* NPo = nullptr;

    // fine sequence + pos (pos add fused into GEMM epilogue, mode 1)
    k_transpose<<<tg, tb>>>(x, SEQ);
    k_posup<<<4096, 256>>>(pos_fine, POSF, 64, 64);
    k_posdown<<<256, 256>>>(pos_glob, POSG);
    k_gemm_tc<<<gemF, 256, smem_bytes>>>(SEQ, Wt, NP, NP, NP, NP, 1, U, NPo, NPo, bt, 1, POSF, NP, 4095, 0);

    // gates (fine): pooled LN context + 3 gate GEMMs in ONE launch (grid.z=3)
    k_colmean_a<<<dim3(16, BATCH), 256>>>(U, P16, 256);
    k_colmean_b<<<BATCH, 256>>>(P16, PART, 1.0f / NTOK);
    k_ln<<<BATCH, 256>>>(PART, ln_g, ln_b, CLN);
    k_gatebias<<<dim3(3, BATCH), 256>>>(CLN, Wf, bf, Ww, bw, Wo, bo, FB, WB, OB);
    k_gemm_tc<<<gemF3, 256, smem_bytes>>>(U, Wf, NP, Ww, NP, Wo, 1, GA, GB, GO, NP, 0, NP, NP, 0, 1);
    k_gates<<<MFINE, 256>>>(U, GA, GB, GO, FB, WB, OB, NTOK);

    // bidirectional chunked scan
    k_scan1<<<dim3(32, BATCH), 256>>>(GA, GB, AGA, ABF, ABB);
    k_scan2<<<BATCH, 256>>>(AGA, ABF, ABB, SIF, SIB);
    k_scan3<<<dim3(32, BATCH), 256>>>(GA, GB, GO, U, SIF, SIB, YF, YB);

    // rho mixing: 3-pair GEMM, sigmoid-mix fused (mode 2) -> Y
    k_gemm_tc<<<gemF, 256, smem_bytes>>>(U, Wr, YF, Wr + 65536, YB, Wr + 131072, 3, Y, NPo, NPo, br, 2, YF, YB, 0, 0);

    // global branch
    k_pool<<<dim3(256, BATCH), 256>>>(SEQ, SEQG);
    k_gemm_tc<<<gemG, 256, smem_bytes>>>(SEQG, Wt, NP, NP, NP, NP, 1, UG, NPo, NPo, bt, 1, POSG, NP, 255, 0);
    k_colmean_a<<<dim3(16, BATCH), 256>>>(UG, P16, 16);
    k_colmean_b<<<BATCH, 256>>>(P16, PARTG, 1.0f / NTOKG);
    k_ln<<<BATCH, 256>>>(PARTG, ln_g, ln_b, CLNG);
    k_gatebias<<<dim3(3, BATCH), 256>>>(CLNG, Wf, bf, Ww, bw, Wo, bo, FBG, WBG, OBG);
    k_gemm_tc<<<gemG3, 256, smem_bytes>>>(UG, Wf, NP, Ww, NP, Wo, 1, GAG, GBG, GOG, NP, 0, NP, NP, 0, 1);
    k_gates<<<MGLOB, 256>>>(UG, GAG, GBG, GOG, FBG, WBG, OBG, NTOKG);
    k_scanglob<<<BATCH, 256>>>(GAG, GBG, GOG, UG, YG);
    k_upsample<<<dim3(4096, BATCH), 256>>>(YG, YGS);

    // lam mixing: 3-pair GEMM, lam-add fused (mode 3) -> Z
    k_gemm_tc<<<gemF, 256, smem_bytes>>>(Y, Wgi, YGS, Wgi + 65536, U, Wgi + 131072, 3, Z, NPo, NPo, bgi, 3, Y, YGS, 0, 0);

    // local depthwise branch; eta sigmoid-mix fused (mode 2) -> UO
    k_dwconv<<<dim3(64, BATCH), 256>>>(SEQ, dw_w, dw_b, VM);
    k_gemm_tc<<<gemF, 256, smem_bytes>>>(VM, Wl, NP, NP, NP, NP, 1, V, NPo, NPo, bl, 0, NP, NP, 0, 0);
    k_gemm_tc<<<gemF, 256, smem_bytes>>>(V, Wlf, Z, Wlf + 65536, NP, NP, 2, UO, NPo, NPo, blf, 2, V, Z, 0, 0);

    // output proj + residual
    k_gemm_tc<<<gemF, 256, smem_bytes>>>(UO, Wout, NP, NP, NP, NP, 1, PROJ, NPo, NPo, bout, 0, NP, NP, 0, 0);
    k_output<<<tg, tb>>>(PROJ, x, outp);
}

// round 6
// speedup vs baseline: 2.9915x; 1.3902x over previous
#include <cuda_runtime.h>
#include <math.h>
#include <stdint.h>

#define BATCH 8
#define CDIM  256
#define NTOK  4096
#define NTOKG 256
#define MFINE 32768
#define MGLOB 2048
#define LN_EPS 1e-5f

static const size_t U_SZ  = (size_t)MFINE * CDIM;
static const size_t SG_SZ = (size_t)MGLOB * CDIM;

static const size_t OFF_SEQ   = 0*U_SZ;
static const size_t OFF_U     = 1*U_SZ;
static const size_t OFF_GA    = 2*U_SZ;
static const size_t OFF_GB    = 3*U_SZ;
static const size_t OFF_GO    = 4*U_SZ;
static const size_t OFF_YF    = 5*U_SZ;
static const size_t OFF_YB    = 6*U_SZ;
static const size_t OFF_Y     = 7*U_SZ;
static const size_t OFF_YGS   = 8*U_SZ;
static const size_t OFF_Z     = 9*U_SZ;
static const size_t OFF_VM    = 10*U_SZ;
static const size_t OFF_V     = 11*U_SZ;
static const size_t OFF_UOUT  = 12*U_SZ;
static const size_t OFF_PROJ  = 13*U_SZ;
static const size_t SMALL0    = 14*U_SZ;
static const size_t OFF_SEQG  = SMALL0 + 0*SG_SZ;
static const size_t OFF_UG    = SMALL0 + 1*SG_SZ;
static const size_t OFF_GAG   = SMALL0 + 2*SG_SZ;
static const size_t OFF_GBG   = SMALL0 + 3*SG_SZ;
static const size_t OFF_GOG   = SMALL0 + 4*SG_SZ;
static const size_t OFF_YG    = SMALL0 + 5*SG_SZ;
static const size_t SMALL1    = SMALL0 + 6*SG_SZ;
static const size_t OFF_POSF  = SMALL1;
static const size_t OFF_POSG  = OFF_POSF + 4096*256;
static const size_t OFF_PART  = OFF_POSG + 65536;
static const size_t OFF_PARTG = OFF_PART + 2048;
static const size_t OFF_CLN   = OFF_PARTG + 2048;
static const size_t OFF_CLNG  = OFF_CLN + 2048;
static const size_t OFF_FB    = OFF_CLNG + 2048;
static const size_t OFF_WB    = OFF_FB + 2048;
static const size_t OFF_OB    = OFF_WB + 2048;
static const size_t OFF_FBG   = OFF_OB + 2048;
static const size_t OFF_WBG   = OFF_FBG + 2048;
static const size_t OFF_OBG   = OFF_WBG + 2048;
static const size_t OFF_AGA   = OFF_OBG + 2048;
static const size_t OFF_ABF   = OFF_AGA + 65536;
static const size_t OFF_ABB   = OFF_ABF + 65536;
static const size_t OFF_SIF   = OFF_ABB + 65536;
static const size_t OFF_SIB   = OFF_SIF + 65536;
static const size_t OFF_P16   = OFF_SIB + 65536;           // 8*16*256
static const size_t TOTAL_SCRATCH = OFF_P16 + 32768 + 1024;

__device__ __align__(16) float g_scratch[TOTAL_SCRATCH];

__device__ __forceinline__ float sigf(float x) { return 1.0f / (1.0f + expf(-x)); }
__device__ __forceinline__ int clampi(int v, int lo, int hi) { return v < lo ? lo : (v > hi ? hi : v); }

__device__ __forceinline__ void mma_tf32(float* c, const uint32_t* a, const uint32_t* b) {
    asm volatile(
        "mma.sync.aligned.m16n8k8.row.col.f32.tf32.tf32.f32 "
        "{%0,%1,%2,%3}, {%4,%5,%6,%7}, {%8,%9}, {%0,%1,%2,%3};\n"
        : "+f"(c[0]), "+f"(c[1]), "+f"(c[2]), "+f"(c[3])
        : "r"(a[0]), "r"(a[1]), "r"(a[2]), "r"(a[3]), "r"(b[0]), "r"(b[1]));
}

__device__ __forceinline__ void cpa16(uint32_t dst, const void* src) {
    asm volatile("cp.async.cg.shared.global [%0], [%1], 16;" :: "r"(dst), "l"(src));
}
#define CP_COMMIT() asm volatile("cp.async.commit_group;")
#define CP_WAIT1()  asm volatile("cp.async.wait_group 1;")

__device__ __forceinline__ const float* selp(const float* a0, const float* a1,
                                             const float* a2, int p) {
    return p == 0 ? a0 : (p == 1 ? a1 : a2);
}

// ---------- x [B,C,4096] -> seq [B*4096, C] ----------
__global__ void k_transpose(const float* __restrict__ x, float* __restrict__ seq) {
    __shared__ float tile[32][33];
    int b = blockIdx.z;
    int t0 = blockIdx.x * 32, c0 = blockIdx.y * 32;
    int tx = threadIdx.x, ty = threadIdx.y;
    const float* src = x + (size_t)b * CDIM * NTOK;
#pragma unroll
    for (int j = 0; j < 4; j++)
        tile[ty + 8*j][tx] = src[(size_t)(c0 + ty + 8*j) * NTOK + t0 + tx];
    __syncthreads();
    float* dst = seq + (size_t)b * NTOK * CDIM;
#pragma unroll
    for (int j = 0; j < 4; j++)
        dst[(size_t)(t0 + ty + 8*j) * CDIM + c0 + tx] = tile[tx][ty + 8*j];
}

// ---------- proj [B,4096,C] + x -> out [B,C,4096] ----------
__global__ void k_output(const float* __restrict__ proj, const float* __restrict__ x,
                         float* __restrict__ outp) {
    __shared__ float tile[32][33];
    int b = blockIdx.z;
    int t0 = blockIdx.x * 32, c0 = blockIdx.y * 32;
    int tx = threadIdx.x, ty = threadIdx.y;
    const float* src = proj + (size_t)b * NTOK * CDIM;
#pragma unroll
    for (int j = 0; j < 4; j++)
        tile[ty + 8*j][tx] = src[(size_t)(t0 + ty + 8*j) * CDIM + c0 + tx];
    __syncthreads();
    size_t base = (size_t)b * CDIM * NTOK;
#pragma unroll
    for (int j = 0; j < 4; j++) {
        size_t o = base + (size_t)(c0 + ty + 8*j) * NTOK + t0 + tx;
        outp[o] = x[o] + tile[tx][ty + 8*j];
    }
}

// ---------- pos bilinear upsample ----------
__global__ void k_posup(const float* __restrict__ pos, float* __restrict__ outp, int OH, int OW) {
    int t = blockIdx.x, c = threadIdx.x;
    int oh = t / OW, ow = t % OW;
    float sy = (oh + 0.5f) * (32.0f / OH) - 0.5f;
    float sx = (ow + 0.5f) * (32.0f / OW) - 0.5f;
    int y0 = (int)floorf(sy); float fy = sy - y0;
    int x0 = (int)floorf(sx); float fx = sx - x0;
    int y0c = clampi(y0, 0, 31), y1c = clampi(y0 + 1, 0, 31);
    int x0c = clampi(x0, 0, 31), x1c = clampi(x0 + 1, 0, 31);
    const float* p = pos + (size_t)c * 1024;
    float v = (1.f - fy) * ((1.f - fx) * p[y0c*32 + x0c] + fx * p[y0c*32 + x1c])
            + fy * ((1.f - fx) * p[y1c*32 + x0c] + fx * p[y1c*32 + x1c]);
    outp[(size_t)t * CDIM + c] = v;
}

// ---------- pos antialiased downsample 32->16 ----------
__global__ void k_posdown(const float* __restrict__ pos, float* __restrict__ outp) {
    int t = blockIdx.x, c = threadIdx.x;
    int gh = t / 16, gw = t % 16;
    const float W4[4] = {0.125f, 0.375f, 0.375f, 0.125f};
    float wy[4], wx[4]; int ky[4], kx[4];
    float sy = 0.f, sx = 0.f;
#pragma unroll
    for (int d = 0; d < 4; d++) {
        ky[d] = 2*gh - 1 + d; wy[d] = (ky[d] >= 0 && ky[d] < 32) ? W4[d] : 0.f; sy += wy[d];
        kx[d] = 2*gw - 1 + d; wx[d] = (kx[d] >= 0 && kx[d] < 32) ? W4[d] : 0.f; sx += wx[d];
    }
    const float* p = pos + (size_t)c * 1024;
    float acc = 0.f;
#pragma unroll
    for (int d = 0; d < 4; d++) {
        if (wy[d] == 0.f) continue;
        float rowacc = 0.f;
#pragma unroll
        for (int e = 0; e < 4; e++)
            if (wx[e] != 0.f) rowacc += wx[e] * p[ky[d]*32 + kx[e]];
        acc += wy[d] * rowacc;
    }
    outp[(size_t)t * CDIM + c] = acc / (sy * sx);
}

// ---------- tf32 tensor-core GEMM, 3-stage cp.async pipeline, fused epilogues ----
#define AS_STRIDE 36
#define BS_STRIDE 136
#define A_ELEMS (128*AS_STRIDE)
#define B_ELEMS (32*BS_STRIDE)
#define STAGE_ELEMS (A_ELEMS + B_ELEMS)
#define NSTAGE 3
extern __shared__ float smx[];

__global__ void __launch_bounds__(256, 2)
k_gemm_tc(const float* __restrict__ A0, const float* __restrict__ W0,
          const float* __restrict__ A1, const float* __restrict__ W1,
          const float* __restrict__ A2, const float* __restrict__ W2,
          int npairs,
          float* __restrict__ C0, float* __restrict__ C1, float* __restrict__ C2,
          const float* __restrict__ bias, int mode,
          const float* __restrict__ P1, const float* __restrict__ P2,
          int tokmask, int multi) {
    int bx = blockIdx.x, by = blockIdx.y, bz = blockIdx.z;
    int tid = threadIdx.x;
    int warp = tid >> 5, lane = tid & 31;
    int wm = warp >> 2, wn = warp & 3;
    int g = lane >> 2, tq = lane & 3;

    uint32_t smem_u32 = (uint32_t)__cvta_generic_to_shared(smx);

    float acc[4][4][4];
#pragma unroll
    for (int i = 0; i < 4; i++)
#pragma unroll
        for (int j = 0; j < 4; j++)
#pragma unroll
            for (int r = 0; r < 4; r++) acc[i][j][r] = 0.f;

    int nst = (multi ? 1 : npairs) * 8;

    auto load_stage = [&](int st, int buf) {
        int p = multi ? bz : (st >> 3);
        const float* A = multi ? A0 : selp(A0, A1, A2, p);
        const float* W = selp(W0, W1, W2, p);
        int k0 = (st & 7) * 32;
        uint32_t abase = smem_u32 + (uint32_t)(buf * STAGE_ELEMS) * 4u;
        uint32_t bbase = abase + (uint32_t)A_ELEMS * 4u;
#pragma unroll
        for (int i = 0; i < 4; i++) {
            int idx = tid + 256 * i;
            int row = idx >> 3, c4 = idx & 7;
            cpa16(abase + (uint32_t)(row * AS_STRIDE + c4 * 4) * 4u,
                  A + (size_t)(by * 128 + row) * 256 + k0 + c4 * 4);
        }
#pragma unroll
        for (int i = 0; i < 4; i++) {
            int idx = tid + 256 * i;
            int row = idx >> 5, c4 = idx & 31;
            cpa16(bbase + (uint32_t)(row * BS_STRIDE + c4 * 4) * 4u,
                  W + (size_t)(k0 + row) * 256 + bx * 128 + c4 * 4);
        }
        CP_COMMIT();
    };

    // prologue: stages 0 and 1 in flight
    load_stage(0, 0);
    load_stage(1, 1);

    for (int st = 0; st < nst; st++) {
        CP_WAIT1();                 // stage st's group complete (<=1 pending)
        __syncthreads();            // prev compute done -> safe to overwrite its buffer
        int nx = st + NSTAGE - 1;
        if (nx < nst) load_stage(nx, nx % NSTAGE);
        else CP_COMMIT();           // keep wait_group arithmetic exact at the tail

        int pb = st % NSTAGE;
        const uint32_t* Asu = (const uint32_t*)(smx + pb * STAGE_ELEMS);
        const uint32_t* Bsu = Asu + A_ELEMS;
#pragma unroll
        for (int ks = 0; ks < 32; ks += 8) {
            uint32_t af[4][4];
#pragma unroll
            for (int mt = 0; mt < 4; mt++) {
                int mb = wm * 64 + mt * 16;
                af[mt][0] = Asu[(mb + g) * AS_STRIDE + ks + tq];
                af[mt][1] = Asu[(mb + g + 8) * AS_STRIDE + ks + tq];
                af[mt][2] = Asu[(mb + g) * AS_STRIDE + ks + tq + 4];
                af[mt][3] = Asu[(mb + g + 8) * AS_STRIDE + ks + tq + 4];
            }
            uint32_t bf[4][2];
#pragma unroll
            for (int nt = 0; nt < 4; nt++) {
                int nb = wn * 32 + nt * 8;
                bf[nt][0] = Bsu[(ks + tq) * BS_STRIDE + nb + g];
                bf[nt][1] = Bsu[(ks + tq + 4) * BS_STRIDE + nb + g];
            }
#pragma unroll
            for (int mt = 0; mt < 4; mt++)
#pragma unroll
                for (int nt = 0; nt < 4; nt++)
                    mma_tf32(acc[mt][nt], af[mt], bf[nt]);
        }
    }

    float* C = multi ? (bz == 0 ? C0 : (bz == 1 ? C1 : C2)) : C0;
#pragma unroll
    for (int mt = 0; mt < 4; mt++) {
        int r0 = by * 128 + wm * 64 + mt * 16 + g;
#pragma unroll
        for (int nt = 0; nt < 4; nt++) {
            int col = bx * 128 + wn * 32 + nt * 8 + tq * 2;
            float b0 = 0.f, b1 = 0.f;
            if (bias) { b0 = bias[col]; b1 = bias[col + 1]; }
#pragma unroll
            for (int h = 0; h < 2; h++) {
                int r = r0 + h * 8;
                float t0 = acc[mt][nt][2*h + 0] + b0;
                float t1 = acc[mt][nt][2*h + 1] + b1;
                size_t i0 = (size_t)r * 256 + col;
                float o0, o1;
                if (mode == 0) {
                    o0 = t0; o1 = t1;
                } else if (mode == 1) {
                    size_t pi = (size_t)(r & tokmask) * 256 + col;
                    o0 = t0 + P1[pi]; o1 = t1 + P1[pi + 1];
                } else if (mode == 2) {
                    float s0 = sigf(t0), s1 = sigf(t1);
                    o0 = s0 * P1[i0] + (1.f - s0) * P2[i0];
                    o1 = s1 * P1[i0 + 1] + (1.f - s1) * P2[i0 + 1];
                } else {
                    o0 = P1[i0] + sigf(t0) * P2[i0];
                    o1 = P1[i0 + 1] + sigf(t1) * P2[i0 + 1];
                }
                *(float2*)(C + i0) = make_float2(o0, o1);
            }
        }
    }
}

// ---------- column-mean stage A ----------
__global__ void k_colmean_a(const float* __restrict__ U, float* __restrict__ part16, int chunk) {
    int j = blockIdx.x, b = blockIdx.y, c = threadIdx.x;
    const float* p = U + ((size_t)(b * gridDim.x + j) * chunk) * CDIM + c;
    float s0 = 0.f, s1 = 0.f, s2 = 0.f, s3 = 0.f;
    for (int t = 0; t < chunk; t += 4) {
        s0 += p[(size_t)t * CDIM];
        s1 += p[(size_t)(t + 1) * CDIM];
        s2 += p[(size_t)(t + 2) * CDIM];
        s3 += p[(size_t)(t + 3) * CDIM];
    }
    part16[(b * 16 + j) * 256 + c] = s0 + s1 + s2 + s3;
}

// ---------- fused: final mean reduce + layernorm ----------
__global__ void k_ctx(const float* __restrict__ part16, float inv,
                      const float* __restrict__ g, const float* __restrict__ be,
                      float* __restrict__ cln) {
    int b = blockIdx.x, c = threadIdx.x;
    __shared__ float red[256];
    float m = 0.f;
    for (int j = 0; j < 16; j++) m += part16[(b * 16 + j) * 256 + c];
    m *= inv;
    red[c] = m; __syncthreads();
    for (int s = 128; s > 0; s >>= 1) { if (c < s) red[c] += red[c + s]; __syncthreads(); }
    float mu = red[0] * (1.f / 256.f); __syncthreads();
    float d = m - mu;
    red[c] = d * d; __syncthreads();
    for (int s = 128; s > 0; s >>= 1) { if (c < s) red[c] += red[c + s]; __syncthreads(); }
    float var = red[0] * (1.f / 256.f);
    cln[b * 256 + c] = d * rsqrtf(var + LN_EPS) * g[c] + be[c];
}

// ---------- per-batch gate bias ----------
__global__ void k_gatebias(const float* __restrict__ cln,
                           const float* __restrict__ Wf, const float* __restrict__ bf,
                           const float* __restrict__ Ww, const float* __restrict__ bw,
                           const float* __restrict__ Wo, const float* __restrict__ bo,
                           float* __restrict__ fb, float* __restrict__ wb, float* __restrict__ ob) {
    int which = blockIdx.x, b = blockIdx.y, c = threadIdx.x;
    __shared__ float sc[256];
    sc[c] = cln[b * 256 + c]; __syncthreads();
    const float* W  = (which == 0) ? Wf : (which == 1) ? Ww : Wo;
    const float* bi = (which == 0) ? bf : (which == 1) ? bw : bo;
    float* o        = (which == 0) ? fb : (which == 1) ? wb : ob;
    float acc = bi[c];
    for (int k = 0; k < 256; k++) acc += sc[k] * W[(size_t)(256 + k) * 256 + c];
    o[b * 256 + c] = acc;
}

// ---------- gate nonlinearities ----------
__global__ void k_gates(const float* __restrict__ U, float* __restrict__ GA,
                        float* __restrict__ GB, float* __restrict__ GO,
                        const float* __restrict__ fb, const float* __restrict__ wb,
                        const float* __restrict__ ob, int ntok) {
    int r = blockIdx.x, c = threadIdx.x;
    int b = r / ntok;
    size_t i = (size_t)r * CDIM + c;
    int bc = b * CDIM + c;
    float u = U[i];
    float araw = GA[i] + fb[bc];
    float a = 1.0f / (1.0f + expf(araw));
    float g = sigf(GB[i] + wb[bc]);
    float o = sigf(GO[i] + ob[bc]);
    GA[i] = a; GB[i] = (1.0f - a) * g * u; GO[i] = o;
}

// ---------- scan phase 1 ----------
__global__ void k_scan1(const float* __restrict__ GA, const float* __restrict__ GB,
                        float* __restrict__ AGA, float* __restrict__ ABF, float* __restrict__ ABB) {
    int j = blockIdx.x, b = blockIdx.y, c = threadIdx.x;
    size_t base = ((size_t)b * NTOK + j * 128) * CDIM + c;
    float A = 1.f, sf = 0.f;
    for (int t = 0; t < 128; t++) {
        float a = GA[base + (size_t)t * CDIM], bb = GB[base + (size_t)t * CDIM];
        A *= a; sf = a * sf + bb;
    }
    float sb = 0.f;
    for (int t = 127; t >= 0; t--) {
        float a = GA[base + (size_t)t * CDIM], bb = GB[base + (size_t)t * CDIM];
        sb = a * sb + bb;
    }
    int o = (b * 32 + j) * 256 + c;
    AGA[o] = A; ABF[o] = sf; ABB[o] = sb;
}

// ---------- scan phase 2 ----------
__global__ void k_scan2(const float* __restrict__ AGA, const float* __restrict__ ABF,
                        const float* __restrict__ ABB, float* __restrict__ SIF, float* __restrict__ SIB) {
    int b = blockIdx.x, c = threadIdx.x;
    float s = 0.f;
    for (int j = 0; j < 32; j++) {
        int o = (b * 32 + j) * 256 + c;
        SIF[o] = s; s = AGA[o] * s + ABF[o];
    }
    s = 0.f;
    for (int j = 31; j >= 0; j--) {
        int o = (b * 32 + j) * 256 + c;
        SIB[o] = s; s = AGA[o] * s + ABB[o];
    }
}

// ---------- scan phase 3 ----------
__global__ void k_scan3(const float* __restrict__ GA, const float* __restrict__ GB,
                        const float* __restrict__ GO, const float* __restrict__ U,
                        const float* __restrict__ SIF, const float* __restrict__ SIB,
                        float* __restrict__ YF, float* __restrict__ YB) {
    int j = blockIdx.x, b = blockIdx.y, c = threadIdx.x;
    size_t base = ((size_t)b * NTOK + j * 128) * CDIM + c;
    int ao = (b * 32 + j) * 256 + c;
    float s = SIF[ao];
    for (int t = 0; t < 128; t++) {
        size_t i = base + (size_t)t * CDIM;
        s = GA[i] * s + GB[i];
        float o = GO[i];
        YF[i] = o * s + (1.f - o) * U[i];
    }
    s = SIB[ao];
    for (int t = 127; t >= 0; t--) {
        size_t i = base + (size_t)t * CDIM;
        s = GA[i] * s + GB[i];
        float o = GO[i];
        YB[i] = o * s + (1.f - o) * U[i];
    }
}

// ---------- global branch serial scan ----------
__global__ void k_scanglob(const float* __restrict__ GA, const float* __restrict__ GB,
                           const float* __restrict__ GO, const float* __restrict__ U,
                           float* __restrict__ YG) {
    int b = blockIdx.x, c = threadIdx.x;
    size_t base = (size_t)b * NTOKG * CDIM + c;
    float s = 0.f;
    for (int t = 0; t < NTOKG; t++) {
        size_t i = base + (size_t)t * CDIM;
        s = GA[i] * s + GB[i];
        float o = GO[i];
        YG[i] = o * s + (1.f - o) * U[i];
    }
}

// ---------- 4x4 avg pool ----------
__global__ void k_pool(const float* __restrict__ seq, float* __restrict__ seqg) {
    int tg = blockIdx.x, b = blockIdx.y, c = threadIdx.x;
    int gh = tg / 16, gw = tg % 16;
    float s = 0.f;
#pragma unroll
    for (int i = 0; i < 4; i++)
#pragma unroll
        for (int j = 0; j < 4; j++)
            s += seq[((size_t)b * NTOK + (gh * 4 + i) * 64 + gw * 4 + j) * CDIM + c];
    seqg[((size_t)b * NTOKG + tg) * CDIM + c] = s * (1.0f / 16.0f);
}

// ---------- bilinear upsample y_g 16x16 -> 64x64 ----------
__global__ void k_upsample(const float* __restrict__ YG, float* __restrict__ YGS) {
    int t = blockIdx.x, b = blockIdx.y, c = threadIdx.x;
    int oh = t / 64, ow = t % 64;
    float sy = (oh + 0.5f) * 0.25f - 0.5f;
    float sx = (ow + 0.5f) * 0.25f - 0.5f;
    int y0 = (int)floorf(sy); float fy = sy - y0;
    int x0 = (int)floorf(sx); float fx = sx - x0;
    int y0c = clampi(y0, 0, 15), y1c = clampi(y0 + 1, 0, 15);
    int x0c = clampi(x0, 0, 15), x1c = clampi(x0 + 1, 0, 15);
    const float* base = YG + (size_t)b * NTOKG * CDIM + c;
    float v00 = base[(size_t)(y0c * 16 + x0c) * CDIM];
    float v01 = base[(size_t)(y0c * 16 + x1c) * CDIM];
    float v10 = base[(size_t)(y1c * 16 + x0c) * CDIM];
    float v11 = base[(size_t)(y1c * 16 + x1c) * CDIM];
    YGS[((size_t)b * NTOK + t) * CDIM + c] =
        (1.f - fy) * ((1.f - fx) * v00 + fx * v01) + fy * ((1.f - fx) * v10 + fx * v11);
}

// ---------- depthwise 3x3 conv ----------
__global__ void k_dwconv(const float* __restrict__ seq, const float* __restrict__ w,
                         const float* __restrict__ bias, float* __restrict__ VM) {
    int h = blockIdx.x, b = blockIdx.y, c = threadIdx.x;
    float wr[9];
#pragma unroll
    for (int k = 0; k < 9; k++) wr[k] = w[c * 9 + k];
    float bi = bias[c];
    const float* sp = seq + (size_t)b * NTOK * CDIM + c;
    for (int x = 0; x < 64; x++) {
        float acc = bi;
#pragma unroll
        for (int i = 0; i < 3; i++) {
            int hh = h + i - 1;
            if (hh < 0 || hh > 63) continue;
#pragma unroll
            for (int j = 0; j < 3; j++) {
                int ww = x + j - 1;
                if (ww < 0 || ww > 63) continue;
                acc += wr[i * 3 + j] * sp[(size_t)(hh * 64 + ww) * CDIM];
            }
        }
        VM[((size_t)b * NTOK + h * 64 + x) * CDIM + c] = acc;
    }
}

extern "C" void kernel_launch(void* const* d_in, const int* in_sizes, int n_in,
                              void* d_out, int out_size) {
    const float* x        = (const float*)d_in[0];
    const float* Wt       = (const float*)d_in[1];
    const float* bt       = (const float*)d_in[2];
    const float* pos_fine = (const float*)d_in[3];
    const float* pos_glob = (const float*)d_in[4];
    const float* ln_g     = (const float*)d_in[5];
    const float* ln_b     = (const float*)d_in[6];
    const float* Wf       = (const float*)d_in[7];
    const float* bf       = (const float*)d_in[8];
    const float* Ww       = (const float*)d_in[9];
    const float* bw       = (const float*)d_in[10];
    const float* Wo       = (const float*)d_in[11];
    const float* bo       = (const float*)d_in[12];
    const float* Wr       = (const float*)d_in[13];
    const float* br       = (const float*)d_in[14];
    const float* Wgi      = (const float*)d_in[15];
    const float* bgi      = (const float*)d_in[16];
    const float* dw_w     = (const float*)d_in[17];
    const float* dw_b     = (const float*)d_in[18];
    const float* Wl       = (const float*)d_in[19];
    const float* bl       = (const float*)d_in[20];
    const float* Wlf      = (const float*)d_in[21];
    const float* blf      = (const float*)d_in[22];
    const float* Wout     = (const float*)d_in[23];
    const float* bout     = (const float*)d_in[24];
    float* outp = (float*)d_out;

    float* S = nullptr;
    cudaGetSymbolAddress((void**)&S, g_scratch);
    float* SEQ  = S + OFF_SEQ;  float* U    = S + OFF_U;
    float* GA   = S + OFF_GA;   float* GB   = S + OFF_GB;   float* GO  = S + OFF_GO;
    float* YF   = S + OFF_YF;   float* YB   = S + OFF_YB;   float* Y   = S + OFF_Y;
    float* YGS  = S + OFF_YGS;  float* Z    = S + OFF_Z;
    float* VM   = S + OFF_VM;   float* V    = S + OFF_V;
    float* UO   = S + OFF_UOUT; float* PROJ = S + OFF_PROJ;
    float* SEQG = S + OFF_SEQG; float* UG   = S + OFF_UG;
    float* GAG  = S + OFF_GAG;  float* GBG  = S + OFF_GBG;  float* GOG = S + OFF_GOG;
    float* YG   = S + OFF_YG;
    float* POSF = S + OFF_POSF; float* POSG = S + OFF_POSG;
    float* CLN  = S + OFF_CLN;  float* CLNG = S + OFF_CLNG;
    float* FB = S + OFF_FB, *WB = S + OFF_WB, *OB = S + OFF_OB;
    float* FBG = S + OFF_FBG, *WBG = S + OFF_WBG, *OBG = S + OFF_OBG;
    float* AGA = S + OFF_AGA, *ABF = S + OFF_ABF, *ABB = S + OFF_ABB;
    float* SIF = S + OFF_SIF, *SIB = S + OFF_SIB;
    float* P16 = S + OFF_P16;

    static int smem_set = 0;
    int smem_bytes = NSTAGE * STAGE_ELEMS * 4;
    if (!smem_set) {
        cudaFuncSetAttribute(k_gemm_tc, cudaFuncAttributeMaxDynamicSharedMemorySize, smem_bytes);
        smem_set = 1;
    }

    dim3 tb(32, 8);
    dim3 tg(128, 8, 8);
    dim3 gemF(2, MFINE / 128), gemG(2, MGLOB / 128);
    dim3 gemF3(2, MFINE / 128, 3), gemG3(2, MGLOB / 128, 3);
    const float* NP = nullptr;
    float* NPo = nullptr;

    // fine sequence + pos (pos add fused into GEMM epilogue, mode 1)
    k_transpose<<<tg, tb>>>(x, SEQ);
    k_posup<<<4096, 256>>>(pos_fine, POSF, 64, 64);
    k_posdown<<<256, 256>>>(pos_glob, POSG);
    k_gemm_tc<<<gemF, 256, smem_bytes>>>(SEQ, Wt, NP, NP, NP, NP, 1, U, NPo, NPo, bt, 1, POSF, NP, 4095, 0);

    // gates (fine)
    k_colmean_a<<<dim3(16, BATCH), 256>>>(U, P16, 256);
    k_ctx<<<BATCH, 256>>>(P16, 1.0f / NTOK, ln_g, ln_b, CLN);
    k_gatebias<<<dim3(3, BATCH), 256>>>(CLN, Wf, bf, Ww, bw, Wo, bo, FB, WB, OB);
    k_gemm_tc<<<gemF3, 256, smem_bytes>>>(U, Wf, NP, Ww, NP, Wo, 1, GA, GB, GO, NP, 0, NP, NP, 0, 1);
    k_gates<<<MFINE, 256>>>(U, GA, GB, GO, FB, WB, OB, NTOK);

    // bidirectional chunked scan
    k_scan1<<<dim3(32, BATCH), 256>>>(GA, GB, AGA, ABF, ABB);
    k_scan2<<<BATCH, 256>>>(AGA, ABF, ABB, SIF, SIB);
    k_scan3<<<dim3(32, BATCH), 256>>>(GA, GB, GO, U, SIF, SIB, YF, YB);

    // rho mixing: 3-pair GEMM, sigmoid-mix fused (mode 2) -> Y
    k_gemm_tc<<<gemF, 256, smem_bytes>>>(U, Wr, YF, Wr + 65536, YB, Wr + 131072, 3, Y, NPo, NPo, br, 2, YF, YB, 0, 0);

    // global branch
    k_pool<<<dim3(256, BATCH), 256>>>(SEQ, SEQG);
    k_gemm_tc<<<gemG, 256, smem_bytes>>>(SEQG, Wt, NP, NP, NP, NP, 1, UG, NPo, NPo, bt, 1, POSG, NP, 255, 0);
    k_colmean_a<<<dim3(16, BATCH), 256>>>(UG, P16, 16);
    k_ctx<<<BATCH, 256>>>(P16, 1.0f / NTOKG, ln_g, ln_b, CLNG);
    k_gatebias<<<dim3(3, BATCH), 256>>>(CLNG, Wf, bf, Ww, bw, Wo, bo, FBG, WBG, OBG);
    k_gemm_tc<<<gemG3, 256, smem_bytes>>>(UG, Wf, NP, Ww, NP, Wo, 1, GAG, GBG, GOG, NP, 0, NP, NP, 0, 1);
    k_gates<<<MGLOB, 256>>>(UG, GAG, GBG, GOG, FBG, WBG, OBG, NTOKG);
    k_scanglob<<<BATCH, 256>>>(GAG, GBG, GOG, UG, YG);
    k_upsample<<<dim3(4096, BATCH), 256>>>(YG, YGS);

    // lam mixing: 3-pair GEMM, lam-add fused (mode 3) -> Z
    k_gemm_tc<<<gemF, 256, smem_bytes>>>(Y, Wgi, YGS, Wgi + 65536, U, Wgi + 131072, 3, Z, NPo, NPo, bgi, 3, Y, YGS, 0, 0);

    // local depthwise branch; eta sigmoid-mix fused (mode 2) -> UO
    k_dwconv<<<dim3(64, BATCH), 256>>>(SEQ, dw_w, dw_b, VM);
    k_gemm_tc<<<gemF, 256, smem_bytes>>>(VM, Wl, NP, NP, NP, NP, 1, V, NPo, NPo, bl, 0, NP, NP, 0, 0);
    k_gemm_tc<<<gemF, 256, smem_bytes>>>(V, Wlf, Z, Wlf + 65536, NP, NP, 2, UO, NPo, NPo, blf, 2, V, Z, 0, 0);

    // output proj + residual
    k_gemm_tc<<<gemF, 256, smem_bytes>>>(UO, Wout, NP, NP, NP, NP, 1, PROJ, NPo, NPo, bout, 0, NP, NP, 0, 0);
    k_output<<<tg, tb>>>(PROJ, x, outp);
}

// round 9
// speedup vs baseline: 3.1432x; 1.0507x over previous
#include <cuda_runtime.h>
#include <math.h>
#include <stdint.h>

#define BATCH 8
#define CDIM  256
#define NTOK  4096
#define NTOKG 256
#define MFINE 32768
#define MGLOB 2048
#define LN_EPS 1e-5f

static const size_t U_SZ  = (size_t)MFINE * CDIM;
static const size_t SG_SZ = (size_t)MGLOB * CDIM;

static const size_t OFF_SEQ   = 0*U_SZ;
static const size_t OFF_U     = 1*U_SZ;
static const size_t OFF_GA    = 2*U_SZ;
static const size_t OFF_GB    = 3*U_SZ;
static const size_t OFF_GO    = 4*U_SZ;
static const size_t OFF_YF    = 5*U_SZ;
static const size_t OFF_YB    = 6*U_SZ;
static const size_t OFF_Y     = 7*U_SZ;
static const size_t OFF_YGS   = 8*U_SZ;
static const size_t OFF_Z     = 9*U_SZ;
static const size_t OFF_VM    = 10*U_SZ;
static const size_t OFF_V     = 11*U_SZ;
static const size_t OFF_UOUT  = 12*U_SZ;
static const size_t OFF_PROJ  = 13*U_SZ;
static const size_t SMALL0    = 14*U_SZ;
static const size_t OFF_SEQG  = SMALL0 + 0*SG_SZ;
static const size_t OFF_UG    = SMALL0 + 1*SG_SZ;
static const size_t OFF_GAG   = SMALL0 + 2*SG_SZ;
static const size_t OFF_GBG   = SMALL0 + 3*SG_SZ;
static const size_t OFF_GOG   = SMALL0 + 4*SG_SZ;
static const size_t OFF_YG    = SMALL0 + 5*SG_SZ;
static const size_t SMALL1    = SMALL0 + 6*SG_SZ;
static const size_t OFF_POSF  = SMALL1;
static const size_t OFF_POSG  = OFF_POSF + 4096*256;
static const size_t OFF_CLN   = OFF_POSG + 65536;
static const size_t OFF_CLNG  = OFF_CLN + 2048;
static const size_t OFF_FB    = OFF_CLNG + 2048;
static const size_t OFF_WB    = OFF_FB + 2048;
static const size_t OFF_OB    = OFF_WB + 2048;
static const size_t OFF_FBG   = OFF_OB + 2048;
static const size_t OFF_WBG   = OFF_FBG + 2048;
static const size_t OFF_OBG   = OFF_WBG + 2048;
static const size_t OFF_AGA   = OFF_OBG + 2048;
static const size_t OFF_ABF   = OFF_AGA + 65536;
static const size_t OFF_ABB   = OFF_ABF + 65536;
static const size_t OFF_SIF   = OFF_ABB + 65536;
static const size_t OFF_SIB   = OFF_SIF + 65536;
static const size_t OFF_P16   = OFF_SIB + 65536;           // 8*16*256
static const size_t TOTAL_SCRATCH = OFF_P16 + 32768 + 1024;

__device__ __align__(16) float g_scratch[TOTAL_SCRATCH];

__device__ __forceinline__ float sigf(float x) { return 1.0f / (1.0f + expf(-x)); }
__device__ __forceinline__ int clampi(int v, int lo, int hi) { return v < lo ? lo : (v > hi ? hi : v); }

__device__ __forceinline__ void mma_tf32(float* c, const uint32_t* a, const uint32_t* b) {
    asm volatile(
        "mma.sync.aligned.m16n8k8.row.col.f32.tf32.tf32.f32 "
        "{%0,%1,%2,%3}, {%4,%5,%6,%7}, {%8,%9}, {%0,%1,%2,%3};\n"
        : "+f"(c[0]), "+f"(c[1]), "+f"(c[2]), "+f"(c[3])
        : "r"(a[0]), "r"(a[1]), "r"(a[2]), "r"(a[3]), "r"(b[0]), "r"(b[1]));
}

__device__ __forceinline__ void cpa16(uint32_t dst, const void* src) {
    asm volatile("cp.async.cg.shared.global [%0], [%1], 16;" :: "r"(dst), "l"(src));
}
#define CP_COMMIT() asm volatile("cp.async.commit_group;")
#define CP_WAIT1()  asm volatile("cp.async.wait_group 1;")

__device__ __forceinline__ const float* selp(const float* a0, const float* a1,
                                             const float* a2, int p) {
    return p == 0 ? a0 : (p == 1 ? a1 : a2);
}

// ---------- x [B,C,4096] -> seq [B*4096, C] ----------
__global__ void k_transpose(const float* __restrict__ x, float* __restrict__ seq) {
    __shared__ float tile[32][33];
    int b = blockIdx.z;
    int t0 = blockIdx.x * 32, c0 = blockIdx.y * 32;
    int tx = threadIdx.x, ty = threadIdx.y;
    const float* src = x + (size_t)b * CDIM * NTOK;
#pragma unroll
    for (int j = 0; j < 4; j++)
        tile[ty + 8*j][tx] = src[(size_t)(c0 + ty + 8*j) * NTOK + t0 + tx];
    __syncthreads();
    float* dst = seq + (size_t)b * NTOK * CDIM;
#pragma unroll
    for (int j = 0; j < 4; j++)
        dst[(size_t)(t0 + ty + 8*j) * CDIM + c0 + tx] = tile[tx][ty + 8*j];
}

// ---------- proj [B,4096,C] + x -> out [B,C,4096] ----------
__global__ void k_output(const float* __restrict__ proj, const float* __restrict__ x,
                         float* __restrict__ outp) {
    __shared__ float tile[32][33];
    int b = blockIdx.z;
    int t0 = blockIdx.x * 32, c0 = blockIdx.y * 32;
    int tx = threadIdx.x, ty = threadIdx.y;
    const float* src = proj + (size_t)b * NTOK * CDIM;
#pragma unroll
    for (int j = 0; j < 4; j++)
        tile[ty + 8*j][tx] = src[(size_t)(t0 + ty + 8*j) * CDIM + c0 + tx];
    __syncthreads();
    size_t base = (size_t)b * CDIM * NTOK;
#pragma unroll
    for (int j = 0; j < 4; j++) {
        size_t o = base + (size_t)(c0 + ty + 8*j) * NTOK + t0 + tx;
        outp[o] = x[o] + tile[tx][ty + 8*j];
    }
}

// ---------- pos bilinear upsample ----------
__global__ void k_posup(const float* __restrict__ pos, float* __restrict__ outp, int OH, int OW) {
    int t = blockIdx.x, c = threadIdx.x;
    int oh = t / OW, ow = t % OW;
    float sy = (oh + 0.5f) * (32.0f / OH) - 0.5f;
    float sx = (ow + 0.5f) * (32.0f / OW) - 0.5f;
    int y0 = (int)floorf(sy); float fy = sy - y0;
    int x0 = (int)floorf(sx); float fx = sx - x0;
    int y0c = clampi(y0, 0, 31), y1c = clampi(y0 + 1, 0, 31);
    int x0c = clampi(x0, 0, 31), x1c = clampi(x0 + 1, 0, 31);
    const float* p = pos + (size_t)c * 1024;
    float v = (1.f - fy) * ((1.f - fx) * p[y0c*32 + x0c] + fx * p[y0c*32 + x1c])
            + fy * ((1.f - fx) * p[y1c*32 + x0c] + fx * p[y1c*32 + x1c]);
    outp[(size_t)t * CDIM + c] = v;
}

// ---------- pos antialiased downsample 32->16 ----------
__global__ void k_posdown(const float* __restrict__ pos, float* __restrict__ outp) {
    int t = blockIdx.x, c = threadIdx.x;
    int gh = t / 16, gw = t % 16;
    const float W4[4] = {0.125f, 0.375f, 0.375f, 0.125f};
    float wy[4], wx[4]; int ky[4], kx[4];
    float sy = 0.f, sx = 0.f;
#pragma unroll
    for (int d = 0; d < 4; d++) {
        ky[d] = 2*gh - 1 + d; wy[d] = (ky[d] >= 0 && ky[d] < 32) ? W4[d] : 0.f; sy += wy[d];
        kx[d] = 2*gw - 1 + d; wx[d] = (kx[d] >= 0 && kx[d] < 32) ? W4[d] : 0.f; sx += wx[d];
    }
    const float* p = pos + (size_t)c * 1024;
    float acc = 0.f;
#pragma unroll
    for (int d = 0; d < 4; d++) {
        if (wy[d] == 0.f) continue;
        float rowacc = 0.f;
#pragma unroll
        for (int e = 0; e < 4; e++)
            if (wx[e] != 0.f) rowacc += wx[e] * p[ky[d]*32 + kx[e]];
        acc += wy[d] * rowacc;
    }
    outp[(size_t)t * CDIM + c] = acc / (sy * sx);
}

// ---------- tf32 mma.sync GEMM, 3-stage cp.async, frag double-buffer ----------
// modes: 0 store | 1 t+P1[(r&tokmask)*256+col] | 2 s=sig(t): s*P1+(1-s)*P2
//        3 P1+sig(t)*P2 | 4 gate: x=t+TB[b*256+col]; z0 -> 1/(1+e^x), else sig(x)
//        (mode 4: TB = z==0?P1 : z==1?P2 : bias;  tokmask = ntok)
#define AS_STRIDE 36
#define BS_STRIDE 136
#define A_ELEMS (128*AS_STRIDE)
#define B_ELEMS (32*BS_STRIDE)
#define STAGE_ELEMS (A_ELEMS + B_ELEMS)
#define NSTAGE 3
extern __shared__ float smx[];

__global__ void __launch_bounds__(256, 2)
k_gemm_tc(const float* __restrict__ A0, const float* __restrict__ W0,
          const float* __restrict__ A1, const float* __restrict__ W1,
          const float* __restrict__ A2, const float* __restrict__ W2,
          int npairs,
          float* __restrict__ C0, float* __restrict__ C1, float* __restrict__ C2,
          const float* __restrict__ bias, int mode,
          const float* __restrict__ P1, const float* __restrict__ P2,
          int tokmask, int multi) {
    int bx = blockIdx.x, by = blockIdx.y, bz = blockIdx.z;
    int tid = threadIdx.x;
    int warp = tid >> 5, lane = tid & 31;
    int wm = warp >> 2, wn = warp & 3;
    int g = lane >> 2, tq = lane & 3;

    uint32_t smem_u32 = (uint32_t)__cvta_generic_to_shared(smx);

    float acc[4][4][4];
#pragma unroll
    for (int i = 0; i < 4; i++)
#pragma unroll
        for (int j = 0; j < 4; j++)
#pragma unroll
            for (int r = 0; r < 4; r++) acc[i][j][r] = 0.f;

    int nst = (multi ? 1 : npairs) * 8;

    auto load_stage = [&](int st, int buf) {
        int p = multi ? bz : (st >> 3);
        const float* A = multi ? A0 : selp(A0, A1, A2, p);
        const float* W = selp(W0, W1, W2, p);
        int k0 = (st & 7) * 32;
        uint32_t abase = smem_u32 + (uint32_t)(buf * STAGE_ELEMS) * 4u;
        uint32_t bbase = abase + (uint32_t)A_ELEMS * 4u;
#pragma unroll
        for (int i = 0; i < 4; i++) {
            int idx = tid + 256 * i;
            int row = idx >> 3, c4 = idx & 7;
            cpa16(abase + (uint32_t)(row * AS_STRIDE + c4 * 4) * 4u,
                  A + (size_t)(by * 128 + row) * 256 + k0 + c4 * 4);
        }
#pragma unroll
        for (int i = 0; i < 4; i++) {
            int idx = tid + 256 * i;
            int row = idx >> 5, c4 = idx & 31;
            cpa16(bbase + (uint32_t)(row * BS_STRIDE + c4 * 4) * 4u,
                  W + (size_t)(k0 + row) * 256 + bx * 128 + c4 * 4);
        }
        CP_COMMIT();
    };

    load_stage(0, 0);
    load_stage(1, 1);

    for (int st = 0; st < nst; st++) {
        CP_WAIT1();
        __syncthreads();
        int nx = st + NSTAGE - 1;
        if (nx < nst) load_stage(nx, nx % NSTAGE);
        else CP_COMMIT();

        int pb = st % NSTAGE;
        const uint32_t* Asu = (const uint32_t*)(smx + pb * STAGE_ELEMS);
        const uint32_t* Bsu = Asu + A_ELEMS;

        uint32_t af[2][4][4], bf[2][4][2];
        auto ldfrag = [&](int ks, int buf) {
#pragma unroll
            for (int mt = 0; mt < 4; mt++) {
                int mb = wm * 64 + mt * 16;
                af[buf][mt][0] = Asu[(mb + g) * AS_STRIDE + ks + tq];
                af[buf][mt][1] = Asu[(mb + g + 8) * AS_STRIDE + ks + tq];
                af[buf][mt][2] = Asu[(mb + g) * AS_STRIDE + ks + tq + 4];
                af[buf][mt][3] = Asu[(mb + g + 8) * AS_STRIDE + ks + tq + 4];
            }
#pragma unroll
            for (int nt = 0; nt < 4; nt++) {
                int nb = wn * 32 + nt * 8;
                bf[buf][nt][0] = Bsu[(ks + tq) * BS_STRIDE + nb + g];
                bf[buf][nt][1] = Bsu[(ks + tq + 4) * BS_STRIDE + nb + g];
            }
        };

        ldfrag(0, 0);
#pragma unroll
        for (int kk = 0; kk < 4; kk++) {
            int cur = kk & 1;
            if (kk < 3) ldfrag((kk + 1) * 8, cur ^ 1);
#pragma unroll
            for (int mt = 0; mt < 4; mt++)
#pragma unroll
                for (int nt = 0; nt < 4; nt++)
                    mma_tf32(acc[mt][nt], af[cur][mt], bf[cur][nt]);
        }
    }

    float* C = multi ? (bz == 0 ? C0 : (bz == 1 ? C1 : C2)) : C0;
    int batch4 = (mode == 4) ? (by * 128) / tokmask : 0;
    const float* TB4 = (mode == 4) ? (bz == 0 ? P1 : (bz == 1 ? P2 : bias)) : nullptr;
#pragma unroll
    for (int mt = 0; mt < 4; mt++) {
        int r0 = by * 128 + wm * 64 + mt * 16 + g;
#pragma unroll
        for (int nt = 0; nt < 4; nt++) {
            int col = bx * 128 + wn * 32 + nt * 8 + tq * 2;
            float b0 = 0.f, b1 = 0.f;
            if (bias && mode != 4) { b0 = bias[col]; b1 = bias[col + 1]; }
#pragma unroll
            for (int h = 0; h < 2; h++) {
                int r = r0 + h * 8;
                float t0 = acc[mt][nt][2*h + 0] + b0;
                float t1 = acc[mt][nt][2*h + 1] + b1;
                size_t i0 = (size_t)r * 256 + col;
                float o0, o1;
                if (mode == 0) {
                    o0 = t0; o1 = t1;
                } else if (mode == 1) {
                    size_t pi = (size_t)(r & tokmask) * 256 + col;
                    o0 = t0 + P1[pi]; o1 = t1 + P1[pi + 1];
                } else if (mode == 2) {
                    float s0 = sigf(t0), s1 = sigf(t1);
                    o0 = s0 * P1[i0] + (1.f - s0) * P2[i0];
                    o1 = s1 * P1[i0 + 1] + (1.f - s1) * P2[i0 + 1];
                } else if (mode == 3) {
                    o0 = P1[i0] + sigf(t0) * P2[i0];
                    o1 = P1[i0 + 1] + sigf(t1) * P2[i0 + 1];
                } else {
                    float x0 = t0 + TB4[batch4 * 256 + col];
                    float x1 = t1 + TB4[batch4 * 256 + col + 1];
                    if (bz == 0) { o0 = 1.f / (1.f + expf(x0)); o1 = 1.f / (1.f + expf(x1)); }
                    else         { o0 = sigf(x0); o1 = sigf(x1); }
                }
                *(float2*)(C + i0) = make_float2(o0, o1);
            }
        }
    }
}

// ---------- column-mean stage A ----------
__global__ void k_colmean_a(const float* __restrict__ U, float* __restrict__ part16, int chunk) {
    int j = blockIdx.x, b = blockIdx.y, c = threadIdx.x;
    const float* p = U + ((size_t)(b * gridDim.x + j) * chunk) * CDIM + c;
    float s0 = 0.f, s1 = 0.f, s2 = 0.f, s3 = 0.f;
    for (int t = 0; t < chunk; t += 4) {
        s0 += p[(size_t)t * CDIM];
        s1 += p[(size_t)(t + 1) * CDIM];
        s2 += p[(size_t)(t + 2) * CDIM];
        s3 += p[(size_t)(t + 3) * CDIM];
    }
    part16[(b * 16 + j) * 256 + c] = s0 + s1 + s2 + s3;
}

// ---------- fused mean reduce + layernorm ----------
__global__ void k_ctx(const float* __restrict__ part16, float inv,
                      const float* __restrict__ g, const float* __restrict__ be,
                      float* __restrict__ cln) {
    int b = blockIdx.x, c = threadIdx.x;
    __shared__ float red[256];
    float m = 0.f;
    for (int j = 0; j < 16; j++) m += part16[(b * 16 + j) * 256 + c];
    m *= inv;
    red[c] = m; __syncthreads();
    for (int s = 128; s > 0; s >>= 1) { if (c < s) red[c] += red[c + s]; __syncthreads(); }
    float mu = red[0] * (1.f / 256.f); __syncthreads();
    float d = m - mu;
    red[c] = d * d; __syncthreads();
    for (int s = 128; s > 0; s >>= 1) { if (c < s) red[c] += red[c + s]; __syncthreads(); }
    float var = red[0] * (1.f / 256.f);
    cln[b * 256 + c] = d * rsqrtf(var + LN_EPS) * g[c] + be[c];
}

// ---------- per-batch gate bias tables ----------
__global__ void k_gatebias(const float* __restrict__ cln,
                           const float* __restrict__ Wf, const float* __restrict__ bf,
                           const float* __restrict__ Ww, const float* __restrict__ bw,
                           const float* __restrict__ Wo, const float* __restrict__ bo,
                           float* __restrict__ fb, float* __restrict__ wb, float* __restrict__ ob) {
    int which = blockIdx.x, b = blockIdx.y, c = threadIdx.x;
    __shared__ float sc[256];
    sc[c] = cln[b * 256 + c]; __syncthreads();
    const float* W  = (which == 0) ? Wf : (which == 1) ? Ww : Wo;
    const float* bi = (which == 0) ? bf : (which == 1) ? bw : bo;
    float* o        = (which == 0) ? fb : (which == 1) ? wb : ob;
    float acc = bi[c];
    for (int k = 0; k < 256; k++) acc += sc[k] * W[(size_t)(256 + k) * 256 + c];
    o[b * 256 + c] = acc;
}

// ---------- scan phase 1 (gates fused: GA=a, GB=g; b=(1-a)*g*u) ----------
__global__ void k_scan1(const float* __restrict__ GA, const float* __restrict__ GB,
                        const float* __restrict__ U,
                        float* __restrict__ AGA, float* __restrict__ ABF, float* __restrict__ ABB) {
    int j = blockIdx.x, b = blockIdx.y, c = threadIdx.x;
    size_t base = ((size_t)b * NTOK + j * 128) * CDIM + c;
    float A = 1.f, sf = 0.f;
    for (int t = 0; t < 128; t++) {
        size_t i = base + (size_t)t * CDIM;
        float a = GA[i];
        float bb = (1.f - a) * GB[i] * U[i];
        A *= a; sf = a * sf + bb;
    }
    float sb = 0.f;
    for (int t = 127; t >= 0; t--) {
        size_t i = base + (size_t)t * CDIM;
        float a = GA[i];
        float bb = (1.f - a) * GB[i] * U[i];
        sb = a * sb + bb;
    }
    int o = (b * 32 + j) * 256 + c;
    AGA[o] = A; ABF[o] = sf; ABB[o] = sb;
}

// ---------- scan phase 2 ----------
__global__ void k_scan2(const float* __restrict__ AGA, const float* __restrict__ ABF,
                        const float* __restrict__ ABB, float* __restrict__ SIF, float* __restrict__ SIB) {
    int b = blockIdx.x, c = threadIdx.x;
    float s = 0.f;
    for (int j = 0; j < 32; j++) {
        int o = (b * 32 + j) * 256 + c;
        SIF[o] = s; s = AGA[o] * s + ABF[o];
    }
    s = 0.f;
    for (int j = 31; j >= 0; j--) {
        int o = (b * 32 + j) * 256 + c;
        SIB[o] = s; s = AGA[o] * s + ABB[o];
    }
}

// ---------- scan phase 3 (gates fused) ----------
__global__ void k_scan3(const float* __restrict__ GA, const float* __restrict__ GB,
                        const float* __restrict__ GO, const float* __restrict__ U,
                        const float* __restrict__ SIF, const float* __restrict__ SIB,
                        float* __restrict__ YF, float* __restrict__ YB) {
    int j = blockIdx.x, b = blockIdx.y, c = threadIdx.x;
    size_t base = ((size_t)b * NTOK + j * 128) * CDIM + c;
    int ao = (b * 32 + j) * 256 + c;
    float s = SIF[ao];
    for (int t = 0; t < 128; t++) {
        size_t i = base + (size_t)t * CDIM;
        float a = GA[i], u = U[i];
        float bb = (1.f - a) * GB[i] * u;
        s = a * s + bb;
        float o = GO[i];
        YF[i] = o * s + (1.f - o) * u;
    }
    s = SIB[ao];
    for (int t = 127; t >= 0; t--) {
        size_t i = base + (size_t)t * CDIM;
        float a = GA[i], u = U[i];
        float bb = (1.f - a) * GB[i] * u;
        s = a * s + bb;
        float o = GO[i];
        YB[i] = o * s + (1.f - o) * u;
    }
}

// ---------- global branch serial scan (gates fused) ----------
__global__ void k_scanglob(const float* __restrict__ GA, const float* __restrict__ GB,
                           const float* __restrict__ GO, const float* __restrict__ U,
                           float* __restrict__ YG) {
    int b = blockIdx.x, c = threadIdx.x;
    size_t base = (size_t)b * NTOKG * CDIM + c;
    float s = 0.f;
    for (int t = 0; t < NTOKG; t++) {
        size_t i = base + (size_t)t * CDIM;
        float a = GA[i], u = U[i];
        float bb = (1.f - a) * GB[i] * u;
        s = a * s + bb;
        float o = GO[i];
        YG[i] = o * s + (1.f - o) * u;
    }
}

// ---------- 4x4 avg pool ----------
__global__ void k_pool(const float* __restrict__ seq, float* __restrict__ seqg) {
    int tg = blockIdx.x, b = blockIdx.y, c = threadIdx.x;
    int gh = tg / 16, gw = tg % 16;
    float s = 0.f;
#pragma unroll
    for (int i = 0; i < 4; i++)
#pragma unroll
        for (int j = 0; j < 4; j++)
            s += seq[((size_t)b * NTOK + (gh * 4 + i) * 64 + gw * 4 + j) * CDIM + c];
    seqg[((size_t)b * NTOKG + tg) * CDIM + c] = s * (1.0f / 16.0f);
}

// ---------- bilinear upsample y_g 16x16 -> 64x64 ----------
__global__ void k_upsample(const float* __restrict__ YG, float* __restrict__ YGS) {
    int t = blockIdx.x, b = blockIdx.y, c = threadIdx.x;
    int oh = t / 64, ow = t % 64;
    float sy = (oh + 0.5f) * 0.25f - 0.5f;
    float sx = (ow + 0.5f) * 0.25f - 0.5f;
    int y0 = (int)floorf(sy); float fy = sy - y0;
    int x0 = (int)floorf(sx); float fx = sx - x0;
    int y0c = clampi(y0, 0, 15), y1c = clampi(y0 + 1, 0, 15);
    int x0c = clampi(x0, 0, 15), x1c = clampi(x0 + 1, 0, 15);
    const float* base = YG + (size_t)b * NTOKG * CDIM + c;
    float v00 = base[(size_t)(y0c * 16 + x0c) * CDIM];
    float v01 = base[(size_t)(y0c * 16 + x1c) * CDIM];
    float v10 = base[(size_t)(y1c * 16 + x0c) * CDIM];
    float v11 = base[(size_t)(y1c * 16 + x1c) * CDIM];
    YGS[((size_t)b * NTOK + t) * CDIM + c] =
        (1.f - fy) * ((1.f - fx) * v00 + fx * v01) + fy * ((1.f - fx) * v10 + fx * v11);
}

// ---------- depthwise 3x3 conv, sliding window (3 loads/output) ----------
__global__ void k_dwconv(const float* __restrict__ seq, const float* __restrict__ w,
                         const float* __restrict__ bias, float* __restrict__ VM) {
    int h = blockIdx.x, b = blockIdx.y, c = threadIdx.x;
    float wr[9];
#pragma unroll
    for (int k = 0; k < 9; k++) wr[k] = w[c * 9 + k];
    float bi = bias[c];
    const float* sp = seq + (size_t)b * NTOK * CDIM + c;
    bool h0ok = (h - 1) >= 0, h2ok = (h + 1) < 64;
    size_t r0 = (size_t)(h - 1) * 64, r1 = (size_t)h * 64, r2 = (size_t)(h + 1) * 64;
    float m0 = 0.f, m1 = 0.f, m2 = 0.f;              // col x-1
    float c0 = h0ok ? sp[(r0 + 0) * CDIM] : 0.f;     // col x
    float c1 = sp[(r1 + 0) * CDIM];
    float c2 = h2ok ? sp[(r2 + 0) * CDIM] : 0.f;
    float n0 = h0ok ? sp[(r0 + 1) * CDIM] : 0.f;     // col x+1
    float n1 = sp[(r1 + 1) * CDIM];
    float n2 = h2ok ? sp[(r2 + 1) * CDIM] : 0.f;
    float* vout = VM + ((size_t)b * NTOK + (size_t)h * 64) * CDIM + c;
    for (int x = 0; x < 64; x++) {
        float acc = bi
            + wr[0] * m0 + wr[1] * c0 + wr[2] * n0
            + wr[3] * m1 + wr[4] * c1 + wr[5] * n1
            + wr[6] * m2 + wr[7] * c2 + wr[8] * n2;
        vout[(size_t)x * CDIM] = acc;
        m0 = c0; m1 = c1; m2 = c2;
        c0 = n0; c1 = n1; c2 = n2;
        if (x + 2 < 64) {
            n0 = h0ok ? sp[(r0 + x + 2) * CDIM] : 0.f;
            n1 = sp[(r1 + x + 2) * CDIM];
            n2 = h2ok ? sp[(r2 + x + 2) * CDIM] : 0.f;
        } else { n0 = n1 = n2 = 0.f; }
    }
}

extern "C" void kernel_launch(void* const* d_in, const int* in_sizes, int n_in,
                              void* d_out, int out_size) {
    const float* x        = (const float*)d_in[0];
    const float* Wt       = (const float*)d_in[1];
    const float* bt       = (const float*)d_in[2];
    const float* pos_fine = (const float*)d_in[3];
    const float* pos_glob = (const float*)d_in[4];
    const float* ln_g     = (const float*)d_in[5];
    const float* ln_b     = (const float*)d_in[6];
    const float* Wf       = (const float*)d_in[7];
    const float* bf       = (const float*)d_in[8];
    const float* Ww       = (const float*)d_in[9];
    const float* bw       = (const float*)d_in[10];
    const float* Wo       = (const float*)d_in[11];
    const float* bo       = (const float*)d_in[12];
    const float* Wr       = (const float*)d_in[13];
    const float* br       = (const float*)d_in[14];
    const float* Wgi      = (const float*)d_in[15];
    const float* bgi      = (const float*)d_in[16];
    const float* dw_w     = (const float*)d_in[17];
    const float* dw_b     = (const float*)d_in[18];
    const float* Wl       = (const float*)d_in[19];
    const float* bl       = (const float*)d_in[20];
    const float* Wlf      = (const float*)d_in[21];
    const float* blf      = (const float*)d_in[22];
    const float* Wout     = (const float*)d_in[23];
    const float* bout     = (const float*)d_in[24];
    float* outp = (float*)d_out;

    float* S = nullptr;
    cudaGetSymbolAddress((void**)&S, g_scratch);
    float* SEQ  = S + OFF_SEQ;  float* U    = S + OFF_U;
    float* GA   = S + OFF_GA;   float* GB   = S + OFF_GB;   float* GO  = S + OFF_GO;
    float* YF   = S + OFF_YF;   float* YB   = S + OFF_YB;   float* Y   = S + OFF_Y;
    float* YGS  = S + OFF_YGS;  float* Z    = S + OFF_Z;
    float* VM   = S + OFF_VM;   float* V    = S + OFF_V;
    float* UO   = S + OFF_UOUT; float* PROJ = S + OFF_PROJ;
    float* SEQG = S + OFF_SEQG; float* UG   = S + OFF_UG;
    float* GAG  = S + OFF_GAG;  float* GBG  = S + OFF_GBG;  float* GOG = S + OFF_GOG;
    float* YG   = S + OFF_YG;
    float* POSF = S + OFF_POSF; float* POSG = S + OFF_POSG;
    float* CLN  = S + OFF_CLN;  float* CLNG = S + OFF_CLNG;
    float* FB = S + OFF_FB, *WB = S + OFF_WB, *OB = S + OFF_OB;
    float* FBG = S + OFF_FBG, *WBG = S + OFF_WBG, *OBG = S + OFF_OBG;
    float* AGA = S + OFF_AGA, *ABF = S + OFF_ABF, *ABB = S + OFF_ABB;
    float* SIF = S + OFF_SIF, *SIB = S + OFF_SIB;
    float* P16 = S + OFF_P16;

    static int smem_set = 0;
    int smem_bytes = NSTAGE * STAGE_ELEMS * 4;
    if (!smem_set) {
        cudaFuncSetAttribute(k_gemm_tc, cudaFuncAttributeMaxDynamicSharedMemorySize, smem_bytes);
        smem_set = 1;
    }

    dim3 tb(32, 8);
    dim3 tg(128, 8, 8);
    dim3 gemF(2, MFINE / 128), gemG(2, MGLOB / 128);
    dim3 gemF3(2, MFINE / 128, 3), gemG3(2, MGLOB / 128, 3);
    const float* NP = nullptr;
    float* NPo = nullptr;

    // fine sequence + pos (pos add fused, mode 1)
    k_transpose<<<tg, tb>>>(x, SEQ);
    k_posup<<<4096, 256>>>(pos_fine, POSF, 64, 64);
    k_posdown<<<256, 256>>>(pos_glob, POSG);
    k_gemm_tc<<<gemF, 256, smem_bytes>>>(SEQ, Wt, NP, NP, NP, NP, 1, U, NPo, NPo, bt, 1, POSF, NP, 4095, 0);

    // gates (fine): context, bias tables, then ONE multi GEMM with fused gate epilogue (mode 4)
    k_colmean_a<<<dim3(16, BATCH), 256>>>(U, P16, 256);
    k_ctx<<<BATCH, 256>>>(P16, 1.0f / NTOK, ln_g, ln_b, CLN);
    k_gatebias<<<dim3(3, BATCH), 256>>>(CLN, Wf, bf, Ww, bw, Wo, bo, FB, WB, OB);
    k_gemm_tc<<<gemF3, 256, smem_bytes>>>(U, Wf, NP, Ww, NP, Wo, 1, GA, GB, GO, OB, 4, FB, WB, NTOK, 1);

    // bidirectional chunked scan (gate b computed on the fly)
    k_scan1<<<dim3(32, BATCH), 256>>>(GA, GB, U, AGA, ABF, ABB);
    k_scan2<<<BATCH, 256>>>(AGA, ABF, ABB, SIF, SIB);
    k_scan3<<<dim3(32, BATCH), 256>>>(GA, GB, GO, U, SIF, SIB, YF, YB);

    // rho mixing: 3-pair GEMM, sigmoid-mix fused (mode 2) -> Y
    k_gemm_tc<<<gemF, 256, smem_bytes>>>(U, Wr, YF, Wr + 65536, YB, Wr + 131072, 3, Y, NPo, NPo, br, 2, YF, YB, 0, 0);

    // global branch
    k_pool<<<dim3(256, BATCH), 256>>>(SEQ, SEQG);
    k_gemm_tc<<<gemG, 256, smem_bytes>>>(SEQG, Wt, NP, NP, NP, NP, 1, UG, NPo, NPo, bt, 1, POSG, NP, 255, 0);
    k_colmean_a<<<dim3(16, BATCH), 256>>>(UG, P16, 16);
    k_ctx<<<BATCH, 256>>>(P16, 1.0f / NTOKG, ln_g, ln_b, CLNG);
    k_gatebias<<<dim3(3, BATCH), 256>>>(CLNG, Wf, bf, Ww, bw, Wo, bo, FBG, WBG, OBG);
    k_gemm_tc<<<gemG3, 256, smem_bytes>>>(UG, Wf, NP, Ww, NP, Wo, 1, GAG, GBG, GOG, OBG, 4, FBG, WBG, NTOKG, 1);
    k_scanglob<<<BATCH, 256>>>(GAG, GBG, GOG, UG, YG);
    k_upsample<<<dim3(4096, BATCH), 256>>>(YG, YGS);

    // lam mixing: 3-pair GEMM, lam-add fused (mode 3) -> Z
    k_gemm_tc<<<gemF, 256, smem_bytes>>>(Y, Wgi, YGS, Wgi + 65536, U, Wgi + 131072, 3, Z, NPo, NPo, bgi, 3, Y, YGS, 0, 0);

    // local depthwise branch; eta sigmoid-mix fused (mode 2) -> UO
    k_dwconv<<<dim3(64, BATCH), 256>>>(SEQ, dw_w, dw_b, VM);
    k_gemm_tc<<<gemF, 256, smem_bytes>>>(VM, Wl, NP, NP, NP, NP, 1, V, NPo, NPo, bl, 0, NP, NP, 0, 0);
    k_gemm_tc<<<gemF, 256, smem_bytes>>>(V, Wlf, Z, Wlf + 65536, NP, NP, 2, UO, NPo, NPo, blf, 2, V, Z, 0, 0);

    // output proj + residual
    k_gemm_tc<<<gemF, 256, smem_bytes>>>(UO, Wout, NP, NP, NP, NP, 1, PROJ, NPo, NPo, bout, 0, NP, NP, 0, 0);
    k_output<<<tg, tb>>>(PROJ, x, outp);
}

// round 10
// speedup vs baseline: 3.3385x; 1.0621x over previous
#include <cuda_runtime.h>
#include <cuda_bf16.h>
#include <math.h>
#include <stdint.h>

#define BATCH 8
#define CDIM  256
#define NTOK  4096
#define NTOKG 256
#define MFINE 32768
#define MGLOB 2048
#define LN_EPS 1e-5f

static const size_t U_SZ  = (size_t)MFINE * CDIM;
static const size_t H_SZ  = U_SZ / 2;          // float-slots for one bf16 buffer
static const size_t SG_SZ = (size_t)MGLOB * CDIM;

static const size_t OFF_SEQ   = 0*U_SZ;
static const size_t OFF_U     = 1*U_SZ;
static const size_t OFF_GA    = 2*U_SZ;
static const size_t OFF_GB    = 3*U_SZ;
static const size_t OFF_GO    = 4*U_SZ;
static const size_t OFF_YF    = 5*U_SZ;
static const size_t OFF_YB    = 6*U_SZ;
static const size_t OFF_Y     = 7*U_SZ;
static const size_t OFF_YGS   = 8*U_SZ;
static const size_t OFF_Z     = 9*U_SZ;
static const size_t OFF_VM    = 10*U_SZ;
static const size_t OFF_V     = 11*U_SZ;
static const size_t OFF_UOUT  = 12*U_SZ;
static const size_t OFF_PROJ  = 13*U_SZ;
static const size_t SMALL0    = 14*U_SZ;
static const size_t OFF_SEQG  = SMALL0 + 0*SG_SZ;
static const size_t OFF_UG    = SMALL0 + 1*SG_SZ;
static const size_t OFF_GAG   = SMALL0 + 2*SG_SZ;
static const size_t OFF_GBG   = SMALL0 + 3*SG_SZ;
static const size_t OFF_GOG   = SMALL0 + 4*SG_SZ;
static const size_t OFF_YG    = SMALL0 + 5*SG_SZ;
static const size_t SMALL1    = SMALL0 + 6*SG_SZ;
static const size_t OFF_POSF  = SMALL1;
static const size_t OFF_POSG  = OFF_POSF + 4096*256;
static const size_t OFF_CLN   = OFF_POSG + 65536;
static const size_t OFF_CLNG  = OFF_CLN + 2048;
static const size_t OFF_FB    = OFF_CLNG + 2048;
static const size_t OFF_WB    = OFF_FB + 2048;
static const size_t OFF_OB    = OFF_WB + 2048;
static const size_t OFF_FBG   = OFF_OB + 2048;
static const size_t OFF_WBG   = OFF_FBG + 2048;
static const size_t OFF_OBG   = OFF_WBG + 2048;
static const size_t OFF_AGA   = OFF_OBG + 2048;
static const size_t OFF_ABF   = OFF_AGA + 65536;
static const size_t OFF_ABB   = OFF_ABF + 65536;
static const size_t OFF_SIF   = OFF_ABB + 65536;
static const size_t OFF_SIB   = OFF_SIF + 65536;
static const size_t OFF_P16   = OFF_SIB + 65536;           // 8*16*256
static const size_t OFF_WBW   = OFF_P16 + 32768;           // bf16x2 weights: 1408*256 u32
static const size_t OFF_U16   = OFF_WBW + 360448;
static const size_t OFF_YF16  = OFF_U16  + H_SZ;
static const size_t OFF_YB16  = OFF_YF16 + H_SZ;
static const size_t OFF_Y16   = OFF_YB16 + H_SZ;
static const size_t OFF_YGS16 = OFF_Y16  + H_SZ;
static const size_t OFF_V16   = OFF_YGS16+ H_SZ;
static const size_t OFF_Z16   = OFF_V16  + H_SZ;
static const size_t TOTAL_SCRATCH = OFF_Z16 + H_SZ + 1024;

__device__ __align__(16) float g_scratch[TOTAL_SCRATCH];

__device__ __forceinline__ float sigf(float x) { return 1.0f / (1.0f + expf(-x)); }
__device__ __forceinline__ int clampi(int v, int lo, int hi) { return v < lo ? lo : (v > hi ? hi : v); }

__device__ __forceinline__ void mma_tf32(float* c, const uint32_t* a, const uint32_t* b) {
    asm volatile(
        "mma.sync.aligned.m16n8k8.row.col.f32.tf32.tf32.f32 "
        "{%0,%1,%2,%3}, {%4,%5,%6,%7}, {%8,%9}, {%0,%1,%2,%3};\n"
        : "+f"(c[0]), "+f"(c[1]), "+f"(c[2]), "+f"(c[3])
        : "r"(a[0]), "r"(a[1]), "r"(a[2]), "r"(a[3]), "r"(b[0]), "r"(b[1]));
}
__device__ __forceinline__ void mma_bf16(float* c, const uint32_t* a, const uint32_t* b) {
    asm volatile(
        "mma.sync.aligned.m16n8k16.row.col.f32.bf16.bf16.f32 "
        "{%0,%1,%2,%3}, {%4,%5,%6,%7}, {%8,%9}, {%0,%1,%2,%3};\n"
        : "+f"(c[0]), "+f"(c[1]), "+f"(c[2]), "+f"(c[3])
        : "r"(a[0]), "r"(a[1]), "r"(a[2]), "r"(a[3]), "r"(b[0]), "r"(b[1]));
}

__device__ __forceinline__ void cpa16(uint32_t dst, const void* src) {
    asm volatile("cp.async.cg.shared.global [%0], [%1], 16;" :: "r"(dst), "l"(src));
}
#define CP_COMMIT() asm volatile("cp.async.commit_group;")
#define CP_WAIT1()  asm volatile("cp.async.wait_group 1;")
#define CP_WAIT2()  asm volatile("cp.async.wait_group 2;")

__device__ __forceinline__ const float* selp(const float* a0, const float* a1,
                                             const float* a2, int p) {
    return p == 0 ? a0 : (p == 1 ? a1 : a2);
}
__device__ __forceinline__ const __nv_bfloat16* selh(const __nv_bfloat16* a0,
                                                     const __nv_bfloat16* a1,
                                                     const __nv_bfloat16* a2, int p) {
    return p == 0 ? a0 : (p == 1 ? a1 : a2);
}
__device__ __forceinline__ const uint32_t* selw(const uint32_t* a0, const uint32_t* a1,
                                                const uint32_t* a2, int p) {
    return p == 0 ? a0 : (p == 1 ? a1 : a2);
}

// ---------- x [B,C,4096] -> seq [B*4096, C] ----------
__global__ void k_transpose(const float* __restrict__ x, float* __restrict__ seq) {
    __shared__ float tile[32][33];
    int b = blockIdx.z;
    int t0 = blockIdx.x * 32, c0 = blockIdx.y * 32;
    int tx = threadIdx.x, ty = threadIdx.y;
    const float* src = x + (size_t)b * CDIM * NTOK;
#pragma unroll
    for (int j = 0; j < 4; j++)
        tile[ty + 8*j][tx] = src[(size_t)(c0 + ty + 8*j) * NTOK + t0 + tx];
    __syncthreads();
    float* dst = seq + (size_t)b * NTOK * CDIM;
#pragma unroll
    for (int j = 0; j < 4; j++)
        dst[(size_t)(t0 + ty + 8*j) * CDIM + c0 + tx] = tile[tx][ty + 8*j];
}

// ---------- proj [B,4096,C] + x -> out [B,C,4096] ----------
__global__ void k_output(const float* __restrict__ proj, const float* __restrict__ x,
                         float* __restrict__ outp) {
    __shared__ float tile[32][33];
    int b = blockIdx.z;
    int t0 = blockIdx.x * 32, c0 = blockIdx.y * 32;
    int tx = threadIdx.x, ty = threadIdx.y;
    const float* src = proj + (size_t)b * NTOK * CDIM;
#pragma unroll
    for (int j = 0; j < 4; j++)
        tile[ty + 8*j][tx] = src[(size_t)(t0 + ty + 8*j) * CDIM + c0 + tx];
    __syncthreads();
    size_t base = (size_t)b * CDIM * NTOK;
#pragma unroll
    for (int j = 0; j < 4; j++) {
        size_t o = base + (size_t)(c0 + ty + 8*j) * NTOK + t0 + tx;
        outp[o] = x[o] + tile[tx][ty + 8*j];
    }
}

// ---------- pos bilinear upsample ----------
__global__ void k_posup(const float* __restrict__ pos, float* __restrict__ outp, int OH, int OW) {
    int t = blockIdx.x, c = threadIdx.x;
    int oh = t / OW, ow = t % OW;
    float sy = (oh + 0.5f) * (32.0f / OH) - 0.5f;
    float sx = (ow + 0.5f) * (32.0f / OW) - 0.5f;
    int y0 = (int)floorf(sy); float fy = sy - y0;
    int x0 = (int)floorf(sx); float fx = sx - x0;
    int y0c = clampi(y0, 0, 31), y1c = clampi(y0 + 1, 0, 31);
    int x0c = clampi(x0, 0, 31), x1c = clampi(x0 + 1, 0, 31);
    const float* p = pos + (size_t)c * 1024;
    float v = (1.f - fy) * ((1.f - fx) * p[y0c*32 + x0c] + fx * p[y0c*32 + x1c])
            + fy * ((1.f - fx) * p[y1c*32 + x0c] + fx * p[y1c*32 + x1c]);
    outp[(size_t)t * CDIM + c] = v;
}

// ---------- pos antialiased downsample 32->16 ----------
__global__ void k_posdown(const float* __restrict__ pos, float* __restrict__ outp) {
    int t = blockIdx.x, c = threadIdx.x;
    int gh = t / 16, gw = t % 16;
    const float W4[4] = {0.125f, 0.375f, 0.375f, 0.125f};
    float wy[4], wx[4]; int ky[4], kx[4];
    float sy = 0.f, sx = 0.f;
#pragma unroll
    for (int d = 0; d < 4; d++) {
        ky[d] = 2*gh - 1 + d; wy[d] = (ky[d] >= 0 && ky[d] < 32) ? W4[d] : 0.f; sy += wy[d];
        kx[d] = 2*gw - 1 + d; wx[d] = (kx[d] >= 0 && kx[d] < 32) ? W4[d] : 0.f; sx += wx[d];
    }
    const float* p = pos + (size_t)c * 1024;
    float acc = 0.f;
#pragma unroll
    for (int d = 0; d < 4; d++) {
        if (wy[d] == 0.f) continue;
        float rowacc = 0.f;
#pragma unroll
        for (int e = 0; e < 4; e++)
            if (wx[e] != 0.f) rowacc += wx[e] * p[ky[d]*32 + kx[e]];
        acc += wy[d] * rowacc;
    }
    outp[(size_t)t * CDIM + c] = acc / (sy * sx);
}

// ---------- weight interleave: 6 fine gate-path weights -> bf16x2 [k2][256] ----------
// rows: Wf 0..127 | Ww 128..255 | Wo 256..383 | Wr 384..767 | Wgi 768..1151 | Wlf 1152..1407
__global__ void k_wcvt(const float* __restrict__ Wf, const float* __restrict__ Ww,
                       const float* __restrict__ Wo, const float* __restrict__ Wr,
                       const float* __restrict__ Wgi, const float* __restrict__ Wlf,
                       uint32_t* __restrict__ WB) {
    int r = blockIdx.x, c = threadIdx.x;
    const float* src; int k2;
    if (r < 128)       { src = Wf;  k2 = r; }
    else if (r < 256)  { src = Ww;  k2 = r - 128; }
    else if (r < 384)  { src = Wo;  k2 = r - 256; }
    else if (r < 768)  { src = Wr;  k2 = r - 384; }
    else if (r < 1152) { src = Wgi; k2 = r - 768; }
    else               { src = Wlf; k2 = r - 1152; }
    float lo = src[(size_t)(2*k2) * 256 + c];
    float hi = src[(size_t)(2*k2 + 1) * 256 + c];
    __nv_bfloat162 p2 = __floats2bfloat162_rn(lo, hi);
    WB[(size_t)r * 256 + c] = *(uint32_t*)&p2;
}

// ================= tf32 mma.sync GEMM (value path + global branch) =================
// modes: 0 store | 1 t+P1[(r&tokmask)*256+col] | 2 s=sig(t): s*P1+(1-s)*P2
//        3 P1+sig(t)*P2 | 4 gate (TB = z==0?P1:z==1?P2:bias, 1/(1+e^x) for z0)
#define AS_STRIDE 36
#define BS_STRIDE 136
#define A_ELEMS (128*AS_STRIDE)
#define B_ELEMS (32*BS_STRIDE)
#define STAGE_ELEMS (A_ELEMS + B_ELEMS)
#define NSTAGE 3
extern __shared__ float smx[];

__global__ void __launch_bounds__(256, 2)
k_gemm_tc(const float* __restrict__ A0, const float* __restrict__ W0,
          const float* __restrict__ A1, const float* __restrict__ W1,
          const float* __restrict__ A2, const float* __restrict__ W2,
          int npairs,
          float* __restrict__ C0, float* __restrict__ C1, float* __restrict__ C2,
          const float* __restrict__ bias, int mode,
          const float* __restrict__ P1, const float* __restrict__ P2,
          int tokmask, int multi, __nv_bfloat16* __restrict__ D0) {
    int bx = blockIdx.x, by = blockIdx.y, bz = blockIdx.z;
    int tid = threadIdx.x;
    int warp = tid >> 5, lane = tid & 31;
    int wm = warp >> 2, wn = warp & 3;
    int g = lane >> 2, tq = lane & 3;

    uint32_t smem_u32 = (uint32_t)__cvta_generic_to_shared(smx);

    float acc[4][4][4];
#pragma unroll
    for (int i = 0; i < 4; i++)
#pragma unroll
        for (int j = 0; j < 4; j++)
#pragma unroll
            for (int r = 0; r < 4; r++) acc[i][j][r] = 0.f;

    int nst = (multi ? 1 : npairs) * 8;

    auto load_stage = [&](int st, int buf) {
        int p = multi ? bz : (st >> 3);
        const float* A = multi ? A0 : selp(A0, A1, A2, p);
        const float* W = selp(W0, W1, W2, p);
        int k0 = (st & 7) * 32;
        uint32_t abase = smem_u32 + (uint32_t)(buf * STAGE_ELEMS) * 4u;
        uint32_t bbase = abase + (uint32_t)A_ELEMS * 4u;
#pragma unroll
        for (int i = 0; i < 4; i++) {
            int idx = tid + 256 * i;
            int row = idx >> 3, c4 = idx & 7;
            cpa16(abase + (uint32_t)(row * AS_STRIDE + c4 * 4) * 4u,
                  A + (size_t)(by * 128 + row) * 256 + k0 + c4 * 4);
        }
#pragma unroll
        for (int i = 0; i < 4; i++) {
            int idx = tid + 256 * i;
            int row = idx >> 5, c4 = idx & 31;
            cpa16(bbase + (uint32_t)(row * BS_STRIDE + c4 * 4) * 4u,
                  W + (size_t)(k0 + row) * 256 + bx * 128 + c4 * 4);
        }
        CP_COMMIT();
    };

    load_stage(0, 0);
    load_stage(1, 1);

    for (int st = 0; st < nst; st++) {
        CP_WAIT1();
        __syncthreads();
        int nx = st + NSTAGE - 1;
        if (nx < nst) load_stage(nx, nx % NSTAGE);
        else CP_COMMIT();

        int pb = st % NSTAGE;
        const uint32_t* Asu = (const uint32_t*)(smx + pb * STAGE_ELEMS);
        const uint32_t* Bsu = Asu + A_ELEMS;
#pragma unroll
        for (int ks = 0; ks < 32; ks += 8) {
            uint32_t af[4][4], bf[4][2];
#pragma unroll
            for (int mt = 0; mt < 4; mt++) {
                int mb = wm * 64 + mt * 16;
                af[mt][0] = Asu[(mb + g) * AS_STRIDE + ks + tq];
                af[mt][1] = Asu[(mb + g + 8) * AS_STRIDE + ks + tq];
                af[mt][2] = Asu[(mb + g) * AS_STRIDE + ks + tq + 4];
                af[mt][3] = Asu[(mb + g + 8) * AS_STRIDE + ks + tq + 4];
            }
#pragma unroll
            for (int nt = 0; nt < 4; nt++) {
                int nb = wn * 32 + nt * 8;
                bf[nt][0] = Bsu[(ks + tq) * BS_STRIDE + nb + g];
                bf[nt][1] = Bsu[(ks + tq + 4) * BS_STRIDE + nb + g];
            }
#pragma unroll
            for (int mt = 0; mt < 4; mt++)
#pragma unroll
                for (int nt = 0; nt < 4; nt++)
                    mma_tf32(acc[mt][nt], af[mt], bf[nt]);
        }
    }

    float* C = multi ? (bz == 0 ? C0 : (bz == 1 ? C1 : C2)) : C0;
    int batch4 = (mode == 4) ? (by * 128) / tokmask : 0;
    const float* TB4 = (mode == 4) ? (bz == 0 ? P1 : (bz == 1 ? P2 : bias)) : nullptr;
#pragma unroll
    for (int mt = 0; mt < 4; mt++) {
        int r0 = by * 128 + wm * 64 + mt * 16 + g;
#pragma unroll
        for (int nt = 0; nt < 4; nt++) {
            int col = bx * 128 + wn * 32 + nt * 8 + tq * 2;
            float b0 = 0.f, b1 = 0.f;
            if (bias && mode != 4) { b0 = bias[col]; b1 = bias[col + 1]; }
#pragma unroll
            for (int h = 0; h < 2; h++) {
                int r = r0 + h * 8;
                float t0 = acc[mt][nt][2*h + 0] + b0;
                float t1 = acc[mt][nt][2*h + 1] + b1;
                size_t i0 = (size_t)r * 256 + col;
                float o0, o1;
                if (mode == 0) {
                    o0 = t0; o1 = t1;
                } else if (mode == 1) {
                    size_t pi = (size_t)(r & tokmask) * 256 + col;
                    o0 = t0 + P1[pi]; o1 = t1 + P1[pi + 1];
                } else if (mode == 2) {
                    float s0 = sigf(t0), s1 = sigf(t1);
                    o0 = s0 * P1[i0] + (1.f - s0) * P2[i0];
                    o1 = s1 * P1[i0 + 1] + (1.f - s1) * P2[i0 + 1];
                } else if (mode == 3) {
                    o0 = P1[i0] + sigf(t0) * P2[i0];
                    o1 = P1[i0 + 1] + sigf(t1) * P2[i0 + 1];
                } else {
                    float x0 = t0 + TB4[batch4 * 256 + col];
                    float x1 = t1 + TB4[batch4 * 256 + col + 1];
                    if (bz == 0) { o0 = 1.f / (1.f + expf(x0)); o1 = 1.f / (1.f + expf(x1)); }
                    else         { o0 = sigf(x0); o1 = sigf(x1); }
                }
                *(float2*)(C + i0) = make_float2(o0, o1);
                if (D0) *(__nv_bfloat162*)((__nv_bfloat16*)D0 + i0) = __floats2bfloat162_rn(o0, o1);
            }
        }
    }
}

// ================= bf16 mma.sync GEMM (gate path) =================
// A: bf16 row-major [M][256]; W: pre-interleaved bf16x2 [k2][256] u32.
#define BA_STR 20
#define BB_STR 136
#define BA_EL (128*BA_STR)
#define BB_EL (16*BB_STR)
#define BSTG_EL (BA_EL + BB_EL)
#define NSTB 4

__global__ void __launch_bounds__(256, 2)
k_gemm_bf(const __nv_bfloat16* __restrict__ A0, const uint32_t* __restrict__ W0,
          const __nv_bfloat16* __restrict__ A1, const uint32_t* __restrict__ W1,
          const __nv_bfloat16* __restrict__ A2, const uint32_t* __restrict__ W2,
          int npairs,
          float* __restrict__ C0, float* __restrict__ C1, float* __restrict__ C2,
          const float* __restrict__ bias, int mode,
          const float* __restrict__ P1, const float* __restrict__ P2,
          int tokmask, int multi, __nv_bfloat16* __restrict__ D0) {
    int bx = blockIdx.x, by = blockIdx.y, bz = blockIdx.z;
    int tid = threadIdx.x;
    int warp = tid >> 5, lane = tid & 31;
    int wm = warp >> 2, wn = warp & 3;
    int g = lane >> 2, tq = lane & 3;

    uint32_t smem_u32 = (uint32_t)__cvta_generic_to_shared(smx);

    float acc[4][4][4];
#pragma unroll
    for (int i = 0; i < 4; i++)
#pragma unroll
        for (int j = 0; j < 4; j++)
#pragma unroll
            for (int r = 0; r < 4; r++) acc[i][j][r] = 0.f;

    int nst = (multi ? 1 : npairs) * 8;

    auto load_stage = [&](int st, int buf) {
        int p = multi ? bz : (st >> 3);
        const __nv_bfloat16* A = multi ? A0 : selh(A0, A1, A2, p);
        const uint32_t* W = selw(W0, W1, W2, p);
        int k0 = (st & 7) * 32;          // bf16 k-offset
        int k2b = k0 >> 1;               // u32 row offset into W
        uint32_t abase = smem_u32 + (uint32_t)(buf * BSTG_EL) * 4u;
        uint32_t bbase = abase + (uint32_t)BA_EL * 4u;
#pragma unroll
        for (int i = 0; i < 2; i++) {
            int idx = tid + 256 * i;
            int row = idx >> 2, c4 = idx & 3;
            cpa16(abase + (uint32_t)(row * BA_STR + c4 * 4) * 4u,
                  A + (size_t)(by * 128 + row) * 256 + k0 + c4 * 8);
        }
#pragma unroll
        for (int i = 0; i < 2; i++) {
            int idx = tid + 256 * i;
            int row = idx >> 5, c4 = idx & 31;
            cpa16(bbase + (uint32_t)(row * BB_STR + c4 * 4) * 4u,
                  W + (size_t)(k2b + row) * 256 + bx * 128 + c4 * 4);
        }
        CP_COMMIT();
    };

    load_stage(0, 0);
    load_stage(1, 1);
    load_stage(2, 2);

    for (int st = 0; st < nst; st++) {
        CP_WAIT2();
        __syncthreads();
        int nx = st + NSTB - 1;
        if (nx < nst) load_stage(nx, nx % NSTB);
        else CP_COMMIT();

        int pb = st % NSTB;
        const uint32_t* Asu = (const uint32_t*)(smx + pb * BSTG_EL);
        const uint32_t* Bsu = Asu + BA_EL;
#pragma unroll
        for (int s = 0; s < 2; s++) {
            int ko = 8 * s;
            uint32_t af[4][4], bf[4][2];
#pragma unroll
            for (int mt = 0; mt < 4; mt++) {
                int mb = wm * 64 + mt * 16;
                af[mt][0] = Asu[(mb + g) * BA_STR + ko + tq];
                af[mt][1] = Asu[(mb + g + 8) * BA_STR + ko + tq];
                af[mt][2] = Asu[(mb + g) * BA_STR + ko + tq + 4];
                af[mt][3] = Asu[(mb + g + 8) * BA_STR + ko + tq + 4];
            }
#pragma unroll
            for (int nt = 0; nt < 4; nt++) {
                int nb = wn * 32 + nt * 8;
                bf[nt][0] = Bsu[(ko + tq) * BB_STR + nb + g];
                bf[nt][1] = Bsu[(ko + tq + 4) * BB_STR + nb + g];
            }
#pragma unroll
            for (int mt = 0; mt < 4; mt++)
#pragma unroll
                for (int nt = 0; nt < 4; nt++)
                    mma_bf16(acc[mt][nt], af[mt], bf[nt]);
        }
    }

    float* C = multi ? (bz == 0 ? C0 : (bz == 1 ? C1 : C2)) : C0;
    int batch4 = (mode == 4) ? (by * 128) / tokmask : 0;
    const float* TB4 = (mode == 4) ? (bz == 0 ? P1 : (bz == 1 ? P2 : bias)) : nullptr;
#pragma unroll
    for (int mt = 0; mt < 4; mt++) {
        int r0 = by * 128 + wm * 64 + mt * 16 + g;
#pragma unroll
        for (int nt = 0; nt < 4; nt++) {
            int col = bx * 128 + wn * 32 + nt * 8 + tq * 2;
            float b0 = 0.f, b1 = 0.f;
            if (bias && mode != 4) { b0 = bias[col]; b1 = bias[col + 1]; }
#pragma unroll
            for (int h = 0; h < 2; h++) {
                int r = r0 + h * 8;
                float t0 = acc[mt][nt][2*h + 0] + b0;
                float t1 = acc[mt][nt][2*h + 1] + b1;
                size_t i0 = (size_t)r * 256 + col;
                float o0, o1;
                if (mode == 0) {
                    o0 = t0; o1 = t1;
                } else if (mode == 1) {
                    size_t pi = (size_t)(r & tokmask) * 256 + col;
                    o0 = t0 + P1[pi]; o1 = t1 + P1[pi + 1];
                } else if (mode == 2) {
                    float s0 = sigf(t0), s1 = sigf(t1);
                    o0 = s0 * P1[i0] + (1.f - s0) * P2[i0];
                    o1 = s1 * P1[i0 + 1] + (1.f - s1) * P2[i0 + 1];
                } else if (mode == 3) {
                    o0 = P1[i0] + sigf(t0) * P2[i0];
                    o1 = P1[i0 + 1] + sigf(t1) * P2[i0 + 1];
                } else {
                    float x0 = t0 + TB4[batch4 * 256 + col];
                    float x1 = t1 + TB4[batch4 * 256 + col + 1];
                    if (bz == 0) { o0 = 1.f / (1.f + expf(x0)); o1 = 1.f / (1.f + expf(x1)); }
                    else         { o0 = sigf(x0); o1 = sigf(x1); }
                }
                *(float2*)(C + i0) = make_float2(o0, o1);
                if (D0) *(__nv_bfloat162*)((__nv_bfloat16*)D0 + i0) = __floats2bfloat162_rn(o0, o1);
            }
        }
    }
}

// ---------- column-mean stage A ----------
__global__ void k_colmean_a(const float* __restrict__ U, float* __restrict__ part16, int chunk) {
    int j = blockIdx.x, b = blockIdx.y, c = threadIdx.x;
    const float* p = U + ((size_t)(b * gridDim.x + j) * chunk) * CDIM + c;
    float s0 = 0.f, s1 = 0.f, s2 = 0.f, s3 = 0.f;
    for (int t = 0; t < chunk; t += 4) {
        s0 += p[(size_t)t * CDIM];
        s1 += p[(size_t)(t + 1) * CDIM];
        s2 += p[(size_t)(t + 2) * CDIM];
        s3 += p[(size_t)(t + 3) * CDIM];
    }
    part16[(b * 16 + j) * 256 + c] = s0 + s1 + s2 + s3;
}

// ---------- fused mean reduce + layernorm ----------
__global__ void k_ctx(const float* __restrict__ part16, float inv,
                      const float* __restrict__ g, const float* __restrict__ be,
                      float* __restrict__ cln) {
    int b = blockIdx.x, c = threadIdx.x;
    __shared__ float red[256];
    float m = 0.f;
    for (int j = 0; j < 16; j++) m += part16[(b * 16 + j) * 256 + c];
    m *= inv;
    red[c] = m; __syncthreads();
    for (int s = 128; s > 0; s >>= 1) { if (c < s) red[c] += red[c + s]; __syncthreads(); }
    float mu = red[0] * (1.f / 256.f); __syncthreads();
    float d = m - mu;
    red[c] = d * d; __syncthreads();
    for (int s = 128; s > 0; s >>= 1) { if (c < s) red[c] += red[c + s]; __syncthreads(); }
    float var = red[0] * (1.f / 256.f);
    cln[b * 256 + c] = d * rsqrtf(var + LN_EPS) * g[c] + be[c];
}

// ---------- per-batch gate bias tables ----------
__global__ void k_gatebias(const float* __restrict__ cln,
                           const float* __restrict__ Wf, const float* __restrict__ bf,
                           const float* __restrict__ Ww, const float* __restrict__ bw,
                           const float* __restrict__ Wo, const float* __restrict__ bo,
                           float* __restrict__ fb, float* __restrict__ wb, float* __restrict__ ob) {
    int which = blockIdx.x, b = blockIdx.y, c = threadIdx.x;
    __shared__ float sc[256];
    sc[c] = cln[b * 256 + c]; __syncthreads();
    const float* W  = (which == 0) ? Wf : (which == 1) ? Ww : Wo;
    const float* bi = (which == 0) ? bf : (which == 1) ? bw : bo;
    float* o        = (which == 0) ? fb : (which == 1) ? wb : ob;
    float acc = bi[c];
    for (int k = 0; k < 256; k++) acc += sc[k] * W[(size_t)(256 + k) * 256 + c];
    o[b * 256 + c] = acc;
}

// ---------- scan phase 1 (GA=a, GB=g; b=(1-a)*g*u) ----------
__global__ void k_scan1(const float* __restrict__ GA, const float* __restrict__ GB,
                        const float* __restrict__ U,
                        float* __restrict__ AGA, float* __restrict__ ABF, float* __restrict__ ABB) {
    int j = blockIdx.x, b = blockIdx.y, c = threadIdx.x;
    size_t base = ((size_t)b * NTOK + j * 128) * CDIM + c;
    float A = 1.f, sf = 0.f;
    for (int t = 0; t < 128; t++) {
        size_t i = base + (size_t)t * CDIM;
        float a = GA[i];
        float bb = (1.f - a) * GB[i] * U[i];
        A *= a; sf = a * sf + bb;
    }
    float sb = 0.f;
    for (int t = 127; t >= 0; t--) {
        size_t i = base + (size_t)t * CDIM;
        float a = GA[i];
        float bb = (1.f - a) * GB[i] * U[i];
        sb = a * sb + bb;
    }
    int o = (b * 32 + j) * 256 + c;
    AGA[o] = A; ABF[o] = sf; ABB[o] = sb;
}

// ---------- scan phase 2 ----------
__global__ void k_scan2(const float* __restrict__ AGA, const float* __restrict__ ABF,
                        const float* __restrict__ ABB, float* __restrict__ SIF, float* __restrict__ SIB) {
    int b = blockIdx.x, c = threadIdx.x;
    float s = 0.f;
    for (int j = 0; j < 32; j++) {
        int o = (b * 32 + j) * 256 + c;
        SIF[o] = s; s = AGA[o] * s + ABF[o];
    }
    s = 0.f;
    for (int j = 31; j >= 0; j--) {
        int o = (b * 32 + j) * 256 + c;
        SIB[o] = s; s = AGA[o] * s + ABB[o];
    }
}

// ---------- scan phase 3 (+bf16 mirrors of YF, YB) ----------
__global__ void k_scan3(const float* __restrict__ GA, const float* __restrict__ GB,
                        const float* __restrict__ GO, const float* __restrict__ U,
                        const float* __restrict__ SIF, const float* __restrict__ SIB,
                        float* __restrict__ YF, float* __restrict__ YB,
                        __nv_bfloat16* __restrict__ YF16, __nv_bfloat16* __restrict__ YB16) {
    int j = blockIdx.x, b = blockIdx.y, c = threadIdx.x;
    size_t base = ((size_t)b * NTOK + j * 128) * CDIM + c;
    int ao = (b * 32 + j) * 256 + c;
    float s = SIF[ao];
    for (int t = 0; t < 128; t++) {
        size_t i = base + (size_t)t * CDIM;
        float a = GA[i], u = U[i];
        float bb = (1.f - a) * GB[i] * u;
        s = a * s + bb;
        float o = GO[i];
        float y = o * s + (1.f - o) * u;
        YF[i] = y; YF16[i] = __float2bfloat16_rn(y);
    }
    s = SIB[ao];
    for (int t = 127; t >= 0; t--) {
        size_t i = base + (size_t)t * CDIM;
        float a = GA[i], u = U[i];
        float bb = (1.f - a) * GB[i] * u;
        s = a * s + bb;
        float o = GO[i];
        float y = o * s + (1.f - o) * u;
        YB[i] = y; YB16[i] = __float2bfloat16_rn(y);
    }
}

// ---------- global branch serial scan ----------
__global__ void k_scanglob(const float* __restrict__ GA, const float* __restrict__ GB,
                           const float* __restrict__ GO, const float* __restrict__ U,
                           float* __restrict__ YG) {
    int b = blockIdx.x, c = threadIdx.x;
    size_t base = (size_t)b * NTOKG * CDIM + c;
    float s = 0.f;
    for (int t = 0; t < NTOKG; t++) {
        size_t i = base + (size_t)t * CDIM;
        float a = GA[i], u = U[i];
        float bb = (1.f - a) * GB[i] * u;
        s = a * s + bb;
        float o = GO[i];
        YG[i] = o * s + (1.f - o) * u;
    }
}

// ---------- 4x4 avg pool ----------
__global__ void k_pool(const float* __restrict__ seq, float* __restrict__ seqg) {
    int tg = blockIdx.x, b = blockIdx.y, c = threadIdx.x;
    int gh = tg / 16, gw = tg % 16;
    float s = 0.f;
#pragma unroll
    for (int i = 0; i < 4; i++)
#pragma unroll
        for (int j = 0; j < 4; j++)
            s += seq[((size_t)b * NTOK + (gh * 4 + i) * 64 + gw * 4 + j) * CDIM + c];
    seqg[((size_t)b * NTOKG + tg) * CDIM + c] = s * (1.0f / 16.0f);
}

// ---------- bilinear upsample (+bf16 mirror) ----------
__global__ void k_upsample(const float* __restrict__ YG, float* __restrict__ YGS,
                           __nv_bfloat16* __restrict__ YGS16) {
    int t = blockIdx.x, b = blockIdx.y, c = threadIdx.x;
    int oh = t / 64, ow = t % 64;
    float sy = (oh + 0.5f) * 0.25f - 0.5f;
    float sx = (ow + 0.5f) * 0.25f - 0.5f;
    int y0 = (int)floorf(sy); float fy = sy - y0;
    int x0 = (int)floorf(sx); float fx = sx - x0;
    int y0c = clampi(y0, 0, 15), y1c = clampi(y0 + 1, 0, 15);
    int x0c = clampi(x0, 0, 15), x1c = clampi(x0 + 1, 0, 15);
    const float* base = YG + (size_t)b * NTOKG * CDIM + c;
    float v00 = base[(size_t)(y0c * 16 + x0c) * CDIM];
    float v01 = base[(size_t)(y0c * 16 + x1c) * CDIM];
    float v10 = base[(size_t)(y1c * 16 + x0c) * CDIM];
    float v11 = base[(size_t)(y1c * 16 + x1c) * CDIM];
    float v = (1.f - fy) * ((1.f - fx) * v00 + fx * v01) + fy * ((1.f - fx) * v10 + fx * v11);
    size_t i = ((size_t)b * NTOK + t) * CDIM + c;
    YGS[i] = v; YGS16[i] = __float2bfloat16_rn(v);
}

// ---------- depthwise 3x3 conv, sliding window ----------
__global__ void k_dwconv(const float* __restrict__ seq, const float* __restrict__ w,
                         const float* __restrict__ bias, float* __restrict__ VM) {
    int h = blockIdx.x, b = blockIdx.y, c = threadIdx.x;
    float wr[9];
#pragma unroll
    for (int k = 0; k < 9; k++) wr[k] = w[c * 9 + k];
    float bi = bias[c];
    const float* sp = seq + (size_t)b * NTOK * CDIM + c;
    bool h0ok = (h - 1) >= 0, h2ok = (h + 1) < 64;
    size_t r0 = (size_t)(h - 1) * 64, r1 = (size_t)h * 64, r2 = (size_t)(h + 1) * 64;
    float m0 = 0.f, m1 = 0.f, m2 = 0.f;
    float c0 = h0ok ? sp[(r0 + 0) * CDIM] : 0.f;
    float c1 = sp[(r1 + 0) * CDIM];
    float c2 = h2ok ? sp[(r2 + 0) * CDIM] : 0.f;
    float n0 = h0ok ? sp[(r0 + 1) * CDIM] : 0.f;
    float n1 = sp[(r1 + 1) * CDIM];
    float n2 = h2ok ? sp[(r2 + 1) * CDIM] : 0.f;
    float* vout = VM + ((size_t)b * NTOK + (size_t)h * 64) * CDIM + c;
    for (int x = 0; x < 64; x++) {
        float acc = bi
            + wr[0] * m0 + wr[1] * c0 + wr[2] * n0
            + wr[3] * m1 + wr[4] * c1 + wr[5] * n1
            + wr[6] * m2 + wr[7] * c2 + wr[8] * n2;
        vout[(size_t)x * CDIM] = acc;
        m0 = c0; m1 = c1; m2 = c2;
        c0 = n0; c1 = n1; c2 = n2;
        if (x + 2 < 64) {
            n0 = h0ok ? sp[(r0 + x + 2) * CDIM] : 0.f;
            n1 = sp[(r1 + x + 2) * CDIM];
            n2 = h2ok ? sp[(r2 + x + 2) * CDIM] : 0.f;
        } else { n0 = n1 = n2 = 0.f; }
    }
}

extern "C" void kernel_launch(void* const* d_in, const int* in_sizes, int n_in,
                              void* d_out, int out_size) {
    const float* x        = (const float*)d_in[0];
    const float* Wt       = (const float*)d_in[1];
    const float* bt       = (const float*)d_in[2];
    const float* pos_fine = (const float*)d_in[3];
    const float* pos_glob = (const float*)d_in[4];
    const float* ln_g     = (const float*)d_in[5];
    const float* ln_b     = (const float*)d_in[6];
    const float* Wf       = (const float*)d_in[7];
    const float* bf       = (const float*)d_in[8];
    const float* Ww       = (const float*)d_in[9];
    const float* bw       = (const float*)d_in[10];
    const float* Wo       = (const float*)d_in[11];
    const float* bo       = (const float*)d_in[12];
    const float* Wr       = (const float*)d_in[13];
    const float* br       = (const float*)d_in[14];
    const float* Wgi      = (const float*)d_in[15];
    const float* bgi      = (const float*)d_in[16];
    const float* dw_w     = (const float*)d_in[17];
    const float* dw_b     = (const float*)d_in[18];
    const float* Wl       = (const float*)d_in[19];
    const float* bl       = (const float*)d_in[20];
    const float* Wlf      = (const float*)d_in[21];
    const float* blf      = (const float*)d_in[22];
    const float* Wout     = (const float*)d_in[23];
    const float* bout     = (const float*)d_in[24];
    float* outp = (float*)d_out;

    float* S = nullptr;
    cudaGetSymbolAddress((void**)&S, g_scratch);
    float* SEQ  = S + OFF_SEQ;  float* U    = S + OFF_U;
    float* GA   = S + OFF_GA;   float* GB   = S + OFF_GB;   float* GO  = S + OFF_GO;
    float* YF   = S + OFF_YF;   float* YB   = S + OFF_YB;   float* Y   = S + OFF_Y;
    float* YGS  = S + OFF_YGS;  float* Z    = S + OFF_Z;
    float* VM   = S + OFF_VM;   float* V    = S + OFF_V;
    float* UO   = S + OFF_UOUT; float* PROJ = S + OFF_PROJ;
    float* SEQG = S + OFF_SEQG; float* UG   = S + OFF_UG;
    float* GAG  = S + OFF_GAG;  float* GBG  = S + OFF_GBG;  float* GOG = S + OFF_GOG;
    float* YG   = S + OFF_YG;
    float* POSF = S + OFF_POSF; float* POSG = S + OFF_POSG;
    float* CLN  = S + OFF_CLN;  float* CLNG = S + OFF_CLNG;
    float* FB = S + OFF_FB, *WB = S + OFF_WB, *OB = S + OFF_OB;
    float* FBG = S + OFF_FBG, *WBG = S + OFF_WBG, *OBG = S + OFF_OBG;
    float* AGA = S + OFF_AGA, *ABF = S + OFF_ABF, *ABB = S + OFF_ABB;
    float* SIF = S + OFF_SIF, *SIB = S + OFF_SIB;
    float* P16 = S + OFF_P16;
    uint32_t* WBW = (uint32_t*)(S + OFF_WBW);
    __nv_bfloat16* U16   = (__nv_bfloat16*)(S + OFF_U16);
    __nv_bfloat16* YF16  = (__nv_bfloat16*)(S + OFF_YF16);
    __nv_bfloat16* YB16  = (__nv_bfloat16*)(S + OFF_YB16);
    __nv_bfloat16* Y16   = (__nv_bfloat16*)(S + OFF_Y16);
    __nv_bfloat16* YGS16 = (__nv_bfloat16*)(S + OFF_YGS16);
    __nv_bfloat16* V16   = (__nv_bfloat16*)(S + OFF_V16);
    __nv_bfloat16* Z16   = (__nv_bfloat16*)(S + OFF_Z16);

    // interleaved weight blocks (k2-row offsets)
    uint32_t* WBf  = WBW + (size_t)0    * 256;
    uint32_t* WBw  = WBW + (size_t)128  * 256;
    uint32_t* WBo  = WBW + (size_t)256  * 256;
    uint32_t* WBr0 = WBW + (size_t)384  * 256;
    uint32_t* WBr1 = WBW + (size_t)512  * 256;
    uint32_t* WBr2 = WBW + (size_t)640  * 256;
    uint32_t* WBg0 = WBW + (size_t)768  * 256;
    uint32_t* WBg1 = WBW + (size_t)896  * 256;
    uint32_t* WBg2 = WBW + (size_t)1024 * 256;
    uint32_t* WBl0 = WBW + (size_t)1152 * 256;
    uint32_t* WBl1 = WBW + (size_t)1280 * 256;

    static int smem_set = 0;
    int smem_tf = NSTAGE * STAGE_ELEMS * 4;
    int smem_bf = NSTB * BSTG_EL * 4;
    if (!smem_set) {
        cudaFuncSetAttribute(k_gemm_tc, cudaFuncAttributeMaxDynamicSharedMemorySize, smem_tf);
        cudaFuncSetAttribute(k_gemm_bf, cudaFuncAttributeMaxDynamicSharedMemorySize, smem_bf);
        smem_set = 1;
    }

    dim3 tb(32, 8);
    dim3 tg(128, 8, 8);
    dim3 gemF(2, MFINE / 128), gemG(2, MGLOB / 128);
    dim3 gemF3(2, MFINE / 128, 3), gemG3(2, MGLOB / 128, 3);
    const float* NP = nullptr;
    float* NPo = nullptr;
    __nv_bfloat16* NPh = nullptr;
    const __nv_bfloat16* NPhc = nullptr;
    const uint32_t* NPw = nullptr;

    // prep
    k_transpose<<<tg, tb>>>(x, SEQ);
    k_wcvt<<<1408, 256>>>(Wf, Ww, Wo, Wr, Wgi, Wlf, WBW);
    k_posup<<<4096, 256>>>(pos_fine, POSF, 64, 64);
    k_posdown<<<256, 256>>>(pos_glob, POSG);

    // U = SEQ@Wt + bt + pos (tf32, mode 1) -> U + U16
    k_gemm_tc<<<gemF, 256, smem_tf>>>(SEQ, Wt, NP, NP, NP, NP, 1, U, NPo, NPo, bt, 1, POSF, NP, 4095, 0, U16);

    // gates (fine): bf16 multi GEMM with fused gate epilogue (mode 4)
    k_colmean_a<<<dim3(16, BATCH), 256>>>(U, P16, 256);
    k_ctx<<<BATCH, 256>>>(P16, 1.0f / NTOK, ln_g, ln_b, CLN);
    k_gatebias<<<dim3(3, BATCH), 256>>>(CLN, Wf, bf, Ww, bw, Wo, bo, FB, WB, OB);
    k_gemm_bf<<<gemF3, 256, smem_bf>>>(U16, WBf, NPhc, WBw, NPhc, WBo, 1, GA, GB, GO, OB, 4, FB, WB, NTOK, 1, NPh);

    // bidirectional chunked scan
    k_scan1<<<dim3(32, BATCH), 256>>>(GA, GB, U, AGA, ABF, ABB);
    k_scan2<<<BATCH, 256>>>(AGA, ABF, ABB, SIF, SIB);
    k_scan3<<<dim3(32, BATCH), 256>>>(GA, GB, GO, U, SIF, SIB, YF, YB, YF16, YB16);

    // rho mixing: bf16 3-pair, sigmoid-mix fused (mode 2) -> Y + Y16
    k_gemm_bf<<<gemF, 256, smem_bf>>>(U16, WBr0, YF16, WBr1, YB16, WBr2, 3, Y, NPo, NPo, br, 2, YF, YB, 0, 0, Y16);

    // global branch (all tf32)
    k_pool<<<dim3(256, BATCH), 256>>>(SEQ, SEQG);
    k_gemm_tc<<<gemG, 256, smem_tf>>>(SEQG, Wt, NP, NP, NP, NP, 1, UG, NPo, NPo, bt, 1, POSG, NP, 255, 0, NPh);
    k_colmean_a<<<dim3(16, BATCH), 256>>>(UG, P16, 16);
    k_ctx<<<BATCH, 256>>>(P16, 1.0f / NTOKG, ln_g, ln_b, CLNG);
    k_gatebias<<<dim3(3, BATCH), 256>>>(CLNG, Wf, bf, Ww, bw, Wo, bo, FBG, WBG, OBG);
    k_gemm_tc<<<gemG3, 256, smem_tf>>>(UG, Wf, NP, Ww, NP, Wo, 1, GAG, GBG, GOG, OBG, 4, FBG, WBG, NTOKG, 1, NPh);
    k_scanglob<<<BATCH, 256>>>(GAG, GBG, GOG, UG, YG);
    k_upsample<<<dim3(4096, BATCH), 256>>>(YG, YGS, YGS16);

    // lam mixing: bf16 3-pair, lam-add fused (mode 3) -> Z + Z16
    k_gemm_bf<<<gemF, 256, smem_bf>>>(Y16, WBg0, YGS16, WBg1, U16, WBg2, 3, Z, NPo, NPo, bgi, 3, Y, YGS, 0, 0, Z16);

    // local depthwise branch; V tf32 (value path) -> V + V16; eta bf16 (mode 2) -> UO
    k_dwconv<<<dim3(64, BATCH), 256>>>(SEQ, dw_w, dw_b, VM);
    k_gemm_tc<<<gemF, 256, smem_tf>>>(VM, Wl, NP, NP, NP, NP, 1, V, NPo, NPo, bl, 0, NP, NP, 0, 0, V16);
    k_gemm_bf<<<gemF, 256, smem_bf>>>(V16, WBl0, Z16, WBl1, NPhc, NPw, 2, UO, NPo, NPo, blf, 2, V, Z, 0, 0, NPh);

    // output proj + residual (tf32)
    k_gemm_tc<<<gemF, 256, smem_tf>>>(UO, Wout, NP, NP, NP, NP, 1, PROJ, NPo, NPo, bout, 0, NP, NP, 0, 0, NPh);
    k_output<<<tg, tb>>>(PROJ, x, outp);
}

// round 11
// speedup vs baseline: 3.4097x; 1.0213x over previous
#include <cuda_runtime.h>
#include <cuda_bf16.h>
#include <math.h>
#include <stdint.h>

#define BATCH 8
#define CDIM  256
#define NTOK  4096
#define NTOKG 256
#define MFINE 32768
#define MGLOB 2048
#define LN_EPS 1e-5f

static const size_t U_SZ  = (size_t)MFINE * CDIM;
static const size_t H_SZ  = U_SZ / 2;          // float-slots for one bf16 buffer
static const size_t SG_SZ = (size_t)MGLOB * CDIM;

static const size_t OFF_SEQ   = 0*U_SZ;
static const size_t OFF_U     = 1*U_SZ;
static const size_t OFF_GA    = 2*U_SZ;
static const size_t OFF_GB    = 3*U_SZ;
static const size_t OFF_GO    = 4*U_SZ;
static const size_t OFF_YF    = 5*U_SZ;
static const size_t OFF_YB    = 6*U_SZ;
static const size_t OFF_Y     = 7*U_SZ;
static const size_t OFF_YGS   = 8*U_SZ;
static const size_t OFF_Z     = 9*U_SZ;
static const size_t OFF_VM    = 10*U_SZ;
static const size_t OFF_V     = 11*U_SZ;
static const size_t OFF_UOUT  = 12*U_SZ;
static const size_t OFF_PROJ  = 13*U_SZ;
static const size_t SMALL0    = 14*U_SZ;
static const size_t OFF_SEQG  = SMALL0 + 0*SG_SZ;
static const size_t OFF_UG    = SMALL0 + 1*SG_SZ;
static const size_t OFF_GAG   = SMALL0 + 2*SG_SZ;
static const size_t OFF_GBG   = SMALL0 + 3*SG_SZ;
static const size_t OFF_GOG   = SMALL0 + 4*SG_SZ;
static const size_t OFF_YG    = SMALL0 + 5*SG_SZ;
static const size_t SMALL1    = SMALL0 + 6*SG_SZ;
static const size_t OFF_POSF  = SMALL1;
static const size_t OFF_POSG  = OFF_POSF + 4096*256;
static const size_t OFF_CLN   = OFF_POSG + 65536;
static const size_t OFF_CLNG  = OFF_CLN + 2048;
static const size_t OFF_FB    = OFF_CLNG + 2048;
static const size_t OFF_WB    = OFF_FB + 2048;
static const size_t OFF_OB    = OFF_WB + 2048;
static const size_t OFF_FBG   = OFF_OB + 2048;
static const size_t OFF_WBG   = OFF_FBG + 2048;
static const size_t OFF_OBG   = OFF_WBG + 2048;
static const size_t OFF_AGA   = OFF_OBG + 2048;
static const size_t OFF_ABF   = OFF_AGA + 65536;
static const size_t OFF_ABB   = OFF_ABF + 65536;
static const size_t OFF_SIF   = OFF_ABB + 65536;
static const size_t OFF_SIB   = OFF_SIF + 65536;
static const size_t OFF_P16   = OFF_SIB + 65536;           // 8*16*256
static const size_t OFF_WBW   = OFF_P16 + 32768;           // bf16x2 weights: 1792*256 u32
static const size_t OFF_U16   = OFF_WBW + 458752;
static const size_t OFF_YF16  = OFF_U16  + H_SZ;
static const size_t OFF_YB16  = OFF_YF16 + H_SZ;
static const size_t OFF_Y16   = OFF_YB16 + H_SZ;
static const size_t OFF_YGS16 = OFF_Y16  + H_SZ;
static const size_t OFF_V16   = OFF_YGS16+ H_SZ;
static const size_t OFF_Z16   = OFF_V16  + H_SZ;
static const size_t OFF_SEQ16 = OFF_Z16  + H_SZ;
static const size_t OFF_VM16  = OFF_SEQ16+ H_SZ;
static const size_t OFF_UO16  = OFF_VM16 + H_SZ;
static const size_t TOTAL_SCRATCH = OFF_UO16 + H_SZ + 1024;

__device__ __align__(16) float g_scratch[TOTAL_SCRATCH];

__device__ __forceinline__ float sigf(float x) { return 1.0f / (1.0f + expf(-x)); }
__device__ __forceinline__ int clampi(int v, int lo, int hi) { return v < lo ? lo : (v > hi ? hi : v); }

__device__ __forceinline__ void mma_tf32(float* c, const uint32_t* a, const uint32_t* b) {
    asm volatile(
        "mma.sync.aligned.m16n8k8.row.col.f32.tf32.tf32.f32 "
        "{%0,%1,%2,%3}, {%4,%5,%6,%7}, {%8,%9}, {%0,%1,%2,%3};\n"
        : "+f"(c[0]), "+f"(c[1]), "+f"(c[2]), "+f"(c[3])
        : "r"(a[0]), "r"(a[1]), "r"(a[2]), "r"(a[3]), "r"(b[0]), "r"(b[1]));
}
__device__ __forceinline__ void mma_bf16(float* c, const uint32_t* a, const uint32_t* b) {
    asm volatile(
        "mma.sync.aligned.m16n8k16.row.col.f32.bf16.bf16.f32 "
        "{%0,%1,%2,%3}, {%4,%5,%6,%7}, {%8,%9}, {%0,%1,%2,%3};\n"
        : "+f"(c[0]), "+f"(c[1]), "+f"(c[2]), "+f"(c[3])
        : "r"(a[0]), "r"(a[1]), "r"(a[2]), "r"(a[3]), "r"(b[0]), "r"(b[1]));
}

__device__ __forceinline__ void cpa16(uint32_t dst, const void* src) {
    asm volatile("cp.async.cg.shared.global [%0], [%1], 16;" :: "r"(dst), "l"(src));
}
#define CP_COMMIT() asm volatile("cp.async.commit_group;")
#define CP_WAIT1()  asm volatile("cp.async.wait_group 1;")
#define CP_WAIT2()  asm volatile("cp.async.wait_group 2;")

__device__ __forceinline__ const float* selp(const float* a0, const float* a1,
                                             const float* a2, int p) {
    return p == 0 ? a0 : (p == 1 ? a1 : a2);
}
__device__ __forceinline__ const __nv_bfloat16* selh(const __nv_bfloat16* a0,
                                                     const __nv_bfloat16* a1,
                                                     const __nv_bfloat16* a2, int p) {
    return p == 0 ? a0 : (p == 1 ? a1 : a2);
}
__device__ __forceinline__ const uint32_t* selw(const uint32_t* a0, const uint32_t* a1,
                                                const uint32_t* a2, int p) {
    return p == 0 ? a0 : (p == 1 ? a1 : a2);
}

// ---------- x [B,C,4096] -> seq [B*4096, C] (+bf16 mirror) ----------
__global__ void k_transpose(const float* __restrict__ x, float* __restrict__ seq,
                            __nv_bfloat16* __restrict__ seq16) {
    __shared__ float tile[32][33];
    int b = blockIdx.z;
    int t0 = blockIdx.x * 32, c0 = blockIdx.y * 32;
    int tx = threadIdx.x, ty = threadIdx.y;
    const float* src = x + (size_t)b * CDIM * NTOK;
#pragma unroll
    for (int j = 0; j < 4; j++)
        tile[ty + 8*j][tx] = src[(size_t)(c0 + ty + 8*j) * NTOK + t0 + tx];
    __syncthreads();
    float* dst = seq + (size_t)b * NTOK * CDIM;
    __nv_bfloat16* dsth = seq16 + (size_t)b * NTOK * CDIM;
#pragma unroll
    for (int j = 0; j < 4; j++) {
        float v = tile[tx][ty + 8*j];
        size_t o = (size_t)(t0 + ty + 8*j) * CDIM + c0 + tx;
        dst[o] = v; dsth[o] = __float2bfloat16_rn(v);
    }
}

// ---------- proj [B,4096,C] + x -> out [B,C,4096] ----------
__global__ void k_output(const float* __restrict__ proj, const float* __restrict__ x,
                         float* __restrict__ outp) {
    __shared__ float tile[32][33];
    int b = blockIdx.z;
    int t0 = blockIdx.x * 32, c0 = blockIdx.y * 32;
    int tx = threadIdx.x, ty = threadIdx.y;
    const float* src = proj + (size_t)b * NTOK * CDIM;
#pragma unroll
    for (int j = 0; j < 4; j++)
        tile[ty + 8*j][tx] = src[(size_t)(t0 + ty + 8*j) * CDIM + c0 + tx];
    __syncthreads();
    size_t base = (size_t)b * CDIM * NTOK;
#pragma unroll
    for (int j = 0; j < 4; j++) {
        size_t o = base + (size_t)(c0 + ty + 8*j) * NTOK + t0 + tx;
        outp[o] = x[o] + tile[tx][ty + 8*j];
    }
}

// ---------- pos bilinear upsample ----------
__global__ void k_posup(const float* __restrict__ pos, float* __restrict__ outp, int OH, int OW) {
    int t = blockIdx.x, c = threadIdx.x;
    int oh = t / OW, ow = t % OW;
    float sy = (oh + 0.5f) * (32.0f / OH) - 0.5f;
    float sx = (ow + 0.5f) * (32.0f / OW) - 0.5f;
    int y0 = (int)floorf(sy); float fy = sy - y0;
    int x0 = (int)floorf(sx); float fx = sx - x0;
    int y0c = clampi(y0, 0, 31), y1c = clampi(y0 + 1, 0, 31);
    int x0c = clampi(x0, 0, 31), x1c = clampi(x0 + 1, 0, 31);
    const float* p = pos + (size_t)c * 1024;
    float v = (1.f - fy) * ((1.f - fx) * p[y0c*32 + x0c] + fx * p[y0c*32 + x1c])
            + fy * ((1.f - fx) * p[y1c*32 + x0c] + fx * p[y1c*32 + x1c]);
    outp[(size_t)t * CDIM + c] = v;
}

// ---------- pos antialiased downsample 32->16 ----------
__global__ void k_posdown(const float* __restrict__ pos, float* __restrict__ outp) {
    int t = blockIdx.x, c = threadIdx.x;
    int gh = t / 16, gw = t % 16;
    const float W4[4] = {0.125f, 0.375f, 0.375f, 0.125f};
    float wy[4], wx[4]; int ky[4], kx[4];
    float sy = 0.f, sx = 0.f;
#pragma unroll
    for (int d = 0; d < 4; d++) {
        ky[d] = 2*gh - 1 + d; wy[d] = (ky[d] >= 0 && ky[d] < 32) ? W4[d] : 0.f; sy += wy[d];
        kx[d] = 2*gw - 1 + d; wx[d] = (kx[d] >= 0 && kx[d] < 32) ? W4[d] : 0.f; sx += wx[d];
    }
    const float* p = pos + (size_t)c * 1024;
    float acc = 0.f;
#pragma unroll
    for (int d = 0; d < 4; d++) {
        if (wy[d] == 0.f) continue;
        float rowacc = 0.f;
#pragma unroll
        for (int e = 0; e < 4; e++)
            if (wx[e] != 0.f) rowacc += wx[e] * p[ky[d]*32 + kx[e]];
        acc += wy[d] * rowacc;
    }
    outp[(size_t)t * CDIM + c] = acc / (sy * sx);
}

// ---------- weight interleave: 9 weights -> bf16x2 [k2][256] ----------
// rows: Wf 0..127 | Ww 128..255 | Wo 256..383 | Wr 384..767 | Wgi 768..1151 |
//       Wlf 1152..1407 | Wt 1408..1535 | Wl 1536..1663 | Wout 1664..1791
__global__ void k_wcvt(const float* __restrict__ Wf, const float* __restrict__ Ww,
                       const float* __restrict__ Wo, const float* __restrict__ Wr,
                       const float* __restrict__ Wgi, const float* __restrict__ Wlf,
                       const float* __restrict__ Wt, const float* __restrict__ Wl,
                       const float* __restrict__ Wout, uint32_t* __restrict__ WB) {
    int r = blockIdx.x, c = threadIdx.x;
    const float* src; int k2;
    if (r < 128)       { src = Wf;   k2 = r; }
    else if (r < 256)  { src = Ww;   k2 = r - 128; }
    else if (r < 384)  { src = Wo;   k2 = r - 256; }
    else if (r < 768)  { src = Wr;   k2 = r - 384; }
    else if (r < 1152) { src = Wgi;  k2 = r - 768; }
    else if (r < 1408) { src = Wlf;  k2 = r - 1152; }
    else if (r < 1536) { src = Wt;   k2 = r - 1408; }
    else if (r < 1664) { src = Wl;   k2 = r - 1536; }
    else               { src = Wout; k2 = r - 1664; }
    float lo = src[(size_t)(2*k2) * 256 + c];
    float hi = src[(size_t)(2*k2 + 1) * 256 + c];
    __nv_bfloat162 p2 = __floats2bfloat162_rn(lo, hi);
    WB[(size_t)r * 256 + c] = *(uint32_t*)&p2;
}

// ================= tf32 mma.sync GEMM (global branch only) =================
#define AS_STRIDE 36
#define BS_STRIDE 136
#define A_ELEMS (128*AS_STRIDE)
#define B_ELEMS (32*BS_STRIDE)
#define STAGE_ELEMS (A_ELEMS + B_ELEMS)
#define NSTAGE 3
extern __shared__ float smx[];

__global__ void __launch_bounds__(256, 2)
k_gemm_tc(const float* __restrict__ A0, const float* __restrict__ W0,
          const float* __restrict__ A1, const float* __restrict__ W1,
          const float* __restrict__ A2, const float* __restrict__ W2,
          int npairs,
          float* __restrict__ C0, float* __restrict__ C1, float* __restrict__ C2,
          const float* __restrict__ bias, int mode,
          const float* __restrict__ P1, const float* __restrict__ P2,
          int tokmask, int multi, __nv_bfloat16* __restrict__ D0) {
    int bx = blockIdx.x, by = blockIdx.y, bz = blockIdx.z;
    int tid = threadIdx.x;
    int warp = tid >> 5, lane = tid & 31;
    int wm = warp >> 2, wn = warp & 3;
    int g = lane >> 2, tq = lane & 3;

    uint32_t smem_u32 = (uint32_t)__cvta_generic_to_shared(smx);

    float acc[4][4][4];
#pragma unroll
    for (int i = 0; i < 4; i++)
#pragma unroll
        for (int j = 0; j < 4; j++)
#pragma unroll
            for (int r = 0; r < 4; r++) acc[i][j][r] = 0.f;

    int nst = (multi ? 1 : npairs) * 8;

    auto load_stage = [&](int st, int buf) {
        int p = multi ? bz : (st >> 3);
        const float* A = multi ? A0 : selp(A0, A1, A2, p);
        const float* W = selp(W0, W1, W2, p);
        int k0 = (st & 7) * 32;
        uint32_t abase = smem_u32 + (uint32_t)(buf * STAGE_ELEMS) * 4u;
        uint32_t bbase = abase + (uint32_t)A_ELEMS * 4u;
#pragma unroll
        for (int i = 0; i < 4; i++) {
            int idx = tid + 256 * i;
            int row = idx >> 3, c4 = idx & 7;
            cpa16(abase + (uint32_t)(row * AS_STRIDE + c4 * 4) * 4u,
                  A + (size_t)(by * 128 + row) * 256 + k0 + c4 * 4);
        }
#pragma unroll
        for (int i = 0; i < 4; i++) {
            int idx = tid + 256 * i;
            int row = idx >> 5, c4 = idx & 31;
            cpa16(bbase + (uint32_t)(row * BS_STRIDE + c4 * 4) * 4u,
                  W + (size_t)(k0 + row) * 256 + bx * 128 + c4 * 4);
        }
        CP_COMMIT();
    };

    load_stage(0, 0);
    load_stage(1, 1);

    for (int st = 0; st < nst; st++) {
        CP_WAIT1();
        __syncthreads();
        int nx = st + NSTAGE - 1;
        if (nx < nst) load_stage(nx, nx % NSTAGE);
        else CP_COMMIT();

        int pb = st % NSTAGE;
        const uint32_t* Asu = (const uint32_t*)(smx + pb * STAGE_ELEMS);
        const uint32_t* Bsu = Asu + A_ELEMS;
#pragma unroll
        for (int ks = 0; ks < 32; ks += 8) {
            uint32_t af[4][4], bf[4][2];
#pragma unroll
            for (int mt = 0; mt < 4; mt++) {
                int mb = wm * 64 + mt * 16;
                af[mt][0] = Asu[(mb + g) * AS_STRIDE + ks + tq];
                af[mt][1] = Asu[(mb + g + 8) * AS_STRIDE + ks + tq];
                af[mt][2] = Asu[(mb + g) * AS_STRIDE + ks + tq + 4];
                af[mt][3] = Asu[(mb + g + 8) * AS_STRIDE + ks + tq + 4];
            }
#pragma unroll
            for (int nt = 0; nt < 4; nt++) {
                int nb = wn * 32 + nt * 8;
                bf[nt][0] = Bsu[(ks + tq) * BS_STRIDE + nb + g];
                bf[nt][1] = Bsu[(ks + tq + 4) * BS_STRIDE + nb + g];
            }
#pragma unroll
            for (int mt = 0; mt < 4; mt++)
#pragma unroll
                for (int nt = 0; nt < 4; nt++)
                    mma_tf32(acc[mt][nt], af[mt], bf[nt]);
        }
    }

    float* C = multi ? (bz == 0 ? C0 : (bz == 1 ? C1 : C2)) : C0;
    int batch4 = (mode == 4) ? (by * 128) / tokmask : 0;
    const float* TB4 = (mode == 4) ? (bz == 0 ? P1 : (bz == 1 ? P2 : bias)) : nullptr;
#pragma unroll
    for (int mt = 0; mt < 4; mt++) {
        int r0 = by * 128 + wm * 64 + mt * 16 + g;
#pragma unroll
        for (int nt = 0; nt < 4; nt++) {
            int col = bx * 128 + wn * 32 + nt * 8 + tq * 2;
            float b0 = 0.f, b1 = 0.f;
            if (bias && mode != 4) { b0 = bias[col]; b1 = bias[col + 1]; }
#pragma unroll
            for (int h = 0; h < 2; h++) {
                int r = r0 + h * 8;
                float t0 = acc[mt][nt][2*h + 0] + b0;
                float t1 = acc[mt][nt][2*h + 1] + b1;
                size_t i0 = (size_t)r * 256 + col;
                float o0, o1;
                if (mode == 0) {
                    o0 = t0; o1 = t1;
                } else if (mode == 1) {
                    size_t pi = (size_t)(r & tokmask) * 256 + col;
                    o0 = t0 + P1[pi]; o1 = t1 + P1[pi + 1];
                } else if (mode == 2) {
                    float s0 = sigf(t0), s1 = sigf(t1);
                    o0 = s0 * P1[i0] + (1.f - s0) * P2[i0];
                    o1 = s1 * P1[i0 + 1] + (1.f - s1) * P2[i0 + 1];
                } else if (mode == 3) {
                    o0 = P1[i0] + sigf(t0) * P2[i0];
                    o1 = P1[i0 + 1] + sigf(t1) * P2[i0 + 1];
                } else {
                    float x0 = t0 + TB4[batch4 * 256 + col];
                    float x1 = t1 + TB4[batch4 * 256 + col + 1];
                    if (bz == 0) { o0 = 1.f / (1.f + expf(x0)); o1 = 1.f / (1.f + expf(x1)); }
                    else         { o0 = sigf(x0); o1 = sigf(x1); }
                }
                *(float2*)(C + i0) = make_float2(o0, o1);
                if (D0) *(__nv_bfloat162*)((__nv_bfloat16*)D0 + i0) = __floats2bfloat162_rn(o0, o1);
            }
        }
    }
}

// ================= bf16 mma.sync GEMM (all fine GEMMs) =================
#define BA_STR 20
#define BB_STR 136
#define BA_EL (128*BA_STR)
#define BB_EL (16*BB_STR)
#define BSTG_EL (BA_EL + BB_EL)
#define NSTB 4

__global__ void __launch_bounds__(256, 2)
k_gemm_bf(const __nv_bfloat16* __restrict__ A0, const uint32_t* __restrict__ W0,
          const __nv_bfloat16* __restrict__ A1, const uint32_t* __restrict__ W1,
          const __nv_bfloat16* __restrict__ A2, const uint32_t* __restrict__ W2,
          int npairs,
          float* __restrict__ C0, float* __restrict__ C1, float* __restrict__ C2,
          const float* __restrict__ bias, int mode,
          const float* __restrict__ P1, const float* __restrict__ P2,
          int tokmask, int multi, __nv_bfloat16* __restrict__ D0) {
    int bx = blockIdx.x, by = blockIdx.y, bz = blockIdx.z;
    int tid = threadIdx.x;
    int warp = tid >> 5, lane = tid & 31;
    int wm = warp >> 2, wn = warp & 3;
    int g = lane >> 2, tq = lane & 3;

    uint32_t smem_u32 = (uint32_t)__cvta_generic_to_shared(smx);

    float acc[4][4][4];
#pragma unroll
    for (int i = 0; i < 4; i++)
#pragma unroll
        for (int j = 0; j < 4; j++)
#pragma unroll
            for (int r = 0; r < 4; r++) acc[i][j][r] = 0.f;

    int nst = (multi ? 1 : npairs) * 8;

    auto load_stage = [&](int st, int buf) {
        int p = multi ? bz : (st >> 3);
        const __nv_bfloat16* A = multi ? A0 : selh(A0, A1, A2, p);
        const uint32_t* W = selw(W0, W1, W2, p);
        int k0 = (st & 7) * 32;
        int k2b = k0 >> 1;
        uint32_t abase = smem_u32 + (uint32_t)(buf * BSTG_EL) * 4u;
        uint32_t bbase = abase + (uint32_t)BA_EL * 4u;
#pragma unroll
        for (int i = 0; i < 2; i++) {
            int idx = tid + 256 * i;
            int row = idx >> 2, c4 = idx & 3;
            cpa16(abase + (uint32_t)(row * BA_STR + c4 * 4) * 4u,
                  A + (size_t)(by * 128 + row) * 256 + k0 + c4 * 8);
        }
#pragma unroll
        for (int i = 0; i < 2; i++) {
            int idx = tid + 256 * i;
            int row = idx >> 5, c4 = idx & 31;
            cpa16(bbase + (uint32_t)(row * BB_STR + c4 * 4) * 4u,
                  W + (size_t)(k2b + row) * 256 + bx * 128 + c4 * 4);
        }
        CP_COMMIT();
    };

    load_stage(0, 0);
    load_stage(1, 1);
    load_stage(2, 2);

    for (int st = 0; st < nst; st++) {
        CP_WAIT2();
        __syncthreads();
        int nx = st + NSTB - 1;
        if (nx < nst) load_stage(nx, nx % NSTB);
        else CP_COMMIT();

        int pb = st % NSTB;
        const uint32_t* Asu = (const uint32_t*)(smx + pb * BSTG_EL);
        const uint32_t* Bsu = Asu + BA_EL;
#pragma unroll
        for (int s = 0; s < 2; s++) {
            int ko = 8 * s;
            uint32_t af[4][4], bf[4][2];
#pragma unroll
            for (int mt = 0; mt < 4; mt++) {
                int mb = wm * 64 + mt * 16;
                af[mt][0] = Asu[(mb + g) * BA_STR + ko + tq];
                af[mt][1] = Asu[(mb + g + 8) * BA_STR + ko + tq];
                af[mt][2] = Asu[(mb + g) * BA_STR + ko + tq + 4];
                af[mt][3] = Asu[(mb + g + 8) * BA_STR + ko + tq + 4];
            }
#pragma unroll
            for (int nt = 0; nt < 4; nt++) {
                int nb = wn * 32 + nt * 8;
                bf[nt][0] = Bsu[(ko + tq) * BB_STR + nb + g];
                bf[nt][1] = Bsu[(ko + tq + 4) * BB_STR + nb + g];
            }
#pragma unroll
            for (int mt = 0; mt < 4; mt++)
#pragma unroll
                for (int nt = 0; nt < 4; nt++)
                    mma_bf16(acc[mt][nt], af[mt], bf[nt]);
        }
    }

    float* C = multi ? (bz == 0 ? C0 : (bz == 1 ? C1 : C2)) : C0;
    int batch4 = (mode == 4) ? (by * 128) / tokmask : 0;
    const float* TB4 = (mode == 4) ? (bz == 0 ? P1 : (bz == 1 ? P2 : bias)) : nullptr;
#pragma unroll
    for (int mt = 0; mt < 4; mt++) {
        int r0 = by * 128 + wm * 64 + mt * 16 + g;
#pragma unroll
        for (int nt = 0; nt < 4; nt++) {
            int col = bx * 128 + wn * 32 + nt * 8 + tq * 2;
            float b0 = 0.f, b1 = 0.f;
            if (bias && mode != 4) { b0 = bias[col]; b1 = bias[col + 1]; }
#pragma unroll
            for (int h = 0; h < 2; h++) {
                int r = r0 + h * 8;
                float t0 = acc[mt][nt][2*h + 0] + b0;
                float t1 = acc[mt][nt][2*h + 1] + b1;
                size_t i0 = (size_t)r * 256 + col;
                float o0, o1;
                if (mode == 0) {
                    o0 = t0; o1 = t1;
                } else if (mode == 1) {
                    size_t pi = (size_t)(r & tokmask) * 256 + col;
                    o0 = t0 + P1[pi]; o1 = t1 + P1[pi + 1];
                } else if (mode == 2) {
                    float s0 = sigf(t0), s1 = sigf(t1);
                    o0 = s0 * P1[i0] + (1.f - s0) * P2[i0];
                    o1 = s1 * P1[i0 + 1] + (1.f - s1) * P2[i0 + 1];
                } else if (mode == 3) {
                    o0 = P1[i0] + sigf(t0) * P2[i0];
                    o1 = P1[i0 + 1] + sigf(t1) * P2[i0 + 1];
                } else {
                    float x0 = t0 + TB4[batch4 * 256 + col];
                    float x1 = t1 + TB4[batch4 * 256 + col + 1];
                    if (bz == 0) { o0 = 1.f / (1.f + expf(x0)); o1 = 1.f / (1.f + expf(x1)); }
                    else         { o0 = sigf(x0); o1 = sigf(x1); }
                }
                *(float2*)(C + i0) = make_float2(o0, o1);
                if (D0) *(__nv_bfloat162*)((__nv_bfloat16*)D0 + i0) = __floats2bfloat162_rn(o0, o1);
            }
        }
    }
}

// ---------- column-mean stage A ----------
__global__ void k_colmean_a(const float* __restrict__ U, float* __restrict__ part16, int chunk) {
    int j = blockIdx.x, b = blockIdx.y, c = threadIdx.x;
    const float* p = U + ((size_t)(b * gridDim.x + j) * chunk) * CDIM + c;
    float s0 = 0.f, s1 = 0.f, s2 = 0.f, s3 = 0.f;
    for (int t = 0; t < chunk; t += 4) {
        s0 += p[(size_t)t * CDIM];
        s1 += p[(size_t)(t + 1) * CDIM];
        s2 += p[(size_t)(t + 2) * CDIM];
        s3 += p[(size_t)(t + 3) * CDIM];
    }
    part16[(b * 16 + j) * 256 + c] = s0 + s1 + s2 + s3;
}

// ---------- fused mean reduce + layernorm ----------
__global__ void k_ctx(const float* __restrict__ part16, float inv,
                      const float* __restrict__ g, const float* __restrict__ be,
                      float* __restrict__ cln) {
    int b = blockIdx.x, c = threadIdx.x;
    __shared__ float red[256];
    float m = 0.f;
    for (int j = 0; j < 16; j++) m += part16[(b * 16 + j) * 256 + c];
    m *= inv;
    red[c] = m; __syncthreads();
    for (int s = 128; s > 0; s >>= 1) { if (c < s) red[c] += red[c + s]; __syncthreads(); }
    float mu = red[0] * (1.f / 256.f); __syncthreads();
    float d = m - mu;
    red[c] = d * d; __syncthreads();
    for (int s = 128; s > 0; s >>= 1) { if (c < s) red[c] += red[c + s]; __syncthreads(); }
    float var = red[0] * (1.f / 256.f);
    cln[b * 256 + c] = d * rsqrtf(var + LN_EPS) * g[c] + be[c];
}

// ---------- per-batch gate bias tables ----------
__global__ void k_gatebias(const float* __restrict__ cln,
                           const float* __restrict__ Wf, const float* __restrict__ bf,
                           const float* __restrict__ Ww, const float* __restrict__ bw,
                           const float* __restrict__ Wo, const float* __restrict__ bo,
                           float* __restrict__ fb, float* __restrict__ wb, float* __restrict__ ob) {
    int which = blockIdx.x, b = blockIdx.y, c = threadIdx.x;
    __shared__ float sc[256];
    sc[c] = cln[b * 256 + c]; __syncthreads();
    const float* W  = (which == 0) ? Wf : (which == 1) ? Ww : Wo;
    const float* bi = (which == 0) ? bf : (which == 1) ? bw : bo;
    float* o        = (which == 0) ? fb : (which == 1) ? wb : ob;
    float acc = bi[c];
    for (int k = 0; k < 256; k++) acc += sc[k] * W[(size_t)(256 + k) * 256 + c];
    o[b * 256 + c] = acc;
}

// ---------- scan phase 1 (GA=a, GB=g; b=(1-a)*g*u) ----------
__global__ void k_scan1(const float* __restrict__ GA, const float* __restrict__ GB,
                        const float* __restrict__ U,
                        float* __restrict__ AGA, float* __restrict__ ABF, float* __restrict__ ABB) {
    int j = blockIdx.x, b = blockIdx.y, c = threadIdx.x;
    size_t base = ((size_t)b * NTOK + j * 128) * CDIM + c;
    float A = 1.f, sf = 0.f;
    for (int t = 0; t < 128; t++) {
        size_t i = base + (size_t)t * CDIM;
        float a = GA[i];
        float bb = (1.f - a) * GB[i] * U[i];
        A *= a; sf = a * sf + bb;
    }
    float sb = 0.f;
    for (int t = 127; t >= 0; t--) {
        size_t i = base + (size_t)t * CDIM;
        float a = GA[i];
        float bb = (1.f - a) * GB[i] * U[i];
        sb = a * sb + bb;
    }
    int o = (b * 32 + j) * 256 + c;
    AGA[o] = A; ABF[o] = sf; ABB[o] = sb;
}

// ---------- scan phase 2 ----------
__global__ void k_scan2(const float* __restrict__ AGA, const float* __restrict__ ABF,
                        const float* __restrict__ ABB, float* __restrict__ SIF, float* __restrict__ SIB) {
    int b = blockIdx.x, c = threadIdx.x;
    float s = 0.f;
    for (int j = 0; j < 32; j++) {
        int o = (b * 32 + j) * 256 + c;
        SIF[o] = s; s = AGA[o] * s + ABF[o];
    }
    s = 0.f;
    for (int j = 31; j >= 0; j--) {
        int o = (b * 32 + j) * 256 + c;
        SIB[o] = s; s = AGA[o] * s + ABB[o];
    }
}

// ---------- scan phase 3 (+bf16 mirrors of YF, YB) ----------
__global__ void k_scan3(const float* __restrict__ GA, const float* __restrict__ GB,
                        const float* __restrict__ GO, const float* __restrict__ U,
                        const float* __restrict__ SIF, const float* __restrict__ SIB,
                        float* __restrict__ YF, float* __restrict__ YB,
                        __nv_bfloat16* __restrict__ YF16, __nv_bfloat16* __restrict__ YB16) {
    int j = blockIdx.x, b = blockIdx.y, c = threadIdx.x;
    size_t base = ((size_t)b * NTOK + j * 128) * CDIM + c;
    int ao = (b * 32 + j) * 256 + c;
    float s = SIF[ao];
    for (int t = 0; t < 128; t++) {
        size_t i = base + (size_t)t * CDIM;
        float a = GA[i], u = U[i];
        float bb = (1.f - a) * GB[i] * u;
        s = a * s + bb;
        float o = GO[i];
        float y = o * s + (1.f - o) * u;
        YF[i] = y; YF16[i] = __float2bfloat16_rn(y);
    }
    s = SIB[ao];
    for (int t = 127; t >= 0; t--) {
        size_t i = base + (size_t)t * CDIM;
        float a = GA[i], u = U[i];
        float bb = (1.f - a) * GB[i] * u;
        s = a * s + bb;
        float o = GO[i];
        float y = o * s + (1.f - o) * u;
        YB[i] = y; YB16[i] = __float2bfloat16_rn(y);
    }
}

// ---------- global branch serial scan ----------
__global__ void k_scanglob(const float* __restrict__ GA, const float* __restrict__ GB,
                           const float* __restrict__ GO, const float* __restrict__ U,
                           float* __restrict__ YG) {
    int b = blockIdx.x, c = threadIdx.x;
    size_t base = (size_t)b * NTOKG * CDIM + c;
    float s = 0.f;
    for (int t = 0; t < NTOKG; t++) {
        size_t i = base + (size_t)t * CDIM;
        float a = GA[i], u = U[i];
        float bb = (1.f - a) * GB[i] * u;
        s = a * s + bb;
        float o = GO[i];
        YG[i] = o * s + (1.f - o) * u;
    }
}

// ---------- 4x4 avg pool ----------
__global__ void k_pool(const float* __restrict__ seq, float* __restrict__ seqg) {
    int tg = blockIdx.x, b = blockIdx.y, c = threadIdx.x;
    int gh = tg / 16, gw = tg % 16;
    float s = 0.f;
#pragma unroll
    for (int i = 0; i < 4; i++)
#pragma unroll
        for (int j = 0; j < 4; j++)
            s += seq[((size_t)b * NTOK + (gh * 4 + i) * 64 + gw * 4 + j) * CDIM + c];
    seqg[((size_t)b * NTOKG + tg) * CDIM + c] = s * (1.0f / 16.0f);
}

// ---------- bilinear upsample (+bf16 mirror) ----------
__global__ void k_upsample(const float* __restrict__ YG, float* __restrict__ YGS,
                           __nv_bfloat16* __restrict__ YGS16) {
    int t = blockIdx.x, b = blockIdx.y, c = threadIdx.x;
    int oh = t / 64, ow = t % 64;
    float sy = (oh + 0.5f) * 0.25f - 0.5f;
    float sx = (ow + 0.5f) * 0.25f - 0.5f;
    int y0 = (int)floorf(sy); float fy = sy - y0;
    int x0 = (int)floorf(sx); float fx = sx - x0;
    int y0c = clampi(y0, 0, 15), y1c = clampi(y0 + 1, 0, 15);
    int x0c = clampi(x0, 0, 15), x1c = clampi(x0 + 1, 0, 15);
    const float* base = YG + (size_t)b * NTOKG * CDIM + c;
    float v00 = base[(size_t)(y0c * 16 + x0c) * CDIM];
    float v01 = base[(size_t)(y0c * 16 + x1c) * CDIM];
    float v10 = base[(size_t)(y1c * 16 + x0c) * CDIM];
    float v11 = base[(size_t)(y1c * 16 + x1c) * CDIM];
    float v = (1.f - fy) * ((1.f - fx) * v00 + fx * v01) + fy * ((1.f - fx) * v10 + fx * v11);
    size_t i = ((size_t)b * NTOK + t) * CDIM + c;
    YGS[i] = v; YGS16[i] = __float2bfloat16_rn(v);
}

// ---------- depthwise 3x3 conv, sliding window (+bf16 mirror) ----------
__global__ void k_dwconv(const float* __restrict__ seq, const float* __restrict__ w,
                         const float* __restrict__ bias, float* __restrict__ VM,
                         __nv_bfloat16* __restrict__ VM16) {
    int h = blockIdx.x, b = blockIdx.y, c = threadIdx.x;
    float wr[9];
#pragma unroll
    for (int k = 0; k < 9; k++) wr[k] = w[c * 9 + k];
    float bi = bias[c];
    const float* sp = seq + (size_t)b * NTOK * CDIM + c;
    bool h0ok = (h - 1) >= 0, h2ok = (h + 1) < 64;
    size_t r0 = (size_t)(h - 1) * 64, r1 = (size_t)h * 64, r2 = (size_t)(h + 1) * 64;
    float m0 = 0.f, m1 = 0.f, m2 = 0.f;
    float c0 = h0ok ? sp[(r0 + 0) * CDIM] : 0.f;
    float c1 = sp[(r1 + 0) * CDIM];
    float c2 = h2ok ? sp[(r2 + 0) * CDIM] : 0.f;
    float n0 = h0ok ? sp[(r0 + 1) * CDIM] : 0.f;
    float n1 = sp[(r1 + 1) * CDIM];
    float n2 = h2ok ? sp[(r2 + 1) * CDIM] : 0.f;
    size_t obase = ((size_t)b * NTOK + (size_t)h * 64) * CDIM + c;
    for (int x = 0; x < 64; x++) {
        float acc = bi
            + wr[0] * m0 + wr[1] * c0 + wr[2] * n0
            + wr[3] * m1 + wr[4] * c1 + wr[5] * n1
            + wr[6] * m2 + wr[7] * c2 + wr[8] * n2;
        VM[obase + (size_t)x * CDIM] = acc;
        VM16[obase + (size_t)x * CDIM] = __float2bfloat16_rn(acc);
        m0 = c0; m1 = c1; m2 = c2;
        c0 = n0; c1 = n1; c2 = n2;
        if (x + 2 < 64) {
            n0 = h0ok ? sp[(r0 + x + 2) * CDIM] : 0.f;
            n1 = sp[(r1 + x + 2) * CDIM];
            n2 = h2ok ? sp[(r2 + x + 2) * CDIM] : 0.f;
        } else { n0 = n1 = n2 = 0.f; }
    }
}

extern "C" void kernel_launch(void* const* d_in, const int* in_sizes, int n_in,
                              void* d_out, int out_size) {
    const float* x        = (const float*)d_in[0];
    const float* Wt       = (const float*)d_in[1];
    const float* bt       = (const float*)d_in[2];
    const float* pos_fine = (const float*)d_in[3];
    const float* pos_glob = (const float*)d_in[4];
    const float* ln_g     = (const float*)d_in[5];
    const float* ln_b     = (const float*)d_in[6];
    const float* Wf       = (const float*)d_in[7];
    const float* bf       = (const float*)d_in[8];
    const float* Ww       = (const float*)d_in[9];
    const float* bw       = (const float*)d_in[10];
    const float* Wo       = (const float*)d_in[11];
    const float* bo       = (const float*)d_in[12];
    const float* Wr       = (const float*)d_in[13];
    const float* br       = (const float*)d_in[14];
    const float* Wgi      = (const float*)d_in[15];
    const float* bgi      = (const float*)d_in[16];
    const float* dw_w     = (const float*)d_in[17];
    const float* dw_b     = (const float*)d_in[18];
    const float* Wl       = (const float*)d_in[19];
    const float* bl       = (const float*)d_in[20];
    const float* Wlf      = (const float*)d_in[21];
    const float* blf      = (const float*)d_in[22];
    const float* Wout     = (const float*)d_in[23];
    const float* bout     = (const float*)d_in[24];
    float* outp = (float*)d_out;

    float* S = nullptr;
    cudaGetSymbolAddress((void**)&S, g_scratch);
    float* SEQ  = S + OFF_SEQ;  float* U    = S + OFF_U;
    float* GA   = S + OFF_GA;   float* GB   = S + OFF_GB;   float* GO  = S + OFF_GO;
    float* YF   = S + OFF_YF;   float* YB   = S + OFF_YB;   float* Y   = S + OFF_Y;
    float* YGS  = S + OFF_YGS;  float* Z    = S + OFF_Z;
    float* VM   = S + OFF_VM;   float* V    = S + OFF_V;
    float* UO   = S + OFF_UOUT; float* PROJ = S + OFF_PROJ;
    float* SEQG = S + OFF_SEQG; float* UG   = S + OFF_UG;
    float* GAG  = S + OFF_GAG;  float* GBG  = S + OFF_GBG;  float* GOG = S + OFF_GOG;
    float* YG   = S + OFF_YG;
    float* POSF = S + OFF_POSF; float* POSG = S + OFF_POSG;
    float* CLN  = S + OFF_CLN;  float* CLNG = S + OFF_CLNG;
    float* FB = S + OFF_FB, *WB = S + OFF_WB, *OB = S + OFF_OB;
    float* FBG = S + OFF_FBG, *WBG = S + OFF_WBG, *OBG = S + OFF_OBG;
    float* AGA = S + OFF_AGA, *ABF = S + OFF_ABF, *ABB = S + OFF_ABB;
    float* SIF = S + OFF_SIF, *SIB = S + OFF_SIB;
    float* P16 = S + OFF_P16;
    uint32_t* WBW = (uint32_t*)(S + OFF_WBW);
    __nv_bfloat16* U16   = (__nv_bfloat16*)(S + OFF_U16);
    __nv_bfloat16* YF16  = (__nv_bfloat16*)(S + OFF_YF16);
    __nv_bfloat16* YB16  = (__nv_bfloat16*)(S + OFF_YB16);
    __nv_bfloat16* Y16   = (__nv_bfloat16*)(S + OFF_Y16);
    __nv_bfloat16* YGS16 = (__nv_bfloat16*)(S + OFF_YGS16);
    __nv_bfloat16* V16   = (__nv_bfloat16*)(S + OFF_V16);
    __nv_bfloat16* Z16   = (__nv_bfloat16*)(S + OFF_Z16);
    __nv_bfloat16* SEQ16 = (__nv_bfloat16*)(S + OFF_SEQ16);
    __nv_bfloat16* VM16  = (__nv_bfloat16*)(S + OFF_VM16);
    __nv_bfloat16* UO16  = (__nv_bfloat16*)(S + OFF_UO16);

    uint32_t* WBf  = WBW + (size_t)0    * 256;
    uint32_t* WBw  = WBW + (size_t)128  * 256;
    uint32_t* WBo  = WBW + (size_t)256  * 256;
    uint32_t* WBr0 = WBW + (size_t)384  * 256;
    uint32_t* WBr1 = WBW + (size_t)512  * 256;
    uint32_t* WBr2 = WBW + (size_t)640  * 256;
    uint32_t* WBg0 = WBW + (size_t)768  * 256;
    uint32_t* WBg1 = WBW + (size_t)896  * 256;
    uint32_t* WBg2 = WBW + (size_t)1024 * 256;
    uint32_t* WBl0 = WBW + (size_t)1152 * 256;
    uint32_t* WBl1 = WBW + (size_t)1280 * 256;
    uint32_t* WBt  = WBW + (size_t)1408 * 256;
    uint32_t* WBl  = WBW + (size_t)1536 * 256;
    uint32_t* WBout= WBW + (size_t)1664 * 256;

    static int smem_set = 0;
    int smem_tf = NSTAGE * STAGE_ELEMS * 4;
    int smem_bf = NSTB * BSTG_EL * 4;
    if (!smem_set) {
        cudaFuncSetAttribute(k_gemm_tc, cudaFuncAttributeMaxDynamicSharedMemorySize, smem_tf);
        cudaFuncSetAttribute(k_gemm_bf, cudaFuncAttributeMaxDynamicSharedMemorySize, smem_bf);
        smem_set = 1;
    }

    dim3 tb(32, 8);
    dim3 tg(128, 8, 8);
    dim3 gemF(2, MFINE / 128), gemG(2, MGLOB / 128);
    dim3 gemG3(2, MGLOB / 128, 3), gemF3(2, MFINE / 128, 3);
    const float* NP = nullptr;
    float* NPo = nullptr;
    __nv_bfloat16* NPh = nullptr;
    const __nv_bfloat16* NPhc = nullptr;
    const uint32_t* NPw = nullptr;

    // prep
    k_transpose<<<tg, tb>>>(x, SEQ, SEQ16);
    k_wcvt<<<1792, 256>>>(Wf, Ww, Wo, Wr, Wgi, Wlf, Wt, Wl, Wout, WBW);
    k_posup<<<4096, 256>>>(pos_fine, POSF, 64, 64);
    k_posdown<<<256, 256>>>(pos_glob, POSG);

    // U = SEQ@Wt + bt + pos (bf16, mode 1) -> U + U16
    k_gemm_bf<<<gemF, 256, smem_bf>>>(SEQ16, WBt, NPhc, NPw, NPhc, NPw, 1, U, NPo, NPo, bt, 1, POSF, NP, 4095, 0, U16);

    // gates (fine): bf16 multi GEMM with fused gate epilogue (mode 4)
    k_colmean_a<<<dim3(16, BATCH), 256>>>(U, P16, 256);
    k_ctx<<<BATCH, 256>>>(P16, 1.0f / NTOK, ln_g, ln_b, CLN);
    k_gatebias<<<dim3(3, BATCH), 256>>>(CLN, Wf, bf, Ww, bw, Wo, bo, FB, WB, OB);
    k_gemm_bf<<<gemF3, 256, smem_bf>>>(U16, WBf, NPhc, WBw, NPhc, WBo, 1, GA, GB, GO, OB, 4, FB, WB, NTOK, 1, NPh);

    // bidirectional chunked scan
    k_scan1<<<dim3(32, BATCH), 256>>>(GA, GB, U, AGA, ABF, ABB);
    k_scan2<<<BATCH, 256>>>(AGA, ABF, ABB, SIF, SIB);
    k_scan3<<<dim3(32, BATCH), 256>>>(GA, GB, GO, U, SIF, SIB, YF, YB, YF16, YB16);

    // rho mixing: bf16 3-pair, sigmoid-mix fused (mode 2) -> Y + Y16
    k_gemm_bf<<<gemF, 256, smem_bf>>>(U16, WBr0, YF16, WBr1, YB16, WBr2, 3, Y, NPo, NPo, br, 2, YF, YB, 0, 0, Y16);

    // global branch (tf32)
    k_pool<<<dim3(256, BATCH), 256>>>(SEQ, SEQG);
    k_gemm_tc<<<gemG, 256, smem_tf>>>(SEQG, Wt, NP, NP, NP, NP, 1, UG, NPo, NPo, bt, 1, POSG, NP, 255, 0, NPh);
    k_colmean_a<<<dim3(16, BATCH), 256>>>(UG, P16, 16);
    k_ctx<<<BATCH, 256>>>(P16, 1.0f / NTOKG, ln_g, ln_b, CLNG);
    k_gatebias<<<dim3(3, BATCH), 256>>>(CLNG, Wf, bf, Ww, bw, Wo, bo, FBG, WBG, OBG);
    k_gemm_tc<<<gemG3, 256, smem_tf>>>(UG, Wf, NP, Ww, NP, Wo, 1, GAG, GBG, GOG, OBG, 4, FBG, WBG, NTOKG, 1, NPh);
    k_scanglob<<<BATCH, 256>>>(GAG, GBG, GOG, UG, YG);
    k_upsample<<<dim3(4096, BATCH), 256>>>(YG, YGS, YGS16);

    // lam mixing: bf16 3-pair, lam-add fused (mode 3) -> Z + Z16
    k_gemm_bf<<<gemF, 256, smem_bf>>>(Y16, WBg0, YGS16, WBg1, U16, WBg2, 3, Z, NPo, NPo, bgi, 3, Y, YGS, 0, 0, Z16);

    // local depthwise branch (bf16 value GEMMs)
    k_dwconv<<<dim3(64, BATCH), 256>>>(SEQ, dw_w, dw_b, VM, VM16);
    k_gemm_bf<<<gemF, 256, smem_bf>>>(VM16, WBl, NPhc, NPw, NPhc, NPw, 1, V, NPo, NPo, bl, 0, NP, NP, 0, 0, V16);
    k_gemm_bf<<<gemF, 256, smem_bf>>>(V16, WBl0, Z16, WBl1, NPhc, NPw, 2, UO, NPo, NPo, blf, 2, V, Z, 0, 0, UO16);

    // output proj + residual (bf16)
    k_gemm_bf<<<gemF, 256, smem_bf>>>(UO16, WBout, NPhc, NPw, NPhc, NPw, 1, PROJ, NPo, NPo, bout, 0, NP, NP, 0, 0, NPh);
    k_output<<<tg, tb>>>(PROJ, x, outp);
}

// round 12
// speedup vs baseline: 3.9145x; 1.1481x over previous
#include <cuda_runtime.h>
#include <cuda_bf16.h>
#include <math.h>
#include <stdint.h>

#define BATCH 8
#define CDIM  256
#define NTOK  4096
#define NTOKG 256
#define MFINE 32768
#define MGLOB 2048
#define LN_EPS 1e-5f

static const size_t U_SZ  = (size_t)MFINE * CDIM;
static const size_t H_SZ  = U_SZ / 2;
static const size_t SG_SZ = (size_t)MGLOB * CDIM;

static const size_t OFF_SEQ   = 0*U_SZ;
static const size_t OFF_U     = 1*U_SZ;
static const size_t OFF_GA    = 2*U_SZ;
static const size_t OFF_GB    = 3*U_SZ;
static const size_t OFF_GO    = 4*U_SZ;
static const size_t OFF_PROJ  = 5*U_SZ;
static const size_t SMALL0    = 6*U_SZ;
static const size_t OFF_SEQG  = SMALL0 + 0*SG_SZ;
static const size_t OFF_UG    = SMALL0 + 1*SG_SZ;
static const size_t OFF_GAG   = SMALL0 + 2*SG_SZ;
static const size_t OFF_GBG   = SMALL0 + 3*SG_SZ;
static const size_t OFF_GOG   = SMALL0 + 4*SG_SZ;
static const size_t OFF_YG    = SMALL0 + 5*SG_SZ;
static const size_t SMALL1    = SMALL0 + 6*SG_SZ;
static const size_t OFF_POSF  = SMALL1;
static const size_t OFF_POSG  = OFF_POSF + 4096*256;
static const size_t OFF_CLN   = OFF_POSG + 65536;
static const size_t OFF_CLNG  = OFF_CLN + 2048;
static const size_t OFF_FB    = OFF_CLNG + 2048;
static const size_t OFF_WB    = OFF_FB + 2048;
static const size_t OFF_OB    = OFF_WB + 2048;
static const size_t OFF_FBG   = OFF_OB + 2048;
static const size_t OFF_WBG   = OFF_FBG + 2048;
static const size_t OFF_OBG   = OFF_WBG + 2048;
static const size_t OFF_AGA   = OFF_OBG + 2048;
static const size_t OFF_ABF   = OFF_AGA + 65536;
static const size_t OFF_ABB   = OFF_ABF + 65536;
static const size_t OFF_SIF   = OFF_ABB + 65536;
static const size_t OFF_SIB   = OFF_SIF + 65536;
static const size_t OFF_P16   = OFF_SIB + 65536;
static const size_t OFF_WBW   = OFF_P16 + 32768;           // bf16x2 weights: 1792*256 u32
static const size_t OFF_U16   = OFF_WBW + 458752;
static const size_t OFF_YF16  = OFF_U16  + H_SZ;
static const size_t OFF_YB16  = OFF_YF16 + H_SZ;
static const size_t OFF_Y16   = OFF_YB16 + H_SZ;
static const size_t OFF_YGS16 = OFF_Y16  + H_SZ;
static const size_t OFF_V16   = OFF_YGS16+ H_SZ;
static const size_t OFF_Z16   = OFF_V16  + H_SZ;
static const size_t OFF_SEQ16 = OFF_Z16  + H_SZ;
static const size_t OFF_VM16  = OFF_SEQ16+ H_SZ;
static const size_t OFF_UO16  = OFF_VM16 + H_SZ;
static const size_t TOTAL_SCRATCH = OFF_UO16 + H_SZ + 1024;

__device__ __align__(16) float g_scratch[TOTAL_SCRATCH];

__device__ __forceinline__ float sigf(float x) { return 1.0f / (1.0f + expf(-x)); }
__device__ __forceinline__ int clampi(int v, int lo, int hi) { return v < lo ? lo : (v > hi ? hi : v); }

__device__ __forceinline__ void mma_tf32(float* c, const uint32_t* a, const uint32_t* b) {
    asm volatile(
        "mma.sync.aligned.m16n8k8.row.col.f32.tf32.tf32.f32 "
        "{%0,%1,%2,%3}, {%4,%5,%6,%7}, {%8,%9}, {%0,%1,%2,%3};\n"
        : "+f"(c[0]), "+f"(c[1]), "+f"(c[2]), "+f"(c[3])
        : "r"(a[0]), "r"(a[1]), "r"(a[2]), "r"(a[3]), "r"(b[0]), "r"(b[1]));
}
__device__ __forceinline__ void mma_bf16(float* c, const uint32_t* a, const uint32_t* b) {
    asm volatile(
        "mma.sync.aligned.m16n8k16.row.col.f32.bf16.bf16.f32 "
        "{%0,%1,%2,%3}, {%4,%5,%6,%7}, {%8,%9}, {%0,%1,%2,%3};\n"
        : "+f"(c[0]), "+f"(c[1]), "+f"(c[2]), "+f"(c[3])
        : "r"(a[0]), "r"(a[1]), "r"(a[2]), "r"(a[3]), "r"(b[0]), "r"(b[1]));
}
__device__ __forceinline__ void ldsm4(uint32_t* r, uint32_t saddr) {
    asm volatile("ldmatrix.sync.aligned.m8n8.x4.shared.b16 {%0,%1,%2,%3}, [%4];"
        : "=r"(r[0]), "=r"(r[1]), "=r"(r[2]), "=r"(r[3]) : "r"(saddr));
}

__device__ __forceinline__ void cpa16(uint32_t dst, const void* src) {
    asm volatile("cp.async.cg.shared.global [%0], [%1], 16;" :: "r"(dst), "l"(src));
}
#define CP_COMMIT() asm volatile("cp.async.commit_group;")
#define CP_WAIT1()  asm volatile("cp.async.wait_group 1;")
#define CP_WAIT2()  asm volatile("cp.async.wait_group 2;")

__device__ __forceinline__ const float* selp(const float* a0, const float* a1,
                                             const float* a2, int p) {
    return p == 0 ? a0 : (p == 1 ? a1 : a2);
}
__device__ __forceinline__ const __nv_bfloat16* selh(const __nv_bfloat16* a0,
                                                     const __nv_bfloat16* a1,
                                                     const __nv_bfloat16* a2, int p) {
    return p == 0 ? a0 : (p == 1 ? a1 : a2);
}
__device__ __forceinline__ const uint32_t* selw(const uint32_t* a0, const uint32_t* a1,
                                                const uint32_t* a2, int p) {
    return p == 0 ? a0 : (p == 1 ? a1 : a2);
}

// ---------- x [B,C,4096] -> seq [B*4096, C] (+bf16 mirror) ----------
__global__ void k_transpose(const float* __restrict__ x, float* __restrict__ seq,
                            __nv_bfloat16* __restrict__ seq16) {
    __shared__ float tile[32][33];
    int b = blockIdx.z;
    int t0 = blockIdx.x * 32, c0 = blockIdx.y * 32;
    int tx = threadIdx.x, ty = threadIdx.y;
    const float* src = x + (size_t)b * CDIM * NTOK;
#pragma unroll
    for (int j = 0; j < 4; j++)
        tile[ty + 8*j][tx] = src[(size_t)(c0 + ty + 8*j) * NTOK + t0 + tx];
    __syncthreads();
    float* dst = seq + (size_t)b * NTOK * CDIM;
    __nv_bfloat16* dsth = seq16 + (size_t)b * NTOK * CDIM;
#pragma unroll
    for (int j = 0; j < 4; j++) {
        float v = tile[tx][ty + 8*j];
        size_t o = (size_t)(t0 + ty + 8*j) * CDIM + c0 + tx;
        dst[o] = v; dsth[o] = __float2bfloat16_rn(v);
    }
}

// ---------- proj [B,4096,C] + x -> out [B,C,4096] ----------
__global__ void k_output(const float* __restrict__ proj, const float* __restrict__ x,
                         float* __restrict__ outp) {
    __shared__ float tile[32][33];
    int b = blockIdx.z;
    int t0 = blockIdx.x * 32, c0 = blockIdx.y * 32;
    int tx = threadIdx.x, ty = threadIdx.y;
    const float* src = proj + (size_t)b * NTOK * CDIM;
#pragma unroll
    for (int j = 0; j < 4; j++)
        tile[ty + 8*j][tx] = src[(size_t)(t0 + ty + 8*j) * CDIM + c0 + tx];
    __syncthreads();
    size_t base = (size_t)b * CDIM * NTOK;
#pragma unroll
    for (int j = 0; j < 4; j++) {
        size_t o = base + (size_t)(c0 + ty + 8*j) * NTOK + t0 + tx;
        outp[o] = x[o] + tile[tx][ty + 8*j];
    }
}

// ---------- pos bilinear upsample ----------
__global__ void k_posup(const float* __restrict__ pos, float* __restrict__ outp, int OH, int OW) {
    int t = blockIdx.x, c = threadIdx.x;
    int oh = t / OW, ow = t % OW;
    float sy = (oh + 0.5f) * (32.0f / OH) - 0.5f;
    float sx = (ow + 0.5f) * (32.0f / OW) - 0.5f;
    int y0 = (int)floorf(sy); float fy = sy - y0;
    int x0 = (int)floorf(sx); float fx = sx - x0;
    int y0c = clampi(y0, 0, 31), y1c = clampi(y0 + 1, 0, 31);
    int x0c = clampi(x0, 0, 31), x1c = clampi(x0 + 1, 0, 31);
    const float* p = pos + (size_t)c * 1024;
    float v = (1.f - fy) * ((1.f - fx) * p[y0c*32 + x0c] + fx * p[y0c*32 + x1c])
            + fy * ((1.f - fx) * p[y1c*32 + x0c] + fx * p[y1c*32 + x1c]);
    outp[(size_t)t * CDIM + c] = v;
}

// ---------- pos antialiased downsample 32->16 ----------
__global__ void k_posdown(const float* __restrict__ pos, float* __restrict__ outp) {
    int t = blockIdx.x, c = threadIdx.x;
    int gh = t / 16, gw = t % 16;
    const float W4[4] = {0.125f, 0.375f, 0.375f, 0.125f};
    float wy[4], wx[4]; int ky[4], kx[4];
    float sy = 0.f, sx = 0.f;
#pragma unroll
    for (int d = 0; d < 4; d++) {
        ky[d] = 2*gh - 1 + d; wy[d] = (ky[d] >= 0 && ky[d] < 32) ? W4[d] : 0.f; sy += wy[d];
        kx[d] = 2*gw - 1 + d; wx[d] = (kx[d] >= 0 && kx[d] < 32) ? W4[d] : 0.f; sx += wx[d];
    }
    const float* p = pos + (size_t)c * 1024;
    float acc = 0.f;
#pragma unroll
    for (int d = 0; d < 4; d++) {
        if (wy[d] == 0.f) continue;
        float rowacc = 0.f;
#pragma unroll
        for (int e = 0; e < 4; e++)
            if (wx[e] != 0.f) rowacc += wx[e] * p[ky[d]*32 + kx[e]];
        acc += wy[d] * rowacc;
    }
    outp[(size_t)t * CDIM + c] = acc / (sy * sx);
}

// ---------- weight interleave: 9 weights -> bf16x2 [k2][256] ----------
__global__ void k_wcvt(const float* __restrict__ Wf, const float* __restrict__ Ww,
                       const float* __restrict__ Wo, const float* __restrict__ Wr,
                       const float* __restrict__ Wgi, const float* __restrict__ Wlf,
                       const float* __restrict__ Wt, const float* __restrict__ Wl,
                       const float* __restrict__ Wout, uint32_t* __restrict__ WB) {
    int r = blockIdx.x, c = threadIdx.x;
    const float* src; int k2;
    if (r < 128)       { src = Wf;   k2 = r; }
    else if (r < 256)  { src = Ww;   k2 = r - 128; }
    else if (r < 384)  { src = Wo;   k2 = r - 256; }
    else if (r < 768)  { src = Wr;   k2 = r - 384; }
    else if (r < 1152) { src = Wgi;  k2 = r - 768; }
    else if (r < 1408) { src = Wlf;  k2 = r - 1152; }
    else if (r < 1536) { src = Wt;   k2 = r - 1408; }
    else if (r < 1664) { src = Wl;   k2 = r - 1536; }
    else               { src = Wout; k2 = r - 1664; }
    float lo = src[(size_t)(2*k2) * 256 + c];
    float hi = src[(size_t)(2*k2 + 1) * 256 + c];
    __nv_bfloat162 p2 = __floats2bfloat162_rn(lo, hi);
    WB[(size_t)r * 256 + c] = *(uint32_t*)&p2;
}

// ================= tf32 mma.sync GEMM (global branch only) =================
#define AS_STRIDE 36
#define BS_STRIDE 136
#define A_ELEMS (128*AS_STRIDE)
#define B_ELEMS (32*BS_STRIDE)
#define STAGE_ELEMS (A_ELEMS + B_ELEMS)
#define NSTAGE 3
extern __shared__ float smx[];

__global__ void __launch_bounds__(256, 2)
k_gemm_tc(const float* __restrict__ A0, const float* __restrict__ W0,
          const float* __restrict__ A1, const float* __restrict__ W1,
          const float* __restrict__ A2, const float* __restrict__ W2,
          int npairs,
          float* __restrict__ C0, float* __restrict__ C1, float* __restrict__ C2,
          const float* __restrict__ bias, int mode,
          const float* __restrict__ P1, const float* __restrict__ P2,
          int tokmask, int multi, __nv_bfloat16* __restrict__ D0) {
    int bx = blockIdx.x, by = blockIdx.y, bz = blockIdx.z;
    int tid = threadIdx.x;
    int warp = tid >> 5, lane = tid & 31;
    int wm = warp >> 2, wn = warp & 3;
    int g = lane >> 2, tq = lane & 3;

    uint32_t smem_u32 = (uint32_t)__cvta_generic_to_shared(smx);

    float acc[4][4][4];
#pragma unroll
    for (int i = 0; i < 4; i++)
#pragma unroll
        for (int j = 0; j < 4; j++)
#pragma unroll
            for (int r = 0; r < 4; r++) acc[i][j][r] = 0.f;

    int nst = (multi ? 1 : npairs) * 8;

    auto load_stage = [&](int st, int buf) {
        int p = multi ? bz : (st >> 3);
        const float* A = multi ? A0 : selp(A0, A1, A2, p);
        const float* W = selp(W0, W1, W2, p);
        int k0 = (st & 7) * 32;
        uint32_t abase = smem_u32 + (uint32_t)(buf * STAGE_ELEMS) * 4u;
        uint32_t bbase = abase + (uint32_t)A_ELEMS * 4u;
#pragma unroll
        for (int i = 0; i < 4; i++) {
            int idx = tid + 256 * i;
            int row = idx >> 3, c4 = idx & 7;
            cpa16(abase + (uint32_t)(row * AS_STRIDE + c4 * 4) * 4u,
                  A + (size_t)(by * 128 + row) * 256 + k0 + c4 * 4);
        }
#pragma unroll
        for (int i = 0; i < 4; i++) {
            int idx = tid + 256 * i;
            int row = idx >> 5, c4 = idx & 31;
            cpa16(bbase + (uint32_t)(row * BS_STRIDE + c4 * 4) * 4u,
                  W + (size_t)(k0 + row) * 256 + bx * 128 + c4 * 4);
        }
        CP_COMMIT();
    };

    load_stage(0, 0);
    load_stage(1, 1);

    for (int st = 0; st < nst; st++) {
        CP_WAIT1();
        __syncthreads();
        int nx = st + NSTAGE - 1;
        if (nx < nst) load_stage(nx, nx % NSTAGE);
        else CP_COMMIT();

        int pb = st % NSTAGE;
        const uint32_t* Asu = (const uint32_t*)(smx + pb * STAGE_ELEMS);
        const uint32_t* Bsu = Asu + A_ELEMS;
#pragma unroll
        for (int ks = 0; ks < 32; ks += 8) {
            uint32_t af[4][4], bf[4][2];
#pragma unroll
            for (int mt = 0; mt < 4; mt++) {
                int mb = wm * 64 + mt * 16;
                af[mt][0] = Asu[(mb + g) * AS_STRIDE + ks + tq];
                af[mt][1] = Asu[(mb + g + 8) * AS_STRIDE + ks + tq];
                af[mt][2] = Asu[(mb + g) * AS_STRIDE + ks + tq + 4];
                af[mt][3] = Asu[(mb + g + 8) * AS_STRIDE + ks + tq + 4];
            }
#pragma unroll
            for (int nt = 0; nt < 4; nt++) {
                int nb = wn * 32 + nt * 8;
                bf[nt][0] = Bsu[(ks + tq) * BS_STRIDE + nb + g];
                bf[nt][1] = Bsu[(ks + tq + 4) * BS_STRIDE + nb + g];
            }
#pragma unroll
            for (int mt = 0; mt < 4; mt++)
#pragma unroll
                for (int nt = 0; nt < 4; nt++)
                    mma_tf32(acc[mt][nt], af[mt], bf[nt]);
        }
    }

    float* C = multi ? (bz == 0 ? C0 : (bz == 1 ? C1 : C2)) : C0;
    int batch4 = (mode == 4) ? (by * 128) / tokmask : 0;
    const float* TB4 = (mode == 4) ? (bz == 0 ? P1 : (bz == 1 ? P2 : bias)) : nullptr;
#pragma unroll
    for (int mt = 0; mt < 4; mt++) {
        int r0 = by * 128 + wm * 64 + mt * 16 + g;
#pragma unroll
        for (int nt = 0; nt < 4; nt++) {
            int col = bx * 128 + wn * 32 + nt * 8 + tq * 2;
            float b0 = 0.f, b1 = 0.f;
            if (bias && mode != 4) { b0 = bias[col]; b1 = bias[col + 1]; }
#pragma unroll
            for (int h = 0; h < 2; h++) {
                int r = r0 + h * 8;
                float t0 = acc[mt][nt][2*h + 0] + b0;
                float t1 = acc[mt][nt][2*h + 1] + b1;
                size_t i0 = (size_t)r * 256 + col;
                float o0, o1;
                if (mode == 0) {
                    o0 = t0; o1 = t1;
                } else if (mode == 1) {
                    size_t pi = (size_t)(r & tokmask) * 256 + col;
                    o0 = t0 + P1[pi]; o1 = t1 + P1[pi + 1];
                } else if (mode == 2) {
                    float s0 = sigf(t0), s1 = sigf(t1);
                    o0 = s0 * P1[i0] + (1.f - s0) * P2[i0];
                    o1 = s1 * P1[i0 + 1] + (1.f - s1) * P2[i0 + 1];
                } else if (mode == 3) {
                    o0 = P1[i0] + sigf(t0) * P2[i0];
                    o1 = P1[i0 + 1] + sigf(t1) * P2[i0 + 1];
                } else {
                    float x0 = t0 + TB4[batch4 * 256 + col];
                    float x1 = t1 + TB4[batch4 * 256 + col + 1];
                    if (bz == 0) { o0 = 1.f / (1.f + expf(x0)); o1 = 1.f / (1.f + expf(x1)); }
                    else         { o0 = sigf(x0); o1 = sigf(x1); }
                }
                if (C) *(float2*)(C + i0) = make_float2(o0, o1);
                if (D0) *(__nv_bfloat162*)((__nv_bfloat16*)D0 + i0) = __floats2bfloat162_rn(o0, o1);
            }
        }
    }
}

// ================= bf16 mma.sync GEMM (all fine GEMMs) =================
// modes 2/3: P1/P2 interpreted as bf16 mirrors.
#define BA_STR 20
#define BB_STR 136
#define BA_EL (128*BA_STR)
#define BB_EL (16*BB_STR)
#define BSTG_EL (BA_EL + BB_EL)
#define NSTB 4

__global__ void __launch_bounds__(256, 2)
k_gemm_bf(const __nv_bfloat16* __restrict__ A0, const uint32_t* __restrict__ W0,
          const __nv_bfloat16* __restrict__ A1, const uint32_t* __restrict__ W1,
          const __nv_bfloat16* __restrict__ A2, const uint32_t* __restrict__ W2,
          int npairs,
          float* __restrict__ C0, float* __restrict__ C1, float* __restrict__ C2,
          const float* __restrict__ bias, int mode,
          const float* __restrict__ P1, const float* __restrict__ P2,
          int tokmask, int multi, __nv_bfloat16* __restrict__ D0) {
    int bx = blockIdx.x, by = blockIdx.y, bz = blockIdx.z;
    int tid = threadIdx.x;
    int warp = tid >> 5, lane = tid & 31;
    int wm = warp >> 2, wn = warp & 3;
    int g = lane >> 2, tq = lane & 3;

    uint32_t smem_u32 = (uint32_t)__cvta_generic_to_shared(smx);

    float acc[4][4][4];
#pragma unroll
    for (int i = 0; i < 4; i++)
#pragma unroll
        for (int j = 0; j < 4; j++)
#pragma unroll
            for (int r = 0; r < 4; r++) acc[i][j][r] = 0.f;

    int nst = (multi ? 1 : npairs) * 8;

    auto load_stage = [&](int st, int buf) {
        int p = multi ? bz : (st >> 3);
        const __nv_bfloat16* A = multi ? A0 : selh(A0, A1, A2, p);
        const uint32_t* W = selw(W0, W1, W2, p);
        int k0 = (st & 7) * 32;
        int k2b = k0 >> 1;
        uint32_t abase = smem_u32 + (uint32_t)(buf * BSTG_EL) * 4u;
        uint32_t bbase = abase + (uint32_t)BA_EL * 4u;
#pragma unroll
        for (int i = 0; i < 2; i++) {
            int idx = tid + 256 * i;
            int row = idx >> 2, c4 = idx & 3;
            cpa16(abase + (uint32_t)(row * BA_STR + c4 * 4) * 4u,
                  A + (size_t)(by * 128 + row) * 256 + k0 + c4 * 8);
        }
#pragma unroll
        for (int i = 0; i < 2; i++) {
            int idx = tid + 256 * i;
            int row = idx >> 5, c4 = idx & 31;
            cpa16(bbase + (uint32_t)(row * BB_STR + c4 * 4) * 4u,
                  W + (size_t)(k2b + row) * 256 + bx * 128 + c4 * 4);
        }
        CP_COMMIT();
    };

    load_stage(0, 0);
    load_stage(1, 1);
    load_stage(2, 2);

    int lrow = lane & 15;
    uint32_t kside = (uint32_t)((lane >> 4) << 4);   // 0 or 16 bytes

    for (int st = 0; st < nst; st++) {
        CP_WAIT2();
        __syncthreads();
        int nx = st + NSTB - 1;
        if (nx < nst) load_stage(nx, nx % NSTB);
        else CP_COMMIT();

        int pb = st % NSTB;
        uint32_t abyte = smem_u32 + (uint32_t)(pb * BSTG_EL) * 4u;
        const uint32_t* Bsu = (const uint32_t*)(smx + pb * BSTG_EL) + BA_EL;
#pragma unroll
        for (int s = 0; s < 2; s++) {
            int ko = 8 * s;
            uint32_t af[4][4], bf[4][2];
#pragma unroll
            for (int mt = 0; mt < 4; mt++) {
                uint32_t addr = abyte
                    + (uint32_t)((wm * 64 + mt * 16 + lrow) * BA_STR) * 4u
                    + kside + (uint32_t)(s * 32);
                ldsm4(af[mt], addr);
            }
#pragma unroll
            for (int nt = 0; nt < 4; nt++) {
                int nb = wn * 32 + nt * 8;
                bf[nt][0] = Bsu[(ko + tq) * BB_STR + nb + g];
                bf[nt][1] = Bsu[(ko + tq + 4) * BB_STR + nb + g];
            }
#pragma unroll
            for (int mt = 0; mt < 4; mt++)
#pragma unroll
                for (int nt = 0; nt < 4; nt++)
                    mma_bf16(acc[mt][nt], af[mt], bf[nt]);
        }
    }

    float* C = multi ? (bz == 0 ? C0 : (bz == 1 ? C1 : C2)) : C0;
    int batch4 = (mode == 4) ? (by * 128) / tokmask : 0;
    const float* TB4 = (mode == 4) ? (bz == 0 ? P1 : (bz == 1 ? P2 : bias)) : nullptr;
    const __nv_bfloat16* P1h = (const __nv_bfloat16*)P1;
    const __nv_bfloat16* P2h = (const __nv_bfloat16*)P2;
#pragma unroll
    for (int mt = 0; mt < 4; mt++) {
        int r0 = by * 128 + wm * 64 + mt * 16 + g;
#pragma unroll
        for (int nt = 0; nt < 4; nt++) {
            int col = bx * 128 + wn * 32 + nt * 8 + tq * 2;
            float b0 = 0.f, b1 = 0.f;
            if (bias && mode != 4) { b0 = bias[col]; b1 = bias[col + 1]; }
#pragma unroll
            for (int h = 0; h < 2; h++) {
                int r = r0 + h * 8;
                float t0 = acc[mt][nt][2*h + 0] + b0;
                float t1 = acc[mt][nt][2*h + 1] + b1;
                size_t i0 = (size_t)r * 256 + col;
                float o0, o1;
                if (mode == 0) {
                    o0 = t0; o1 = t1;
                } else if (mode == 1) {
                    size_t pi = (size_t)(r & tokmask) * 256 + col;
                    o0 = t0 + P1[pi]; o1 = t1 + P1[pi + 1];
                } else if (mode == 2) {
                    __nv_bfloat162 p1 = *(const __nv_bfloat162*)(P1h + i0);
                    __nv_bfloat162 p2 = *(const __nv_bfloat162*)(P2h + i0);
                    float s0 = sigf(t0), s1 = sigf(t1);
                    o0 = s0 * __bfloat162float(p1.x) + (1.f - s0) * __bfloat162float(p2.x);
                    o1 = s1 * __bfloat162float(p1.y) + (1.f - s1) * __bfloat162float(p2.y);
                } else if (mode == 3) {
                    __nv_bfloat162 p1 = *(const __nv_bfloat162*)(P1h + i0);
                    __nv_bfloat162 p2 = *(const __nv_bfloat162*)(P2h + i0);
                    o0 = __bfloat162float(p1.x) + sigf(t0) * __bfloat162float(p2.x);
                    o1 = __bfloat162float(p1.y) + sigf(t1) * __bfloat162float(p2.y);
                } else {
                    float x0 = t0 + TB4[batch4 * 256 + col];
                    float x1 = t1 + TB4[batch4 * 256 + col + 1];
                    if (bz == 0) { o0 = 1.f / (1.f + expf(x0)); o1 = 1.f / (1.f + expf(x1)); }
                    else         { o0 = sigf(x0); o1 = sigf(x1); }
                }
                if (C) *(float2*)(C + i0) = make_float2(o0, o1);
                if (D0) *(__nv_bfloat162*)((__nv_bfloat16*)D0 + i0) = __floats2bfloat162_rn(o0, o1);
            }
        }
    }
}

// ---------- column-mean stage A ----------
__global__ void k_colmean_a(const float* __restrict__ U, float* __restrict__ part16, int chunk) {
    int j = blockIdx.x, b = blockIdx.y, c = threadIdx.x;
    const float* p = U + ((size_t)(b * gridDim.x + j) * chunk) * CDIM + c;
    float s0 = 0.f, s1 = 0.f, s2 = 0.f, s3 = 0.f;
    for (int t = 0; t < chunk; t += 4) {
        s0 += p[(size_t)t * CDIM];
        s1 += p[(size_t)(t + 1) * CDIM];
        s2 += p[(size_t)(t + 2) * CDIM];
        s3 += p[(size_t)(t + 3) * CDIM];
    }
    part16[(b * 16 + j) * 256 + c] = s0 + s1 + s2 + s3;
}

// ---------- fused mean reduce + layernorm ----------
__global__ void k_ctx(const float* __restrict__ part16, float inv,
                      const float* __restrict__ g, const float* __restrict__ be,
                      float* __restrict__ cln) {
    int b = blockIdx.x, c = threadIdx.x;
    __shared__ float red[256];
    float m = 0.f;
    for (int j = 0; j < 16; j++) m += part16[(b * 16 + j) * 256 + c];
    m *= inv;
    red[c] = m; __syncthreads();
    for (int s = 128; s > 0; s >>= 1) { if (c < s) red[c] += red[c + s]; __syncthreads(); }
    float mu = red[0] * (1.f / 256.f); __syncthreads();
    float d = m - mu;
    red[c] = d * d; __syncthreads();
    for (int s = 128; s > 0; s >>= 1) { if (c < s) red[c] += red[c + s]; __syncthreads(); }
    float var = red[0] * (1.f / 256.f);
    cln[b * 256 + c] = d * rsqrtf(var + LN_EPS) * g[c] + be[c];
}

// ---------- per-batch gate bias tables ----------
__global__ void k_gatebias(const float* __restrict__ cln,
                           const float* __restrict__ Wf, const float* __restrict__ bf,
                           const float* __restrict__ Ww, const float* __restrict__ bw,
                           const float* __restrict__ Wo, const float* __restrict__ bo,
                           float* __restrict__ fb, float* __restrict__ wb, float* __restrict__ ob) {
    int which = blockIdx.x, b = blockIdx.y, c = threadIdx.x;
    __shared__ float sc[256];
    sc[c] = cln[b * 256 + c]; __syncthreads();
    const float* W  = (which == 0) ? Wf : (which == 1) ? Ww : Wo;
    const float* bi = (which == 0) ? bf : (which == 1) ? bw : bo;
    float* o        = (which == 0) ? fb : (which == 1) ? wb : ob;
    float acc = bi[c];
    for (int k = 0; k < 256; k++) acc += sc[k] * W[(size_t)(256 + k) * 256 + c];
    o[b * 256 + c] = acc;
}

// ---------- scan phase 1 (GA=a, GB=g; b=(1-a)*g*u) ----------
__global__ void k_scan1(const float* __restrict__ GA, const float* __restrict__ GB,
                        const float* __restrict__ U,
                        float* __restrict__ AGA, float* __restrict__ ABF, float* __restrict__ ABB) {
    int j = blockIdx.x, b = blockIdx.y, c = threadIdx.x;
    size_t base = ((size_t)b * NTOK + j * 128) * CDIM + c;
    float A = 1.f, sf = 0.f;
    for (int t = 0; t < 128; t++) {
        size_t i = base + (size_t)t * CDIM;
        float a = GA[i];
        float bb = (1.f - a) * GB[i] * U[i];
        A *= a; sf = a * sf + bb;
    }
    float sb = 0.f;
    for (int t = 127; t >= 0; t--) {
        size_t i = base + (size_t)t * CDIM;
        float a = GA[i];
        float bb = (1.f - a) * GB[i] * U[i];
        sb = a * sb + bb;
    }
    int o = (b * 32 + j) * 256 + c;
    AGA[o] = A; ABF[o] = sf; ABB[o] = sb;
}

// ---------- scan phase 2 ----------
__global__ void k_scan2(const float* __restrict__ AGA, const float* __restrict__ ABF,
                        const float* __restrict__ ABB, float* __restrict__ SIF, float* __restrict__ SIB) {
    int b = blockIdx.x, c = threadIdx.x;
    float s = 0.f;
    for (int j = 0; j < 32; j++) {
        int o = (b * 32 + j) * 256 + c;
        SIF[o] = s; s = AGA[o] * s + ABF[o];
    }
    s = 0.f;
    for (int j = 31; j >= 0; j--) {
        int o = (b * 32 + j) * 256 + c;
        SIB[o] = s; s = AGA[o] * s + ABB[o];
    }
}

// ---------- scan phase 3 (bf16 outputs only) ----------
__global__ void k_scan3(const float* __restrict__ GA, const float* __restrict__ GB,
                        const float* __restrict__ GO, const float* __restrict__ U,
                        const float* __restrict__ SIF, const float* __restrict__ SIB,
                        __nv_bfloat16* __restrict__ YF16, __nv_bfloat16* __restrict__ YB16) {
    int j = blockIdx.x, b = blockIdx.y, c = threadIdx.x;
    size_t base = ((size_t)b * NTOK + j * 128) * CDIM + c;
    int ao = (b * 32 + j) * 256 + c;
    float s = SIF[ao];
    for (int t = 0; t < 128; t++) {
        size_t i = base + (size_t)t * CDIM;
        float a = GA[i], u = U[i];
        float bb = (1.f - a) * GB[i] * u;
        s = a * s + bb;
        float o = GO[i];
        YF16[i] = __float2bfloat16_rn(o * s + (1.f - o) * u);
    }
    s = SIB[ao];
    for (int t = 127; t >= 0; t--) {
        size_t i = base + (size_t)t * CDIM;
        float a = GA[i], u = U[i];
        float bb = (1.f - a) * GB[i] * u;
        s = a * s + bb;
        float o = GO[i];
        YB16[i] = __float2bfloat16_rn(o * s + (1.f - o) * u);
    }
}

// ---------- global branch serial scan ----------
__global__ void k_scanglob(const float* __restrict__ GA, const float* __restrict__ GB,
                           const float* __restrict__ GO, const float* __restrict__ U,
                           float* __restrict__ YG) {
    int b = blockIdx.x, c = threadIdx.x;
    size_t base = (size_t)b * NTOKG * CDIM + c;
    float s = 0.f;
    for (int t = 0; t < NTOKG; t++) {
        size_t i = base + (size_t)t * CDIM;
        float a = GA[i], u = U[i];
        float bb = (1.f - a) * GB[i] * u;
        s = a * s + bb;
        float o = GO[i];
        YG[i] = o * s + (1.f - o) * u;
    }
}

// ---------- 4x4 avg pool ----------
__global__ void k_pool(const float* __restrict__ seq, float* __restrict__ seqg) {
    int tg = blockIdx.x, b = blockIdx.y, c = threadIdx.x;
    int gh = tg / 16, gw = tg % 16;
    float s = 0.f;
#pragma unroll
    for (int i = 0; i < 4; i++)
#pragma unroll
        for (int j = 0; j < 4; j++)
            s += seq[((size_t)b * NTOK + (gh * 4 + i) * 64 + gw * 4 + j) * CDIM + c];
    seqg[((size_t)b * NTOKG + tg) * CDIM + c] = s * (1.0f / 16.0f);
}

// ---------- bilinear upsample (bf16 output only) ----------
__global__ void k_upsample(const float* __restrict__ YG, __nv_bfloat16* __restrict__ YGS16) {
    int t = blockIdx.x, b = blockIdx.y, c = threadIdx.x;
    int oh = t / 64, ow = t % 64;
    float sy = (oh + 0.5f) * 0.25f - 0.5f;
    float sx = (ow + 0.5f) * 0.25f - 0.5f;
    int y0 = (int)floorf(sy); float fy = sy - y0;
    int x0 = (int)floorf(sx); float fx = sx - x0;
    int y0c = clampi(y0, 0, 15), y1c = clampi(y0 + 1, 0, 15);
    int x0c = clampi(x0, 0, 15), x1c = clampi(x0 + 1, 0, 15);
    const float* base = YG + (size_t)b * NTOKG * CDIM + c;
    float v00 = base[(size_t)(y0c * 16 + x0c) * CDIM];
    float v01 = base[(size_t)(y0c * 16 + x1c) * CDIM];
    float v10 = base[(size_t)(y1c * 16 + x0c) * CDIM];
    float v11 = base[(size_t)(y1c * 16 + x1c) * CDIM];
    float v = (1.f - fy) * ((1.f - fx) * v00 + fx * v01) + fy * ((1.f - fx) * v10 + fx * v11);
    YGS16[((size_t)b * NTOK + t) * CDIM + c] = __float2bfloat16_rn(v);
}

// ---------- depthwise 3x3 conv, sliding window (bf16 output only) ----------
__global__ void k_dwconv(const float* __restrict__ seq, const float* __restrict__ w,
                         const float* __restrict__ bias, __nv_bfloat16* __restrict__ VM16) {
    int h = blockIdx.x, b = blockIdx.y, c = threadIdx.x;
    float wr[9];
#pragma unroll
    for (int k = 0; k < 9; k++) wr[k] = w[c * 9 + k];
    float bi = bias[c];
    const float* sp = seq + (size_t)b * NTOK * CDIM + c;
    bool h0ok = (h - 1) >= 0, h2ok = (h + 1) < 64;
    size_t r0 = (size_t)(h - 1) * 64, r1 = (size_t)h * 64, r2 = (size_t)(h + 1) * 64;
    float m0 = 0.f, m1 = 0.f, m2 = 0.f;
    float c0 = h0ok ? sp[(r0 + 0) * CDIM] : 0.f;
    float c1 = sp[(r1 + 0) * CDIM];
    float c2 = h2ok ? sp[(r2 + 0) * CDIM] : 0.f;
    float n0 = h0ok ? sp[(r0 + 1) * CDIM] : 0.f;
    float n1 = sp[(r1 + 1) * CDIM];
    float n2 = h2ok ? sp[(r2 + 1) * CDIM] : 0.f;
    size_t obase = ((size_t)b * NTOK + (size_t)h * 64) * CDIM + c;
    for (int x = 0; x < 64; x++) {
        float acc = bi
            + wr[0] * m0 + wr[1] * c0 + wr[2] * n0
            + wr[3] * m1 + wr[4] * c1 + wr[5] * n1
            + wr[6] * m2 + wr[7] * c2 + wr[8] * n2;
        VM16[obase + (size_t)x * CDIM] = __float2bfloat16_rn(acc);
        m0 = c0; m1 = c1; m2 = c2;
        c0 = n0; c1 = n1; c2 = n2;
        if (x + 2 < 64) {
            n0 = h0ok ? sp[(r0 + x + 2) * CDIM] : 0.f;
            n1 = sp[(r1 + x + 2) * CDIM];
            n2 = h2ok ? sp[(r2 + x + 2) * CDIM] : 0.f;
        } else { n0 = n1 = n2 = 0.f; }
    }
}

extern "C" void kernel_launch(void* const* d_in, const int* in_sizes, int n_in,
                              void* d_out, int out_size) {
    const float* x        = (const float*)d_in[0];
    const float* Wt       = (const float*)d_in[1];
    const float* bt       = (const float*)d_in[2];
    const float* pos_fine = (const float*)d_in[3];
    const float* pos_glob = (const float*)d_in[4];
    const float* ln_g     = (const float*)d_in[5];
    const float* ln_b     = (const float*)d_in[6];
    const float* Wf       = (const float*)d_in[7];
    const float* bf       = (const float*)d_in[8];
    const float* Ww       = (const float*)d_in[9];
    const float* bw       = (const float*)d_in[10];
    const float* Wo       = (const float*)d_in[11];
    const float* bo       = (const float*)d_in[12];
    const float* Wr       = (const float*)d_in[13];
    const float* br       = (const float*)d_in[14];
    const float* Wgi      = (const float*)d_in[15];
    const float* bgi      = (const float*)d_in[16];
    const float* dw_w     = (const float*)d_in[17];
    const float* dw_b     = (const float*)d_in[18];
    const float* Wl       = (const float*)d_in[19];
    const float* bl       = (const float*)d_in[20];
    const float* Wlf      = (const float*)d_in[21];
    const float* blf      = (const float*)d_in[22];
    const float* Wout     = (const float*)d_in[23];
    const float* bout     = (const float*)d_in[24];
    float* outp = (float*)d_out;

    float* S = nullptr;
    cudaGetSymbolAddress((void**)&S, g_scratch);
    float* SEQ  = S + OFF_SEQ;  float* U    = S + OFF_U;
    float* GA   = S + OFF_GA;   float* GB   = S + OFF_GB;   float* GO  = S + OFF_GO;
    float* PROJ = S + OFF_PROJ;
    float* SEQG = S + OFF_SEQG; float* UG   = S + OFF_UG;
    float* GAG  = S + OFF_GAG;  float* GBG  = S + OFF_GBG;  float* GOG = S + OFF_GOG;
    float* YG   = S + OFF_YG;
    float* POSF = S + OFF_POSF; float* POSG = S + OFF_POSG;
    float* CLN  = S + OFF_CLN;  float* CLNG = S + OFF_CLNG;
    float* FB = S + OFF_FB, *WB = S + OFF_WB, *OB = S + OFF_OB;
    float* FBG = S + OFF_FBG, *WBG = S + OFF_WBG, *OBG = S + OFF_OBG;
    float* AGA = S + OFF_AGA, *ABF = S + OFF_ABF, *ABB = S + OFF_ABB;
    float* SIF = S + OFF_SIF, *SIB = S + OFF_SIB;
    float* P16 = S + OFF_P16;
    uint32_t* WBW = (uint32_t*)(S + OFF_WBW);
    __nv_bfloat16* U16   = (__nv_bfloat16*)(S + OFF_U16);
    __nv_bfloat16* YF16  = (__nv_bfloat16*)(S + OFF_YF16);
    __nv_bfloat16* YB16  = (__nv_bfloat16*)(S + OFF_YB16);
    __nv_bfloat16* Y16   = (__nv_bfloat16*)(S + OFF_Y16);
    __nv_bfloat16* YGS16 = (__nv_bfloat16*)(S + OFF_YGS16);
    __nv_bfloat16* V16   = (__nv_bfloat16*)(S + OFF_V16);
    __nv_bfloat16* Z16   = (__nv_bfloat16*)(S + OFF_Z16);
    __nv_bfloat16* SEQ16 = (__nv_bfloat16*)(S + OFF_SEQ16);
    __nv_bfloat16* VM16  = (__nv_bfloat16*)(S + OFF_VM16);
    __nv_bfloat16* UO16  = (__nv_bfloat16*)(S + OFF_UO16);

    uint32_t* WBf  = WBW + (size_t)0    * 256;
    uint32_t* WBw  = WBW + (size_t)128  * 256;
    uint32_t* WBo  = WBW + (size_t)256  * 256;
    uint32_t* WBr0 = WBW + (size_t)384  * 256;
    uint32_t* WBr1 = WBW + (size_t)512  * 256;
    uint32_t* WBr2 = WBW + (size_t)640  * 256;
    uint32_t* WBg0 = WBW + (size_t)768  * 256;
    uint32_t* WBg1 = WBW + (size_t)896  * 256;
    uint32_t* WBg2 = WBW + (size_t)1024 * 256;
    uint32_t* WBl0 = WBW + (size_t)1152 * 256;
    uint32_t* WBl1 = WBW + (size_t)1280 * 256;
    uint32_t* WBt  = WBW + (size_t)1408 * 256;
    uint32_t* WBl  = WBW + (size_t)1536 * 256;
    uint32_t* WBout= WBW + (size_t)1664 * 256;

    static int smem_set = 0;
    int smem_tf = NSTAGE * STAGE_ELEMS * 4;
    int smem_bf = NSTB * BSTG_EL * 4;
    if (!smem_set) {
        cudaFuncSetAttribute(k_gemm_tc, cudaFuncAttributeMaxDynamicSharedMemorySize, smem_tf);
        cudaFuncSetAttribute(k_gemm_bf, cudaFuncAttributeMaxDynamicSharedMemorySize, smem_bf);
        smem_set = 1;
    }

    dim3 tb(32, 8);
    dim3 tg(128, 8, 8);
    dim3 gemF(2, MFINE / 128), gemG(2, MGLOB / 128);
    dim3 gemG3(2, MGLOB / 128, 3), gemF3(2, MFINE / 128, 3);
    const float* NP = nullptr;
    float* NPo = nullptr;
    __nv_bfloat16* NPh = nullptr;
    const __nv_bfloat16* NPhc = nullptr;
    const uint32_t* NPw = nullptr;

    // prep
    k_transpose<<<tg, tb>>>(x, SEQ, SEQ16);
    k_wcvt<<<1792, 256>>>(Wf, Ww, Wo, Wr, Wgi, Wlf, Wt, Wl, Wout, WBW);
    k_posup<<<4096, 256>>>(pos_fine, POSF, 64, 64);
    k_posdown<<<256, 256>>>(pos_glob, POSG);

    // U = SEQ@Wt + bt + pos (bf16, mode 1) -> U (needed fp32) + U16
    k_gemm_bf<<<gemF, 256, smem_bf>>>(SEQ16, WBt, NPhc, NPw, NPhc, NPw, 1, U, NPo, NPo, bt, 1, POSF, NP, 4095, 0, U16);

    // gates (fine): mode 4, fp32 outputs needed by scans
    k_colmean_a<<<dim3(16, BATCH), 256>>>(U, P16, 256);
    k_ctx<<<BATCH, 256>>>(P16, 1.0f / NTOK, ln_g, ln_b, CLN);
    k_gatebias<<<dim3(3, BATCH), 256>>>(CLN, Wf, bf, Ww, bw, Wo, bo, FB, WB, OB);
    k_gemm_bf<<<gemF3, 256, smem_bf>>>(U16, WBf, NPhc, WBw, NPhc, WBo, 1, GA, GB, GO, OB, 4, FB, WB, NTOK, 1, NPh);

    // bidirectional chunked scan (bf16 Y outputs only)
    k_scan1<<<dim3(32, BATCH), 256>>>(GA, GB, U, AGA, ABF, ABB);
    k_scan2<<<BATCH, 256>>>(AGA, ABF, ABB, SIF, SIB);
    k_scan3<<<dim3(32, BATCH), 256>>>(GA, GB, GO, U, SIF, SIB, YF16, YB16);

    // rho mixing: mode 2 on bf16 mirrors -> Y16 only
    k_gemm_bf<<<gemF, 256, smem_bf>>>(U16, WBr0, YF16, WBr1, YB16, WBr2, 3, NPo, NPo, NPo, br, 2,
                                      (const float*)YF16, (const float*)YB16, 0, 0, Y16);

    // global branch (tf32)
    k_pool<<<dim3(256, BATCH), 256>>>(SEQ, SEQG);
    k_gemm_tc<<<gemG, 256, smem_tf>>>(SEQG, Wt, NP, NP, NP, NP, 1, UG, NPo, NPo, bt, 1, POSG, NP, 255, 0, NPh);
    k_colmean_a<<<dim3(16, BATCH), 256>>>(UG, P16, 16);
    k_ctx<<<BATCH, 256>>>(P16, 1.0f / NTOKG, ln_g, ln_b, CLNG);
    k_gatebias<<<dim3(3, BATCH), 256>>>(CLNG, Wf, bf, Ww, bw, Wo, bo, FBG, WBG, OBG);
    k_gemm_tc<<<gemG3, 256, smem_tf>>>(UG, Wf, NP, Ww, NP, Wo, 1, GAG, GBG, GOG, OBG, 4, FBG, WBG, NTOKG, 1, NPh);
    k_scanglob<<<BATCH, 256>>>(GAG, GBG, GOG, UG, YG);
    k_upsample<<<dim3(4096, BATCH), 256>>>(YG, YGS16);

    // lam mixing: mode 3 on bf16 mirrors -> Z16 only
    k_gemm_bf<<<gemF, 256, smem_bf>>>(Y16, WBg0, YGS16, WBg1, U16, WBg2, 3, NPo, NPo, NPo, bgi, 3,
                                      (const float*)Y16, (const float*)YGS16, 0, 0, Z16);

    // local depthwise branch
    k_dwconv<<<dim3(64, BATCH), 256>>>(SEQ, dw_w, dw_b, VM16);
    k_gemm_bf<<<gemF, 256, smem_bf>>>(VM16, WBl, NPhc, NPw, NPhc, NPw, 1, NPo, NPo, NPo, bl, 0, NP, NP, 0, 0, V16);
    k_gemm_bf<<<gemF, 256, smem_bf>>>(V16, WBl0, Z16, WBl1, NPhc, NPw, 2, NPo, NPo, NPo, blf, 2,
                                      (const float*)V16, (const float*)Z16, 0, 0, UO16);

    // output proj + residual
    k_gemm_bf<<<gemF, 256, smem_bf>>>(UO16, WBout, NPhc, NPw, NPhc, NPw, 1, PROJ, NPo, NPo, bout, 0, NP, NP, 0, 0, NPh);
    k_output<<<tg, tb>>>(PROJ, x, outp);
}

// round 13
// speedup vs baseline: 5.1245x; 1.3091x over previous
#include <cuda_runtime.h>
#include <cuda_bf16.h>
#include <math.h>
#include <stdint.h>

#define BATCH 8
#define CDIM  256
#define NTOK  4096
#define NTOKG 256
#define MFINE 32768
#define MGLOB 2048
#define LN_EPS 1e-5f

static const size_t U_SZ  = (size_t)MFINE * CDIM;
static const size_t H_SZ  = U_SZ / 2;
static const size_t SG_SZ = (size_t)MGLOB * CDIM;

static const size_t OFF_SEQ   = 0*U_SZ;
static const size_t OFF_PROJ  = 1*U_SZ;
static const size_t SMALL0    = 2*U_SZ;
static const size_t OFF_SEQG  = SMALL0 + 0*SG_SZ;
static const size_t OFF_UG    = SMALL0 + 1*SG_SZ;
static const size_t OFF_GAG   = SMALL0 + 2*SG_SZ;
static const size_t OFF_GBG   = SMALL0 + 3*SG_SZ;
static const size_t OFF_GOG   = SMALL0 + 4*SG_SZ;
static const size_t OFF_YG    = SMALL0 + 5*SG_SZ;
static const size_t SMALL1    = SMALL0 + 6*SG_SZ;
static const size_t OFF_POSF  = SMALL1;
static const size_t OFF_POSG  = OFF_POSF + 4096*256;
static const size_t OFF_CLN   = OFF_POSG + 65536;
static const size_t OFF_CLNG  = OFF_CLN + 2048;
static const size_t OFF_FB    = OFF_CLNG + 2048;
static const size_t OFF_WB    = OFF_FB + 2048;
static const size_t OFF_OB    = OFF_WB + 2048;
static const size_t OFF_FBG   = OFF_OB + 2048;
static const size_t OFF_WBG   = OFF_FBG + 2048;
static const size_t OFF_OBG   = OFF_WBG + 2048;
static const size_t OFF_AGA   = OFF_OBG + 2048;
static const size_t OFF_ABF   = OFF_AGA + 65536;
static const size_t OFF_ABB   = OFF_ABF + 65536;
static const size_t OFF_SIF   = OFF_ABB + 65536;
static const size_t OFF_SIB   = OFF_SIF + 65536;
static const size_t OFF_P16   = OFF_SIB + 65536;
static const size_t OFF_P16G  = OFF_P16 + 32768;
static const size_t OFF_WBW   = OFF_P16G + 32768;          // bf16x2 weights: 1792*256 u32
static const size_t OFF_U16   = OFF_WBW + 458752;
static const size_t OFF_YF16  = OFF_U16  + H_SZ;
static const size_t OFF_YB16  = OFF_YF16 + H_SZ;
static const size_t OFF_Y16   = OFF_YB16 + H_SZ;
static const size_t OFF_YGS16 = OFF_Y16  + H_SZ;
static const size_t OFF_V16   = OFF_YGS16+ H_SZ;
static const size_t OFF_Z16   = OFF_V16  + H_SZ;
static const size_t OFF_SEQ16 = OFF_Z16  + H_SZ;
static const size_t OFF_VM16  = OFF_SEQ16+ H_SZ;
static const size_t OFF_UO16  = OFF_VM16 + H_SZ;
static const size_t OFF_GA16  = OFF_UO16 + H_SZ;
static const size_t OFF_GB16  = OFF_GA16 + H_SZ;
static const size_t OFF_GO16  = OFF_GB16 + H_SZ;
static const size_t TOTAL_SCRATCH = OFF_GO16 + H_SZ + 1024;

__device__ __align__(16) float g_scratch[TOTAL_SCRATCH];

__device__ __forceinline__ float sigf(float x) { return 1.0f / (1.0f + expf(-x)); }
__device__ __forceinline__ int clampi(int v, int lo, int hi) { return v < lo ? lo : (v > hi ? hi : v); }

__device__ __forceinline__ void mma_tf32(float* c, const uint32_t* a, const uint32_t* b) {
    asm volatile(
        "mma.sync.aligned.m16n8k8.row.col.f32.tf32.tf32.f32 "
        "{%0,%1,%2,%3}, {%4,%5,%6,%7}, {%8,%9}, {%0,%1,%2,%3};\n"
        : "+f"(c[0]), "+f"(c[1]), "+f"(c[2]), "+f"(c[3])
        : "r"(a[0]), "r"(a[1]), "r"(a[2]), "r"(a[3]), "r"(b[0]), "r"(b[1]));
}
__device__ __forceinline__ void mma_bf16(float* c, const uint32_t* a, const uint32_t* b) {
    asm volatile(
        "mma.sync.aligned.m16n8k16.row.col.f32.bf16.bf16.f32 "
        "{%0,%1,%2,%3}, {%4,%5,%6,%7}, {%8,%9}, {%0,%1,%2,%3};\n"
        : "+f"(c[0]), "+f"(c[1]), "+f"(c[2]), "+f"(c[3])
        : "r"(a[0]), "r"(a[1]), "r"(a[2]), "r"(a[3]), "r"(b[0]), "r"(b[1]));
}
__device__ __forceinline__ void ldsm4(uint32_t* r, uint32_t saddr) {
    asm volatile("ldmatrix.sync.aligned.m8n8.x4.shared.b16 {%0,%1,%2,%3}, [%4];"
        : "=r"(r[0]), "=r"(r[1]), "=r"(r[2]), "=r"(r[3]) : "r"(saddr));
}

__device__ __forceinline__ void cpa16(uint32_t dst, const void* src) {
    asm volatile("cp.async.cg.shared.global [%0], [%1], 16;" :: "r"(dst), "l"(src));
}
#define CP_COMMIT() asm volatile("cp.async.commit_group;")
#define CP_WAIT1()  asm volatile("cp.async.wait_group 1;")
#define CP_WAIT2()  asm volatile("cp.async.wait_group 2;")

__device__ __forceinline__ const float* selp(const float* a0, const float* a1,
                                             const float* a2, int p) {
    return p == 0 ? a0 : (p == 1 ? a1 : a2);
}
__device__ __forceinline__ const __nv_bfloat16* selh(const __nv_bfloat16* a0,
                                                     const __nv_bfloat16* a1,
                                                     const __nv_bfloat16* a2, int p) {
    return p == 0 ? a0 : (p == 1 ? a1 : a2);
}
__device__ __forceinline__ const uint32_t* selw(const uint32_t* a0, const uint32_t* a1,
                                                const uint32_t* a2, int p) {
    return p == 0 ? a0 : (p == 1 ? a1 : a2);
}

// ---------- x [B,C,4096] -> seq [B*4096, C] (+bf16 mirror) ----------
__global__ void k_transpose(const float* __restrict__ x, float* __restrict__ seq,
                            __nv_bfloat16* __restrict__ seq16) {
    __shared__ float tile[32][33];
    int b = blockIdx.z;
    int t0 = blockIdx.x * 32, c0 = blockIdx.y * 32;
    int tx = threadIdx.x, ty = threadIdx.y;
    const float* src = x + (size_t)b * CDIM * NTOK;
#pragma unroll
    for (int j = 0; j < 4; j++)
        tile[ty + 8*j][tx] = src[(size_t)(c0 + ty + 8*j) * NTOK + t0 + tx];
    __syncthreads();
    float* dst = seq + (size_t)b * NTOK * CDIM;
    __nv_bfloat16* dsth = seq16 + (size_t)b * NTOK * CDIM;
#pragma unroll
    for (int j = 0; j < 4; j++) {
        float v = tile[tx][ty + 8*j];
        size_t o = (size_t)(t0 + ty + 8*j) * CDIM + c0 + tx;
        dst[o] = v; dsth[o] = __float2bfloat16_rn(v);
    }
}

// ---------- proj [B,4096,C] + x -> out [B,C,4096] ----------
__global__ void k_output(const float* __restrict__ proj, const float* __restrict__ x,
                         float* __restrict__ outp) {
    __shared__ float tile[32][33];
    int b = blockIdx.z;
    int t0 = blockIdx.x * 32, c0 = blockIdx.y * 32;
    int tx = threadIdx.x, ty = threadIdx.y;
    const float* src = proj + (size_t)b * NTOK * CDIM;
#pragma unroll
    for (int j = 0; j < 4; j++)
        tile[ty + 8*j][tx] = src[(size_t)(t0 + ty + 8*j) * CDIM + c0 + tx];
    __syncthreads();
    size_t base = (size_t)b * CDIM * NTOK;
#pragma unroll
    for (int j = 0; j < 4; j++) {
        size_t o = base + (size_t)(c0 + ty + 8*j) * NTOK + t0 + tx;
        outp[o] = x[o] + tile[tx][ty + 8*j];
    }
}

// ---------- pos bilinear upsample ----------
__global__ void k_posup(const float* __restrict__ pos, float* __restrict__ outp, int OH, int OW) {
    int t = blockIdx.x, c = threadIdx.x;
    int oh = t / OW, ow = t % OW;
    float sy = (oh + 0.5f) * (32.0f / OH) - 0.5f;
    float sx = (ow + 0.5f) * (32.0f / OW) - 0.5f;
    int y0 = (int)floorf(sy); float fy = sy - y0;
    int x0 = (int)floorf(sx); float fx = sx - x0;
    int y0c = clampi(y0, 0, 31), y1c = clampi(y0 + 1, 0, 31);
    int x0c = clampi(x0, 0, 31), x1c = clampi(x0 + 1, 0, 31);
    const float* p = pos + (size_t)c * 1024;
    float v = (1.f - fy) * ((1.f - fx) * p[y0c*32 + x0c] + fx * p[y0c*32 + x1c])
            + fy * ((1.f - fx) * p[y1c*32 + x0c] + fx * p[y1c*32 + x1c]);
    outp[(size_t)t * CDIM + c] = v;
}

// ---------- pos antialiased downsample 32->16 ----------
__global__ void k_posdown(const float* __restrict__ pos, float* __restrict__ outp) {
    int t = blockIdx.x, c = threadIdx.x;
    int gh = t / 16, gw = t % 16;
    const float W4[4] = {0.125f, 0.375f, 0.375f, 0.125f};
    float wy[4], wx[4]; int ky[4], kx[4];
    float sy = 0.f, sx = 0.f;
#pragma unroll
    for (int d = 0; d < 4; d++) {
        ky[d] = 2*gh - 1 + d; wy[d] = (ky[d] >= 0 && ky[d] < 32) ? W4[d] : 0.f; sy += wy[d];
        kx[d] = 2*gw - 1 + d; wx[d] = (kx[d] >= 0 && kx[d] < 32) ? W4[d] : 0.f; sx += wx[d];
    }
    const float* p = pos + (size_t)c * 1024;
    float acc = 0.f;
#pragma unroll
    for (int d = 0; d < 4; d++) {
        if (wy[d] == 0.f) continue;
        float rowacc = 0.f;
#pragma unroll
        for (int e = 0; e < 4; e++)
            if (wx[e] != 0.f) rowacc += wx[e] * p[ky[d]*32 + kx[e]];
        acc += wy[d] * rowacc;
    }
    outp[(size_t)t * CDIM + c] = acc / (sy * sx);
}

// ---------- weight interleave ----------
__global__ void k_wcvt(const float* __restrict__ Wf, const float* __restrict__ Ww,
                       const float* __restrict__ Wo, const float* __restrict__ Wr,
                       const float* __restrict__ Wgi, const float* __restrict__ Wlf,
                       const float* __restrict__ Wt, const float* __restrict__ Wl,
                       const float* __restrict__ Wout, uint32_t* __restrict__ WB) {
    int r = blockIdx.x, c = threadIdx.x;
    const float* src; int k2;
    if (r < 128)       { src = Wf;   k2 = r; }
    else if (r < 256)  { src = Ww;   k2 = r - 128; }
    else if (r < 384)  { src = Wo;   k2 = r - 256; }
    else if (r < 768)  { src = Wr;   k2 = r - 384; }
    else if (r < 1152) { src = Wgi;  k2 = r - 768; }
    else if (r < 1408) { src = Wlf;  k2 = r - 1152; }
    else if (r < 1536) { src = Wt;   k2 = r - 1408; }
    else if (r < 1664) { src = Wl;   k2 = r - 1536; }
    else               { src = Wout; k2 = r - 1664; }
    float lo = src[(size_t)(2*k2) * 256 + c];
    float hi = src[(size_t)(2*k2 + 1) * 256 + c];
    __nv_bfloat162 p2 = __floats2bfloat162_rn(lo, hi);
    WB[(size_t)r * 256 + c] = *(uint32_t*)&p2;
}

// ================= tf32 mma.sync GEMM (global branch only) =================
#define AS_STRIDE 36
#define BS_STRIDE 136
#define A_ELEMS (128*AS_STRIDE)
#define B_ELEMS (32*BS_STRIDE)
#define STAGE_ELEMS (A_ELEMS + B_ELEMS)
#define NSTAGE 3
extern __shared__ float smx[];

__global__ void __launch_bounds__(256, 2)
k_gemm_tc(const float* __restrict__ A0, const float* __restrict__ W0,
          const float* __restrict__ A1, const float* __restrict__ W1,
          const float* __restrict__ A2, const float* __restrict__ W2,
          int npairs,
          float* __restrict__ C0, float* __restrict__ C1, float* __restrict__ C2,
          const float* __restrict__ bias, int mode,
          const float* __restrict__ P1, const float* __restrict__ P2,
          int tokmask, int multi, __nv_bfloat16* __restrict__ D0) {
    int bx = blockIdx.x, by = blockIdx.y, bz = blockIdx.z;
    int tid = threadIdx.x;
    int warp = tid >> 5, lane = tid & 31;
    int wm = warp >> 2, wn = warp & 3;
    int g = lane >> 2, tq = lane & 3;

    uint32_t smem_u32 = (uint32_t)__cvta_generic_to_shared(smx);

    float acc[4][4][4];
#pragma unroll
    for (int i = 0; i < 4; i++)
#pragma unroll
        for (int j = 0; j < 4; j++)
#pragma unroll
            for (int r = 0; r < 4; r++) acc[i][j][r] = 0.f;

    int nst = (multi ? 1 : npairs) * 8;

    auto load_stage = [&](int st, int buf) {
        int p = multi ? bz : (st >> 3);
        const float* A = multi ? A0 : selp(A0, A1, A2, p);
        const float* W = selp(W0, W1, W2, p);
        int k0 = (st & 7) * 32;
        uint32_t abase = smem_u32 + (uint32_t)(buf * STAGE_ELEMS) * 4u;
        uint32_t bbase = abase + (uint32_t)A_ELEMS * 4u;
#pragma unroll
        for (int i = 0; i < 4; i++) {
            int idx = tid + 256 * i;
            int row = idx >> 3, c4 = idx & 7;
            cpa16(abase + (uint32_t)(row * AS_STRIDE + c4 * 4) * 4u,
                  A + (size_t)(by * 128 + row) * 256 + k0 + c4 * 4);
        }
#pragma unroll
        for (int i = 0; i < 4; i++) {
            int idx = tid + 256 * i;
            int row = idx >> 5, c4 = idx & 31;
            cpa16(bbase + (uint32_t)(row * BS_STRIDE + c4 * 4) * 4u,
                  W + (size_t)(k0 + row) * 256 + bx * 128 + c4 * 4);
        }
        CP_COMMIT();
    };

    load_stage(0, 0);
    load_stage(1, 1);

    for (int st = 0; st < nst; st++) {
        CP_WAIT1();
        __syncthreads();
        int nx = st + NSTAGE - 1;
        if (nx < nst) load_stage(nx, nx % NSTAGE);
        else CP_COMMIT();

        int pb = st % NSTAGE;
        const uint32_t* Asu = (const uint32_t*)(smx + pb * STAGE_ELEMS);
        const uint32_t* Bsu = Asu + A_ELEMS;
#pragma unroll
        for (int ks = 0; ks < 32; ks += 8) {
            uint32_t af[4][4], bf[4][2];
#pragma unroll
            for (int mt = 0; mt < 4; mt++) {
                int mb = wm * 64 + mt * 16;
                af[mt][0] = Asu[(mb + g) * AS_STRIDE + ks + tq];
                af[mt][1] = Asu[(mb + g + 8) * AS_STRIDE + ks + tq];
                af[mt][2] = Asu[(mb + g) * AS_STRIDE + ks + tq + 4];
                af[mt][3] = Asu[(mb + g + 8) * AS_STRIDE + ks + tq + 4];
            }
#pragma unroll
            for (int nt = 0; nt < 4; nt++) {
                int nb = wn * 32 + nt * 8;
                bf[nt][0] = Bsu[(ks + tq) * BS_STRIDE + nb + g];
                bf[nt][1] = Bsu[(ks + tq + 4) * BS_STRIDE + nb + g];
            }
#pragma unroll
            for (int mt = 0; mt < 4; mt++)
#pragma unroll
                for (int nt = 0; nt < 4; nt++)
                    mma_tf32(acc[mt][nt], af[mt], bf[nt]);
        }
    }

    float* C = multi ? (bz == 0 ? C0 : (bz == 1 ? C1 : C2)) : C0;
    int batch4 = (mode == 4) ? (by * 128) / tokmask : 0;
    const float* TB4 = (mode == 4) ? (bz == 0 ? P1 : (bz == 1 ? P2 : bias)) : nullptr;
#pragma unroll
    for (int mt = 0; mt < 4; mt++) {
        int r0 = by * 128 + wm * 64 + mt * 16 + g;
#pragma unroll
        for (int nt = 0; nt < 4; nt++) {
            int col = bx * 128 + wn * 32 + nt * 8 + tq * 2;
            float b0 = 0.f, b1 = 0.f;
            if (bias && mode != 4) { b0 = bias[col]; b1 = bias[col + 1]; }
#pragma unroll
            for (int h = 0; h < 2; h++) {
                int r = r0 + h * 8;
                float t0 = acc[mt][nt][2*h + 0] + b0;
                float t1 = acc[mt][nt][2*h + 1] + b1;
                size_t i0 = (size_t)r * 256 + col;
                float o0, o1;
                if (mode == 0) {
                    o0 = t0; o1 = t1;
                } else if (mode == 1) {
                    size_t pi = (size_t)(r & tokmask) * 256 + col;
                    o0 = t0 + P1[pi]; o1 = t1 + P1[pi + 1];
                } else if (mode == 2) {
                    float s0 = sigf(t0), s1 = sigf(t1);
                    o0 = s0 * P1[i0] + (1.f - s0) * P2[i0];
                    o1 = s1 * P1[i0 + 1] + (1.f - s1) * P2[i0 + 1];
                } else if (mode == 3) {
                    o0 = P1[i0] + sigf(t0) * P2[i0];
                    o1 = P1[i0 + 1] + sigf(t1) * P2[i0 + 1];
                } else {
                    float x0 = t0 + TB4[batch4 * 256 + col];
                    float x1 = t1 + TB4[batch4 * 256 + col + 1];
                    if (bz == 0) { o0 = 1.f / (1.f + expf(x0)); o1 = 1.f / (1.f + expf(x1)); }
                    else         { o0 = sigf(x0); o1 = sigf(x1); }
                }
                if (C) *(float2*)(C + i0) = make_float2(o0, o1);
                if (D0) *(__nv_bfloat162*)((__nv_bfloat16*)D0 + i0) = __floats2bfloat162_rn(o0, o1);
            }
        }
    }
}

// ================= bf16 mma.sync GEMM (all fine GEMMs) =================
// modes 2/3: P1/P2 interpreted as bf16 mirrors. multi: bz selects W, C, D.
#define BA_STR 20
#define BB_STR 136
#define BA_EL (128*BA_STR)
#define BB_EL (16*BB_STR)
#define BSTG_EL (BA_EL + BB_EL)
#define NSTB 4

__global__ void __launch_bounds__(256, 2)
k_gemm_bf(const __nv_bfloat16* __restrict__ A0, const uint32_t* __restrict__ W0,
          const __nv_bfloat16* __restrict__ A1, const uint32_t* __restrict__ W1,
          const __nv_bfloat16* __restrict__ A2, const uint32_t* __restrict__ W2,
          int npairs,
          float* __restrict__ C0, float* __restrict__ C1, float* __restrict__ C2,
          const float* __restrict__ bias, int mode,
          const float* __restrict__ P1, const float* __restrict__ P2,
          int tokmask, int multi,
          __nv_bfloat16* __restrict__ D0, __nv_bfloat16* __restrict__ D1,
          __nv_bfloat16* __restrict__ D2) {
    int bx = blockIdx.x, by = blockIdx.y, bz = blockIdx.z;
    int tid = threadIdx.x;
    int warp = tid >> 5, lane = tid & 31;
    int wm = warp >> 2, wn = warp & 3;
    int g = lane >> 2, tq = lane & 3;

    uint32_t smem_u32 = (uint32_t)__cvta_generic_to_shared(smx);

    float acc[4][4][4];
#pragma unroll
    for (int i = 0; i < 4; i++)
#pragma unroll
        for (int j = 0; j < 4; j++)
#pragma unroll
            for (int r = 0; r < 4; r++) acc[i][j][r] = 0.f;

    int nst = (multi ? 1 : npairs) * 8;

    auto load_stage = [&](int st, int buf) {
        int p = multi ? bz : (st >> 3);
        const __nv_bfloat16* A = multi ? A0 : selh(A0, A1, A2, p);
        const uint32_t* W = selw(W0, W1, W2, p);
        int k0 = (st & 7) * 32;
        int k2b = k0 >> 1;
        uint32_t abase = smem_u32 + (uint32_t)(buf * BSTG_EL) * 4u;
        uint32_t bbase = abase + (uint32_t)BA_EL * 4u;
#pragma unroll
        for (int i = 0; i < 2; i++) {
            int idx = tid + 256 * i;
            int row = idx >> 2, c4 = idx & 3;
            cpa16(abase + (uint32_t)(row * BA_STR + c4 * 4) * 4u,
                  A + (size_t)(by * 128 + row) * 256 + k0 + c4 * 8);
        }
#pragma unroll
        for (int i = 0; i < 2; i++) {
            int idx = tid + 256 * i;
            int row = idx >> 5, c4 = idx & 31;
            cpa16(bbase + (uint32_t)(row * BB_STR + c4 * 4) * 4u,
                  W + (size_t)(k2b + row) * 256 + bx * 128 + c4 * 4);
        }
        CP_COMMIT();
    };

    load_stage(0, 0);
    load_stage(1, 1);
    load_stage(2, 2);

    int lrow = lane & 15;
    uint32_t kside = (uint32_t)((lane >> 4) << 4);

    for (int st = 0; st < nst; st++) {
        CP_WAIT2();
        __syncthreads();
        int nx = st + NSTB - 1;
        if (nx < nst) load_stage(nx, nx % NSTB);
        else CP_COMMIT();

        int pb = st % NSTB;
        uint32_t abyte = smem_u32 + (uint32_t)(pb * BSTG_EL) * 4u;
        const uint32_t* Bsu = (const uint32_t*)(smx + pb * BSTG_EL) + BA_EL;
#pragma unroll
        for (int s = 0; s < 2; s++) {
            int ko = 8 * s;
            uint32_t af[4][4], bf[4][2];
#pragma unroll
            for (int mt = 0; mt < 4; mt++) {
                uint32_t addr = abyte
                    + (uint32_t)((wm * 64 + mt * 16 + lrow) * BA_STR) * 4u
                    + kside + (uint32_t)(s * 32);
                ldsm4(af[mt], addr);
            }
#pragma unroll
            for (int nt = 0; nt < 4; nt++) {
                int nb = wn * 32 + nt * 8;
                bf[nt][0] = Bsu[(ko + tq) * BB_STR + nb + g];
                bf[nt][1] = Bsu[(ko + tq + 4) * BB_STR + nb + g];
            }
#pragma unroll
            for (int mt = 0; mt < 4; mt++)
#pragma unroll
                for (int nt = 0; nt < 4; nt++)
                    mma_bf16(acc[mt][nt], af[mt], bf[nt]);
        }
    }

    float* C = multi ? (bz == 0 ? C0 : (bz == 1 ? C1 : C2)) : C0;
    __nv_bfloat16* D = multi ? (bz == 0 ? D0 : (bz == 1 ? D1 : D2)) : D0;
    int batch4 = (mode == 4) ? (by * 128) / tokmask : 0;
    const float* TB4 = (mode == 4) ? (bz == 0 ? P1 : (bz == 1 ? P2 : bias)) : nullptr;
    const __nv_bfloat16* P1h = (const __nv_bfloat16*)P1;
    const __nv_bfloat16* P2h = (const __nv_bfloat16*)P2;
#pragma unroll
    for (int mt = 0; mt < 4; mt++) {
        int r0 = by * 128 + wm * 64 + mt * 16 + g;
#pragma unroll
        for (int nt = 0; nt < 4; nt++) {
            int col = bx * 128 + wn * 32 + nt * 8 + tq * 2;
            float b0 = 0.f, b1 = 0.f;
            if (bias && mode != 4) { b0 = bias[col]; b1 = bias[col + 1]; }
#pragma unroll
            for (int h = 0; h < 2; h++) {
                int r = r0 + h * 8;
                float t0 = acc[mt][nt][2*h + 0] + b0;
                float t1 = acc[mt][nt][2*h + 1] + b1;
                size_t i0 = (size_t)r * 256 + col;
                float o0, o1;
                if (mode == 0) {
                    o0 = t0; o1 = t1;
                } else if (mode == 1) {
                    size_t pi = (size_t)(r & tokmask) * 256 + col;
                    o0 = t0 + P1[pi]; o1 = t1 + P1[pi + 1];
                } else if (mode == 2) {
                    __nv_bfloat162 p1 = *(const __nv_bfloat162*)(P1h + i0);
                    __nv_bfloat162 p2 = *(const __nv_bfloat162*)(P2h + i0);
                    float s0 = sigf(t0), s1 = sigf(t1);
                    o0 = s0 * __bfloat162float(p1.x) + (1.f - s0) * __bfloat162float(p2.x);
                    o1 = s1 * __bfloat162float(p1.y) + (1.f - s1) * __bfloat162float(p2.y);
                } else if (mode == 3) {
                    __nv_bfloat162 p1 = *(const __nv_bfloat162*)(P1h + i0);
                    __nv_bfloat162 p2 = *(const __nv_bfloat162*)(P2h + i0);
                    o0 = __bfloat162float(p1.x) + sigf(t0) * __bfloat162float(p2.x);
                    o1 = __bfloat162float(p1.y) + sigf(t1) * __bfloat162float(p2.y);
                } else {
                    float x0 = t0 + TB4[batch4 * 256 + col];
                    float x1 = t1 + TB4[batch4 * 256 + col + 1];
                    if (bz == 0) { o0 = 1.f / (1.f + expf(x0)); o1 = 1.f / (1.f + expf(x1)); }
                    else         { o0 = sigf(x0); o1 = sigf(x1); }
                }
                if (C) *(float2*)(C + i0) = make_float2(o0, o1);
                if (D) *(__nv_bfloat162*)(D + i0) = __floats2bfloat162_rn(o0, o1);
            }
        }
    }
}

// ---------- column-mean stage A (fp32 input, global branch) ----------
__global__ void k_colmean_a(const float* __restrict__ U, float* __restrict__ part16, int chunk) {
    int j = blockIdx.x, b = blockIdx.y, c = threadIdx.x;
    const float* p = U + ((size_t)(b * gridDim.x + j) * chunk) * CDIM + c;
    float s0 = 0.f, s1 = 0.f, s2 = 0.f, s3 = 0.f;
    for (int t = 0; t < chunk; t += 4) {
        s0 += p[(size_t)t * CDIM];
        s1 += p[(size_t)(t + 1) * CDIM];
        s2 += p[(size_t)(t + 2) * CDIM];
        s3 += p[(size_t)(t + 3) * CDIM];
    }
    part16[(b * 16 + j) * 256 + c] = s0 + s1 + s2 + s3;
}

// ---------- column-mean stage A (bf16 input, fine path) ----------
__global__ void k_colmean_a16(const __nv_bfloat16* __restrict__ U, float* __restrict__ part16,
                              int chunk) {
    int j = blockIdx.x, b = blockIdx.y, c = threadIdx.x;
    const __nv_bfloat16* p = U + ((size_t)(b * gridDim.x + j) * chunk) * CDIM + c;
    float s0 = 0.f, s1 = 0.f, s2 = 0.f, s3 = 0.f;
    for (int t = 0; t < chunk; t += 4) {
        s0 += __bfloat162float(p[(size_t)t * CDIM]);
        s1 += __bfloat162float(p[(size_t)(t + 1) * CDIM]);
        s2 += __bfloat162float(p[(size_t)(t + 2) * CDIM]);
        s3 += __bfloat162float(p[(size_t)(t + 3) * CDIM]);
    }
    part16[(b * 16 + j) * 256 + c] = s0 + s1 + s2 + s3;
}

// ---------- fused mean reduce + layernorm ----------
__global__ void k_ctx(const float* __restrict__ part16, float inv,
                      const float* __restrict__ g, const float* __restrict__ be,
                      float* __restrict__ cln) {
    int b = blockIdx.x, c = threadIdx.x;
    __shared__ float red[256];
    float m = 0.f;
    for (int j = 0; j < 16; j++) m += part16[(b * 16 + j) * 256 + c];
    m *= inv;
    red[c] = m; __syncthreads();
    for (int s = 128; s > 0; s >>= 1) { if (c < s) red[c] += red[c + s]; __syncthreads(); }
    float mu = red[0] * (1.f / 256.f); __syncthreads();
    float d = m - mu;
    red[c] = d * d; __syncthreads();
    for (int s = 128; s > 0; s >>= 1) { if (c < s) red[c] += red[c + s]; __syncthreads(); }
    float var = red[0] * (1.f / 256.f);
    cln[b * 256 + c] = d * rsqrtf(var + LN_EPS) * g[c] + be[c];
}

// ---------- per-batch gate bias tables ----------
__global__ void k_gatebias(const float* __restrict__ cln,
                           const float* __restrict__ Wf, const float* __restrict__ bf,
                           const float* __restrict__ Ww, const float* __restrict__ bw,
                           const float* __restrict__ Wo, const float* __restrict__ bo,
                           float* __restrict__ fb, float* __restrict__ wb, float* __restrict__ ob) {
    int which = blockIdx.x, b = blockIdx.y, c = threadIdx.x;
    __shared__ float sc[256];
    sc[c] = cln[b * 256 + c]; __syncthreads();
    const float* W  = (which == 0) ? Wf : (which == 1) ? Ww : Wo;
    const float* bi = (which == 0) ? bf : (which == 1) ? bw : bo;
    float* o        = (which == 0) ? fb : (which == 1) ? wb : ob;
    float acc = bi[c];
    for (int k = 0; k < 256; k++) acc += sc[k] * W[(size_t)(256 + k) * 256 + c];
    o[b * 256 + c] = acc;
}

// ---------- scan phase 1 (bf16 inputs) ----------
__global__ void k_scan1(const __nv_bfloat16* __restrict__ GA, const __nv_bfloat16* __restrict__ GB,
                        const __nv_bfloat16* __restrict__ U,
                        float* __restrict__ AGA, float* __restrict__ ABF, float* __restrict__ ABB) {
    int j = blockIdx.x, b = blockIdx.y, c = threadIdx.x;
    size_t base = ((size_t)b * NTOK + j * 128) * CDIM + c;
    float A = 1.f, sf = 0.f;
    for (int t = 0; t < 128; t++) {
        size_t i = base + (size_t)t * CDIM;
        float a = __bfloat162float(GA[i]);
        float bb = (1.f - a) * __bfloat162float(GB[i]) * __bfloat162float(U[i]);
        A *= a; sf = a * sf + bb;
    }
    float sb = 0.f;
    for (int t = 127; t >= 0; t--) {
        size_t i = base + (size_t)t * CDIM;
        float a = __bfloat162float(GA[i]);
        float bb = (1.f - a) * __bfloat162float(GB[i]) * __bfloat162float(U[i]);
        sb = a * sb + bb;
    }
    int o = (b * 32 + j) * 256 + c;
    AGA[o] = A; ABF[o] = sf; ABB[o] = sb;
}

// ---------- scan phase 2 ----------
__global__ void k_scan2(const float* __restrict__ AGA, const float* __restrict__ ABF,
                        const float* __restrict__ ABB, float* __restrict__ SIF, float* __restrict__ SIB) {
    int b = blockIdx.x, c = threadIdx.x;
    float s = 0.f;
    for (int j = 0; j < 32; j++) {
        int o = (b * 32 + j) * 256 + c;
        SIF[o] = s; s = AGA[o] * s + ABF[o];
    }
    s = 0.f;
    for (int j = 31; j >= 0; j--) {
        int o = (b * 32 + j) * 256 + c;
        SIB[o] = s; s = AGA[o] * s + ABB[o];
    }
}

// ---------- scan phase 3 (bf16 in/out) ----------
__global__ void k_scan3(const __nv_bfloat16* __restrict__ GA, const __nv_bfloat16* __restrict__ GB,
                        const __nv_bfloat16* __restrict__ GO, const __nv_bfloat16* __restrict__ U,
                        const float* __restrict__ SIF, const float* __restrict__ SIB,
                        __nv_bfloat16* __restrict__ YF16, __nv_bfloat16* __restrict__ YB16) {
    int j = blockIdx.x, b = blockIdx.y, c = threadIdx.x;
    size_t base = ((size_t)b * NTOK + j * 128) * CDIM + c;
    int ao = (b * 32 + j) * 256 + c;
    float s = SIF[ao];
    for (int t = 0; t < 128; t++) {
        size_t i = base + (size_t)t * CDIM;
        float a = __bfloat162float(GA[i]);
        float u = __bfloat162float(U[i]);
        float bb = (1.f - a) * __bfloat162float(GB[i]) * u;
        s = a * s + bb;
        float o = __bfloat162float(GO[i]);
        YF16[i] = __float2bfloat16_rn(o * s + (1.f - o) * u);
    }
    s = SIB[ao];
    for (int t = 127; t >= 0; t--) {
        size_t i = base + (size_t)t * CDIM;
        float a = __bfloat162float(GA[i]);
        float u = __bfloat162float(U[i]);
        float bb = (1.f - a) * __bfloat162float(GB[i]) * u;
        s = a * s + bb;
        float o = __bfloat162float(GO[i]);
        YB16[i] = __float2bfloat16_rn(o * s + (1.f - o) * u);
    }
}

// ---------- global branch serial scan ----------
__global__ void k_scanglob(const float* __restrict__ GA, const float* __restrict__ GB,
                           const float* __restrict__ GO, const float* __restrict__ U,
                           float* __restrict__ YG) {
    int b = blockIdx.x, c = threadIdx.x;
    size_t base = (size_t)b * NTOKG * CDIM + c;
    float s = 0.f;
    for (int t = 0; t < NTOKG; t++) {
        size_t i = base + (size_t)t * CDIM;
        float a = GA[i], u = U[i];
        float bb = (1.f - a) * GB[i] * u;
        s = a * s + bb;
        float o = GO[i];
        YG[i] = o * s + (1.f - o) * u;
    }
}

// ---------- 4x4 avg pool ----------
__global__ void k_pool(const float* __restrict__ seq, float* __restrict__ seqg) {
    int tg = blockIdx.x, b = blockIdx.y, c = threadIdx.x;
    int gh = tg / 16, gw = tg % 16;
    float s = 0.f;
#pragma unroll
    for (int i = 0; i < 4; i++)
#pragma unroll
        for (int j = 0; j < 4; j++)
            s += seq[((size_t)b * NTOK + (gh * 4 + i) * 64 + gw * 4 + j) * CDIM + c];
    seqg[((size_t)b * NTOKG + tg) * CDIM + c] = s * (1.0f / 16.0f);
}

// ---------- bilinear upsample (bf16 output only) ----------
__global__ void k_upsample(const float* __restrict__ YG, __nv_bfloat16* __restrict__ YGS16) {
    int t = blockIdx.x, b = blockIdx.y, c = threadIdx.x;
    int oh = t / 64, ow = t % 64;
    float sy = (oh + 0.5f) * 0.25f - 0.5f;
    float sx = (ow + 0.5f) * 0.25f - 0.5f;
    int y0 = (int)floorf(sy); float fy = sy - y0;
    int x0 = (int)floorf(sx); float fx = sx - x0;
    int y0c = clampi(y0, 0, 15), y1c = clampi(y0 + 1, 0, 15);
    int x0c = clampi(x0, 0, 15), x1c = clampi(x0 + 1, 0, 15);
    const float* base = YG + (size_t)b * NTOKG * CDIM + c;
    float v00 = base[(size_t)(y0c * 16 + x0c) * CDIM];
    float v01 = base[(size_t)(y0c * 16 + x1c) * CDIM];
    float v10 = base[(size_t)(y1c * 16 + x0c) * CDIM];
    float v11 = base[(size_t)(y1c * 16 + x1c) * CDIM];
    float v = (1.f - fy) * ((1.f - fx) * v00 + fx * v01) + fy * ((1.f - fx) * v10 + fx * v11);
    YGS16[((size_t)b * NTOK + t) * CDIM + c] = __float2bfloat16_rn(v);
}

// ---------- depthwise 3x3 conv, sliding window (bf16 output only) ----------
__global__ void k_dwconv(const float* __restrict__ seq, const float* __restrict__ w,
                         const float* __restrict__ bias, __nv_bfloat16* __restrict__ VM16) {
    int h = blockIdx.x, b = blockIdx.y, c = threadIdx.x;
    float wr[9];
#pragma unroll
    for (int k = 0; k < 9; k++) wr[k] = w[c * 9 + k];
    float bi = bias[c];
    const float* sp = seq + (size_t)b * NTOK * CDIM + c;
    bool h0ok = (h - 1) >= 0, h2ok = (h + 1) < 64;
    size_t r0 = (size_t)(h - 1) * 64, r1 = (size_t)h * 64, r2 = (size_t)(h + 1) * 64;
    float m0 = 0.f, m1 = 0.f, m2 = 0.f;
    float c0 = h0ok ? sp[(r0 + 0) * CDIM] : 0.f;
    float c1 = sp[(r1 + 0) * CDIM];
    float c2 = h2ok ? sp[(r2 + 0) * CDIM] : 0.f;
    float n0 = h0ok ? sp[(r0 + 1) * CDIM] : 0.f;
    float n1 = sp[(r1 + 1) * CDIM];
    float n2 = h2ok ? sp[(r2 + 1) * CDIM] : 0.f;
    size_t obase = ((size_t)b * NTOK + (size_t)h * 64) * CDIM + c;
    for (int x = 0; x < 64; x++) {
        float acc = bi
            + wr[0] * m0 + wr[1] * c0 + wr[2] * n0
            + wr[3] * m1 + wr[4] * c1 + wr[5] * n1
            + wr[6] * m2 + wr[7] * c2 + wr[8] * n2;
        VM16[obase + (size_t)x * CDIM] = __float2bfloat16_rn(acc);
        m0 = c0; m1 = c1; m2 = c2;
        c0 = n0; c1 = n1; c2 = n2;
        if (x + 2 < 64) {
            n0 = h0ok ? sp[(r0 + x + 2) * CDIM] : 0.f;
            n1 = sp[(r1 + x + 2) * CDIM];
            n2 = h2ok ? sp[(r2 + x + 2) * CDIM] : 0.f;
        } else { n0 = n1 = n2 = 0.f; }
    }
}

extern "C" void kernel_launch(void* const* d_in, const int* in_sizes, int n_in,
                              void* d_out, int out_size) {
    const float* x        = (const float*)d_in[0];
    const float* Wt       = (const float*)d_in[1];
    const float* bt       = (const float*)d_in[2];
    const float* pos_fine = (const float*)d_in[3];
    const float* pos_glob = (const float*)d_in[4];
    const float* ln_g     = (const float*)d_in[5];
    const float* ln_b     = (const float*)d_in[6];
    const float* Wf       = (const float*)d_in[7];
    const float* bf       = (const float*)d_in[8];
    const float* Ww       = (const float*)d_in[9];
    const float* bw       = (const float*)d_in[10];
    const float* Wo       = (const float*)d_in[11];
    const float* bo       = (const float*)d_in[12];
    const float* Wr       = (const float*)d_in[13];
    const float* br       = (const float*)d_in[14];
    const float* Wgi      = (const float*)d_in[15];
    const float* bgi      = (const float*)d_in[16];
    const float* dw_w     = (const float*)d_in[17];
    const float* dw_b     = (const float*)d_in[18];
    const float* Wl       = (const float*)d_in[19];
    const float* bl       = (const float*)d_in[20];
    const float* Wlf      = (const float*)d_in[21];
    const float* blf      = (const float*)d_in[22];
    const float* Wout     = (const float*)d_in[23];
    const float* bout     = (const float*)d_in[24];
    float* outp = (float*)d_out;

    float* S = nullptr;
    cudaGetSymbolAddress((void**)&S, g_scratch);
    float* SEQ  = S + OFF_SEQ;  float* PROJ = S + OFF_PROJ;
    float* SEQG = S + OFF_SEQG; float* UG   = S + OFF_UG;
    float* GAG  = S + OFF_GAG;  float* GBG  = S + OFF_GBG;  float* GOG = S + OFF_GOG;
    float* YG   = S + OFF_YG;
    float* POSF = S + OFF_POSF; float* POSG = S + OFF_POSG;
    float* CLN  = S + OFF_CLN;  float* CLNG = S + OFF_CLNG;
    float* FB = S + OFF_FB, *WB = S + OFF_WB, *OB = S + OFF_OB;
    float* FBG = S + OFF_FBG, *WBG = S + OFF_WBG, *OBG = S + OFF_OBG;
    float* AGA = S + OFF_AGA, *ABF = S + OFF_ABF, *ABB = S + OFF_ABB;
    float* SIF = S + OFF_SIF, *SIB = S + OFF_SIB;
    float* P16 = S + OFF_P16;   float* P16G = S + OFF_P16G;
    uint32_t* WBW = (uint32_t*)(S + OFF_WBW);
    __nv_bfloat16* U16   = (__nv_bfloat16*)(S + OFF_U16);
    __nv_bfloat16* YF16  = (__nv_bfloat16*)(S + OFF_YF16);
    __nv_bfloat16* YB16  = (__nv_bfloat16*)(S + OFF_YB16);
    __nv_bfloat16* Y16   = (__nv_bfloat16*)(S + OFF_Y16);
    __nv_bfloat16* YGS16 = (__nv_bfloat16*)(S + OFF_YGS16);
    __nv_bfloat16* V16   = (__nv_bfloat16*)(S + OFF_V16);
    __nv_bfloat16* Z16   = (__nv_bfloat16*)(S + OFF_Z16);
    __nv_bfloat16* SEQ16 = (__nv_bfloat16*)(S + OFF_SEQ16);
    __nv_bfloat16* VM16  = (__nv_bfloat16*)(S + OFF_VM16);
    __nv_bfloat16* UO16  = (__nv_bfloat16*)(S + OFF_UO16);
    __nv_bfloat16* GA16  = (__nv_bfloat16*)(S + OFF_GA16);
    __nv_bfloat16* GB16  = (__nv_bfloat16*)(S + OFF_GB16);
    __nv_bfloat16* GO16  = (__nv_bfloat16*)(S + OFF_GO16);

    uint32_t* WBf  = WBW + (size_t)0    * 256;
    uint32_t* WBw  = WBW + (size_t)128  * 256;
    uint32_t* WBo  = WBW + (size_t)256  * 256;
    uint32_t* WBr0 = WBW + (size_t)384  * 256;
    uint32_t* WBr1 = WBW + (size_t)512  * 256;
    uint32_t* WBr2 = WBW + (size_t)640  * 256;
    uint32_t* WBg0 = WBW + (size_t)768  * 256;
    uint32_t* WBg1 = WBW + (size_t)896  * 256;
    uint32_t* WBg2 = WBW + (size_t)1024 * 256;
    uint32_t* WBl0 = WBW + (size_t)1152 * 256;
    uint32_t* WBl1 = WBW + (size_t)1280 * 256;
    uint32_t* WBt  = WBW + (size_t)1408 * 256;
    uint32_t* WBl  = WBW + (size_t)1536 * 256;
    uint32_t* WBout= WBW + (size_t)1664 * 256;

    static int init_done = 0;
    static cudaStream_t s2;
    static cudaEvent_t ev0, ev1;
    int smem_tf = NSTAGE * STAGE_ELEMS * 4;
    int smem_bf = NSTB * BSTG_EL * 4;
    if (!init_done) {
        cudaFuncSetAttribute(k_gemm_tc, cudaFuncAttributeMaxDynamicSharedMemorySize, smem_tf);
        cudaFuncSetAttribute(k_gemm_bf, cudaFuncAttributeMaxDynamicSharedMemorySize, smem_bf);
        cudaStreamCreateWithFlags(&s2, cudaStreamNonBlocking);
        cudaEventCreateWithFlags(&ev0, cudaEventDisableTiming);
        cudaEventCreateWithFlags(&ev1, cudaEventDisableTiming);
        init_done = 1;
    }

    dim3 tb(32, 8);
    dim3 tg(128, 8, 8);
    dim3 gemF(2, MFINE / 128), gemG(2, MGLOB / 128);
    dim3 gemG3(2, MGLOB / 128, 3), gemF3(2, MFINE / 128, 3);
    const float* NP = nullptr;
    float* NPo = nullptr;
    __nv_bfloat16* NPh = nullptr;
    const __nv_bfloat16* NPhc = nullptr;
    const uint32_t* NPw = nullptr;

    // prep needed by BOTH paths first, then fork the global branch
    k_transpose<<<tg, tb>>>(x, SEQ, SEQ16);
    k_posdown<<<256, 256>>>(pos_glob, POSG);
    cudaEventRecord(ev0, 0);

    // ---- global branch on s2 (joins before lam mixing) ----
    cudaStreamWaitEvent(s2, ev0, 0);
    k_pool<<<dim3(256, BATCH), 256, 0, s2>>>(SEQ, SEQG);
    k_gemm_tc<<<gemG, 256, smem_tf, s2>>>(SEQG, Wt, NP, NP, NP, NP, 1, UG, NPo, NPo, bt, 1, POSG, NP, 255, 0, NPh);
    k_colmean_a<<<dim3(16, BATCH), 256, 0, s2>>>(UG, P16G, 16);
    k_ctx<<<BATCH, 256, 0, s2>>>(P16G, 1.0f / NTOKG, ln_g, ln_b, CLNG);
    k_gatebias<<<dim3(3, BATCH), 256, 0, s2>>>(CLNG, Wf, bf, Ww, bw, Wo, bo, FBG, WBG, OBG);
    k_gemm_tc<<<gemG3, 256, smem_tf, s2>>>(UG, Wf, NP, Ww, NP, Wo, 1, GAG, GBG, GOG, OBG, 4, FBG, WBG, NTOKG, 1, NPh);
    k_scanglob<<<BATCH, 256, 0, s2>>>(GAG, GBG, GOG, UG, YG);
    k_upsample<<<dim3(4096, BATCH), 256, 0, s2>>>(YG, YGS16);
    cudaEventRecord(ev1, s2);

    // ---- fine path on stream 0 ----
    k_wcvt<<<1792, 256>>>(Wf, Ww, Wo, Wr, Wgi, Wlf, Wt, Wl, Wout, WBW);
    k_posup<<<4096, 256>>>(pos_fine, POSF, 64, 64);

    // U = SEQ@Wt + bt + pos -> U16 only
    k_gemm_bf<<<gemF, 256, smem_bf>>>(SEQ16, WBt, NPhc, NPw, NPhc, NPw, 1, NPo, NPo, NPo, bt, 1, POSF, NP, 4095, 0, U16, NPh, NPh);

    // gates: mode 4 -> bf16 mirrors only
    k_colmean_a16<<<dim3(16, BATCH), 256>>>(U16, P16, 256);
    k_ctx<<<BATCH, 256>>>(P16, 1.0f / NTOK, ln_g, ln_b, CLN);
    k_gatebias<<<dim3(3, BATCH), 256>>>(CLN, Wf, bf, Ww, bw, Wo, bo, FB, WB, OB);
    k_gemm_bf<<<gemF3, 256, smem_bf>>>(U16, WBf, NPhc, WBw, NPhc, WBo, 1, NPo, NPo, NPo, OB, 4, FB, WB, NTOK, 1, GA16, GB16, GO16);

    // bidirectional chunked scan (bf16)
    k_scan1<<<dim3(32, BATCH), 256>>>(GA16, GB16, U16, AGA, ABF, ABB);
    k_scan2<<<BATCH, 256>>>(AGA, ABF, ABB, SIF, SIB);
    k_scan3<<<dim3(32, BATCH), 256>>>(GA16, GB16, GO16, U16, SIF, SIB, YF16, YB16);

    // rho mixing -> Y16
    k_gemm_bf<<<gemF, 256, smem_bf>>>(U16, WBr0, YF16, WBr1, YB16, WBr2, 3, NPo, NPo, NPo, br, 2,
                                      (const float*)YF16, (const float*)YB16, 0, 0, Y16, NPh, NPh);

    // local depthwise branch (overlaps with s2 tail)
    k_dwconv<<<dim3(64, BATCH), 256>>>(SEQ, dw_w, dw_b, VM16);
    k_gemm_bf<<<gemF, 256, smem_bf>>>(VM16, WBl, NPhc, NPw, NPhc, NPw, 1, NPo, NPo, NPo, bl, 0, NP, NP, 0, 0, V16, NPh, NPh);

    // join global branch
    cudaStreamWaitEvent(0, ev1, 0);

    // lam mixing -> Z16
    k_gemm_bf<<<gemF, 256, smem_bf>>>(Y16, WBg0, YGS16, WBg1, U16, WBg2, 3, NPo, NPo, NPo, bgi, 3,
                                      (const float*)Y16, (const float*)YGS16, 0, 0, Z16, NPh, NPh);

    // eta -> UO16
    k_gemm_bf<<<gemF, 256, smem_bf>>>(V16, WBl0, Z16, WBl1, NPhc, NPw, 2, NPo, NPo, NPo, blf, 2,
                                      (const float*)V16, (const float*)Z16, 0, 0, UO16, NPh, NPh);

    // output proj + residual
    k_gemm_bf<<<gemF, 256, smem_bf>>>(UO16, WBout, NPhc, NPw, NPhc, NPw, 1, PROJ, NPo, NPo, bout, 0, NP, NP, 0, 0, NPh, NPh, NPh);
    k_output<<<tg, tb>>>(PROJ, x, outp);
}

// round 14
// speedup vs baseline: 5.5362x; 1.0803x over previous
#include <cuda_runtime.h>
#include <cuda_bf16.h>
#include <math.h>
#include <stdint.h>

#define BATCH 8
#define CDIM  256
#define NTOK  4096
#define NTOKG 256
#define MFINE 32768
#define MGLOB 2048
#define LN_EPS 1e-5f

static const size_t U_SZ  = (size_t)MFINE * CDIM;
static const size_t H_SZ  = U_SZ / 2;
static const size_t SG_SZ = (size_t)MGLOB * CDIM;

static const size_t OFF_PROJ  = 0*U_SZ;
static const size_t SMALL0    = 1*U_SZ;
static const size_t OFF_SEQG  = SMALL0 + 0*SG_SZ;
static const size_t OFF_UG    = SMALL0 + 1*SG_SZ;
static const size_t OFF_GAG   = SMALL0 + 2*SG_SZ;
static const size_t OFF_GBG   = SMALL0 + 3*SG_SZ;
static const size_t OFF_GOG   = SMALL0 + 4*SG_SZ;
static const size_t OFF_YG    = SMALL0 + 5*SG_SZ;
static const size_t SMALL1    = SMALL0 + 6*SG_SZ;
static const size_t OFF_POSF  = SMALL1;
static const size_t OFF_POSG  = OFF_POSF + 4096*256;
static const size_t OFF_CLN   = OFF_POSG + 65536;
static const size_t OFF_CLNG  = OFF_CLN + 2048;
static const size_t OFF_FB    = OFF_CLNG + 2048;
static const size_t OFF_WB    = OFF_FB + 2048;
static const size_t OFF_OB    = OFF_WB + 2048;
static const size_t OFF_FBG   = OFF_OB + 2048;
static const size_t OFF_WBG   = OFF_FBG + 2048;
static const size_t OFF_OBG   = OFF_WBG + 2048;
static const size_t OFF_AGA   = OFF_OBG + 2048;
static const size_t OFF_ABF   = OFF_AGA + 65536;
static const size_t OFF_ABB   = OFF_ABF + 65536;
static const size_t OFF_SIF   = OFF_ABB + 65536;
static const size_t OFF_SIB   = OFF_SIF + 65536;
static const size_t OFF_P16   = OFF_SIB + 65536;
static const size_t OFF_P16G  = OFF_P16 + 32768;
static const size_t OFF_WBW   = OFF_P16G + 32768;          // bf16x2 weights: 1792*256 u32
static const size_t OFF_U16   = OFF_WBW + 458752;
static const size_t OFF_YF16  = OFF_U16  + H_SZ;
static const size_t OFF_YB16  = OFF_YF16 + H_SZ;
static const size_t OFF_Y16   = OFF_YB16 + H_SZ;
static const size_t OFF_YGS16 = OFF_Y16  + H_SZ;
static const size_t OFF_V16   = OFF_YGS16+ H_SZ;
static const size_t OFF_Z16   = OFF_V16  + H_SZ;
static const size_t OFF_SEQ16 = OFF_Z16  + H_SZ;
static const size_t OFF_VM16  = OFF_SEQ16+ H_SZ;
static const size_t OFF_UO16  = OFF_VM16 + H_SZ;
static const size_t OFF_GA16  = OFF_UO16 + H_SZ;
static const size_t OFF_GB16  = OFF_GA16 + H_SZ;
static const size_t OFF_GO16  = OFF_GB16 + H_SZ;
static const size_t TOTAL_SCRATCH = OFF_GO16 + H_SZ + 1024;

__device__ __align__(16) float g_scratch[TOTAL_SCRATCH];

__device__ __forceinline__ float sigf(float x) { return 1.0f / (1.0f + expf(-x)); }
__device__ __forceinline__ int clampi(int v, int lo, int hi) { return v < lo ? lo : (v > hi ? hi : v); }

__device__ __forceinline__ void mma_tf32(float* c, const uint32_t* a, const uint32_t* b) {
    asm volatile(
        "mma.sync.aligned.m16n8k8.row.col.f32.tf32.tf32.f32 "
        "{%0,%1,%2,%3}, {%4,%5,%6,%7}, {%8,%9}, {%0,%1,%2,%3};\n"
        : "+f"(c[0]), "+f"(c[1]), "+f"(c[2]), "+f"(c[3])
        : "r"(a[0]), "r"(a[1]), "r"(a[2]), "r"(a[3]), "r"(b[0]), "r"(b[1]));
}
__device__ __forceinline__ void mma_bf16(float* c, const uint32_t* a, const uint32_t* b) {
    asm volatile(
        "mma.sync.aligned.m16n8k16.row.col.f32.bf16.bf16.f32 "
        "{%0,%1,%2,%3}, {%4,%5,%6,%7}, {%8,%9}, {%0,%1,%2,%3};\n"
        : "+f"(c[0]), "+f"(c[1]), "+f"(c[2]), "+f"(c[3])
        : "r"(a[0]), "r"(a[1]), "r"(a[2]), "r"(a[3]), "r"(b[0]), "r"(b[1]));
}
__device__ __forceinline__ void ldsm4(uint32_t* r, uint32_t saddr) {
    asm volatile("ldmatrix.sync.aligned.m8n8.x4.shared.b16 {%0,%1,%2,%3}, [%4];"
        : "=r"(r[0]), "=r"(r[1]), "=r"(r[2]), "=r"(r[3]) : "r"(saddr));
}

__device__ __forceinline__ void cpa16(uint32_t dst, const void* src) {
    asm volatile("cp.async.cg.shared.global [%0], [%1], 16;" :: "r"(dst), "l"(src));
}
#define CP_COMMIT() asm volatile("cp.async.commit_group;")
#define CP_WAIT1()  asm volatile("cp.async.wait_group 1;")
#define CP_WAIT2()  asm volatile("cp.async.wait_group 2;")

__device__ __forceinline__ const float* selp(const float* a0, const float* a1,
                                             const float* a2, int p) {
    return p == 0 ? a0 : (p == 1 ? a1 : a2);
}
__device__ __forceinline__ const __nv_bfloat16* selh(const __nv_bfloat16* a0,
                                                     const __nv_bfloat16* a1,
                                                     const __nv_bfloat16* a2, int p) {
    return p == 0 ? a0 : (p == 1 ? a1 : a2);
}
__device__ __forceinline__ const uint32_t* selw(const uint32_t* a0, const uint32_t* a1,
                                                const uint32_t* a2, int p) {
    return p == 0 ? a0 : (p == 1 ? a1 : a2);
}

// ---------- x [B,C,4096] -> seq16 [B*4096, C] ----------
__global__ void k_transpose(const float* __restrict__ x, __nv_bfloat16* __restrict__ seq16) {
    __shared__ float tile[32][33];
    int b = blockIdx.z;
    int t0 = blockIdx.x * 32, c0 = blockIdx.y * 32;
    int tx = threadIdx.x, ty = threadIdx.y;
    const float* src = x + (size_t)b * CDIM * NTOK;
#pragma unroll
    for (int j = 0; j < 4; j++)
        tile[ty + 8*j][tx] = src[(size_t)(c0 + ty + 8*j) * NTOK + t0 + tx];
    __syncthreads();
    __nv_bfloat16* dsth = seq16 + (size_t)b * NTOK * CDIM;
#pragma unroll
    for (int j = 0; j < 4; j++) {
        float v = tile[tx][ty + 8*j];
        dsth[(size_t)(t0 + ty + 8*j) * CDIM + c0 + tx] = __float2bfloat16_rn(v);
    }
}

// ---------- proj [B,4096,C] + x -> out [B,C,4096] ----------
__global__ void k_output(const float* __restrict__ proj, const float* __restrict__ x,
                         float* __restrict__ outp) {
    __shared__ float tile[32][33];
    int b = blockIdx.z;
    int t0 = blockIdx.x * 32, c0 = blockIdx.y * 32;
    int tx = threadIdx.x, ty = threadIdx.y;
    const float* src = proj + (size_t)b * NTOK * CDIM;
#pragma unroll
    for (int j = 0; j < 4; j++)
        tile[ty + 8*j][tx] = src[(size_t)(t0 + ty + 8*j) * CDIM + c0 + tx];
    __syncthreads();
    size_t base = (size_t)b * CDIM * NTOK;
#pragma unroll
    for (int j = 0; j < 4; j++) {
        size_t o = base + (size_t)(c0 + ty + 8*j) * NTOK + t0 + tx;
        outp[o] = x[o] + tile[tx][ty + 8*j];
    }
}

// ---------- pos bilinear upsample ----------
__global__ void k_posup(const float* __restrict__ pos, float* __restrict__ outp, int OH, int OW) {
    int t = blockIdx.x, c = threadIdx.x;
    int oh = t / OW, ow = t % OW;
    float sy = (oh + 0.5f) * (32.0f / OH) - 0.5f;
    float sx = (ow + 0.5f) * (32.0f / OW) - 0.5f;
    int y0 = (int)floorf(sy); float fy = sy - y0;
    int x0 = (int)floorf(sx); float fx = sx - x0;
    int y0c = clampi(y0, 0, 31), y1c = clampi(y0 + 1, 0, 31);
    int x0c = clampi(x0, 0, 31), x1c = clampi(x0 + 1, 0, 31);
    const float* p = pos + (size_t)c * 1024;
    float v = (1.f - fy) * ((1.f - fx) * p[y0c*32 + x0c] + fx * p[y0c*32 + x1c])
            + fy * ((1.f - fx) * p[y1c*32 + x0c] + fx * p[y1c*32 + x1c]);
    outp[(size_t)t * CDIM + c] = v;
}

// ---------- pos antialiased downsample 32->16 ----------
__global__ void k_posdown(const float* __restrict__ pos, float* __restrict__ outp) {
    int t = blockIdx.x, c = threadIdx.x;
    int gh = t / 16, gw = t % 16;
    const float W4[4] = {0.125f, 0.375f, 0.375f, 0.125f};
    float wy[4], wx[4]; int ky[4], kx[4];
    float sy = 0.f, sx = 0.f;
#pragma unroll
    for (int d = 0; d < 4; d++) {
        ky[d] = 2*gh - 1 + d; wy[d] = (ky[d] >= 0 && ky[d] < 32) ? W4[d] : 0.f; sy += wy[d];
        kx[d] = 2*gw - 1 + d; wx[d] = (kx[d] >= 0 && kx[d] < 32) ? W4[d] : 0.f; sx += wx[d];
    }
    const float* p = pos + (size_t)c * 1024;
    float acc = 0.f;
#pragma unroll
    for (int d = 0; d < 4; d++) {
        if (wy[d] == 0.f) continue;
        float rowacc = 0.f;
#pragma unroll
        for (int e = 0; e < 4; e++)
            if (wx[e] != 0.f) rowacc += wx[e] * p[ky[d]*32 + kx[e]];
        acc += wy[d] * rowacc;
    }
    outp[(size_t)t * CDIM + c] = acc / (sy * sx);
}

// ---------- weight interleave ----------
__global__ void k_wcvt(const float* __restrict__ Wf, const float* __restrict__ Ww,
                       const float* __restrict__ Wo, const float* __restrict__ Wr,
                       const float* __restrict__ Wgi, const float* __restrict__ Wlf,
                       const float* __restrict__ Wt, const float* __restrict__ Wl,
                       const float* __restrict__ Wout, uint32_t* __restrict__ WB) {
    int r = blockIdx.x, c = threadIdx.x;
    const float* src; int k2;
    if (r < 128)       { src = Wf;   k2 = r; }
    else if (r < 256)  { src = Ww;   k2 = r - 128; }
    else if (r < 384)  { src = Wo;   k2 = r - 256; }
    else if (r < 768)  { src = Wr;   k2 = r - 384; }
    else if (r < 1152) { src = Wgi;  k2 = r - 768; }
    else if (r < 1408) { src = Wlf;  k2 = r - 1152; }
    else if (r < 1536) { src = Wt;   k2 = r - 1408; }
    else if (r < 1664) { src = Wl;   k2 = r - 1536; }
    else               { src = Wout; k2 = r - 1664; }
    float lo = src[(size_t)(2*k2) * 256 + c];
    float hi = src[(size_t)(2*k2 + 1) * 256 + c];
    __nv_bfloat162 p2 = __floats2bfloat162_rn(lo, hi);
    WB[(size_t)r * 256 + c] = *(uint32_t*)&p2;
}

// ================= tf32 mma.sync GEMM (global branch only) =================
#define AS_STRIDE 36
#define BS_STRIDE 136
#define A_ELEMS (128*AS_STRIDE)
#define B_ELEMS (32*BS_STRIDE)
#define STAGE_ELEMS (A_ELEMS + B_ELEMS)
#define NSTAGE 3
extern __shared__ float smx[];

__global__ void __launch_bounds__(256, 2)
k_gemm_tc(const float* __restrict__ A0, const float* __restrict__ W0,
          const float* __restrict__ A1, const float* __restrict__ W1,
          const float* __restrict__ A2, const float* __restrict__ W2,
          int npairs,
          float* __restrict__ C0, float* __restrict__ C1, float* __restrict__ C2,
          const float* __restrict__ bias, int mode,
          const float* __restrict__ P1, const float* __restrict__ P2,
          int tokmask, int multi, __nv_bfloat16* __restrict__ D0) {
    int bx = blockIdx.x, by = blockIdx.y, bz = blockIdx.z;
    int tid = threadIdx.x;
    int warp = tid >> 5, lane = tid & 31;
    int wm = warp >> 2, wn = warp & 3;
    int g = lane >> 2, tq = lane & 3;

    uint32_t smem_u32 = (uint32_t)__cvta_generic_to_shared(smx);

    float acc[4][4][4];
#pragma unroll
    for (int i = 0; i < 4; i++)
#pragma unroll
        for (int j = 0; j < 4; j++)
#pragma unroll
            for (int r = 0; r < 4; r++) acc[i][j][r] = 0.f;

    int nst = (multi ? 1 : npairs) * 8;

    auto load_stage = [&](int st, int buf) {
        int p = multi ? bz : (st >> 3);
        const float* A = multi ? A0 : selp(A0, A1, A2, p);
        const float* W = selp(W0, W1, W2, p);
        int k0 = (st & 7) * 32;
        uint32_t abase = smem_u32 + (uint32_t)(buf * STAGE_ELEMS) * 4u;
        uint32_t bbase = abase + (uint32_t)A_ELEMS * 4u;
#pragma unroll
        for (int i = 0; i < 4; i++) {
            int idx = tid + 256 * i;
            int row = idx >> 3, c4 = idx & 7;
            cpa16(abase + (uint32_t)(row * AS_STRIDE + c4 * 4) * 4u,
                  A + (size_t)(by * 128 + row) * 256 + k0 + c4 * 4);
        }
#pragma unroll
        for (int i = 0; i < 4; i++) {
            int idx = tid + 256 * i;
            int row = idx >> 5, c4 = idx & 31;
            cpa16(bbase + (uint32_t)(row * BS_STRIDE + c4 * 4) * 4u,
                  W + (size_t)(k0 + row) * 256 + bx * 128 + c4 * 4);
        }
        CP_COMMIT();
    };

    load_stage(0, 0);
    load_stage(1, 1);

    for (int st = 0; st < nst; st++) {
        CP_WAIT1();
        __syncthreads();
        int nx = st + NSTAGE - 1;
        if (nx < nst) load_stage(nx, nx % NSTAGE);
        else CP_COMMIT();

        int pb = st % NSTAGE;
        const uint32_t* Asu = (const uint32_t*)(smx + pb * STAGE_ELEMS);
        const uint32_t* Bsu = Asu + A_ELEMS;
#pragma unroll
        for (int ks = 0; ks < 32; ks += 8) {
            uint32_t af[4][4], bf[4][2];
#pragma unroll
            for (int mt = 0; mt < 4; mt++) {
                int mb = wm * 64 + mt * 16;
                af[mt][0] = Asu[(mb + g) * AS_STRIDE + ks + tq];
                af[mt][1] = Asu[(mb + g + 8) * AS_STRIDE + ks + tq];
                af[mt][2] = Asu[(mb + g) * AS_STRIDE + ks + tq + 4];
                af[mt][3] = Asu[(mb + g + 8) * AS_STRIDE + ks + tq + 4];
            }
#pragma unroll
            for (int nt = 0; nt < 4; nt++) {
                int nb = wn * 32 + nt * 8;
                bf[nt][0] = Bsu[(ks + tq) * BS_STRIDE + nb + g];
                bf[nt][1] = Bsu[(ks + tq + 4) * BS_STRIDE + nb + g];
            }
#pragma unroll
            for (int mt = 0; mt < 4; mt++)
#pragma unroll
                for (int nt = 0; nt < 4; nt++)
                    mma_tf32(acc[mt][nt], af[mt], bf[nt]);
        }
    }

    float* C = multi ? (bz == 0 ? C0 : (bz == 1 ? C1 : C2)) : C0;
    int batch4 = (mode == 4) ? (by * 128) / tokmask : 0;
    const float* TB4 = (mode == 4) ? (bz == 0 ? P1 : (bz == 1 ? P2 : bias)) : nullptr;
#pragma unroll
    for (int mt = 0; mt < 4; mt++) {
        int r0 = by * 128 + wm * 64 + mt * 16 + g;
#pragma unroll
        for (int nt = 0; nt < 4; nt++) {
            int col = bx * 128 + wn * 32 + nt * 8 + tq * 2;
            float b0 = 0.f, b1 = 0.f;
            if (bias && mode != 4) { b0 = bias[col]; b1 = bias[col + 1]; }
#pragma unroll
            for (int h = 0; h < 2; h++) {
                int r = r0 + h * 8;
                float t0 = acc[mt][nt][2*h + 0] + b0;
                float t1 = acc[mt][nt][2*h + 1] + b1;
                size_t i0 = (size_t)r * 256 + col;
                float o0, o1;
                if (mode == 0) {
                    o0 = t0; o1 = t1;
                } else if (mode == 1) {
                    size_t pi = (size_t)(r & tokmask) * 256 + col;
                    o0 = t0 + P1[pi]; o1 = t1 + P1[pi + 1];
                } else if (mode == 2) {
                    float s0 = sigf(t0), s1 = sigf(t1);
                    o0 = s0 * P1[i0] + (1.f - s0) * P2[i0];
                    o1 = s1 * P1[i0 + 1] + (1.f - s1) * P2[i0 + 1];
                } else if (mode == 3) {
                    o0 = P1[i0] + sigf(t0) * P2[i0];
                    o1 = P1[i0 + 1] + sigf(t1) * P2[i0 + 1];
                } else {
                    float x0 = t0 + TB4[batch4 * 256 + col];
                    float x1 = t1 + TB4[batch4 * 256 + col + 1];
                    if (bz == 0) { o0 = 1.f / (1.f + expf(x0)); o1 = 1.f / (1.f + expf(x1)); }
                    else         { o0 = sigf(x0); o1 = sigf(x1); }
                }
                if (C) *(float2*)(C + i0) = make_float2(o0, o1);
                if (D0) *(__nv_bfloat162*)((__nv_bfloat16*)D0 + i0) = __floats2bfloat162_rn(o0, o1);
            }
        }
    }
}

// ================= bf16 mma.sync GEMM (all fine GEMMs) =================
#define BA_STR 20
#define BB_STR 136
#define BA_EL (128*BA_STR)
#define BB_EL (16*BB_STR)
#define BSTG_EL (BA_EL + BB_EL)
#define NSTB 4

__global__ void __launch_bounds__(256, 2)
k_gemm_bf(const __nv_bfloat16* __restrict__ A0, const uint32_t* __restrict__ W0,
          const __nv_bfloat16* __restrict__ A1, const uint32_t* __restrict__ W1,
          const __nv_bfloat16* __restrict__ A2, const uint32_t* __restrict__ W2,
          int npairs,
          float* __restrict__ C0, float* __restrict__ C1, float* __restrict__ C2,
          const float* __restrict__ bias, int mode,
          const float* __restrict__ P1, const float* __restrict__ P2,
          int tokmask, int multi,
          __nv_bfloat16* __restrict__ D0, __nv_bfloat16* __restrict__ D1,
          __nv_bfloat16* __restrict__ D2) {
    int bx = blockIdx.x, by = blockIdx.y, bz = blockIdx.z;
    int tid = threadIdx.x;
    int warp = tid >> 5, lane = tid & 31;
    int wm = warp >> 2, wn = warp & 3;
    int g = lane >> 2, tq = lane & 3;

    uint32_t smem_u32 = (uint32_t)__cvta_generic_to_shared(smx);

    float acc[4][4][4];
#pragma unroll
    for (int i = 0; i < 4; i++)
#pragma unroll
        for (int j = 0; j < 4; j++)
#pragma unroll
            for (int r = 0; r < 4; r++) acc[i][j][r] = 0.f;

    int nst = (multi ? 1 : npairs) * 8;

    auto load_stage = [&](int st, int buf) {
        int p = multi ? bz : (st >> 3);
        const __nv_bfloat16* A = multi ? A0 : selh(A0, A1, A2, p);
        const uint32_t* W = selw(W0, W1, W2, p);
        int k0 = (st & 7) * 32;
        int k2b = k0 >> 1;
        uint32_t abase = smem_u32 + (uint32_t)(buf * BSTG_EL) * 4u;
        uint32_t bbase = abase + (uint32_t)BA_EL * 4u;
#pragma unroll
        for (int i = 0; i < 2; i++) {
            int idx = tid + 256 * i;
            int row = idx >> 2, c4 = idx & 3;
            cpa16(abase + (uint32_t)(row * BA_STR + c4 * 4) * 4u,
                  A + (size_t)(by * 128 + row) * 256 + k0 + c4 * 8);
        }
#pragma unroll
        for (int i = 0; i < 2; i++) {
            int idx = tid + 256 * i;
            int row = idx >> 5, c4 = idx & 31;
            cpa16(bbase + (uint32_t)(row * BB_STR + c4 * 4) * 4u,
                  W + (size_t)(k2b + row) * 256 + bx * 128 + c4 * 4);
        }
        CP_COMMIT();
    };

    load_stage(0, 0);
    load_stage(1, 1);
    load_stage(2, 2);

    int lrow = lane & 15;
    uint32_t kside = (uint32_t)((lane >> 4) << 4);

    for (int st = 0; st < nst; st++) {
        CP_WAIT2();
        __syncthreads();
        int nx = st + NSTB - 1;
        if (nx < nst) load_stage(nx, nx % NSTB);
        else CP_COMMIT();

        int pb = st % NSTB;
        uint32_t abyte = smem_u32 + (uint32_t)(pb * BSTG_EL) * 4u;
        const uint32_t* Bsu = (const uint32_t*)(smx + pb * BSTG_EL) + BA_EL;
#pragma unroll
        for (int s = 0; s < 2; s++) {
            int ko = 8 * s;
            uint32_t af[4][4], bf[4][2];
#pragma unroll
            for (int mt = 0; mt < 4; mt++) {
                uint32_t addr = abyte
                    + (uint32_t)((wm * 64 + mt * 16 + lrow) * BA_STR) * 4u
                    + kside + (uint32_t)(s * 32);
                ldsm4(af[mt], addr);
            }
#pragma unroll
            for (int nt = 0; nt < 4; nt++) {
                int nb = wn * 32 + nt * 8;
                bf[nt][0] = Bsu[(ko + tq) * BB_STR + nb + g];
                bf[nt][1] = Bsu[(ko + tq + 4) * BB_STR + nb + g];
            }
#pragma unroll
            for (int mt = 0; mt < 4; mt++)
#pragma unroll
                for (int nt = 0; nt < 4; nt++)
                    mma_bf16(acc[mt][nt], af[mt], bf[nt]);
        }
    }

    float* C = multi ? (bz == 0 ? C0 : (bz == 1 ? C1 : C2)) : C0;
    __nv_bfloat16* D = multi ? (bz == 0 ? D0 : (bz == 1 ? D1 : D2)) : D0;
    int batch4 = (mode == 4) ? (by * 128) / tokmask : 0;
    const float* TB4 = (mode == 4) ? (bz == 0 ? P1 : (bz == 1 ? P2 : bias)) : nullptr;
    const __nv_bfloat16* P1h = (const __nv_bfloat16*)P1;
    const __nv_bfloat16* P2h = (const __nv_bfloat16*)P2;
#pragma unroll
    for (int mt = 0; mt < 4; mt++) {
        int r0 = by * 128 + wm * 64 + mt * 16 + g;
#pragma unroll
        for (int nt = 0; nt < 4; nt++) {
            int col = bx * 128 + wn * 32 + nt * 8 + tq * 2;
            float b0 = 0.f, b1 = 0.f;
            if (bias && mode != 4) { b0 = bias[col]; b1 = bias[col + 1]; }
#pragma unroll
            for (int h = 0; h < 2; h++) {
                int r = r0 + h * 8;
                float t0 = acc[mt][nt][2*h + 0] + b0;
                float t1 = acc[mt][nt][2*h + 1] + b1;
                size_t i0 = (size_t)r * 256 + col;
                float o0, o1;
                if (mode == 0) {
                    o0 = t0; o1 = t1;
                } else if (mode == 1) {
                    size_t pi = (size_t)(r & tokmask) * 256 + col;
                    o0 = t0 + P1[pi]; o1 = t1 + P1[pi + 1];
                } else if (mode == 2) {
                    __nv_bfloat162 p1 = *(const __nv_bfloat162*)(P1h + i0);
                    __nv_bfloat162 p2 = *(const __nv_bfloat162*)(P2h + i0);
                    float s0 = sigf(t0), s1 = sigf(t1);
                    o0 = s0 * __bfloat162float(p1.x) + (1.f - s0) * __bfloat162float(p2.x);
                    o1 = s1 * __bfloat162float(p1.y) + (1.f - s1) * __bfloat162float(p2.y);
                } else if (mode == 3) {
                    __nv_bfloat162 p1 = *(const __nv_bfloat162*)(P1h + i0);
                    __nv_bfloat162 p2 = *(const __nv_bfloat162*)(P2h + i0);
                    o0 = __bfloat162float(p1.x) + sigf(t0) * __bfloat162float(p2.x);
                    o1 = __bfloat162float(p1.y) + sigf(t1) * __bfloat162float(p2.y);
                } else {
                    float x0 = t0 + TB4[batch4 * 256 + col];
                    float x1 = t1 + TB4[batch4 * 256 + col + 1];
                    if (bz == 0) { o0 = 1.f / (1.f + expf(x0)); o1 = 1.f / (1.f + expf(x1)); }
                    else         { o0 = sigf(x0); o1 = sigf(x1); }
                }
                if (C) *(float2*)(C + i0) = make_float2(o0, o1);
                if (D) *(__nv_bfloat162*)(D + i0) = __floats2bfloat162_rn(o0, o1);
            }
        }
    }
}

// ---------- column-mean stage A (fp32 input, global branch) ----------
__global__ void k_colmean_a(const float* __restrict__ U, float* __restrict__ part16, int chunk) {
    int j = blockIdx.x, b = blockIdx.y, c = threadIdx.x;
    const float* p = U + ((size_t)(b * gridDim.x + j) * chunk) * CDIM + c;
    float s0 = 0.f, s1 = 0.f, s2 = 0.f, s3 = 0.f;
    for (int t = 0; t < chunk; t += 4) {
        s0 += p[(size_t)t * CDIM];
        s1 += p[(size_t)(t + 1) * CDIM];
        s2 += p[(size_t)(t + 2) * CDIM];
        s3 += p[(size_t)(t + 3) * CDIM];
    }
    part16[(b * 16 + j) * 256 + c] = s0 + s1 + s2 + s3;
}

// ---------- column-mean stage A (bf16 input, fine path) ----------
__global__ void k_colmean_a16(const __nv_bfloat16* __restrict__ U, float* __restrict__ part16,
                              int chunk) {
    int j = blockIdx.x, b = blockIdx.y, c = threadIdx.x;
    const __nv_bfloat16* p = U + ((size_t)(b * gridDim.x + j) * chunk) * CDIM + c;
    float s0 = 0.f, s1 = 0.f, s2 = 0.f, s3 = 0.f;
    for (int t = 0; t < chunk; t += 4) {
        s0 += __bfloat162float(p[(size_t)t * CDIM]);
        s1 += __bfloat162float(p[(size_t)(t + 1) * CDIM]);
        s2 += __bfloat162float(p[(size_t)(t + 2) * CDIM]);
        s3 += __bfloat162float(p[(size_t)(t + 3) * CDIM]);
    }
    part16[(b * 16 + j) * 256 + c] = s0 + s1 + s2 + s3;
}

// ---------- fused mean reduce + layernorm ----------
__global__ void k_ctx(const float* __restrict__ part16, float inv,
                      const float* __restrict__ g, const float* __restrict__ be,
                      float* __restrict__ cln) {
    int b = blockIdx.x, c = threadIdx.x;
    __shared__ float red[256];
    float m = 0.f;
    for (int j = 0; j < 16; j++) m += part16[(b * 16 + j) * 256 + c];
    m *= inv;
    red[c] = m; __syncthreads();
    for (int s = 128; s > 0; s >>= 1) { if (c < s) red[c] += red[c + s]; __syncthreads(); }
    float mu = red[0] * (1.f / 256.f); __syncthreads();
    float d = m - mu;
    red[c] = d * d; __syncthreads();
    for (int s = 128; s > 0; s >>= 1) { if (c < s) red[c] += red[c + s]; __syncthreads(); }
    float var = red[0] * (1.f / 256.f);
    cln[b * 256 + c] = d * rsqrtf(var + LN_EPS) * g[c] + be[c];
}

// ---------- per-batch gate bias tables ----------
__global__ void k_gatebias(const float* __restrict__ cln,
                           const float* __restrict__ Wf, const float* __restrict__ bf,
                           const float* __restrict__ Ww, const float* __restrict__ bw,
                           const float* __restrict__ Wo, const float* __restrict__ bo,
                           float* __restrict__ fb, float* __restrict__ wb, float* __restrict__ ob) {
    int which = blockIdx.x, b = blockIdx.y, c = threadIdx.x;
    __shared__ float sc[256];
    sc[c] = cln[b * 256 + c]; __syncthreads();
    const float* W  = (which == 0) ? Wf : (which == 1) ? Ww : Wo;
    const float* bi = (which == 0) ? bf : (which == 1) ? bw : bo;
    float* o        = (which == 0) ? fb : (which == 1) ? wb : ob;
    float acc = bi[c];
    for (int k = 0; k < 256; k++) acc += sc[k] * W[(size_t)(256 + k) * 256 + c];
    o[b * 256 + c] = acc;
}

// ---------- scan phase 1 (bf16 inputs) ----------
__global__ void k_scan1(const __nv_bfloat16* __restrict__ GA, const __nv_bfloat16* __restrict__ GB,
                        const __nv_bfloat16* __restrict__ U,
                        float* __restrict__ AGA, float* __restrict__ ABF, float* __restrict__ ABB) {
    int j = blockIdx.x, b = blockIdx.y, c = threadIdx.x;
    size_t base = ((size_t)b * NTOK + j * 128) * CDIM + c;
    float A = 1.f, sf = 0.f;
    for (int t = 0; t < 128; t++) {
        size_t i = base + (size_t)t * CDIM;
        float a = __bfloat162float(GA[i]);
        float bb = (1.f - a) * __bfloat162float(GB[i]) * __bfloat162float(U[i]);
        A *= a; sf = a * sf + bb;
    }
    float sb = 0.f;
    for (int t = 127; t >= 0; t--) {
        size_t i = base + (size_t)t * CDIM;
        float a = __bfloat162float(GA[i]);
        float bb = (1.f - a) * __bfloat162float(GB[i]) * __bfloat162float(U[i]);
        sb = a * sb + bb;
    }
    int o = (b * 32 + j) * 256 + c;
    AGA[o] = A; ABF[o] = sf; ABB[o] = sb;
}

// ---------- scan phase 2 ----------
__global__ void k_scan2(const float* __restrict__ AGA, const float* __restrict__ ABF,
                        const float* __restrict__ ABB, float* __restrict__ SIF, float* __restrict__ SIB) {
    int b = blockIdx.x, c = threadIdx.x;
    float s = 0.f;
    for (int j = 0; j < 32; j++) {
        int o = (b * 32 + j) * 256 + c;
        SIF[o] = s; s = AGA[o] * s + ABF[o];
    }
    s = 0.f;
    for (int j = 31; j >= 0; j--) {
        int o = (b * 32 + j) * 256 + c;
        SIB[o] = s; s = AGA[o] * s + ABB[o];
    }
}

// ---------- scan phase 3 (bf16 in/out) ----------
__global__ void k_scan3(const __nv_bfloat16* __restrict__ GA, const __nv_bfloat16* __restrict__ GB,
                        const __nv_bfloat16* __restrict__ GO, const __nv_bfloat16* __restrict__ U,
                        const float* __restrict__ SIF, const float* __restrict__ SIB,
                        __nv_bfloat16* __restrict__ YF16, __nv_bfloat16* __restrict__ YB16) {
    int j = blockIdx.x, b = blockIdx.y, c = threadIdx.x;
    size_t base = ((size_t)b * NTOK + j * 128) * CDIM + c;
    int ao = (b * 32 + j) * 256 + c;
    float s = SIF[ao];
    for (int t = 0; t < 128; t++) {
        size_t i = base + (size_t)t * CDIM;
        float a = __bfloat162float(GA[i]);
        float u = __bfloat162float(U[i]);
        float bb = (1.f - a) * __bfloat162float(GB[i]) * u;
        s = a * s + bb;
        float o = __bfloat162float(GO[i]);
        YF16[i] = __float2bfloat16_rn(o * s + (1.f - o) * u);
    }
    s = SIB[ao];
    for (int t = 127; t >= 0; t--) {
        size_t i = base + (size_t)t * CDIM;
        float a = __bfloat162float(GA[i]);
        float u = __bfloat162float(U[i]);
        float bb = (1.f - a) * __bfloat162float(GB[i]) * u;
        s = a * s + bb;
        float o = __bfloat162float(GO[i]);
        YB16[i] = __float2bfloat16_rn(o * s + (1.f - o) * u);
    }
}

// ---------- global branch serial scan ----------
__global__ void k_scanglob(const float* __restrict__ GA, const float* __restrict__ GB,
                           const float* __restrict__ GO, const float* __restrict__ U,
                           float* __restrict__ YG) {
    int b = blockIdx.x, c = threadIdx.x;
    size_t base = (size_t)b * NTOKG * CDIM + c;
    float s = 0.f;
    for (int t = 0; t < NTOKG; t++) {
        size_t i = base + (size_t)t * CDIM;
        float a = GA[i], u = U[i];
        float bb = (1.f - a) * GB[i] * u;
        s = a * s + bb;
        float o = GO[i];
        YG[i] = o * s + (1.f - o) * u;
    }
}

// ---------- 4x4 avg pool (bf16 input) ----------
__global__ void k_pool(const __nv_bfloat16* __restrict__ seq16, float* __restrict__ seqg) {
    int tg = blockIdx.x, b = blockIdx.y, c = threadIdx.x;
    int gh = tg / 16, gw = tg % 16;
    float s = 0.f;
#pragma unroll
    for (int i = 0; i < 4; i++)
#pragma unroll
        for (int j = 0; j < 4; j++)
            s += __bfloat162float(seq16[((size_t)b * NTOK + (gh * 4 + i) * 64 + gw * 4 + j) * CDIM + c]);
    seqg[((size_t)b * NTOKG + tg) * CDIM + c] = s * (1.0f / 16.0f);
}

// ---------- bilinear upsample (bf16 output only) ----------
__global__ void k_upsample(const float* __restrict__ YG, __nv_bfloat16* __restrict__ YGS16) {
    int t = blockIdx.x, b = blockIdx.y, c = threadIdx.x;
    int oh = t / 64, ow = t % 64;
    float sy = (oh + 0.5f) * 0.25f - 0.5f;
    float sx = (ow + 0.5f) * 0.25f - 0.5f;
    int y0 = (int)floorf(sy); float fy = sy - y0;
    int x0 = (int)floorf(sx); float fx = sx - x0;
    int y0c = clampi(y0, 0, 15), y1c = clampi(y0 + 1, 0, 15);
    int x0c = clampi(x0, 0, 15), x1c = clampi(x0 + 1, 0, 15);
    const float* base = YG + (size_t)b * NTOKG * CDIM + c;
    float v00 = base[(size_t)(y0c * 16 + x0c) * CDIM];
    float v01 = base[(size_t)(y0c * 16 + x1c) * CDIM];
    float v10 = base[(size_t)(y1c * 16 + x0c) * CDIM];
    float v11 = base[(size_t)(y1c * 16 + x1c) * CDIM];
    float v = (1.f - fy) * ((1.f - fx) * v00 + fx * v01) + fy * ((1.f - fx) * v10 + fx * v11);
    YGS16[((size_t)b * NTOK + t) * CDIM + c] = __float2bfloat16_rn(v);
}

// ---------- depthwise 3x3 conv, sliding window (bf16 in/out) ----------
__global__ void k_dwconv(const __nv_bfloat16* __restrict__ seq16, const float* __restrict__ w,
                         const float* __restrict__ bias, __nv_bfloat16* __restrict__ VM16) {
    int h = blockIdx.x, b = blockIdx.y, c = threadIdx.x;
    float wr[9];
#pragma unroll
    for (int k = 0; k < 9; k++) wr[k] = w[c * 9 + k];
    float bi = bias[c];
    const __nv_bfloat16* sp = seq16 + (size_t)b * NTOK * CDIM + c;
    bool h0ok = (h - 1) >= 0, h2ok = (h + 1) < 64;
    size_t r0 = (size_t)(h - 1) * 64, r1 = (size_t)h * 64, r2 = (size_t)(h + 1) * 64;
    float m0 = 0.f, m1 = 0.f, m2 = 0.f;
    float c0 = h0ok ? __bfloat162float(sp[(r0 + 0) * CDIM]) : 0.f;
    float c1 = __bfloat162float(sp[(r1 + 0) * CDIM]);
    float c2 = h2ok ? __bfloat162float(sp[(r2 + 0) * CDIM]) : 0.f;
    float n0 = h0ok ? __bfloat162float(sp[(r0 + 1) * CDIM]) : 0.f;
    float n1 = __bfloat162float(sp[(r1 + 1) * CDIM]);
    float n2 = h2ok ? __bfloat162float(sp[(r2 + 1) * CDIM]) : 0.f;
    size_t obase = ((size_t)b * NTOK + (size_t)h * 64) * CDIM + c;
    for (int x = 0; x < 64; x++) {
        float acc = bi
            + wr[0] * m0 + wr[1] * c0 + wr[2] * n0
            + wr[3] * m1 + wr[4] * c1 + wr[5] * n1
            + wr[6] * m2 + wr[7] * c2 + wr[8] * n2;
        VM16[obase + (size_t)x * CDIM] = __float2bfloat16_rn(acc);
        m0 = c0; m1 = c1; m2 = c2;
        c0 = n0; c1 = n1; c2 = n2;
        if (x + 2 < 64) {
            n0 = h0ok ? __bfloat162float(sp[(r0 + x + 2) * CDIM]) : 0.f;
            n1 = __bfloat162float(sp[(r1 + x + 2) * CDIM]);
            n2 = h2ok ? __bfloat162float(sp[(r2 + x + 2) * CDIM]) : 0.f;
        } else { n0 = n1 = n2 = 0.f; }
    }
}

extern "C" void kernel_launch(void* const* d_in, const int* in_sizes, int n_in,
                              void* d_out, int out_size) {
    const float* x        = (const float*)d_in[0];
    const float* Wt       = (const float*)d_in[1];
    const float* bt       = (const float*)d_in[2];
    const float* pos_fine = (const float*)d_in[3];
    const float* pos_glob = (const float*)d_in[4];
    const float* ln_g     = (const float*)d_in[5];
    const float* ln_b     = (const float*)d_in[6];
    const float* Wf       = (const float*)d_in[7];
    const float* bf       = (const float*)d_in[8];
    const float* Ww       = (const float*)d_in[9];
    const float* bw       = (const float*)d_in[10];
    const float* Wo       = (const float*)d_in[11];
    const float* bo       = (const float*)d_in[12];
    const float* Wr       = (const float*)d_in[13];
    const float* br       = (const float*)d_in[14];
    const float* Wgi      = (const float*)d_in[15];
    const float* bgi      = (const float*)d_in[16];
    const float* dw_w     = (const float*)d_in[17];
    const float* dw_b     = (const float*)d_in[18];
    const float* Wl       = (const float*)d_in[19];
    const float* bl       = (const float*)d_in[20];
    const float* Wlf      = (const float*)d_in[21];
    const float* blf      = (const float*)d_in[22];
    const float* Wout     = (const float*)d_in[23];
    const float* bout     = (const float*)d_in[24];
    float* outp = (float*)d_out;

    float* S = nullptr;
    cudaGetSymbolAddress((void**)&S, g_scratch);
    float* PROJ = S + OFF_PROJ;
    float* SEQG = S + OFF_SEQG; float* UG   = S + OFF_UG;
    float* GAG  = S + OFF_GAG;  float* GBG  = S + OFF_GBG;  float* GOG = S + OFF_GOG;
    float* YG   = S + OFF_YG;
    float* POSF = S + OFF_POSF; float* POSG = S + OFF_POSG;
    float* CLN  = S + OFF_CLN;  float* CLNG = S + OFF_CLNG;
    float* FB = S + OFF_FB, *WB = S + OFF_WB, *OB = S + OFF_OB;
    float* FBG = S + OFF_FBG, *WBG = S + OFF_WBG, *OBG = S + OFF_OBG;
    float* AGA = S + OFF_AGA, *ABF = S + OFF_ABF, *ABB = S + OFF_ABB;
    float* SIF = S + OFF_SIF, *SIB = S + OFF_SIB;
    float* P16 = S + OFF_P16;   float* P16G = S + OFF_P16G;
    uint32_t* WBW = (uint32_t*)(S + OFF_WBW);
    __nv_bfloat16* U16   = (__nv_bfloat16*)(S + OFF_U16);
    __nv_bfloat16* YF16  = (__nv_bfloat16*)(S + OFF_YF16);
    __nv_bfloat16* YB16  = (__nv_bfloat16*)(S + OFF_YB16);
    __nv_bfloat16* Y16   = (__nv_bfloat16*)(S + OFF_Y16);
    __nv_bfloat16* YGS16 = (__nv_bfloat16*)(S + OFF_YGS16);
    __nv_bfloat16* V16   = (__nv_bfloat16*)(S + OFF_V16);
    __nv_bfloat16* Z16   = (__nv_bfloat16*)(S + OFF_Z16);
    __nv_bfloat16* SEQ16 = (__nv_bfloat16*)(S + OFF_SEQ16);
    __nv_bfloat16* VM16  = (__nv_bfloat16*)(S + OFF_VM16);
    __nv_bfloat16* UO16  = (__nv_bfloat16*)(S + OFF_UO16);
    __nv_bfloat16* GA16  = (__nv_bfloat16*)(S + OFF_GA16);
    __nv_bfloat16* GB16  = (__nv_bfloat16*)(S + OFF_GB16);
    __nv_bfloat16* GO16  = (__nv_bfloat16*)(S + OFF_GO16);

    uint32_t* WBf  = WBW + (size_t)0    * 256;
    uint32_t* WBw  = WBW + (size_t)128  * 256;
    uint32_t* WBo  = WBW + (size_t)256  * 256;
    uint32_t* WBr0 = WBW + (size_t)384  * 256;
    uint32_t* WBr1 = WBW + (size_t)512  * 256;
    uint32_t* WBr2 = WBW + (size_t)640  * 256;
    uint32_t* WBg0 = WBW + (size_t)768  * 256;
    uint32_t* WBg1 = WBW + (size_t)896  * 256;
    uint32_t* WBg2 = WBW + (size_t)1024 * 256;
    uint32_t* WBl0 = WBW + (size_t)1152 * 256;
    uint32_t* WBl1 = WBW + (size_t)1280 * 256;
    uint32_t* WBt  = WBW + (size_t)1408 * 256;
    uint32_t* WBl  = WBW + (size_t)1536 * 256;
    uint32_t* WBout= WBW + (size_t)1664 * 256;

    static int init_done = 0;
    static cudaStream_t s2, s3;
    static cudaEvent_t ev0, ev1, ev2, ev3;
    int smem_tf = NSTAGE * STAGE_ELEMS * 4;
    int smem_bf = NSTB * BSTG_EL * 4;
    if (!init_done) {
        cudaFuncSetAttribute(k_gemm_tc, cudaFuncAttributeMaxDynamicSharedMemorySize, smem_tf);
        cudaFuncSetAttribute(k_gemm_bf, cudaFuncAttributeMaxDynamicSharedMemorySize, smem_bf);
        cudaStreamCreateWithFlags(&s2, cudaStreamNonBlocking);
        cudaStreamCreateWithFlags(&s3, cudaStreamNonBlocking);
        cudaEventCreateWithFlags(&ev0, cudaEventDisableTiming);
        cudaEventCreateWithFlags(&ev1, cudaEventDisableTiming);
        cudaEventCreateWithFlags(&ev2, cudaEventDisableTiming);
        cudaEventCreateWithFlags(&ev3, cudaEventDisableTiming);
        init_done = 1;
    }

    dim3 tb(32, 8);
    dim3 tg(128, 8, 8);
    dim3 gemF(2, MFINE / 128), gemG(2, MGLOB / 128);
    dim3 gemG3(2, MGLOB / 128, 3), gemF3(2, MFINE / 128, 3);
    const float* NP = nullptr;
    float* NPo = nullptr;
    __nv_bfloat16* NPh = nullptr;
    const __nv_bfloat16* NPhc = nullptr;
    const uint32_t* NPw = nullptr;

    // prep: transpose (both paths), posdown (global), then fork
    k_transpose<<<tg, tb>>>(x, SEQ16);
    k_posdown<<<256, 256>>>(pos_glob, POSG);
    cudaEventRecord(ev0, 0);

    // ---- global branch on s2 ----
    cudaStreamWaitEvent(s2, ev0, 0);
    k_pool<<<dim3(256, BATCH), 256, 0, s2>>>(SEQ16, SEQG);
    k_gemm_tc<<<gemG, 256, smem_tf, s2>>>(SEQG, Wt, NP, NP, NP, NP, 1, UG, NPo, NPo, bt, 1, POSG, NP, 255, 0, NPh);
    k_colmean_a<<<dim3(16, BATCH), 256, 0, s2>>>(UG, P16G, 16);
    k_ctx<<<BATCH, 256, 0, s2>>>(P16G, 1.0f / NTOKG, ln_g, ln_b, CLNG);
    k_gatebias<<<dim3(3, BATCH), 256, 0, s2>>>(CLNG, Wf, bf, Ww, bw, Wo, bo, FBG, WBG, OBG);
    k_gemm_tc<<<gemG3, 256, smem_tf, s2>>>(UG, Wf, NP, Ww, NP, Wo, 1, GAG, GBG, GOG, OBG, 4, FBG, WBG, NTOKG, 1, NPh);
    k_scanglob<<<BATCH, 256, 0, s2>>>(GAG, GBG, GOG, UG, YG);
    k_upsample<<<dim3(4096, BATCH), 256, 0, s2>>>(YG, YGS16);
    cudaEventRecord(ev1, s2);

    // ---- local branch on s3 (dwconv now; V-GEMM after weights ready) ----
    cudaStreamWaitEvent(s3, ev0, 0);
    k_dwconv<<<dim3(64, BATCH), 256, 0, s3>>>(SEQ16, dw_w, dw_b, VM16);

    // ---- fine path on stream 0 ----
    k_wcvt<<<1792, 256>>>(Wf, Ww, Wo, Wr, Wgi, Wlf, Wt, Wl, Wout, WBW);
    k_posup<<<4096, 256>>>(pos_fine, POSF, 64, 64);
    cudaEventRecord(ev3, 0);

    // V-GEMM on s3 (needs WBl from wcvt)
    cudaStreamWaitEvent(s3, ev3, 0);
    k_gemm_bf<<<gemF, 256, smem_bf, s3>>>(VM16, WBl, NPhc, NPw, NPhc, NPw, 1, NPo, NPo, NPo, bl, 0, NP, NP, 0, 0, V16, NPh, NPh);
    cudaEventRecord(ev2, s3);

    // U = SEQ@Wt + bt + pos -> U16
    k_gemm_bf<<<gemF, 256, smem_bf>>>(SEQ16, WBt, NPhc, NPw, NPhc, NPw, 1, NPo, NPo, NPo, bt, 1, POSF, NP, 4095, 0, U16, NPh, NPh);

    // gates: mode 4 -> bf16 mirrors
    k_colmean_a16<<<dim3(16, BATCH), 256>>>(U16, P16, 256);
    k_ctx<<<BATCH, 256>>>(P16, 1.0f / NTOK, ln_g, ln_b, CLN);
    k_gatebias<<<dim3(3, BATCH), 256>>>(CLN, Wf, bf, Ww, bw, Wo, bo, FB, WB, OB);
    k_gemm_bf<<<gemF3, 256, smem_bf>>>(U16, WBf, NPhc, WBw, NPhc, WBo, 1, NPo, NPo, NPo, OB, 4, FB, WB, NTOK, 1, GA16, GB16, GO16);

    // bidirectional chunked scan
    k_scan1<<<dim3(32, BATCH), 256>>>(GA16, GB16, U16, AGA, ABF, ABB);
    k_scan2<<<BATCH, 256>>>(AGA, ABF, ABB, SIF, SIB);
    k_scan3<<<dim3(32, BATCH), 256>>>(GA16, GB16, GO16, U16, SIF, SIB, YF16, YB16);

    // rho mixing -> Y16
    k_gemm_bf<<<gemF, 256, smem_bf>>>(U16, WBr0, YF16, WBr1, YB16, WBr2, 3, NPo, NPo, NPo, br, 2,
                                      (const float*)YF16, (const float*)YB16, 0, 0, Y16, NPh, NPh);

    // join global branch; lam mixing -> Z16
    cudaStreamWaitEvent(0, ev1, 0);
    k_gemm_bf<<<gemF, 256, smem_bf>>>(Y16, WBg0, YGS16, WBg1, U16, WBg2, 3, NPo, NPo, NPo, bgi, 3,
                                      (const float*)Y16, (const float*)YGS16, 0, 0, Z16, NPh, NPh);

    // join local branch; eta -> UO16
    cudaStreamWaitEvent(0, ev2, 0);
    k_gemm_bf<<<gemF, 256, smem_bf>>>(V16, WBl0, Z16, WBl1, NPhc, NPw, 2, NPo, NPo, NPo, blf, 2,
                                      (const float*)V16, (const float*)Z16, 0, 0, UO16, NPh, NPh);

    // output proj + residual
    k_gemm_bf<<<gemF, 256, smem_bf>>>(UO16, WBout, NPhc, NPw, NPhc, NPw, 1, PROJ, NPo, NPo, bout, 0, NP, NP, 0, 0, NPh, NPh, NPh);
    k_output<<<tg, tb>>>(PROJ, x, outp);
}

// round 15
// speedup vs baseline: 5.6012x; 1.0117x over previous
#include <cuda_runtime.h>
#include <cuda_bf16.h>
#include <math.h>
#include <stdint.h>

#define BATCH 8
#define CDIM  256
#define NTOK  4096
#define NTOKG 256
#define MFINE 32768
#define MGLOB 2048
#define LN_EPS 1e-5f

static const size_t U_SZ  = (size_t)MFINE * CDIM;
static const size_t H_SZ  = U_SZ / 2;
static const size_t SG_SZ = (size_t)MGLOB * CDIM;

static const size_t OFF_PROJ  = 0*U_SZ;
static const size_t SMALL0    = 1*U_SZ;
static const size_t OFF_SEQG  = SMALL0 + 0*SG_SZ;
static const size_t OFF_UG    = SMALL0 + 1*SG_SZ;
static const size_t OFF_GAG   = SMALL0 + 2*SG_SZ;
static const size_t OFF_GBG   = SMALL0 + 3*SG_SZ;
static const size_t OFF_GOG   = SMALL0 + 4*SG_SZ;
static const size_t OFF_YG    = SMALL0 + 5*SG_SZ;
static const size_t SMALL1    = SMALL0 + 6*SG_SZ;
static const size_t OFF_POSF  = SMALL1;
static const size_t OFF_POSG  = OFF_POSF + 4096*256;
static const size_t OFF_CLN   = OFF_POSG + 65536;
static const size_t OFF_CLNG  = OFF_CLN + 2048;
static const size_t OFF_FB    = OFF_CLNG + 2048;
static const size_t OFF_WB    = OFF_FB + 2048;
static const size_t OFF_OB    = OFF_WB + 2048;
static const size_t OFF_FBG   = OFF_OB + 2048;
static const size_t OFF_WBG   = OFF_FBG + 2048;
static const size_t OFF_OBG   = OFF_WBG + 2048;
static const size_t OFF_AGA   = OFF_OBG + 2048;
static const size_t OFF_ABF   = OFF_AGA + 65536;
static const size_t OFF_ABB   = OFF_ABF + 65536;
static const size_t OFF_SIF   = OFF_ABB + 65536;
static const size_t OFF_SIB   = OFF_SIF + 65536;
static const size_t OFF_P16   = OFF_SIB + 65536;
static const size_t OFF_P16G  = OFF_P16 + 32768;
static const size_t OFF_MSEQ  = OFF_P16G + 32768;          // 8*256
static const size_t OFF_PART  = OFF_MSEQ + 2048;           // 8*256
static const size_t OFF_WBW   = OFF_PART + 2048;           // bf16x2 weights: 1792*256 u32
static const size_t OFF_U16   = OFF_WBW + 458752;
static const size_t OFF_YF16  = OFF_U16  + H_SZ;
static const size_t OFF_YB16  = OFF_YF16 + H_SZ;
static const size_t OFF_Y16   = OFF_YB16 + H_SZ;
static const size_t OFF_YGS16 = OFF_Y16  + H_SZ;
static const size_t OFF_V16   = OFF_YGS16+ H_SZ;
static const size_t OFF_Z16   = OFF_V16  + H_SZ;
static const size_t OFF_SEQ16 = OFF_Z16  + H_SZ;
static const size_t OFF_VM16  = OFF_SEQ16+ H_SZ;
static const size_t OFF_UO16  = OFF_VM16 + H_SZ;
static const size_t OFF_GA16  = OFF_UO16 + H_SZ;
static const size_t OFF_GB16  = OFF_GA16 + H_SZ;
static const size_t OFF_GO16  = OFF_GB16 + H_SZ;
static const size_t TOTAL_SCRATCH = OFF_GO16 + H_SZ + 1024;

__device__ __align__(16) float g_scratch[TOTAL_SCRATCH];

__device__ __forceinline__ float sigf(float x) { return 1.0f / (1.0f + expf(-x)); }
__device__ __forceinline__ int clampi(int v, int lo, int hi) { return v < lo ? lo : (v > hi ? hi : v); }

__device__ __forceinline__ void mma_tf32(float* c, const uint32_t* a, const uint32_t* b) {
    asm volatile(
        "mma.sync.aligned.m16n8k8.row.col.f32.tf32.tf32.f32 "
        "{%0,%1,%2,%3}, {%4,%5,%6,%7}, {%8,%9}, {%0,%1,%2,%3};\n"
        : "+f"(c[0]), "+f"(c[1]), "+f"(c[2]), "+f"(c[3])
        : "r"(a[0]), "r"(a[1]), "r"(a[2]), "r"(a[3]), "r"(b[0]), "r"(b[1]));
}
__device__ __forceinline__ void mma_bf16(float* c, const uint32_t* a, const uint32_t* b) {
    asm volatile(
        "mma.sync.aligned.m16n8k16.row.col.f32.bf16.bf16.f32 "
        "{%0,%1,%2,%3}, {%4,%5,%6,%7}, {%8,%9}, {%0,%1,%2,%3};\n"
        : "+f"(c[0]), "+f"(c[1]), "+f"(c[2]), "+f"(c[3])
        : "r"(a[0]), "r"(a[1]), "r"(a[2]), "r"(a[3]), "r"(b[0]), "r"(b[1]));
}
__device__ __forceinline__ void ldsm4(uint32_t* r, uint32_t saddr) {
    asm volatile("ldmatrix.sync.aligned.m8n8.x4.shared.b16 {%0,%1,%2,%3}, [%4];"
        : "=r"(r[0]), "=r"(r[1]), "=r"(r[2]), "=r"(r[3]) : "r"(saddr));
}

__device__ __forceinline__ void cpa16(uint32_t dst, const void* src) {
    asm volatile("cp.async.cg.shared.global [%0], [%1], 16;" :: "r"(dst), "l"(src));
}
#define CP_COMMIT() asm volatile("cp.async.commit_group;")
#define CP_WAIT1()  asm volatile("cp.async.wait_group 1;")
#define CP_WAIT2()  asm volatile("cp.async.wait_group 2;")

__device__ __forceinline__ const float* selp(const float* a0, const float* a1,
                                             const float* a2, int p) {
    return p == 0 ? a0 : (p == 1 ? a1 : a2);
}
__device__ __forceinline__ const __nv_bfloat16* selh(const __nv_bfloat16* a0,
                                                     const __nv_bfloat16* a1,
                                                     const __nv_bfloat16* a2, int p) {
    return p == 0 ? a0 : (p == 1 ? a1 : a2);
}
__device__ __forceinline__ const uint32_t* selw(const uint32_t* a0, const uint32_t* a1,
                                                const uint32_t* a2, int p) {
    return p == 0 ? a0 : (p == 1 ? a1 : a2);
}

// ---------- x [B,C,4096] -> seq16 [B*4096, C] ----------
__global__ void k_transpose(const float* __restrict__ x, __nv_bfloat16* __restrict__ seq16) {
    __shared__ float tile[32][33];
    int b = blockIdx.z;
    int t0 = blockIdx.x * 32, c0 = blockIdx.y * 32;
    int tx = threadIdx.x, ty = threadIdx.y;
    const float* src = x + (size_t)b * CDIM * NTOK;
#pragma unroll
    for (int j = 0; j < 4; j++)
        tile[ty + 8*j][tx] = src[(size_t)(c0 + ty + 8*j) * NTOK + t0 + tx];
    __syncthreads();
    __nv_bfloat16* dsth = seq16 + (size_t)b * NTOK * CDIM;
#pragma unroll
    for (int j = 0; j < 4; j++) {
        float v = tile[tx][ty + 8*j];
        dsth[(size_t)(t0 + ty + 8*j) * CDIM + c0 + tx] = __float2bfloat16_rn(v);
    }
}

// ---------- per-(b,c) mean of x over tokens (channel-major: coalesced) ----------
__global__ void k_meanx(const float* __restrict__ x, float* __restrict__ meanseq) {
    int c = blockIdx.x, b = blockIdx.y, t = threadIdx.x;
    const float* p = x + ((size_t)b * CDIM + c) * NTOK;
    float s = 0.f;
    for (int i = t; i < NTOK; i += 256) s += p[i];
    __shared__ float red[256];
    red[t] = s; __syncthreads();
    for (int st = 128; st > 0; st >>= 1) { if (t < st) red[t] += red[t + st]; __syncthreads(); }
    if (t == 0) meanseq[b * CDIM + c] = red[0] * (1.0f / NTOK);
}

// ---------- part[b][c] = meanseq[b]@Wt + bt + mean(pos) ----------
__global__ void k_part(const float* __restrict__ meanseq, const float* __restrict__ Wt,
                       const float* __restrict__ bt, const float* __restrict__ pospart,
                       float* __restrict__ part) {
    int b = blockIdx.x, c = threadIdx.x;
    __shared__ float sm[256];
    sm[c] = meanseq[b * 256 + c]; __syncthreads();
    float acc = bt[c];
    for (int k = 0; k < 256; k++) acc += sm[k] * Wt[(size_t)k * 256 + c];
    float mp = 0.f;
    for (int j = 0; j < 16; j++) mp += pospart[j * 256 + c];
    part[b * 256 + c] = acc + mp * (1.0f / NTOK);
}

// ---------- layernorm over channels of a [B,256] mean ----------
__global__ void k_ln(const float* __restrict__ part, const float* __restrict__ g,
                     const float* __restrict__ be, float* __restrict__ cln) {
    int b = blockIdx.x, c = threadIdx.x;
    __shared__ float red[256];
    float m = part[b * 256 + c];
    red[c] = m; __syncthreads();
    for (int s = 128; s > 0; s >>= 1) { if (c < s) red[c] += red[c + s]; __syncthreads(); }
    float mu = red[0] * (1.f / 256.f); __syncthreads();
    float d = m - mu;
    red[c] = d * d; __syncthreads();
    for (int s = 128; s > 0; s >>= 1) { if (c < s) red[c] += red[c + s]; __syncthreads(); }
    float var = red[0] * (1.f / 256.f);
    cln[b * 256 + c] = d * rsqrtf(var + LN_EPS) * g[c] + be[c];
}

// ---------- proj [B,4096,C] + x -> out [B,C,4096] ----------
__global__ void k_output(const float* __restrict__ proj, const float* __restrict__ x,
                         float* __restrict__ outp) {
    __shared__ float tile[32][33];
    int b = blockIdx.z;
    int t0 = blockIdx.x * 32, c0 = blockIdx.y * 32;
    int tx = threadIdx.x, ty = threadIdx.y;
    const float* src = proj + (size_t)b * NTOK * CDIM;
#pragma unroll
    for (int j = 0; j < 4; j++)
        tile[ty + 8*j][tx] = src[(size_t)(t0 + ty + 8*j) * CDIM + c0 + tx];
    __syncthreads();
    size_t base = (size_t)b * CDIM * NTOK;
#pragma unroll
    for (int j = 0; j < 4; j++) {
        size_t o = base + (size_t)(c0 + ty + 8*j) * NTOK + t0 + tx;
        outp[o] = x[o] + tile[tx][ty + 8*j];
    }
}

// ---------- pos bilinear upsample ----------
__global__ void k_posup(const float* __restrict__ pos, float* __restrict__ outp, int OH, int OW) {
    int t = blockIdx.x, c = threadIdx.x;
    int oh = t / OW, ow = t % OW;
    float sy = (oh + 0.5f) * (32.0f / OH) - 0.5f;
    float sx = (ow + 0.5f) * (32.0f / OW) - 0.5f;
    int y0 = (int)floorf(sy); float fy = sy - y0;
    int x0 = (int)floorf(sx); float fx = sx - x0;
    int y0c = clampi(y0, 0, 31), y1c = clampi(y0 + 1, 0, 31);
    int x0c = clampi(x0, 0, 31), x1c = clampi(x0 + 1, 0, 31);
    const float* p = pos + (size_t)c * 1024;
    float v = (1.f - fy) * ((1.f - fx) * p[y0c*32 + x0c] + fx * p[y0c*32 + x1c])
            + fy * ((1.f - fx) * p[y1c*32 + x0c] + fx * p[y1c*32 + x1c]);
    outp[(size_t)t * CDIM + c] = v;
}

// ---------- pos antialiased downsample 32->16 ----------
__global__ void k_posdown(const float* __restrict__ pos, float* __restrict__ outp) {
    int t = blockIdx.x, c = threadIdx.x;
    int gh = t / 16, gw = t % 16;
    const float W4[4] = {0.125f, 0.375f, 0.375f, 0.125f};
    float wy[4], wx[4]; int ky[4], kx[4];
    float sy = 0.f, sx = 0.f;
#pragma unroll
    for (int d = 0; d < 4; d++) {
        ky[d] = 2*gh - 1 + d; wy[d] = (ky[d] >= 0 && ky[d] < 32) ? W4[d] : 0.f; sy += wy[d];
        kx[d] = 2*gw - 1 + d; wx[d] = (kx[d] >= 0 && kx[d] < 32) ? W4[d] : 0.f; sx += wx[d];
    }
    const float* p = pos + (size_t)c * 1024;
    float acc = 0.f;
#pragma unroll
    for (int d = 0; d < 4; d++) {
        if (wy[d] == 0.f) continue;
        float rowacc = 0.f;
#pragma unroll
        for (int e = 0; e < 4; e++)
            if (wx[e] != 0.f) rowacc += wx[e] * p[ky[d]*32 + kx[e]];
        acc += wy[d] * rowacc;
    }
    outp[(size_t)t * CDIM + c] = acc / (sy * sx);
}

// ---------- weight interleave ----------
__global__ void k_wcvt(const float* __restrict__ Wf, const float* __restrict__ Ww,
                       const float* __restrict__ Wo, const float* __restrict__ Wr,
                       const float* __restrict__ Wgi, const float* __restrict__ Wlf,
                       const float* __restrict__ Wt, const float* __restrict__ Wl,
                       const float* __restrict__ Wout, uint32_t* __restrict__ WB) {
    int r = blockIdx.x, c = threadIdx.x;
    const float* src; int k2;
    if (r < 128)       { src = Wf;   k2 = r; }
    else if (r < 256)  { src = Ww;   k2 = r - 128; }
    else if (r < 384)  { src = Wo;   k2 = r - 256; }
    else if (r < 768)  { src = Wr;   k2 = r - 384; }
    else if (r < 1152) { src = Wgi;  k2 = r - 768; }
    else if (r < 1408) { src = Wlf;  k2 = r - 1152; }
    else if (r < 1536) { src = Wt;   k2 = r - 1408; }
    else if (r < 1664) { src = Wl;   k2 = r - 1536; }
    else               { src = Wout; k2 = r - 1664; }
    float lo = src[(size_t)(2*k2) * 256 + c];
    float hi = src[(size_t)(2*k2 + 1) * 256 + c];
    __nv_bfloat162 p2 = __floats2bfloat162_rn(lo, hi);
    WB[(size_t)r * 256 + c] = *(uint32_t*)&p2;
}

// ================= tf32 mma.sync GEMM (global branch only) =================
#define AS_STRIDE 36
#define BS_STRIDE 136
#define A_ELEMS (128*AS_STRIDE)
#define B_ELEMS (32*BS_STRIDE)
#define STAGE_ELEMS (A_ELEMS + B_ELEMS)
#define NSTAGE 3
extern __shared__ float smx[];

__global__ void __launch_bounds__(256, 2)
k_gemm_tc(const float* __restrict__ A0, const float* __restrict__ W0,
          const float* __restrict__ A1, const float* __restrict__ W1,
          const float* __restrict__ A2, const float* __restrict__ W2,
          int npairs,
          float* __restrict__ C0, float* __restrict__ C1, float* __restrict__ C2,
          const float* __restrict__ bias, int mode,
          const float* __restrict__ P1, const float* __restrict__ P2,
          int tokmask, int multi, __nv_bfloat16* __restrict__ D0) {
    int bx = blockIdx.x, by = blockIdx.y, bz = blockIdx.z;
    int tid = threadIdx.x;
    int warp = tid >> 5, lane = tid & 31;
    int wm = warp >> 2, wn = warp & 3;
    int g = lane >> 2, tq = lane & 3;

    uint32_t smem_u32 = (uint32_t)__cvta_generic_to_shared(smx);

    float acc[4][4][4];
#pragma unroll
    for (int i = 0; i < 4; i++)
#pragma unroll
        for (int j = 0; j < 4; j++)
#pragma unroll
            for (int r = 0; r < 4; r++) acc[i][j][r] = 0.f;

    int nst = (multi ? 1 : npairs) * 8;

    auto load_stage = [&](int st, int buf) {
        int p = multi ? bz : (st >> 3);
        const float* A = multi ? A0 : selp(A0, A1, A2, p);
        const float* W = selp(W0, W1, W2, p);
        int k0 = (st & 7) * 32;
        uint32_t abase = smem_u32 + (uint32_t)(buf * STAGE_ELEMS) * 4u;
        uint32_t bbase = abase + (uint32_t)A_ELEMS * 4u;
#pragma unroll
        for (int i = 0; i < 4; i++) {
            int idx = tid + 256 * i;
            int row = idx >> 3, c4 = idx & 7;
            cpa16(abase + (uint32_t)(row * AS_STRIDE + c4 * 4) * 4u,
                  A + (size_t)(by * 128 + row) * 256 + k0 + c4 * 4);
        }
#pragma unroll
        for (int i = 0; i < 4; i++) {
            int idx = tid + 256 * i;
            int row = idx >> 5, c4 = idx & 31;
            cpa16(bbase + (uint32_t)(row * BS_STRIDE + c4 * 4) * 4u,
                  W + (size_t)(k0 + row) * 256 + bx * 128 + c4 * 4);
        }
        CP_COMMIT();
    };

    load_stage(0, 0);
    load_stage(1, 1);

    for (int st = 0; st < nst; st++) {
        CP_WAIT1();
        __syncthreads();
        int nx = st + NSTAGE - 1;
        if (nx < nst) load_stage(nx, nx % NSTAGE);
        else CP_COMMIT();

        int pb = st % NSTAGE;
        const uint32_t* Asu = (const uint32_t*)(smx + pb * STAGE_ELEMS);
        const uint32_t* Bsu = Asu + A_ELEMS;
#pragma unroll
        for (int ks = 0; ks < 32; ks += 8) {
            uint32_t af[4][4], bf[4][2];
#pragma unroll
            for (int mt = 0; mt < 4; mt++) {
                int mb = wm * 64 + mt * 16;
                af[mt][0] = Asu[(mb + g) * AS_STRIDE + ks + tq];
                af[mt][1] = Asu[(mb + g + 8) * AS_STRIDE + ks + tq];
                af[mt][2] = Asu[(mb + g) * AS_STRIDE + ks + tq + 4];
                af[mt][3] = Asu[(mb + g + 8) * AS_STRIDE + ks + tq + 4];
            }
#pragma unroll
            for (int nt = 0; nt < 4; nt++) {
                int nb = wn * 32 + nt * 8;
                bf[nt][0] = Bsu[(ks + tq) * BS_STRIDE + nb + g];
                bf[nt][1] = Bsu[(ks + tq + 4) * BS_STRIDE + nb + g];
            }
#pragma unroll
            for (int mt = 0; mt < 4; mt++)
#pragma unroll
                for (int nt = 0; nt < 4; nt++)
                    mma_tf32(acc[mt][nt], af[mt], bf[nt]);
        }
    }

    float* C = multi ? (bz == 0 ? C0 : (bz == 1 ? C1 : C2)) : C0;
    int batch4 = (mode == 4) ? (by * 128) / tokmask : 0;
    const float* TB4 = (mode == 4) ? (bz == 0 ? P1 : (bz == 1 ? P2 : bias)) : nullptr;
#pragma unroll
    for (int mt = 0; mt < 4; mt++) {
        int r0 = by * 128 + wm * 64 + mt * 16 + g;
#pragma unroll
        for (int nt = 0; nt < 4; nt++) {
            int col = bx * 128 + wn * 32 + nt * 8 + tq * 2;
            float b0 = 0.f, b1 = 0.f;
            if (bias && mode != 4) { b0 = bias[col]; b1 = bias[col + 1]; }
#pragma unroll
            for (int h = 0; h < 2; h++) {
                int r = r0 + h * 8;
                float t0 = acc[mt][nt][2*h + 0] + b0;
                float t1 = acc[mt][nt][2*h + 1] + b1;
                size_t i0 = (size_t)r * 256 + col;
                float o0, o1;
                if (mode == 0) {
                    o0 = t0; o1 = t1;
                } else if (mode == 1) {
                    size_t pi = (size_t)(r & tokmask) * 256 + col;
                    o0 = t0 + P1[pi]; o1 = t1 + P1[pi + 1];
                } else if (mode == 2) {
                    float s0 = sigf(t0), s1 = sigf(t1);
                    o0 = s0 * P1[i0] + (1.f - s0) * P2[i0];
                    o1 = s1 * P1[i0 + 1] + (1.f - s1) * P2[i0 + 1];
                } else if (mode == 3) {
                    o0 = P1[i0] + sigf(t0) * P2[i0];
                    o1 = P1[i0 + 1] + sigf(t1) * P2[i0 + 1];
                } else {
                    float x0 = t0 + TB4[batch4 * 256 + col];
                    float x1 = t1 + TB4[batch4 * 256 + col + 1];
                    if (bz == 0) { o0 = 1.f / (1.f + expf(x0)); o1 = 1.f / (1.f + expf(x1)); }
                    else         { o0 = sigf(x0); o1 = sigf(x1); }
                }
                if (C) *(float2*)(C + i0) = make_float2(o0, o1);
                if (D0) *(__nv_bfloat162*)((__nv_bfloat16*)D0 + i0) = __floats2bfloat162_rn(o0, o1);
            }
        }
    }
}

// ================= bf16 mma.sync GEMM (all fine GEMMs) =================
#define BA_STR 20
#define BB_STR 136
#define BA_EL (128*BA_STR)
#define BB_EL (16*BB_STR)
#define BSTG_EL (BA_EL + BB_EL)
#define NSTB 4

__global__ void __launch_bounds__(256, 2)
k_gemm_bf(const __nv_bfloat16* __restrict__ A0, const uint32_t* __restrict__ W0,
          const __nv_bfloat16* __restrict__ A1, const uint32_t* __restrict__ W1,
          const __nv_bfloat16* __restrict__ A2, const uint32_t* __restrict__ W2,
          int npairs,
          float* __restrict__ C0, float* __restrict__ C1, float* __restrict__ C2,
          const float* __restrict__ bias, int mode,
          const float* __restrict__ P1, const float* __restrict__ P2,
          int tokmask, int multi,
          __nv_bfloat16* __restrict__ D0, __nv_bfloat16* __restrict__ D1,
          __nv_bfloat16* __restrict__ D2) {
    int bx = blockIdx.x, by = blockIdx.y, bz = blockIdx.z;
    int tid = threadIdx.x;
    int warp = tid >> 5, lane = tid & 31;
    int wm = warp >> 2, wn = warp & 3;
    int g = lane >> 2, tq = lane & 3;

    uint32_t smem_u32 = (uint32_t)__cvta_generic_to_shared(smx);

    float acc[4][4][4];
#pragma unroll
    for (int i = 0; i < 4; i++)
#pragma unroll
        for (int j = 0; j < 4; j++)
#pragma unroll
            for (int r = 0; r < 4; r++) acc[i][j][r] = 0.f;

    int nst = (multi ? 1 : npairs) * 8;

    auto load_stage = [&](int st, int buf) {
        int p = multi ? bz : (st >> 3);
        const __nv_bfloat16* A = multi ? A0 : selh(A0, A1, A2, p);
        const uint32_t* W = selw(W0, W1, W2, p);
        int k0 = (st & 7) * 32;
        int k2b = k0 >> 1;
        uint32_t abase = smem_u32 + (uint32_t)(buf * BSTG_EL) * 4u;
        uint32_t bbase = abase + (uint32_t)BA_EL * 4u;
#pragma unroll
        for (int i = 0; i < 2; i++) {
            int idx = tid + 256 * i;
            int row = idx >> 2, c4 = idx & 3;
            cpa16(abase + (uint32_t)(row * BA_STR + c4 * 4) * 4u,
                  A + (size_t)(by * 128 + row) * 256 + k0 + c4 * 8);
        }
#pragma unroll
        for (int i = 0; i < 2; i++) {
            int idx = tid + 256 * i;
            int row = idx >> 5, c4 = idx & 31;
            cpa16(bbase + (uint32_t)(row * BB_STR + c4 * 4) * 4u,
                  W + (size_t)(k2b + row) * 256 + bx * 128 + c4 * 4);
        }
        CP_COMMIT();
    };

    load_stage(0, 0);
    load_stage(1, 1);
    load_stage(2, 2);

    int lrow = lane & 15;
    uint32_t kside = (uint32_t)((lane >> 4) << 4);

    for (int st = 0; st < nst; st++) {
        CP_WAIT2();
        __syncthreads();
        int nx = st + NSTB - 1;
        if (nx < nst) load_stage(nx, nx % NSTB);
        else CP_COMMIT();

        int pb = st % NSTB;
        uint32_t abyte = smem_u32 + (uint32_t)(pb * BSTG_EL) * 4u;
        const uint32_t* Bsu = (const uint32_t*)(smx + pb * BSTG_EL) + BA_EL;
#pragma unroll
        for (int s = 0; s < 2; s++) {
            int ko = 8 * s;
            uint32_t af[4][4], bf[4][2];
#pragma unroll
            for (int mt = 0; mt < 4; mt++) {
                uint32_t addr = abyte
                    + (uint32_t)((wm * 64 + mt * 16 + lrow) * BA_STR) * 4u
                    + kside + (uint32_t)(s * 32);
                ldsm4(af[mt], addr);
            }
#pragma unroll
            for (int nt = 0; nt < 4; nt++) {
                int nb = wn * 32 + nt * 8;
                bf[nt][0] = Bsu[(ko + tq) * BB_STR + nb + g];
                bf[nt][1] = Bsu[(ko + tq + 4) * BB_STR + nb + g];
            }
#pragma unroll
            for (int mt = 0; mt < 4; mt++)
#pragma unroll
                for (int nt = 0; nt < 4; nt++)
                    mma_bf16(acc[mt][nt], af[mt], bf[nt]);
        }
    }

    float* C = multi ? (bz == 0 ? C0 : (bz == 1 ? C1 : C2)) : C0;
    __nv_bfloat16* D = multi ? (bz == 0 ? D0 : (bz == 1 ? D1 : D2)) : D0;
    int batch4 = (mode == 4) ? (by * 128) / tokmask : 0;
    const float* TB4 = (mode == 4) ? (bz == 0 ? P1 : (bz == 1 ? P2 : bias)) : nullptr;
    const __nv_bfloat16* P1h = (const __nv_bfloat16*)P1;
    const __nv_bfloat16* P2h = (const __nv_bfloat16*)P2;
#pragma unroll
    for (int mt = 0; mt < 4; mt++) {
        int r0 = by * 128 + wm * 64 + mt * 16 + g;
#pragma unroll
        for (int nt = 0; nt < 4; nt++) {
            int col = bx * 128 + wn * 32 + nt * 8 + tq * 2;
            float b0 = 0.f, b1 = 0.f;
            if (bias && mode != 4) { b0 = bias[col]; b1 = bias[col + 1]; }
#pragma unroll
            for (int h = 0; h < 2; h++) {
                int r = r0 + h * 8;
                float t0 = acc[mt][nt][2*h + 0] + b0;
                float t1 = acc[mt][nt][2*h + 1] + b1;
                size_t i0 = (size_t)r * 256 + col;
                float o0, o1;
                if (mode == 0) {
                    o0 = t0; o1 = t1;
                } else if (mode == 1) {
                    size_t pi = (size_t)(r & tokmask) * 256 + col;
                    o0 = t0 + P1[pi]; o1 = t1 + P1[pi + 1];
                } else if (mode == 2) {
                    __nv_bfloat162 p1 = *(const __nv_bfloat162*)(P1h + i0);
                    __nv_bfloat162 p2 = *(const __nv_bfloat162*)(P2h + i0);
                    float s0 = sigf(t0), s1 = sigf(t1);
                    o0 = s0 * __bfloat162float(p1.x) + (1.f - s0) * __bfloat162float(p2.x);
                    o1 = s1 * __bfloat162float(p1.y) + (1.f - s1) * __bfloat162float(p2.y);
                } else if (mode == 3) {
                    __nv_bfloat162 p1 = *(const __nv_bfloat162*)(P1h + i0);
                    __nv_bfloat162 p2 = *(const __nv_bfloat162*)(P2h + i0);
                    o0 = __bfloat162float(p1.x) + sigf(t0) * __bfloat162float(p2.x);
                    o1 = __bfloat162float(p1.y) + sigf(t1) * __bfloat162float(p2.y);
                } else {
                    float x0 = t0 + TB4[batch4 * 256 + col];
                    float x1 = t1 + TB4[batch4 * 256 + col + 1];
                    if (bz == 0) { o0 = 1.f / (1.f + expf(x0)); o1 = 1.f / (1.f + expf(x1)); }
                    else         { o0 = sigf(x0); o1 = sigf(x1); }
                }
                if (C) *(float2*)(C + i0) = make_float2(o0, o1);
                if (D) *(__nv_bfloat162*)(D + i0) = __floats2bfloat162_rn(o0, o1);
            }
        }
    }
}

// ---------- column-mean stage A (fp32 input) ----------
__global__ void k_colmean_a(const float* __restrict__ U, float* __restrict__ part16, int chunk) {
    int j = blockIdx.x, b = blockIdx.y, c = threadIdx.x;
    const float* p = U + ((size_t)(b * gridDim.x + j) * chunk) * CDIM + c;
    float s0 = 0.f, s1 = 0.f, s2 = 0.f, s3 = 0.f;
    for (int t = 0; t < chunk; t += 4) {
        s0 += p[(size_t)t * CDIM];
        s1 += p[(size_t)(t + 1) * CDIM];
        s2 += p[(size_t)(t + 2) * CDIM];
        s3 += p[(size_t)(t + 3) * CDIM];
    }
    part16[(b * 16 + j) * 256 + c] = s0 + s1 + s2 + s3;
}

// ---------- fused mean reduce + layernorm (16 partials) ----------
__global__ void k_ctx(const float* __restrict__ part16, float inv,
                      const float* __restrict__ g, const float* __restrict__ be,
                      float* __restrict__ cln) {
    int b = blockIdx.x, c = threadIdx.x;
    __shared__ float red[256];
    float m = 0.f;
    for (int j = 0; j < 16; j++) m += part16[(b * 16 + j) * 256 + c];
    m *= inv;
    red[c] = m; __syncthreads();
    for (int s = 128; s > 0; s >>= 1) { if (c < s) red[c] += red[c + s]; __syncthreads(); }
    float mu = red[0] * (1.f / 256.f); __syncthreads();
    float d = m - mu;
    red[c] = d * d; __syncthreads();
    for (int s = 128; s > 0; s >>= 1) { if (c < s) red[c] += red[c + s]; __syncthreads(); }
    float var = red[0] * (1.f / 256.f);
    cln[b * 256 + c] = d * rsqrtf(var + LN_EPS) * g[c] + be[c];
}

// ---------- per-batch gate bias tables ----------
__global__ void k_gatebias(const float* __restrict__ cln,
                           const float* __restrict__ Wf, const float* __restrict__ bf,
                           const float* __restrict__ Ww, const float* __restrict__ bw,
                           const float* __restrict__ Wo, const float* __restrict__ bo,
                           float* __restrict__ fb, float* __restrict__ wb, float* __restrict__ ob) {
    int which = blockIdx.x, b = blockIdx.y, c = threadIdx.x;
    __shared__ float sc[256];
    sc[c] = cln[b * 256 + c]; __syncthreads();
    const float* W  = (which == 0) ? Wf : (which == 1) ? Ww : Wo;
    const float* bi = (which == 0) ? bf : (which == 1) ? bw : bo;
    float* o        = (which == 0) ? fb : (which == 1) ? wb : ob;
    float acc = bi[c];
    for (int k = 0; k < 256; k++) acc += sc[k] * W[(size_t)(256 + k) * 256 + c];
    o[b * 256 + c] = acc;
}

// ---------- scan phase 1 (bf16x2 vectorized: 128 threads, 2 ch/thread) ----------
__global__ void k_scan1(const __nv_bfloat16* __restrict__ GA, const __nv_bfloat16* __restrict__ GB,
                        const __nv_bfloat16* __restrict__ U,
                        float* __restrict__ AGA, float* __restrict__ ABF, float* __restrict__ ABB) {
    int j = blockIdx.x, b = blockIdx.y;
    int c = threadIdx.x * 2;
    size_t base = ((size_t)b * NTOK + j * 128) * CDIM + c;
    float A0 = 1.f, A1 = 1.f, sf0 = 0.f, sf1 = 0.f;
    for (int t = 0; t < 128; t++) {
        size_t i = base + (size_t)t * CDIM;
        __nv_bfloat162 a2 = *(const __nv_bfloat162*)(GA + i);
        __nv_bfloat162 g2 = *(const __nv_bfloat162*)(GB + i);
        __nv_bfloat162 u2 = *(const __nv_bfloat162*)(U + i);
        float a0 = __bfloat162float(a2.x), a1 = __bfloat162float(a2.y);
        float b0 = (1.f - a0) * __bfloat162float(g2.x) * __bfloat162float(u2.x);
        float b1 = (1.f - a1) * __bfloat162float(g2.y) * __bfloat162float(u2.y);
        A0 *= a0; A1 *= a1;
        sf0 = a0 * sf0 + b0; sf1 = a1 * sf1 + b1;
    }
    float sb0 = 0.f, sb1 = 0.f;
    for (int t = 127; t >= 0; t--) {
        size_t i = base + (size_t)t * CDIM;
        __nv_bfloat162 a2 = *(const __nv_bfloat162*)(GA + i);
        __nv_bfloat162 g2 = *(const __nv_bfloat162*)(GB + i);
        __nv_bfloat162 u2 = *(const __nv_bfloat162*)(U + i);
        float a0 = __bfloat162float(a2.x), a1 = __bfloat162float(a2.y);
        float b0 = (1.f - a0) * __bfloat162float(g2.x) * __bfloat162float(u2.x);
        float b1 = (1.f - a1) * __bfloat162float(g2.y) * __bfloat162float(u2.y);
        sb0 = a0 * sb0 + b0; sb1 = a1 * sb1 + b1;
    }
    int o = (b * 32 + j) * 256 + c;
    *(float2*)(AGA + o) = make_float2(A0, A1);
    *(float2*)(ABF + o) = make_float2(sf0, sf1);
    *(float2*)(ABB + o) = make_float2(sb0, sb1);
}

// ---------- scan phase 2 ----------
__global__ void k_scan2(const float* __restrict__ AGA, const float* __restrict__ ABF,
                        const float* __restrict__ ABB, float* __restrict__ SIF, float* __restrict__ SIB) {
    int b = blockIdx.x, c = threadIdx.x;
    float s = 0.f;
    for (int j = 0; j < 32; j++) {
        int o = (b * 32 + j) * 256 + c;
        SIF[o] = s; s = AGA[o] * s + ABF[o];
    }
    s = 0.f;
    for (int j = 31; j >= 0; j--) {
        int o = (b * 32 + j) * 256 + c;
        SIB[o] = s; s = AGA[o] * s + ABB[o];
    }
}

// ---------- scan phase 3 (bf16x2 vectorized) ----------
__global__ void k_scan3(const __nv_bfloat16* __restrict__ GA, const __nv_bfloat16* __restrict__ GB,
                        const __nv_bfloat16* __restrict__ GO, const __nv_bfloat16* __restrict__ U,
                        const float* __restrict__ SIF, const float* __restrict__ SIB,
                        __nv_bfloat16* __restrict__ YF16, __nv_bfloat16* __restrict__ YB16) {
    int j = blockIdx.x, b = blockIdx.y;
    int c = threadIdx.x * 2;
    size_t base = ((size_t)b * NTOK + j * 128) * CDIM + c;
    int ao = (b * 32 + j) * 256 + c;
    float2 sfi = *(const float2*)(SIF + ao);
    float s0 = sfi.x, s1 = sfi.y;
    for (int t = 0; t < 128; t++) {
        size_t i = base + (size_t)t * CDIM;
        __nv_bfloat162 a2 = *(const __nv_bfloat162*)(GA + i);
        __nv_bfloat162 g2 = *(const __nv_bfloat162*)(GB + i);
        __nv_bfloat162 o2 = *(const __nv_bfloat162*)(GO + i);
        __nv_bfloat162 u2 = *(const __nv_bfloat162*)(U + i);
        float a0 = __bfloat162float(a2.x), a1 = __bfloat162float(a2.y);
        float u0 = __bfloat162float(u2.x), u1 = __bfloat162float(u2.y);
        s0 = a0 * s0 + (1.f - a0) * __bfloat162float(g2.x) * u0;
        s1 = a1 * s1 + (1.f - a1) * __bfloat162float(g2.y) * u1;
        float o0 = __bfloat162float(o2.x), o1 = __bfloat162float(o2.y);
        *(__nv_bfloat162*)(YF16 + i) =
            __floats2bfloat162_rn(o0 * s0 + (1.f - o0) * u0, o1 * s1 + (1.f - o1) * u1);
    }
    float2 sbi = *(const float2*)(SIB + ao);
    s0 = sbi.x; s1 = sbi.y;
    for (int t = 127; t >= 0; t--) {
        size_t i = base + (size_t)t * CDIM;
        __nv_bfloat162 a2 = *(const __nv_bfloat162*)(GA + i);
        __nv_bfloat162 g2 = *(const __nv_bfloat162*)(GB + i);
        __nv_bfloat162 o2 = *(const __nv_bfloat162*)(GO + i);
        __nv_bfloat162 u2 = *(const __nv_bfloat162*)(U + i);
        float a0 = __bfloat162float(a2.x), a1 = __bfloat162float(a2.y);
        float u0 = __bfloat162float(u2.x), u1 = __bfloat162float(u2.y);
        s0 = a0 * s0 + (1.f - a0) * __bfloat162float(g2.x) * u0;
        s1 = a1 * s1 + (1.f - a1) * __bfloat162float(g2.y) * u1;
        float o0 = __bfloat162float(o2.x), o1 = __bfloat162float(o2.y);
        *(__nv_bfloat162*)(YB16 + i) =
            __floats2bfloat162_rn(o0 * s0 + (1.f - o0) * u0, o1 * s1 + (1.f - o1) * u1);
    }
}

// ---------- global branch serial scan ----------
__global__ void k_scanglob(const float* __restrict__ GA, const float* __restrict__ GB,
                           const float* __restrict__ GO, const float* __restrict__ U,
                           float* __restrict__ YG) {
    int b = blockIdx.x, c = threadIdx.x;
    size_t base = (size_t)b * NTOKG * CDIM + c;
    float s = 0.f;
    for (int t = 0; t < NTOKG; t++) {
        size_t i = base + (size_t)t * CDIM;
        float a = GA[i], u = U[i];
        float bb = (1.f - a) * GB[i] * u;
        s = a * s + bb;
        float o = GO[i];
        YG[i] = o * s + (1.f - o) * u;
    }
}

// ---------- 4x4 avg pool (bf16 input) ----------
__global__ void k_pool(const __nv_bfloat16* __restrict__ seq16, float* __restrict__ seqg) {
    int tg = blockIdx.x, b = blockIdx.y, c = threadIdx.x;
    int gh = tg / 16, gw = tg % 16;
    float s = 0.f;
#pragma unroll
    for (int i = 0; i < 4; i++)
#pragma unroll
        for (int j = 0; j < 4; j++)
            s += __bfloat162float(seq16[((size_t)b * NTOK + (gh * 4 + i) * 64 + gw * 4 + j) * CDIM + c]);
    seqg[((size_t)b * NTOKG + tg) * CDIM + c] = s * (1.0f / 16.0f);
}

// ---------- bilinear upsample (bf16 output only) ----------
__global__ void k_upsample(const float* __restrict__ YG, __nv_bfloat16* __restrict__ YGS16) {
    int t = blockIdx.x, b = blockIdx.y, c = threadIdx.x;
    int oh = t / 64, ow = t % 64;
    float sy = (oh + 0.5f) * 0.25f - 0.5f;
    float sx = (ow + 0.5f) * 0.25f - 0.5f;
    int y0 = (int)floorf(sy); float fy = sy - y0;
    int x0 = (int)floorf(sx); float fx = sx - x0;
    int y0c = clampi(y0, 0, 15), y1c = clampi(y0 + 1, 0, 15);
    int x0c = clampi(x0, 0, 15), x1c = clampi(x0 + 1, 0, 15);
    const float* base = YG + (size_t)b * NTOKG * CDIM + c;
    float v00 = base[(size_t)(y0c * 16 + x0c) * CDIM];
    float v01 = base[(size_t)(y0c * 16 + x1c) * CDIM];
    float v10 = base[(size_t)(y1c * 16 + x0c) * CDIM];
    float v11 = base[(size_t)(y1c * 16 + x1c) * CDIM];
    float v = (1.f - fy) * ((1.f - fx) * v00 + fx * v01) + fy * ((1.f - fx) * v10 + fx * v11);
    YGS16[((size_t)b * NTOK + t) * CDIM + c] = __float2bfloat16_rn(v);
}

// ---------- depthwise 3x3 conv, sliding window (bf16 in/out) ----------
__global__ void k_dwconv(const __nv_bfloat16* __restrict__ seq16, const float* __restrict__ w,
                         const float* __restrict__ bias, __nv_bfloat16* __restrict__ VM16) {
    int h = blockIdx.x, b = blockIdx.y, c = threadIdx.x;
    float wr[9];
#pragma unroll
    for (int k = 0; k < 9; k++) wr[k] = w[c * 9 + k];
    float bi = bias[c];
    const __nv_bfloat16* sp = seq16 + (size_t)b * NTOK * CDIM + c;
    bool h0ok = (h - 1) >= 0, h2ok = (h + 1) < 64;
    size_t r0 = (size_t)(h - 1) * 64, r1 = (size_t)h * 64, r2 = (size_t)(h + 1) * 64;
    float m0 = 0.f, m1 = 0.f, m2 = 0.f;
    float c0 = h0ok ? __bfloat162float(sp[(r0 + 0) * CDIM]) : 0.f;
    float c1 = __bfloat162float(sp[(r1 + 0) * CDIM]);
    float c2 = h2ok ? __bfloat162float(sp[(r2 + 0) * CDIM]) : 0.f;
    float n0 = h0ok ? __bfloat162float(sp[(r0 + 1) * CDIM]) : 0.f;
    float n1 = __bfloat162float(sp[(r1 + 1) * CDIM]);
    float n2 = h2ok ? __bfloat162float(sp[(r2 + 1) * CDIM]) : 0.f;
    size_t obase = ((size_t)b * NTOK + (size_t)h * 64) * CDIM + c;
    for (int x = 0; x < 64; x++) {
        float acc = bi
            + wr[0] * m0 + wr[1] * c0 + wr[2] * n0
            + wr[3] * m1 + wr[4] * c1 + wr[5] * n1
            + wr[6] * m2 + wr[7] * c2 + wr[8] * n2;
        VM16[obase + (size_t)x * CDIM] = __float2bfloat16_rn(acc);
        m0 = c0; m1 = c1; m2 = c2;
        c0 = n0; c1 = n1; c2 = n2;
        if (x + 2 < 64) {
            n0 = h0ok ? __bfloat162float(sp[(r0 + x + 2) * CDIM]) : 0.f;
            n1 = __bfloat162float(sp[(r1 + x + 2) * CDIM]);
            n2 = h2ok ? __bfloat162float(sp[(r2 + x + 2) * CDIM]) : 0.f;
        } else { n0 = n1 = n2 = 0.f; }
    }
}

extern "C" void kernel_launch(void* const* d_in, const int* in_sizes, int n_in,
                              void* d_out, int out_size) {
    const float* x        = (const float*)d_in[0];
    const float* Wt       = (const float*)d_in[1];
    const float* bt       = (const float*)d_in[2];
    const float* pos_fine = (const float*)d_in[3];
    const float* pos_glob = (const float*)d_in[4];
    const float* ln_g     = (const float*)d_in[5];
    const float* ln_b     = (const float*)d_in[6];
    const float* Wf       = (const float*)d_in[7];
    const float* bf       = (const float*)d_in[8];
    const float* Ww       = (const float*)d_in[9];
    const float* bw       = (const float*)d_in[10];
    const float* Wo       = (const float*)d_in[11];
    const float* bo       = (const float*)d_in[12];
    const float* Wr       = (const float*)d_in[13];
    const float* br       = (const float*)d_in[14];
    const float* Wgi      = (const float*)d_in[15];
    const float* bgi      = (const float*)d_in[16];
    const float* dw_w     = (const float*)d_in[17];
    const float* dw_b     = (const float*)d_in[18];
    const float* Wl       = (const float*)d_in[19];
    const float* bl       = (const float*)d_in[20];
    const float* Wlf      = (const float*)d_in[21];
    const float* blf      = (const float*)d_in[22];
    const float* Wout     = (const float*)d_in[23];
    const float* bout     = (const float*)d_in[24];
    float* outp = (float*)d_out;

    float* S = nullptr;
    cudaGetSymbolAddress((void**)&S, g_scratch);
    float* PROJ = S + OFF_PROJ;
    float* SEQG = S + OFF_SEQG; float* UG   = S + OFF_UG;
    float* GAG  = S + OFF_GAG;  float* GBG  = S + OFF_GBG;  float* GOG = S + OFF_GOG;
    float* YG   = S + OFF_YG;
    float* POSF = S + OFF_POSF; float* POSG = S + OFF_POSG;
    float* CLN  = S + OFF_CLN;  float* CLNG = S + OFF_CLNG;
    float* FB = S + OFF_FB, *WB = S + OFF_WB, *OB = S + OFF_OB;
    float* FBG = S + OFF_FBG, *WBG = S + OFF_WBG, *OBG = S + OFF_OBG;
    float* AGA = S + OFF_AGA, *ABF = S + OFF_ABF, *ABB = S + OFF_ABB;
    float* SIF = S + OFF_SIF, *SIB = S + OFF_SIB;
    float* P16 = S + OFF_P16;   float* P16G = S + OFF_P16G;
    float* MSEQ = S + OFF_MSEQ; float* PART = S + OFF_PART;
    uint32_t* WBW = (uint32_t*)(S + OFF_WBW);
    __nv_bfloat16* U16   = (__nv_bfloat16*)(S + OFF_U16);
    __nv_bfloat16* YF16  = (__nv_bfloat16*)(S + OFF_YF16);
    __nv_bfloat16* YB16  = (__nv_bfloat16*)(S + OFF_YB16);
    __nv_bfloat16* Y16   = (__nv_bfloat16*)(S + OFF_Y16);
    __nv_bfloat16* YGS16 = (__nv_bfloat16*)(S + OFF_YGS16);
    __nv_bfloat16* V16   = (__nv_bfloat16*)(S + OFF_V16);
    __nv_bfloat16* Z16   = (__nv_bfloat16*)(S + OFF_Z16);
    __nv_bfloat16* SEQ16 = (__nv_bfloat16*)(S + OFF_SEQ16);
    __nv_bfloat16* VM16  = (__nv_bfloat16*)(S + OFF_VM16);
    __nv_bfloat16* UO16  = (__nv_bfloat16*)(S + OFF_UO16);
    __nv_bfloat16* GA16  = (__nv_bfloat16*)(S + OFF_GA16);
    __nv_bfloat16* GB16  = (__nv_bfloat16*)(S + OFF_GB16);
    __nv_bfloat16* GO16  = (__nv_bfloat16*)(S + OFF_GO16);

    uint32_t* WBf  = WBW + (size_t)0    * 256;
    uint32_t* WBw  = WBW + (size_t)128  * 256;
    uint32_t* WBo  = WBW + (size_t)256  * 256;
    uint32_t* WBr0 = WBW + (size_t)384  * 256;
    uint32_t* WBr1 = WBW + (size_t)512  * 256;
    uint32_t* WBr2 = WBW + (size_t)640  * 256;
    uint32_t* WBg0 = WBW + (size_t)768  * 256;
    uint32_t* WBg1 = WBW + (size_t)896  * 256;
    uint32_t* WBg2 = WBW + (size_t)1024 * 256;
    uint32_t* WBl0 = WBW + (size_t)1152 * 256;
    uint32_t* WBl1 = WBW + (size_t)1280 * 256;
    uint32_t* WBt  = WBW + (size_t)1408 * 256;
    uint32_t* WBl  = WBW + (size_t)1536 * 256;
    uint32_t* WBout= WBW + (size_t)1664 * 256;

    static int init_done = 0;
    static cudaStream_t s2, s3, s4;
    static cudaEvent_t ev0, ev1, ev2, ev3, evCtx;
    int smem_tf = NSTAGE * STAGE_ELEMS * 4;
    int smem_bf = NSTB * BSTG_EL * 4;
    if (!init_done) {
        cudaFuncSetAttribute(k_gemm_tc, cudaFuncAttributeMaxDynamicSharedMemorySize, smem_tf);
        cudaFuncSetAttribute(k_gemm_bf, cudaFuncAttributeMaxDynamicSharedMemorySize, smem_bf);
        cudaStreamCreateWithFlags(&s2, cudaStreamNonBlocking);
        cudaStreamCreateWithFlags(&s3, cudaStreamNonBlocking);
        cudaStreamCreateWithFlags(&s4, cudaStreamNonBlocking);
        cudaEventCreateWithFlags(&ev0, cudaEventDisableTiming);
        cudaEventCreateWithFlags(&ev1, cudaEventDisableTiming);
        cudaEventCreateWithFlags(&ev2, cudaEventDisableTiming);
        cudaEventCreateWithFlags(&ev3, cudaEventDisableTiming);
        cudaEventCreateWithFlags(&evCtx, cudaEventDisableTiming);
        init_done = 1;
    }

    dim3 tb(32, 8);
    dim3 tg(128, 8, 8);
    dim3 gemF(2, MFINE / 128), gemG(2, MGLOB / 128);
    dim3 gemG3(2, MGLOB / 128, 3), gemF3(2, MFINE / 128, 3);
    const float* NP = nullptr;
    float* NPo = nullptr;
    __nv_bfloat16* NPh = nullptr;
    const __nv_bfloat16* NPhc = nullptr;
    const uint32_t* NPw = nullptr;

    // ---- context precompute starts immediately on s4 (needs only x) ----
    k_meanx<<<dim3(CDIM, BATCH), 256, 0, s4>>>(x, MSEQ);

    // prep: transpose (both paths), posdown (global), then fork
    k_transpose<<<tg, tb>>>(x, SEQ16);
    k_posdown<<<256, 256>>>(pos_glob, POSG);
    cudaEventRecord(ev0, 0);

    // ---- global branch on s2 ----
    cudaStreamWaitEvent(s2, ev0, 0);
    k_pool<<<dim3(256, BATCH), 256, 0, s2>>>(SEQ16, SEQG);
    k_gemm_tc<<<gemG, 256, smem_tf, s2>>>(SEQG, Wt, NP, NP, NP, NP, 1, UG, NPo, NPo, bt, 1, POSG, NP, 255, 0, NPh);
    k_colmean_a<<<dim3(16, BATCH), 256, 0, s2>>>(UG, P16G, 16);
    k_ctx<<<BATCH, 256, 0, s2>>>(P16G, 1.0f / NTOKG, ln_g, ln_b, CLNG);
    k_gatebias<<<dim3(3, BATCH), 256, 0, s2>>>(CLNG, Wf, bf, Ww, bw, Wo, bo, FBG, WBG, OBG);
    k_gemm_tc<<<gemG3, 256, smem_tf, s2>>>(UG, Wf, NP, Ww, NP, Wo, 1, GAG, GBG, GOG, OBG, 4, FBG, WBG, NTOKG, 1, NPh);
    k_scanglob<<<BATCH, 256, 0, s2>>>(GAG, GBG, GOG, UG, YG);
    k_upsample<<<dim3(4096, BATCH), 256, 0, s2>>>(YG, YGS16);
    cudaEventRecord(ev1, s2);

    // ---- local branch on s3 ----
    cudaStreamWaitEvent(s3, ev0, 0);
    k_dwconv<<<dim3(64, BATCH), 256, 0, s3>>>(SEQ16, dw_w, dw_b, VM16);

    // ---- fine path on stream 0 ----
    k_wcvt<<<1792, 256>>>(Wf, Ww, Wo, Wr, Wgi, Wlf, Wt, Wl, Wout, WBW);
    k_posup<<<4096, 256>>>(pos_fine, POSF, 64, 64);
    cudaEventRecord(ev3, 0);

    // V-GEMM on s3 (needs WBl from wcvt)
    cudaStreamWaitEvent(s3, ev3, 0);
    k_gemm_bf<<<gemF, 256, smem_bf, s3>>>(VM16, WBl, NPhc, NPw, NPhc, NPw, 1, NPo, NPo, NPo, bl, 0, NP, NP, 0, 0, V16, NPh, NPh);
    cudaEventRecord(ev2, s3);

    // ---- context chain on s4 (hides under U-GEMM): posmean -> part -> LN -> gatebias ----
    cudaStreamWaitEvent(s4, ev3, 0);
    k_colmean_a<<<dim3(16, 1), 256, 0, s4>>>(POSF, P16, 256);
    k_part<<<BATCH, 256, 0, s4>>>(MSEQ, Wt, bt, P16, PART);
    k_ln<<<BATCH, 256, 0, s4>>>(PART, ln_g, ln_b, CLN);
    k_gatebias<<<dim3(3, BATCH), 256, 0, s4>>>(CLN, Wf, bf, Ww, bw, Wo, bo, FB, WB, OB);
    cudaEventRecord(evCtx, s4);

    // U = SEQ@Wt + bt + pos -> U16 (overlaps with s4 context chain)
    k_gemm_bf<<<gemF, 256, smem_bf>>>(SEQ16, WBt, NPhc, NPw, NPhc, NPw, 1, NPo, NPo, NPo, bt, 1, POSF, NP, 4095, 0, U16, NPh, NPh);

    // gates: mode 4 -> bf16 mirrors (waits on context tables)
    cudaStreamWaitEvent(0, evCtx, 0);
    k_gemm_bf<<<gemF3, 256, smem_bf>>>(U16, WBf, NPhc, WBw, NPhc, WBo, 1, NPo, NPo, NPo, OB, 4, FB, WB, NTOK, 1, GA16, GB16, GO16);

    // bidirectional chunked scan (bf16x2 vectorized)
    k_scan1<<<dim3(32, BATCH), 128>>>(GA16, GB16, U16, AGA, ABF, ABB);
    k_scan2<<<BATCH, 256>>>(AGA, ABF, ABB, SIF, SIB);
    k_scan3<<<dim3(32, BATCH), 128>>>(GA16, GB16, GO16, U16, SIF, SIB, YF16, YB16);

    // rho mixing -> Y16
    k_gemm_bf<<<gemF, 256, smem_bf>>>(U16, WBr0, YF16, WBr1, YB16, WBr2, 3, NPo, NPo, NPo, br, 2,
                                      (const float*)YF16, (const float*)YB16, 0, 0, Y16, NPh, NPh);

    // join global branch; lam mixing -> Z16
    cudaStreamWaitEvent(0, ev1, 0);
    k_gemm_bf<<<gemF, 256, smem_bf>>>(Y16, WBg0, YGS16, WBg1, U16, WBg2, 3, NPo, NPo, NPo, bgi, 3,
                                      (const float*)Y16, (const float*)YGS16, 0, 0, Z16, NPh, NPh);

    // join local branch; eta -> UO16
    cudaStreamWaitEvent(0, ev2, 0);
    k_gemm_bf<<<gemF, 256, smem_bf>>>(V16, WBl0, Z16, WBl1, NPhc, NPw, 2, NPo, NPo, NPo, blf, 2,
                                      (const float*)V16, (const float*)Z16, 0, 0, UO16, NPh, NPh);

    // output proj + residual
    k_gemm_bf<<<gemF, 256, smem_bf>>>(UO16, WBout, NPhc, NPw, NPhc, NPw, 1, PROJ, NPo, NPo, bout, 0, NP, NP, 0, 0, NPh, NPh, NPh);
    k_output<<<tg, tb>>>(PROJ, x, outp);
}